// round 1
// baseline (speedup 1.0000x reference)
#include <cuda_runtime.h>
#include <math.h>
#include <math_constants.h>

#define BB   4
#define SS   2048
#define DM   1024
#define NH   16
#define DH   64
#define DFF  4096
#define MTOK (BB*SS)    // 8192 tokens
#define QPB  16         // queries per attention block (1 per warp)

// ---------------- scratch (allocation-free: __device__ globals) ----------------
static __device__ float g_xnorm[MTOK*DM];
static __device__ float g_q    [MTOK*DM];
static __device__ float g_k    [MTOK*DM];
static __device__ float g_v    [MTOK*DM];
static __device__ float g_attn [MTOK*DM];
static __device__ float g_res1 [MTOK*DM];
static __device__ float g_hnorm[MTOK*DM];
static __device__ float g_ff1  [(size_t)MTOK*DFF];
static __device__ float g_ff3  [(size_t)MTOK*DFF];

// ---------------- RMSNorm: one block per row (D=1024, 256 thr * float4) --------
__global__ void rmsnorm_kernel(const float* __restrict__ x,
                               const float* __restrict__ g,
                               float* __restrict__ y) {
    const int row = blockIdx.x;
    const float4* xr = (const float4*)(x + (size_t)row * DM);
    float4*       yr = (float4*)(y + (size_t)row * DM);
    const int t = threadIdx.x;           // 256 threads * 4 = 1024
    float4 xv = xr[t];
    float ss = xv.x*xv.x + xv.y*xv.y + xv.z*xv.z + xv.w*xv.w;
    #pragma unroll
    for (int o = 16; o; o >>= 1) ss += __shfl_xor_sync(0xffffffffu, ss, o);
    __shared__ float sred[8];
    const int warp = t >> 5, lane = t & 31;
    if (lane == 0) sred[warp] = ss;
    __syncthreads();
    if (warp == 0) {
        float v = (lane < 8) ? sred[lane] : 0.f;
        #pragma unroll
        for (int o = 4; o; o >>= 1) v += __shfl_xor_sync(0xffffffffu, v, o);
        if (lane == 0) sred[0] = v;
    }
    __syncthreads();
    const float inv = rsqrtf(sred[0] * (1.0f/(float)DM) + 1e-5f);
    const float4 gv = ((const float4*)g)[t];
    float4 o4;
    o4.x = xv.x*inv*gv.x; o4.y = xv.y*inv*gv.y;
    o4.z = xv.z*inv*gv.z; o4.w = xv.w*inv*gv.w;
    yr[t] = o4;
}

// ---------------- RoPE on Q and K in-place (pairs) ------------------------------
__global__ void rope_kernel(float* __restrict__ Q, float* __restrict__ Kd,
                            const int* __restrict__ pos) {
    const int idx = blockIdx.x * blockDim.x + threadIdx.x;  // MTOK*NH*32
    if (idx >= MTOK*NH*32) return;
    const int i = idx & 31;            // pair index within head
    const int h = (idx >> 5) & (NH-1);
    const int m = idx >> 9;            // token
    const int s = m & (SS-1);
    const float p = (float)pos[s];
    const float inv = 1.0f / powf(10000.0f, (float)(2*i) * (1.0f/(float)DH));
    const float ang = p * inv;
    float sn, cs;
    sincosf(ang, &sn, &cs);
    const size_t base = (size_t)m * DM + h*DH + 2*i;
    float qe = Q[base], qo = Q[base+1];
    Q[base]   = qe*cs - qo*sn;
    Q[base+1] = qe*sn + qo*cs;
    float ke = Kd[base], ko = Kd[base+1];
    Kd[base]   = ke*cs - ko*sn;
    Kd[base+1] = ke*sn + ko*cs;
}

// ---------------- SGEMM NT: C[M,N] = A[M,K] * B[N,K]^T (+ optional R) -----------
// 128x128 block tile, BK=8, 256 threads, 8x8 per-thread register tile.
__global__ __launch_bounds__(256)
void sgemm_nt_kernel(const float* __restrict__ A, const float* __restrict__ B,
                     const float* __restrict__ R, float* __restrict__ C,
                     int M, int N, int K) {
    __shared__ float As[8][128];
    __shared__ float Bs[8][128];
    const int tid = threadIdx.x;
    const int bm = blockIdx.y * 128;
    const int bn = blockIdx.x * 128;
    const int lr = tid >> 1;            // 0..127 load row
    const int lc = (tid & 1) << 2;      // 0 or 4 (float4 col)
    const int ty = (tid >> 4) << 3;     // 0..120 step 8
    const int tx = (tid & 15) << 3;     // 0..120 step 8
    const float* Ap = A + (size_t)(bm + lr) * K + lc;
    const float* Bp = B + (size_t)(bn + lr) * K + lc;

    float acc[8][8];
    #pragma unroll
    for (int i = 0; i < 8; i++)
        #pragma unroll
        for (int j = 0; j < 8; j++) acc[i][j] = 0.f;

    for (int k0 = 0; k0 < K; k0 += 8) {
        const float4 a4 = *(const float4*)(Ap + k0);
        const float4 b4 = *(const float4*)(Bp + k0);
        As[lc+0][lr] = a4.x; As[lc+1][lr] = a4.y; As[lc+2][lr] = a4.z; As[lc+3][lr] = a4.w;
        Bs[lc+0][lr] = b4.x; Bs[lc+1][lr] = b4.y; Bs[lc+2][lr] = b4.z; Bs[lc+3][lr] = b4.w;
        __syncthreads();
        #pragma unroll
        for (int kk = 0; kk < 8; kk++) {
            float ar[8], br[8];
            *(float4*)(ar)   = *(const float4*)&As[kk][ty];
            *(float4*)(ar+4) = *(const float4*)&As[kk][ty+4];
            *(float4*)(br)   = *(const float4*)&Bs[kk][tx];
            *(float4*)(br+4) = *(const float4*)&Bs[kk][tx+4];
            #pragma unroll
            for (int i = 0; i < 8; i++)
                #pragma unroll
                for (int j = 0; j < 8; j++)
                    acc[i][j] = fmaf(ar[i], br[j], acc[i][j]);
        }
        __syncthreads();
    }

    #pragma unroll
    for (int i = 0; i < 8; i++) {
        const size_t row = (size_t)(bm + ty + i);
        float* cp = C + row * N + bn + tx;
        float4 c0 = make_float4(acc[i][0], acc[i][1], acc[i][2], acc[i][3]);
        float4 c1 = make_float4(acc[i][4], acc[i][5], acc[i][6], acc[i][7]);
        if (R) {
            const float* rp = R + row * N + bn + tx;
            const float4 r0 = *(const float4*)rp;
            const float4 r1 = *(const float4*)(rp + 4);
            c0.x += r0.x; c0.y += r0.y; c0.z += r0.z; c0.w += r0.w;
            c1.x += r1.x; c1.y += r1.y; c1.z += r1.z; c1.w += r1.w;
        }
        *(float4*)cp       = c0;
        *(float4*)(cp + 4) = c1;
    }
}

// ---------------- Causal attention (flash-style online softmax) -----------------
// Layout of Q/K/V/O: [B, S, H, DH] (= [MTOK, DM] with head offset h*64).
// Block: 512 thr = 16 warps, one query per warp; K/V tiles of 64 keys in smem.
__global__ __launch_bounds__(512)
void attn_kernel(const float* __restrict__ Q, const float* __restrict__ K,
                 const float* __restrict__ V, float* __restrict__ O) {
    __shared__ float Ks[64][65];
    __shared__ float Vs[64][65];
    __shared__ float Qs[QPB][64];
    __shared__ float Ps[QPB][64];

    const int bh   = blockIdx.y;
    const int b    = bh >> 4, h = bh & (NH-1);
    const int q0   = blockIdx.x * QPB;
    const int warp = threadIdx.x >> 5, lane = threadIdx.x & 31;
    const int q    = q0 + warp;
    const size_t base = ((size_t)b * SS) * DM + h * DH;

    // stage the block's Q rows
    for (int i = threadIdx.x; i < QPB*16; i += 512) {
        const int r = i >> 4, c4 = (i & 15) << 2;
        *(float4*)&Qs[r][c4] = *(const float4*)(Q + base + (size_t)(q0 + r) * DM + c4);
    }

    float m = -CUDART_INF_F, l = 0.f, acc0 = 0.f, acc1 = 0.f;
    const int ntiles = ((q0 + QPB - 1) >> 6) + 1;

    for (int t = 0; t < ntiles; t++) {
        const int k0 = t << 6;
        __syncthreads();   // tiles free to overwrite (also orders Qs writes at t=0)
        for (int i = threadIdx.x; i < 64*16; i += 512) {
            const int r = i >> 4, c4 = (i & 15) << 2;
            const float4 kv = *(const float4*)(K + base + (size_t)(k0 + r) * DM + c4);
            Ks[r][c4] = kv.x; Ks[r][c4+1] = kv.y; Ks[r][c4+2] = kv.z; Ks[r][c4+3] = kv.w;
            const float4 vv = *(const float4*)(V + base + (size_t)(k0 + r) * DM + c4);
            Vs[r][c4] = vv.x; Vs[r][c4+1] = vv.y; Vs[r][c4+2] = vv.z; Vs[r][c4+3] = vv.w;
        }
        __syncthreads();

        // scores: this warp's query vs keys k0+lane, k0+lane+32
        float s0 = 0.f, s1 = 0.f;
        #pragma unroll
        for (int d = 0; d < 64; d++) {
            const float qd = Qs[warp][d];
            s0 = fmaf(qd, Ks[lane][d],      s0);
            s1 = fmaf(qd, Ks[lane + 32][d], s1);
        }
        s0 *= 0.125f; s1 *= 0.125f;   // 1/sqrt(64)
        const bool msk0 = (k0 + lane)      > q;
        const bool msk1 = (k0 + lane + 32) > q;
        if (msk0) s0 = -CUDART_INF_F;
        if (msk1) s1 = -CUDART_INF_F;

        float tmax = fmaxf(s0, s1);
        #pragma unroll
        for (int o = 16; o; o >>= 1) tmax = fmaxf(tmax, __shfl_xor_sync(0xffffffffu, tmax, o));
        const float nm   = fmaxf(m, tmax);         // finite after tile 0
        const float corr = __expf(m - nm);         // 0 on first tile (m = -inf)
        acc0 *= corr; acc1 *= corr; l *= corr;

        const float p0 = msk0 ? 0.f : __expf(s0 - nm);
        const float p1 = msk1 ? 0.f : __expf(s1 - nm);
        m = nm;
        float ps = p0 + p1;
        #pragma unroll
        for (int o = 16; o; o >>= 1) ps += __shfl_xor_sync(0xffffffffu, ps, o);
        l += ps;
        Ps[warp][lane] = p0; Ps[warp][lane + 32] = p1;
        __syncwarp();

        #pragma unroll 8
        for (int j = 0; j < 64; j++) {
            const float p = Ps[warp][j];
            acc0 = fmaf(p, Vs[j][lane],      acc0);
            acc1 = fmaf(p, Vs[j][lane + 32], acc1);
        }
    }

    const float invl = 1.0f / l;
    O[base + (size_t)q * DM + lane]      = acc0 * invl;
    O[base + (size_t)q * DM + lane + 32] = acc1 * invl;
}

// ---------------- SwiGLU elementwise: a = silu(a) * g ---------------------------
__global__ void swiglu_kernel(float* __restrict__ a, const float* __restrict__ g, int n4) {
    const int i = blockIdx.x * blockDim.x + threadIdx.x;
    if (i >= n4) return;
    float4 av = ((const float4*)a)[i];
    const float4 gv = ((const float4*)g)[i];
    av.x = av.x / (1.f + __expf(-av.x)) * gv.x;
    av.y = av.y / (1.f + __expf(-av.y)) * gv.y;
    av.z = av.z / (1.f + __expf(-av.z)) * gv.z;
    av.w = av.w / (1.f + __expf(-av.w)) * gv.w;
    ((float4*)a)[i] = av;
}

// ---------------- launch ---------------------------------------------------------
extern "C" void kernel_launch(void* const* d_in, const int* in_sizes, int n_in,
                              void* d_out, int out_size) {
    const float* x   = (const float*)d_in[0];
    const int*   pos = (const int*)  d_in[1];
    const float* qw  = (const float*)d_in[2];
    const float* kw  = (const float*)d_in[3];
    const float* vw  = (const float*)d_in[4];
    const float* ow  = (const float*)d_in[5];
    const float* g1  = (const float*)d_in[6];
    const float* g2  = (const float*)d_in[7];
    const float* w1  = (const float*)d_in[8];
    const float* w2  = (const float*)d_in[9];
    const float* w3  = (const float*)d_in[10];
    float* out = (float*)d_out;

    float *xnorm, *q, *k, *v, *attn, *res1, *hnorm, *ff1, *ff3;
    cudaGetSymbolAddress((void**)&xnorm, g_xnorm);
    cudaGetSymbolAddress((void**)&q,     g_q);
    cudaGetSymbolAddress((void**)&k,     g_k);
    cudaGetSymbolAddress((void**)&v,     g_v);
    cudaGetSymbolAddress((void**)&attn,  g_attn);
    cudaGetSymbolAddress((void**)&res1,  g_res1);
    cudaGetSymbolAddress((void**)&hnorm, g_hnorm);
    cudaGetSymbolAddress((void**)&ff1,   g_ff1);
    cudaGetSymbolAddress((void**)&ff3,   g_ff3);

    // 1) x_norm = rmsnorm(x, g1)
    rmsnorm_kernel<<<MTOK, 256>>>(x, g1, xnorm);

    // 2) Q,K,V projections
    dim3 gqkv(DM/128, MTOK/128);
    sgemm_nt_kernel<<<gqkv, 256>>>(xnorm, qw, nullptr, q, MTOK, DM, DM);
    sgemm_nt_kernel<<<gqkv, 256>>>(xnorm, kw, nullptr, k, MTOK, DM, DM);
    sgemm_nt_kernel<<<gqkv, 256>>>(xnorm, vw, nullptr, v, MTOK, DM, DM);

    // 3) RoPE on Q,K
    const int nrope = MTOK * NH * 32;
    rope_kernel<<<(nrope + 255) / 256, 256>>>(q, k, pos);

    // 4) causal attention
    dim3 ga(SS / QPB, BB * NH);
    attn_kernel<<<ga, 512>>>(q, k, v, attn);

    // 5) O projection + residual(x)
    sgemm_nt_kernel<<<gqkv, 256>>>(attn, ow, x, res1, MTOK, DM, DM);

    // 6) h_norm = rmsnorm(res1, g2)
    rmsnorm_kernel<<<MTOK, 256>>>(res1, g2, hnorm);

    // 7) FFN up projections
    dim3 gff(DFF/128, MTOK/128);
    sgemm_nt_kernel<<<gff, 256>>>(hnorm, w1, nullptr, ff1, MTOK, DFF, DM);
    sgemm_nt_kernel<<<gff, 256>>>(hnorm, w3, nullptr, ff3, MTOK, DFF, DM);

    // 8) swiglu: ff1 = silu(ff1) * ff3
    const int n4 = (int)((size_t)MTOK * DFF / 4);
    swiglu_kernel<<<(n4 + 255) / 256, 256>>>(ff1, ff3, n4);

    // 9) down projection + residual(res1) -> out
    sgemm_nt_kernel<<<gqkv, 256>>>(ff1, w2, res1, out, MTOK, DM, DFF);
}

// round 3
// speedup vs baseline: 1.9105x; 1.9105x over previous
#include <cuda_runtime.h>
#include <cuda_bf16.h>
#include <math.h>
#include <math_constants.h>
#include <cstdint>

#define BB   4
#define SS   2048
#define DM   1024
#define NH   16
#define DH   64
#define DFF  4096
#define MTOK (BB*SS)      // 8192
#define LDQKV 3072
#define QPB  16

// ---------------- helpers ----------------
__device__ __forceinline__ uint32_t smem_to_u32(const void* p) {
    uint32_t a;
    asm("{ .reg .u64 t; cvta.to.shared.u64 t, %1; cvt.u32.u64 %0, t; }" : "=r"(a) : "l"(p));
    return a;
}
#define CP_ASYNC16(s, g) asm volatile("cp.async.cg.shared.global [%0], [%1], 16;" :: "r"(s), "l"(g))
#define CP_COMMIT()      asm volatile("cp.async.commit_group;" ::: "memory")
#define CP_WAIT1()       asm volatile("cp.async.wait_group 1;" ::: "memory")
#define CP_WAIT0()       asm volatile("cp.async.wait_group 0;" ::: "memory")
#define LDSM4(rg, addr) \
    asm volatile("ldmatrix.sync.aligned.m8n8.x4.shared.b16 {%0,%1,%2,%3}, [%4];" \
        : "=r"((rg)[0]), "=r"((rg)[1]), "=r"((rg)[2]), "=r"((rg)[3]) : "r"(addr))
#define MMA16816(d, a, b0v, b1v) \
    asm volatile("mma.sync.aligned.m16n8k16.row.col.f32.bf16.bf16.f32 " \
        "{%0,%1,%2,%3}, {%4,%5,%6,%7}, {%8,%9}, {%0,%1,%2,%3};" \
        : "+f"((d)[0]), "+f"((d)[1]), "+f"((d)[2]), "+f"((d)[3]) \
        : "r"((a)[0]), "r"((a)[1]), "r"((a)[2]), "r"((a)[3]), "r"(b0v), "r"(b1v))

// ---------------- scratch (__device__ globals) ----------------
static __device__ __nv_bfloat16 g_xn_h[(size_t)MTOK*DM],  g_xn_l[(size_t)MTOK*DM];
static __device__ float         g_qkv [(size_t)MTOK*LDQKV];
static __device__ float         g_attn[(size_t)MTOK*DM];
static __device__ __nv_bfloat16 g_at_h[(size_t)MTOK*DM],  g_at_l[(size_t)MTOK*DM];
static __device__ float         g_res1[(size_t)MTOK*DM];
static __device__ __nv_bfloat16 g_hn_h[(size_t)MTOK*DM],  g_hn_l[(size_t)MTOK*DM];
static __device__ float         g_ff13[(size_t)MTOK*2*DFF];
static __device__ __nv_bfloat16 g_sw_h[(size_t)MTOK*DFF], g_sw_l[(size_t)MTOK*DFF];
static __device__ __nv_bfloat16 g_wqkv_h[3072*1024], g_wqkv_l[3072*1024];
static __device__ __nv_bfloat16 g_ow_h [1024*1024],  g_ow_l [1024*1024];
static __device__ __nv_bfloat16 g_w13_h[2*DFF*1024], g_w13_l[2*DFF*1024];
static __device__ __nv_bfloat16 g_w2_h [1024*DFF],   g_w2_l [1024*DFF];

// ---------------- fp32 -> (hi,lo) bf16 split ----------------
__device__ __forceinline__ void split2(float v, __nv_bfloat16& h, __nv_bfloat16& l) {
    h = __float2bfloat16(v);
    l = __float2bfloat16(v - __bfloat162float(h));
}

__global__ void split_kernel(const float* __restrict__ x,
                             __nv_bfloat16* __restrict__ h,
                             __nv_bfloat16* __restrict__ l, int n4) {
    int i = blockIdx.x * blockDim.x + threadIdx.x;
    if (i >= n4) return;
    float4 v = ((const float4*)x)[i];
    __nv_bfloat162 h0, h1, l0, l1;
    split2(v.x, h0.x, l0.x); split2(v.y, h0.y, l0.y);
    split2(v.z, h1.x, l1.x); split2(v.w, h1.y, l1.y);
    ((__nv_bfloat162*)h)[2*i]   = h0; ((__nv_bfloat162*)h)[2*i+1] = h1;
    ((__nv_bfloat162*)l)[2*i]   = l0; ((__nv_bfloat162*)l)[2*i+1] = l1;
}

// ---------------- RMSNorm -> split bf16 ----------------
__global__ void rmsnorm_split_kernel(const float* __restrict__ x,
                                     const float* __restrict__ g,
                                     __nv_bfloat16* __restrict__ yh,
                                     __nv_bfloat16* __restrict__ yl) {
    const int row = blockIdx.x;
    const float4* xr = (const float4*)(x + (size_t)row * DM);
    const int t = threadIdx.x;
    float4 xv = xr[t];
    float ss = xv.x*xv.x + xv.y*xv.y + xv.z*xv.z + xv.w*xv.w;
    #pragma unroll
    for (int o = 16; o; o >>= 1) ss += __shfl_xor_sync(0xffffffffu, ss, o);
    __shared__ float sred[8];
    const int warp = t >> 5, lane = t & 31;
    if (lane == 0) sred[warp] = ss;
    __syncthreads();
    if (warp == 0) {
        float v = (lane < 8) ? sred[lane] : 0.f;
        #pragma unroll
        for (int o = 4; o; o >>= 1) v += __shfl_xor_sync(0xffffffffu, v, o);
        if (lane == 0) sred[0] = v;
    }
    __syncthreads();
    const float inv = rsqrtf(sred[0] * (1.0f/(float)DM) + 1e-5f);
    const float4 gv = ((const float4*)g)[t];
    float y0 = xv.x*inv*gv.x, y1 = xv.y*inv*gv.y, y2 = xv.z*inv*gv.z, y3 = xv.w*inv*gv.w;
    __nv_bfloat162 h0, h1, l0, l1;
    split2(y0, h0.x, l0.x); split2(y1, h0.y, l0.y);
    split2(y2, h1.x, l1.x); split2(y3, h1.y, l1.y);
    const size_t b2 = (size_t)row * (DM/2) + 2*t;
    ((__nv_bfloat162*)yh)[b2]   = h0; ((__nv_bfloat162*)yh)[b2+1] = h1;
    ((__nv_bfloat162*)yl)[b2]   = l0; ((__nv_bfloat162*)yl)[b2+1] = l1;
}

// ---------------- RoPE (in-place on fused QKV, stride 3072) ----------------
__global__ void rope_kernel(float* __restrict__ qkv, const int* __restrict__ pos) {
    const int idx = blockIdx.x * blockDim.x + threadIdx.x;
    if (idx >= MTOK*NH*32) return;
    const int i = idx & 31;
    const int h = (idx >> 5) & (NH-1);
    const int m = idx >> 9;
    const int s = m & (SS-1);
    const float p = (float)pos[s];
    const float inv = 1.0f / powf(10000.0f, (float)(2*i) * (1.0f/(float)DH));
    float sn, cs;
    sincosf(p * inv, &sn, &cs);
    const size_t bq = (size_t)m * LDQKV + h*DH + 2*i;
    float qe = qkv[bq], qo = qkv[bq+1];
    qkv[bq]   = qe*cs - qo*sn;
    qkv[bq+1] = qe*sn + qo*cs;
    const size_t bk = bq + 1024;
    float ke = qkv[bk], ko = qkv[bk+1];
    qkv[bk]   = ke*cs - ko*sn;
    qkv[bk+1] = ke*sn + ko*cs;
}

// ---------------- mma.sync bf16x3 GEMM: C[M,N]=A[M,K]*B[N,K]^T (+R) ----------
// A,B as (hi,lo) bf16 pairs. CTA tile 128x128, BK=64, 8 warps (warp 32x64).
// smem per stage: Ah|Al|Bh|Bl, each 128 rows x 144B (64 bf16 + 16B pad).
#define ROWB  144
#define TBUF  (128*ROWB)      // 18432
#define STAGE (4*TBUF)        // 73728
__global__ __launch_bounds__(256)
void gemm_mma_bf16x3(const __nv_bfloat16* __restrict__ Ah,
                     const __nv_bfloat16* __restrict__ Al,
                     const __nv_bfloat16* __restrict__ Bh,
                     const __nv_bfloat16* __restrict__ Bl,
                     const float* __restrict__ R,
                     float* __restrict__ C,
                     int N, int K) {
    extern __shared__ char smem[];
    const uint32_t sbase = smem_to_u32(smem);
    const int tid  = threadIdx.x;
    const int lane = tid & 31;
    const int wid  = tid >> 5;
    const int bm = blockIdx.y * 128;
    const int bn = blockIdx.x * 128;
    const int m0w = (wid & 3) * 32;
    const int n0w = (wid >> 2) * 64;

    float acc[2][8][4];
    #pragma unroll
    for (int i = 0; i < 2; i++)
        #pragma unroll
        for (int j = 0; j < 8; j++)
            #pragma unroll
            for (int q = 0; q < 4; q++) acc[i][j][q] = 0.f;

    const int nch = K >> 6;

    auto load_stage = [&](int s, int c) {
        const int k0 = c << 6;
        const uint32_t st = sbase + (uint32_t)s * STAGE;
        #pragma unroll
        for (int i = 0; i < 4; ++i) {
            const int idx = tid + (i << 8);          // 0..1023
            const int row = idx >> 3, cc = idx & 7;  // 16B column within 128B
            const uint32_t so = (uint32_t)(row * ROWB + cc * 16);
            const size_t ga = (size_t)(bm + row) * K + k0 + cc * 8;
            const size_t gb = (size_t)(bn + row) * K + k0 + cc * 8;
            CP_ASYNC16(st + so,            (const char*)(Ah + ga));
            CP_ASYNC16(st + TBUF + so,     (const char*)(Al + ga));
            CP_ASYNC16(st + 2*TBUF + so,   (const char*)(Bh + gb));
            CP_ASYNC16(st + 3*TBUF + so,   (const char*)(Bl + gb));
        }
        CP_COMMIT();
    };

    // per-lane ldmatrix address components
    const int g = lane >> 3, r = lane & 7;
    const int arow = m0w + (g & 1) * 8 + r;       // + mi*16
    const int acol = (g >> 1) * 8;                // + k0
    const int brow = n0w + (g >> 1) * 8 + r;      // + nb*16
    const int bcol = (g & 1) * 8;

    load_stage(0, 0);

    for (int c = 0; c < nch; ++c) {
        if (c + 1 < nch) { load_stage((c + 1) & 1, c + 1); CP_WAIT1(); }
        else             { CP_WAIT0(); }
        __syncthreads();

        const uint32_t st = sbase + (uint32_t)(c & 1) * STAGE;
        #pragma unroll
        for (int ks = 0; ks < 4; ++ks) {
            const int k0 = ks * 16;
            uint32_t AhF[2][4], AlF[2][4], BhF[4][4], BlF[4][4];
            const uint32_t abase = st + (uint32_t)(arow * ROWB + (k0 + acol) * 2);
            #pragma unroll
            for (int mi = 0; mi < 2; ++mi) {
                LDSM4(AhF[mi], abase + (uint32_t)(mi * 16 * ROWB));
                LDSM4(AlF[mi], abase + TBUF + (uint32_t)(mi * 16 * ROWB));
            }
            const uint32_t bbase = st + 2*TBUF + (uint32_t)(brow * ROWB + (k0 + bcol) * 2);
            #pragma unroll
            for (int nb = 0; nb < 4; ++nb) {
                LDSM4(BhF[nb], bbase + (uint32_t)(nb * 16 * ROWB));
                LDSM4(BlF[nb], bbase + TBUF + (uint32_t)(nb * 16 * ROWB));
            }
            #pragma unroll
            for (int mi = 0; mi < 2; ++mi)
                #pragma unroll
                for (int nb = 0; nb < 4; ++nb)
                    #pragma unroll
                    for (int hf = 0; hf < 2; ++hf) {
                        float* d = acc[mi][nb * 2 + hf];
                        MMA16816(d, AhF[mi], BhF[nb][hf*2], BhF[nb][hf*2+1]);
                        MMA16816(d, AhF[mi], BlF[nb][hf*2], BlF[nb][hf*2+1]);
                        MMA16816(d, AlF[mi], BhF[nb][hf*2], BhF[nb][hf*2+1]);
                    }
        }
        __syncthreads();
    }

    // epilogue
    const int erow = lane >> 2;
    const int ecol = (lane & 3) * 2;
    #pragma unroll
    for (int mi = 0; mi < 2; ++mi) {
        #pragma unroll
        for (int nj = 0; nj < 8; ++nj) {
            const float* d = acc[mi][nj];
            const int row0 = bm + m0w + mi * 16 + erow;
            const int col  = bn + n0w + nj * 8 + ecol;
            const size_t o0 = (size_t)row0 * N + col;
            const size_t o1 = o0 + (size_t)8 * N;
            float2 v0 = make_float2(d[0], d[1]);
            float2 v1 = make_float2(d[2], d[3]);
            if (R) {
                const float2 r0 = *(const float2*)(R + o0);
                const float2 r1 = *(const float2*)(R + o1);
                v0.x += r0.x; v0.y += r0.y;
                v1.x += r1.x; v1.y += r1.y;
            }
            *(float2*)(C + o0) = v0;
            *(float2*)(C + o1) = v1;
        }
    }
}

// ---------------- Causal attention (flash-style, fp32), strided QKV ------------
__global__ __launch_bounds__(512)
void attn_kernel(const float* __restrict__ QKV, float* __restrict__ O) {
    __shared__ float Ks[64][65];
    __shared__ float Vs[64][65];
    __shared__ float Qs[QPB][64];
    __shared__ float Ps[QPB][64];

    const int bh   = blockIdx.y;
    const int b    = bh >> 4, h = bh & (NH-1);
    const int q0   = blockIdx.x * QPB;
    const int warp = threadIdx.x >> 5, lane = threadIdx.x & 31;
    const int q    = q0 + warp;
    const size_t baseQ = ((size_t)b * SS) * LDQKV + h * DH;
    const size_t baseK = baseQ + 1024;
    const size_t baseV = baseQ + 2048;
    const size_t baseO = ((size_t)b * SS) * DM + h * DH;

    for (int i = threadIdx.x; i < QPB*16; i += 512) {
        const int r = i >> 4, c4 = (i & 15) << 2;
        *(float4*)&Qs[r][c4] = *(const float4*)(QKV + baseQ + (size_t)(q0 + r) * LDQKV + c4);
    }

    float m = -CUDART_INF_F, l = 0.f, acc0 = 0.f, acc1 = 0.f;
    const int ntiles = ((q0 + QPB - 1) >> 6) + 1;

    for (int t = 0; t < ntiles; t++) {
        const int k0 = t << 6;
        __syncthreads();
        for (int i = threadIdx.x; i < 64*16; i += 512) {
            const int r = i >> 4, c4 = (i & 15) << 2;
            const float4 kv = *(const float4*)(QKV + baseK + (size_t)(k0 + r) * LDQKV + c4);
            Ks[r][c4] = kv.x; Ks[r][c4+1] = kv.y; Ks[r][c4+2] = kv.z; Ks[r][c4+3] = kv.w;
            const float4 vv = *(const float4*)(QKV + baseV + (size_t)(k0 + r) * LDQKV + c4);
            Vs[r][c4] = vv.x; Vs[r][c4+1] = vv.y; Vs[r][c4+2] = vv.z; Vs[r][c4+3] = vv.w;
        }
        __syncthreads();

        float s0 = 0.f, s1 = 0.f;
        #pragma unroll
        for (int d = 0; d < 64; d++) {
            const float qd = Qs[warp][d];
            s0 = fmaf(qd, Ks[lane][d],      s0);
            s1 = fmaf(qd, Ks[lane + 32][d], s1);
        }
        s0 *= 0.125f; s1 *= 0.125f;
        const bool msk0 = (k0 + lane)      > q;
        const bool msk1 = (k0 + lane + 32) > q;
        if (msk0) s0 = -CUDART_INF_F;
        if (msk1) s1 = -CUDART_INF_F;

        float tmax = fmaxf(s0, s1);
        #pragma unroll
        for (int o = 16; o; o >>= 1) tmax = fmaxf(tmax, __shfl_xor_sync(0xffffffffu, tmax, o));
        const float nm   = fmaxf(m, tmax);
        const float corr = __expf(m - nm);
        acc0 *= corr; acc1 *= corr; l *= corr;

        const float p0 = msk0 ? 0.f : __expf(s0 - nm);
        const float p1 = msk1 ? 0.f : __expf(s1 - nm);
        m = nm;
        float ps = p0 + p1;
        #pragma unroll
        for (int o = 16; o; o >>= 1) ps += __shfl_xor_sync(0xffffffffu, ps, o);
        l += ps;
        Ps[warp][lane] = p0; Ps[warp][lane + 32] = p1;
        __syncwarp();

        #pragma unroll 8
        for (int j = 0; j < 64; j++) {
            const float p = Ps[warp][j];
            acc0 = fmaf(p, Vs[j][lane],      acc0);
            acc1 = fmaf(p, Vs[j][lane + 32], acc1);
        }
    }

    const float invl = 1.0f / l;
    O[baseO + (size_t)q * DM + lane]      = acc0 * invl;
    O[baseO + (size_t)q * DM + lane + 32] = acc1 * invl;
}

// ---------------- SwiGLU from fused ff13 -> split bf16 ----------------
__global__ void swiglu_split_kernel(const float* __restrict__ ff13,
                                    __nv_bfloat16* __restrict__ h,
                                    __nv_bfloat16* __restrict__ l) {
    const int i = blockIdx.x * blockDim.x + threadIdx.x;   // MTOK*DFF/4 groups
    if (i >= MTOK * (DFF/4)) return;
    const int row = i >> 10;
    const int col = (i & 1023) << 2;
    const float4 a = *(const float4*)(ff13 + (size_t)row * (2*DFF) + col);
    const float4 g = *(const float4*)(ff13 + (size_t)row * (2*DFF) + DFF + col);
    float v0 = a.x / (1.f + __expf(-a.x)) * g.x;
    float v1 = a.y / (1.f + __expf(-a.y)) * g.y;
    float v2 = a.z / (1.f + __expf(-a.z)) * g.z;
    float v3 = a.w / (1.f + __expf(-a.w)) * g.w;
    __nv_bfloat162 h0, h1, l0, l1;
    split2(v0, h0.x, l0.x); split2(v1, h0.y, l0.y);
    split2(v2, h1.x, l1.x); split2(v3, h1.y, l1.y);
    const size_t b2 = ((size_t)row * DFF + col) >> 1;
    ((__nv_bfloat162*)h)[b2]   = h0; ((__nv_bfloat162*)h)[b2+1] = h1;
    ((__nv_bfloat162*)l)[b2]   = l0; ((__nv_bfloat162*)l)[b2+1] = l1;
}

// ---------------- launch ----------------
extern "C" void kernel_launch(void* const* d_in, const int* in_sizes, int n_in,
                              void* d_out, int out_size) {
    const float* x   = (const float*)d_in[0];
    const int*   pos = (const int*)  d_in[1];
    const float* qw  = (const float*)d_in[2];
    const float* kw  = (const float*)d_in[3];
    const float* vw  = (const float*)d_in[4];
    const float* ow  = (const float*)d_in[5];
    const float* g1  = (const float*)d_in[6];
    const float* g2  = (const float*)d_in[7];
    const float* w1  = (const float*)d_in[8];
    const float* w2  = (const float*)d_in[9];
    const float* w3  = (const float*)d_in[10];
    float* out = (float*)d_out;

    __nv_bfloat16 *xnh, *xnl, *ath, *atl, *hnh, *hnl, *swh, *swl;
    __nv_bfloat16 *wqkvh, *wqkvl, *owh, *owl, *w13h, *w13l, *w2h, *w2l;
    float *qkv, *attn, *res1, *ff13;
    cudaGetSymbolAddress((void**)&xnh, g_xn_h);   cudaGetSymbolAddress((void**)&xnl, g_xn_l);
    cudaGetSymbolAddress((void**)&qkv, g_qkv);
    cudaGetSymbolAddress((void**)&attn, g_attn);
    cudaGetSymbolAddress((void**)&ath, g_at_h);   cudaGetSymbolAddress((void**)&atl, g_at_l);
    cudaGetSymbolAddress((void**)&res1, g_res1);
    cudaGetSymbolAddress((void**)&hnh, g_hn_h);   cudaGetSymbolAddress((void**)&hnl, g_hn_l);
    cudaGetSymbolAddress((void**)&ff13, g_ff13);
    cudaGetSymbolAddress((void**)&swh, g_sw_h);   cudaGetSymbolAddress((void**)&swl, g_sw_l);
    cudaGetSymbolAddress((void**)&wqkvh, g_wqkv_h); cudaGetSymbolAddress((void**)&wqkvl, g_wqkv_l);
    cudaGetSymbolAddress((void**)&owh, g_ow_h);   cudaGetSymbolAddress((void**)&owl, g_ow_l);
    cudaGetSymbolAddress((void**)&w13h, g_w13_h); cudaGetSymbolAddress((void**)&w13l, g_w13_l);
    cudaGetSymbolAddress((void**)&w2h, g_w2_h);   cudaGetSymbolAddress((void**)&w2l, g_w2_l);

    const int GEMM_SMEM = 2 * STAGE;   // 147456 bytes
    cudaFuncSetAttribute(gemm_mma_bf16x3,
                         cudaFuncAttributeMaxDynamicSharedMemorySize, GEMM_SMEM);

    // weight splits (fused QKV and W1||W3 buffers)
    const int MM = 1024 * 1024;
    split_kernel<<<MM/4/256, 256>>>(qw, wqkvh,          wqkvl,          MM/4);
    split_kernel<<<MM/4/256, 256>>>(kw, wqkvh + MM,     wqkvl + MM,     MM/4);
    split_kernel<<<MM/4/256, 256>>>(vw, wqkvh + 2*MM,   wqkvl + 2*MM,   MM/4);
    split_kernel<<<MM/256,   256>>>(w1, w13h,           w13l,           MM);
    split_kernel<<<MM/256,   256>>>(w3, w13h + 4*MM,    w13l + 4*MM,    MM);
    split_kernel<<<MM/4/256, 256>>>(ow, owh,            owl,            MM/4);
    split_kernel<<<MM/256,   256>>>(w2, w2h,            w2l,            MM);

    // 1) rmsnorm(x) -> bf16 split
    rmsnorm_split_kernel<<<MTOK, 256>>>(x, g1, xnh, xnl);

    // 2) fused QKV projection: [8192,3072]
    gemm_mma_bf16x3<<<dim3(LDQKV/128, MTOK/128), 256, GEMM_SMEM>>>(
        xnh, xnl, wqkvh, wqkvl, nullptr, qkv, LDQKV, DM);

    // 3) RoPE
    rope_kernel<<<(MTOK*NH*32 + 255)/256, 256>>>(qkv, pos);

    // 4) attention
    attn_kernel<<<dim3(SS/QPB, BB*NH), 512>>>(qkv, attn);

    // 5) split attn out, O projection + residual(x)
    split_kernel<<<(MTOK*DM/4 + 255)/256, 256>>>(attn, ath, atl, MTOK*DM/4);
    gemm_mma_bf16x3<<<dim3(DM/128, MTOK/128), 256, GEMM_SMEM>>>(
        ath, atl, owh, owl, x, res1, DM, DM);

    // 6) rmsnorm(res1) -> bf16 split
    rmsnorm_split_kernel<<<MTOK, 256>>>(res1, g2, hnh, hnl);

    // 7) fused W1||W3: [8192, 8192]
    gemm_mma_bf16x3<<<dim3(2*DFF/128, MTOK/128), 256, GEMM_SMEM>>>(
        hnh, hnl, w13h, w13l, nullptr, ff13, 2*DFF, DM);

    // 8) swiglu -> split bf16
    swiglu_split_kernel<<<(MTOK*(DFF/4) + 255)/256, 256>>>(ff13, swh, swl);

    // 9) down projection + residual(res1) -> out
    gemm_mma_bf16x3<<<dim3(DM/128, MTOK/128), 256, GEMM_SMEM>>>(
        swh, swl, w2h, w2l, res1, out, DM, DFF);
}

// round 4
// speedup vs baseline: 2.9157x; 1.5261x over previous
#include <cuda_runtime.h>
#include <cuda_bf16.h>
#include <math.h>
#include <math_constants.h>
#include <cstdint>

#define BB   4
#define SS   2048
#define DM   1024
#define NH   16
#define DH   64
#define DFF  4096
#define MTOK (BB*SS)      // 8192
#define LDQKV 3072

// ---------------- helpers ----------------
__device__ __forceinline__ uint32_t smem_to_u32(const void* p) {
    uint32_t a;
    asm("{ .reg .u64 t; cvta.to.shared.u64 t, %1; cvt.u32.u64 %0, t; }" : "=r"(a) : "l"(p));
    return a;
}
#define CP_ASYNC16(s, g) asm volatile("cp.async.cg.shared.global [%0], [%1], 16;" :: "r"(s), "l"(g))
#define CP_COMMIT()      asm volatile("cp.async.commit_group;" ::: "memory")
#define CP_WAIT1()       asm volatile("cp.async.wait_group 1;" ::: "memory")
#define CP_WAIT0()       asm volatile("cp.async.wait_group 0;" ::: "memory")
#define LDSM4(rg, addr) \
    asm volatile("ldmatrix.sync.aligned.m8n8.x4.shared.b16 {%0,%1,%2,%3}, [%4];" \
        : "=r"((rg)[0]), "=r"((rg)[1]), "=r"((rg)[2]), "=r"((rg)[3]) : "r"(addr))
#define MMA16816(d, a, b0v, b1v) \
    asm volatile("mma.sync.aligned.m16n8k16.row.col.f32.bf16.bf16.f32 " \
        "{%0,%1,%2,%3}, {%4,%5,%6,%7}, {%8,%9}, {%0,%1,%2,%3};" \
        : "+f"((d)[0]), "+f"((d)[1]), "+f"((d)[2]), "+f"((d)[3]) \
        : "r"((a)[0]), "r"((a)[1]), "r"((a)[2]), "r"((a)[3]), "r"(b0v), "r"(b1v))

// ---------------- scratch (__device__ globals) ----------------
static __device__ __nv_bfloat16 g_xn_h[(size_t)MTOK*DM],  g_xn_l[(size_t)MTOK*DM];
static __device__ float         g_qkv [(size_t)MTOK*LDQKV];
static __device__ __nv_bfloat16 g_at_h[(size_t)MTOK*DM],  g_at_l[(size_t)MTOK*DM];
static __device__ float         g_res1[(size_t)MTOK*DM];
static __device__ __nv_bfloat16 g_hn_h[(size_t)MTOK*DM],  g_hn_l[(size_t)MTOK*DM];
static __device__ float         g_ff13[(size_t)MTOK*2*DFF];
static __device__ __nv_bfloat16 g_sw_h[(size_t)MTOK*DFF], g_sw_l[(size_t)MTOK*DFF];
static __device__ __nv_bfloat16 g_wqkv_h[3072*1024], g_wqkv_l[3072*1024];
static __device__ __nv_bfloat16 g_ow_h [1024*1024],  g_ow_l [1024*1024];
static __device__ __nv_bfloat16 g_w13_h[2*DFF*1024], g_w13_l[2*DFF*1024];
static __device__ __nv_bfloat16 g_w2_h [1024*DFF],   g_w2_l [1024*DFF];

// ---------------- fp32 -> (hi,lo) bf16 split ----------------
__device__ __forceinline__ void split2(float v, __nv_bfloat16& h, __nv_bfloat16& l) {
    h = __float2bfloat16(v);
    l = __float2bfloat16(v - __bfloat162float(h));
}

__global__ void split_kernel(const float* __restrict__ x,
                             __nv_bfloat16* __restrict__ h,
                             __nv_bfloat16* __restrict__ l, int n4) {
    int i = blockIdx.x * blockDim.x + threadIdx.x;
    if (i >= n4) return;
    float4 v = ((const float4*)x)[i];
    __nv_bfloat162 h0, h1, l0, l1;
    split2(v.x, h0.x, l0.x); split2(v.y, h0.y, l0.y);
    split2(v.z, h1.x, l1.x); split2(v.w, h1.y, l1.y);
    ((__nv_bfloat162*)h)[2*i]   = h0; ((__nv_bfloat162*)h)[2*i+1] = h1;
    ((__nv_bfloat162*)l)[2*i]   = l0; ((__nv_bfloat162*)l)[2*i+1] = l1;
}

// ---------------- RMSNorm -> split bf16 ----------------
__global__ void rmsnorm_split_kernel(const float* __restrict__ x,
                                     const float* __restrict__ g,
                                     __nv_bfloat16* __restrict__ yh,
                                     __nv_bfloat16* __restrict__ yl) {
    const int row = blockIdx.x;
    const float4* xr = (const float4*)(x + (size_t)row * DM);
    const int t = threadIdx.x;
    float4 xv = xr[t];
    float ss = xv.x*xv.x + xv.y*xv.y + xv.z*xv.z + xv.w*xv.w;
    #pragma unroll
    for (int o = 16; o; o >>= 1) ss += __shfl_xor_sync(0xffffffffu, ss, o);
    __shared__ float sred[8];
    const int warp = t >> 5, lane = t & 31;
    if (lane == 0) sred[warp] = ss;
    __syncthreads();
    if (warp == 0) {
        float v = (lane < 8) ? sred[lane] : 0.f;
        #pragma unroll
        for (int o = 4; o; o >>= 1) v += __shfl_xor_sync(0xffffffffu, v, o);
        if (lane == 0) sred[0] = v;
    }
    __syncthreads();
    const float inv = rsqrtf(sred[0] * (1.0f/(float)DM) + 1e-5f);
    const float4 gv = ((const float4*)g)[t];
    float y0 = xv.x*inv*gv.x, y1 = xv.y*inv*gv.y, y2 = xv.z*inv*gv.z, y3 = xv.w*inv*gv.w;
    __nv_bfloat162 h0, h1, l0, l1;
    split2(y0, h0.x, l0.x); split2(y1, h0.y, l0.y);
    split2(y2, h1.x, l1.x); split2(y3, h1.y, l1.y);
    const size_t b2 = (size_t)row * (DM/2) + 2*t;
    ((__nv_bfloat162*)yh)[b2]   = h0; ((__nv_bfloat162*)yh)[b2+1] = h1;
    ((__nv_bfloat162*)yl)[b2]   = l0; ((__nv_bfloat162*)yl)[b2+1] = l1;
}

// ---------------- RoPE (in-place on fused QKV, stride 3072) ----------------
__global__ void rope_kernel(float* __restrict__ qkv, const int* __restrict__ pos) {
    const int idx = blockIdx.x * blockDim.x + threadIdx.x;
    if (idx >= MTOK*NH*32) return;
    const int i = idx & 31;
    const int h = (idx >> 5) & (NH-1);
    const int m = idx >> 9;
    const int s = m & (SS-1);
    const float p = (float)pos[s];
    const float inv = 1.0f / powf(10000.0f, (float)(2*i) * (1.0f/(float)DH));
    float sn, cs;
    sincosf(p * inv, &sn, &cs);
    const size_t bq = (size_t)m * LDQKV + h*DH + 2*i;
    float qe = qkv[bq], qo = qkv[bq+1];
    qkv[bq]   = qe*cs - qo*sn;
    qkv[bq+1] = qe*sn + qo*cs;
    const size_t bk = bq + 1024;
    float ke = qkv[bk], ko = qkv[bk+1];
    qkv[bk]   = ke*cs - ko*sn;
    qkv[bk+1] = ke*sn + ko*cs;
}

// ---------------- mma.sync bf16x3 GEMM: C[M,N]=A[M,K]*B[N,K]^T (+R) ----------
#define ROWB  144
#define TBUF  (128*ROWB)      // 18432
#define STAGE (4*TBUF)        // 73728
__global__ __launch_bounds__(256)
void gemm_mma_bf16x3(const __nv_bfloat16* __restrict__ Ah,
                     const __nv_bfloat16* __restrict__ Al,
                     const __nv_bfloat16* __restrict__ Bh,
                     const __nv_bfloat16* __restrict__ Bl,
                     const float* __restrict__ R,
                     float* __restrict__ C,
                     int N, int K) {
    extern __shared__ char smem[];
    const uint32_t sbase = smem_to_u32(smem);
    const int tid  = threadIdx.x;
    const int lane = tid & 31;
    const int wid  = tid >> 5;
    const int bm = blockIdx.y * 128;
    const int bn = blockIdx.x * 128;
    const int m0w = (wid & 3) * 32;
    const int n0w = (wid >> 2) * 64;

    float acc[2][8][4];
    #pragma unroll
    for (int i = 0; i < 2; i++)
        #pragma unroll
        for (int j = 0; j < 8; j++)
            #pragma unroll
            for (int q = 0; q < 4; q++) acc[i][j][q] = 0.f;

    const int nch = K >> 6;

    auto load_stage = [&](int s, int c) {
        const int k0 = c << 6;
        const uint32_t st = sbase + (uint32_t)s * STAGE;
        #pragma unroll
        for (int i = 0; i < 4; ++i) {
            const int idx = tid + (i << 8);
            const int row = idx >> 3, cc = idx & 7;
            const uint32_t so = (uint32_t)(row * ROWB + cc * 16);
            const size_t ga = (size_t)(bm + row) * K + k0 + cc * 8;
            const size_t gb = (size_t)(bn + row) * K + k0 + cc * 8;
            CP_ASYNC16(st + so,            (const char*)(Ah + ga));
            CP_ASYNC16(st + TBUF + so,     (const char*)(Al + ga));
            CP_ASYNC16(st + 2*TBUF + so,   (const char*)(Bh + gb));
            CP_ASYNC16(st + 3*TBUF + so,   (const char*)(Bl + gb));
        }
        CP_COMMIT();
    };

    const int g = lane >> 3, r = lane & 7;
    const int arow = m0w + (g & 1) * 8 + r;
    const int acol = (g >> 1) * 8;
    const int brow = n0w + (g >> 1) * 8 + r;
    const int bcol = (g & 1) * 8;

    load_stage(0, 0);

    for (int c = 0; c < nch; ++c) {
        if (c + 1 < nch) { load_stage((c + 1) & 1, c + 1); CP_WAIT1(); }
        else             { CP_WAIT0(); }
        __syncthreads();

        const uint32_t st = sbase + (uint32_t)(c & 1) * STAGE;
        #pragma unroll
        for (int ks = 0; ks < 4; ++ks) {
            const int k0 = ks * 16;
            uint32_t AhF[2][4], AlF[2][4], BhF[4][4], BlF[4][4];
            const uint32_t abase = st + (uint32_t)(arow * ROWB + (k0 + acol) * 2);
            #pragma unroll
            for (int mi = 0; mi < 2; ++mi) {
                LDSM4(AhF[mi], abase + (uint32_t)(mi * 16 * ROWB));
                LDSM4(AlF[mi], abase + TBUF + (uint32_t)(mi * 16 * ROWB));
            }
            const uint32_t bbase = st + 2*TBUF + (uint32_t)(brow * ROWB + (k0 + bcol) * 2);
            #pragma unroll
            for (int nb = 0; nb < 4; ++nb) {
                LDSM4(BhF[nb], bbase + (uint32_t)(nb * 16 * ROWB));
                LDSM4(BlF[nb], bbase + TBUF + (uint32_t)(nb * 16 * ROWB));
            }
            #pragma unroll
            for (int mi = 0; mi < 2; ++mi)
                #pragma unroll
                for (int nb = 0; nb < 4; ++nb)
                    #pragma unroll
                    for (int hf = 0; hf < 2; ++hf) {
                        float* d = acc[mi][nb * 2 + hf];
                        MMA16816(d, AhF[mi], BhF[nb][hf*2], BhF[nb][hf*2+1]);
                        MMA16816(d, AhF[mi], BlF[nb][hf*2], BlF[nb][hf*2+1]);
                        MMA16816(d, AlF[mi], BhF[nb][hf*2], BhF[nb][hf*2+1]);
                    }
        }
        __syncthreads();
    }

    const int erow = lane >> 2;
    const int ecol = (lane & 3) * 2;
    #pragma unroll
    for (int mi = 0; mi < 2; ++mi) {
        #pragma unroll
        for (int nj = 0; nj < 8; ++nj) {
            const float* d = acc[mi][nj];
            const int row0 = bm + m0w + mi * 16 + erow;
            const int col  = bn + n0w + nj * 8 + ecol;
            const size_t o0 = (size_t)row0 * N + col;
            const size_t o1 = o0 + (size_t)8 * N;
            float2 v0 = make_float2(d[0], d[1]);
            float2 v1 = make_float2(d[2], d[3]);
            if (R) {
                const float2 r0 = *(const float2*)(R + o0);
                const float2 r1 = *(const float2*)(R + o1);
                v0.x += r0.x; v0.y += r0.y;
                v1.x += r1.x; v1.y += r1.y;
            }
            *(float2*)(C + o0) = v0;
            *(float2*)(C + o1) = v1;
        }
    }
}

// ---------------- Attention v3: register-tiled fp32 flash, split epilogue ------
// Block: 64 queries of one (b,h); 256 threads (8 warps). Key tiles of 64.
// smem: Qs[64][68] | Ks[2][64][68] | Vs[2][64][68] | Ps[64][68] | m/l/c[64]
#define SD 68
#define ATT_SMEM ((6*64*SD + 192) * 4)
__global__ __launch_bounds__(256)
void attn_v3_kernel(const float* __restrict__ QKV,
                    __nv_bfloat16* __restrict__ Oh,
                    __nv_bfloat16* __restrict__ Ol) {
    extern __shared__ float s[];
    float* Qs   = s;
    float* Ks   = s + 64*SD;        // 2 stages
    float* Vs   = s + 3*64*SD;      // 2 stages
    float* Ps   = s + 5*64*SD;
    float* mrow = s + 6*64*SD;
    float* lrow = mrow + 64;
    float* crow = lrow + 64;

    const int tid  = threadIdx.x;
    const int lane = tid & 31, warp = tid >> 5;
    const int bh = blockIdx.y;
    const int b  = bh >> 4, h = bh & (NH-1);
    const int qt = gridDim.x - 1 - blockIdx.x;      // big tiles first
    const int q0 = qt * 64;
    const size_t baseQ = (size_t)b * SS * LDQKV + h * DH;
    const size_t baseK = baseQ + 1024;
    const size_t baseV = baseQ + 2048;

    // Q tile (once)
    #pragma unroll
    for (int i = 0; i < 4; i++) {
        const int idx = tid + i*256;
        const int r = idx >> 4, c4 = (idx & 15) * 4;
        *(float4*)&Qs[r*SD + c4] =
            *(const float4*)(QKV + baseQ + (size_t)(q0 + r)*LDQKV + c4);
    }
    if (tid < 64) { mrow[tid] = -CUDART_INF_F; lrow[tid] = 0.f; }

    const uint32_t sKs = smem_to_u32(Ks);
    const uint32_t sVs = smem_to_u32(Vs);

    auto load_kv = [&](int t, int st) {
        const int k0 = t * 64;
        #pragma unroll
        for (int i = 0; i < 4; i++) {
            const int idx = tid + i*256;
            const int r = idx >> 4, c4 = (idx & 15) * 4;
            const uint32_t off = (uint32_t)((st*64 + r)*SD + c4) * 4;
            CP_ASYNC16(sKs + off, (const char*)(QKV + baseK + (size_t)(k0 + r)*LDQKV + c4));
            CP_ASYNC16(sVs + off, (const char*)(QKV + baseV + (size_t)(k0 + r)*LDQKV + c4));
        }
        CP_COMMIT();
    };

    const int wq = warp >> 2, wk = warp & 3;
    const int qbase = wq*32 + (lane >> 2);        // q rows: qbase + 8i
    const int kbase = wk*16 + (lane & 3);         // QK k cols: kbase + 4j
    const int dbase = wk*16 + (lane & 3)*4;       // PV d cols: dbase + j (contig)

    float accO[4][4];
    #pragma unroll
    for (int i = 0; i < 4; i++)
        #pragma unroll
        for (int j = 0; j < 4; j++) accO[i][j] = 0.f;

    const int ntiles = qt + 1;
    load_kv(0, 0);

    for (int t = 0; t < ntiles; t++) {
        const int st = t & 1;
        if (t + 1 < ntiles) { load_kv(t + 1, (t + 1) & 1); CP_WAIT1(); }
        else                { CP_WAIT0(); }
        __syncthreads();

        // ---- QK^T ----
        float accS[4][4];
        #pragma unroll
        for (int i = 0; i < 4; i++)
            #pragma unroll
            for (int j = 0; j < 4; j++) accS[i][j] = 0.f;

        const float* Kst = Ks + st*64*SD;
        #pragma unroll
        for (int d4 = 0; d4 < 16; d4++) {
            float4 qv[4], kv[4];
            #pragma unroll
            for (int i = 0; i < 4; i++) qv[i] = *(const float4*)&Qs[(qbase + 8*i)*SD + d4*4];
            #pragma unroll
            for (int j = 0; j < 4; j++) kv[j] = *(const float4*)&Kst[(kbase + 4*j)*SD + d4*4];
            #pragma unroll
            for (int i = 0; i < 4; i++)
                #pragma unroll
                for (int j = 0; j < 4; j++) {
                    accS[i][j] = fmaf(qv[i].x, kv[j].x, accS[i][j]);
                    accS[i][j] = fmaf(qv[i].y, kv[j].y, accS[i][j]);
                    accS[i][j] = fmaf(qv[i].z, kv[j].z, accS[i][j]);
                    accS[i][j] = fmaf(qv[i].w, kv[j].w, accS[i][j]);
                }
        }
        const int k0 = t * 64;
        #pragma unroll
        for (int i = 0; i < 4; i++) {
            const int qg = q0 + qbase + 8*i;
            #pragma unroll
            for (int j = 0; j < 4; j++) {
                float sv = accS[i][j] * 0.125f;
                if (k0 + kbase + 4*j > qg) sv = -CUDART_INF_F;
                Ps[(qbase + 8*i)*SD + kbase + 4*j] = sv;
            }
        }
        __syncthreads();

        // ---- online softmax (4 threads per row) ----
        {
            const int row = tid >> 2, qd = tid & 3;
            float* pr = Ps + row*SD + qd*16;
            float4 v0 = *(float4*)(pr + 0);
            float4 v1 = *(float4*)(pr + 4);
            float4 v2 = *(float4*)(pr + 8);
            float4 v3 = *(float4*)(pr + 12);
            float tmax = fmaxf(fmaxf(fmaxf(v0.x, v0.y), fmaxf(v0.z, v0.w)),
                       fmaxf(fmaxf(fmaxf(v1.x, v1.y), fmaxf(v1.z, v1.w)),
                       fmaxf(fmaxf(fmaxf(v2.x, v2.y), fmaxf(v2.z, v2.w)),
                             fmaxf(fmaxf(v3.x, v3.y), fmaxf(v3.z, v3.w)))));
            tmax = fmaxf(tmax, __shfl_xor_sync(0xffffffffu, tmax, 1));
            tmax = fmaxf(tmax, __shfl_xor_sync(0xffffffffu, tmax, 2));
            const float mold = mrow[row];
            const float mnew = fmaxf(mold, tmax);
            v0.x = __expf(v0.x - mnew); v0.y = __expf(v0.y - mnew);
            v0.z = __expf(v0.z - mnew); v0.w = __expf(v0.w - mnew);
            v1.x = __expf(v1.x - mnew); v1.y = __expf(v1.y - mnew);
            v1.z = __expf(v1.z - mnew); v1.w = __expf(v1.w - mnew);
            v2.x = __expf(v2.x - mnew); v2.y = __expf(v2.y - mnew);
            v2.z = __expf(v2.z - mnew); v2.w = __expf(v2.w - mnew);
            v3.x = __expf(v3.x - mnew); v3.y = __expf(v3.y - mnew);
            v3.z = __expf(v3.z - mnew); v3.w = __expf(v3.w - mnew);
            *(float4*)(pr + 0)  = v0;
            *(float4*)(pr + 4)  = v1;
            *(float4*)(pr + 8)  = v2;
            *(float4*)(pr + 12) = v3;
            float psum = (v0.x + v0.y + v0.z + v0.w) + (v1.x + v1.y + v1.z + v1.w)
                       + (v2.x + v2.y + v2.z + v2.w) + (v3.x + v3.y + v3.z + v3.w);
            psum += __shfl_xor_sync(0xffffffffu, psum, 1);
            psum += __shfl_xor_sync(0xffffffffu, psum, 2);
            if (qd == 0) {
                const float corr = __expf(mold - mnew);
                lrow[row] = lrow[row] * corr + psum;
                mrow[row] = mnew;
                crow[row] = corr;
            }
        }
        __syncthreads();

        // ---- PV ----
        const float* Vst = Vs + st*64*SD;
        #pragma unroll
        for (int i = 0; i < 4; i++) {
            const float cr = crow[qbase + 8*i];
            #pragma unroll
            for (int j = 0; j < 4; j++) accO[i][j] *= cr;
        }
        #pragma unroll
        for (int k4 = 0; k4 < 16; k4++) {
            float4 pv[4], vv[4];
            #pragma unroll
            for (int i = 0; i < 4; i++) pv[i] = *(const float4*)&Ps[(qbase + 8*i)*SD + k4*4];
            #pragma unroll
            for (int j = 0; j < 4; j++) vv[j] = *(const float4*)&Vst[(k4*4 + j)*SD + dbase];
            #pragma unroll
            for (int i = 0; i < 4; i++) {
                #pragma unroll
                for (int j = 0; j < 4; j++) {
                    float* a = &accO[i][j];
                    const float vj0 = (&vv[0].x)[j], vj1 = (&vv[1].x)[j];
                    const float vj2 = (&vv[2].x)[j], vj3 = (&vv[3].x)[j];
                    *a = fmaf(pv[i].x, vj0, *a);
                    *a = fmaf(pv[i].y, vj1, *a);
                    *a = fmaf(pv[i].z, vj2, *a);
                    *a = fmaf(pv[i].w, vj3, *a);
                }
            }
        }
        __syncthreads();
    }

    // ---- epilogue: normalize + bf16 split ----
    #pragma unroll
    for (int i = 0; i < 4; i++) {
        const int ql = qbase + 8*i;
        const float inv = 1.0f / lrow[ql];
        const size_t tok = (size_t)b * SS + q0 + ql;
        const size_t off = tok * DM + h * DH + dbase;
        __nv_bfloat162 h0, h1, l0, l1;
        split2(accO[i][0] * inv, h0.x, l0.x);
        split2(accO[i][1] * inv, h0.y, l0.y);
        split2(accO[i][2] * inv, h1.x, l1.x);
        split2(accO[i][3] * inv, h1.y, l1.y);
        *(__nv_bfloat162*)(Oh + off)     = h0;
        *(__nv_bfloat162*)(Oh + off + 2) = h1;
        *(__nv_bfloat162*)(Ol + off)     = l0;
        *(__nv_bfloat162*)(Ol + off + 2) = l1;
    }
}

// ---------------- SwiGLU from fused ff13 -> split bf16 ----------------
__global__ void swiglu_split_kernel(const float* __restrict__ ff13,
                                    __nv_bfloat16* __restrict__ h,
                                    __nv_bfloat16* __restrict__ l) {
    const int i = blockIdx.x * blockDim.x + threadIdx.x;
    if (i >= MTOK * (DFF/4)) return;
    const int row = i >> 10;
    const int col = (i & 1023) << 2;
    const float4 a = *(const float4*)(ff13 + (size_t)row * (2*DFF) + col);
    const float4 g = *(const float4*)(ff13 + (size_t)row * (2*DFF) + DFF + col);
    float v0 = a.x / (1.f + __expf(-a.x)) * g.x;
    float v1 = a.y / (1.f + __expf(-a.y)) * g.y;
    float v2 = a.z / (1.f + __expf(-a.z)) * g.z;
    float v3 = a.w / (1.f + __expf(-a.w)) * g.w;
    __nv_bfloat162 h0, h1, l0, l1;
    split2(v0, h0.x, l0.x); split2(v1, h0.y, l0.y);
    split2(v2, h1.x, l1.x); split2(v3, h1.y, l1.y);
    const size_t b2 = ((size_t)row * DFF + col) >> 1;
    ((__nv_bfloat162*)h)[b2]   = h0; ((__nv_bfloat162*)h)[b2+1] = h1;
    ((__nv_bfloat162*)l)[b2]   = l0; ((__nv_bfloat162*)l)[b2+1] = l1;
}

// ---------------- launch ----------------
extern "C" void kernel_launch(void* const* d_in, const int* in_sizes, int n_in,
                              void* d_out, int out_size) {
    const float* x   = (const float*)d_in[0];
    const int*   pos = (const int*)  d_in[1];
    const float* qw  = (const float*)d_in[2];
    const float* kw  = (const float*)d_in[3];
    const float* vw  = (const float*)d_in[4];
    const float* ow  = (const float*)d_in[5];
    const float* g1  = (const float*)d_in[6];
    const float* g2  = (const float*)d_in[7];
    const float* w1  = (const float*)d_in[8];
    const float* w2  = (const float*)d_in[9];
    const float* w3  = (const float*)d_in[10];
    float* out = (float*)d_out;

    __nv_bfloat16 *xnh, *xnl, *ath, *atl, *hnh, *hnl, *swh, *swl;
    __nv_bfloat16 *wqkvh, *wqkvl, *owh, *owl, *w13h, *w13l, *w2h, *w2l;
    float *qkv, *res1, *ff13;
    cudaGetSymbolAddress((void**)&xnh, g_xn_h);   cudaGetSymbolAddress((void**)&xnl, g_xn_l);
    cudaGetSymbolAddress((void**)&qkv, g_qkv);
    cudaGetSymbolAddress((void**)&ath, g_at_h);   cudaGetSymbolAddress((void**)&atl, g_at_l);
    cudaGetSymbolAddress((void**)&res1, g_res1);
    cudaGetSymbolAddress((void**)&hnh, g_hn_h);   cudaGetSymbolAddress((void**)&hnl, g_hn_l);
    cudaGetSymbolAddress((void**)&ff13, g_ff13);
    cudaGetSymbolAddress((void**)&swh, g_sw_h);   cudaGetSymbolAddress((void**)&swl, g_sw_l);
    cudaGetSymbolAddress((void**)&wqkvh, g_wqkv_h); cudaGetSymbolAddress((void**)&wqkvl, g_wqkv_l);
    cudaGetSymbolAddress((void**)&owh, g_ow_h);   cudaGetSymbolAddress((void**)&owl, g_ow_l);
    cudaGetSymbolAddress((void**)&w13h, g_w13_h); cudaGetSymbolAddress((void**)&w13l, g_w13_l);
    cudaGetSymbolAddress((void**)&w2h, g_w2_h);   cudaGetSymbolAddress((void**)&w2l, g_w2_l);

    const int GEMM_SMEM = 2 * STAGE;   // 147456 bytes
    cudaFuncSetAttribute(gemm_mma_bf16x3,
                         cudaFuncAttributeMaxDynamicSharedMemorySize, GEMM_SMEM);
    cudaFuncSetAttribute(attn_v3_kernel,
                         cudaFuncAttributeMaxDynamicSharedMemorySize, ATT_SMEM);

    // weight splits (fused QKV and W1||W3 buffers)
    const int MM = 1024 * 1024;
    split_kernel<<<MM/4/256, 256>>>(qw, wqkvh,          wqkvl,          MM/4);
    split_kernel<<<MM/4/256, 256>>>(kw, wqkvh + MM,     wqkvl + MM,     MM/4);
    split_kernel<<<MM/4/256, 256>>>(vw, wqkvh + 2*MM,   wqkvl + 2*MM,   MM/4);
    split_kernel<<<MM/256,   256>>>(w1, w13h,           w13l,           MM);
    split_kernel<<<MM/256,   256>>>(w3, w13h + 4*MM,    w13l + 4*MM,    MM);
    split_kernel<<<MM/4/256, 256>>>(ow, owh,            owl,            MM/4);
    split_kernel<<<MM/256,   256>>>(w2, w2h,            w2l,            MM);

    // 1) rmsnorm(x) -> bf16 split
    rmsnorm_split_kernel<<<MTOK, 256>>>(x, g1, xnh, xnl);

    // 2) fused QKV projection: [8192,3072]
    gemm_mma_bf16x3<<<dim3(LDQKV/128, MTOK/128), 256, GEMM_SMEM>>>(
        xnh, xnl, wqkvh, wqkvl, nullptr, qkv, LDQKV, DM);

    // 3) RoPE
    rope_kernel<<<(MTOK*NH*32 + 255)/256, 256>>>(qkv, pos);

    // 4) attention (writes bf16 split directly)
    attn_v3_kernel<<<dim3(SS/64, BB*NH), 256, ATT_SMEM>>>(qkv, ath, atl);

    // 5) O projection + residual(x)
    gemm_mma_bf16x3<<<dim3(DM/128, MTOK/128), 256, GEMM_SMEM>>>(
        ath, atl, owh, owl, x, res1, DM, DM);

    // 6) rmsnorm(res1) -> bf16 split
    rmsnorm_split_kernel<<<MTOK, 256>>>(res1, g2, hnh, hnl);

    // 7) fused W1||W3: [8192, 8192]
    gemm_mma_bf16x3<<<dim3(2*DFF/128, MTOK/128), 256, GEMM_SMEM>>>(
        hnh, hnl, w13h, w13l, nullptr, ff13, 2*DFF, DM);

    // 8) swiglu -> split bf16
    swiglu_split_kernel<<<(MTOK*(DFF/4) + 255)/256, 256>>>(ff13, swh, swl);

    // 9) down projection + residual(res1) -> out
    gemm_mma_bf16x3<<<dim3(DM/128, MTOK/128), 256, GEMM_SMEM>>>(
        swh, swl, w2h, w2l, res1, out, DM, DFF);
}

// round 5
// speedup vs baseline: 3.5612x; 1.2214x over previous
#include <cuda_runtime.h>
#include <cuda_bf16.h>
#include <math.h>
#include <math_constants.h>
#include <cstdint>

#define BB   4
#define SS   2048
#define DM   1024
#define NH   16
#define DH   64
#define DFF  4096
#define MTOK (BB*SS)      // 8192
#define LDX  3072

// ---------------- helpers ----------------
__device__ __forceinline__ uint32_t smem_to_u32(const void* p) {
    uint32_t a;
    asm("{ .reg .u64 t; cvta.to.shared.u64 t, %1; cvt.u32.u64 %0, t; }" : "=r"(a) : "l"(p));
    return a;
}
#define CP_ASYNC16(s, g) asm volatile("cp.async.cg.shared.global [%0], [%1], 16;" :: "r"(s), "l"(g))
#define CP_COMMIT()      asm volatile("cp.async.commit_group;" ::: "memory")
#define CP_WAIT1()       asm volatile("cp.async.wait_group 1;" ::: "memory")
#define CP_WAIT0()       asm volatile("cp.async.wait_group 0;" ::: "memory")
#define LDSM4(rg, addr) \
    asm volatile("ldmatrix.sync.aligned.m8n8.x4.shared.b16 {%0,%1,%2,%3}, [%4];" \
        : "=r"((rg)[0]), "=r"((rg)[1]), "=r"((rg)[2]), "=r"((rg)[3]) : "r"(addr))
#define LDSM4T(rg, addr) \
    asm volatile("ldmatrix.sync.aligned.m8n8.x4.trans.shared.b16 {%0,%1,%2,%3}, [%4];" \
        : "=r"((rg)[0]), "=r"((rg)[1]), "=r"((rg)[2]), "=r"((rg)[3]) : "r"(addr))
#define MMA16816(d, a, b0v, b1v) \
    asm volatile("mma.sync.aligned.m16n8k16.row.col.f32.bf16.bf16.f32 " \
        "{%0,%1,%2,%3}, {%4,%5,%6,%7}, {%8,%9}, {%0,%1,%2,%3};" \
        : "+f"((d)[0]), "+f"((d)[1]), "+f"((d)[2]), "+f"((d)[3]) \
        : "r"((a)[0]), "r"((a)[1]), "r"((a)[2]), "r"((a)[3]), "r"(b0v), "r"(b1v))

// ---------------- scratch (__device__ globals) ----------------
static __device__ __nv_bfloat16 g_xn_h[(size_t)MTOK*DM],  g_xn_l[(size_t)MTOK*DM];
static __device__ __nv_bfloat16 g_qkv_h[(size_t)MTOK*LDX], g_qkv_l[(size_t)MTOK*LDX];
static __device__ __nv_bfloat16 g_at_h[(size_t)MTOK*DM],  g_at_l[(size_t)MTOK*DM];
static __device__ float         g_res1[(size_t)MTOK*DM];
static __device__ __nv_bfloat16 g_hn_h[(size_t)MTOK*DM],  g_hn_l[(size_t)MTOK*DM];
static __device__ __nv_bfloat16 g_sw_h[(size_t)MTOK*DFF], g_sw_l[(size_t)MTOK*DFF];
static __device__ __nv_bfloat16 g_wqkv_h[3072*1024], g_wqkv_l[3072*1024];
static __device__ __nv_bfloat16 g_ow_h [1024*1024],  g_ow_l [1024*1024];
static __device__ __nv_bfloat16 g_w13_h[2*DFF*1024], g_w13_l[2*DFF*1024];   // interleaved rows
static __device__ __nv_bfloat16 g_w2_h [1024*DFF],   g_w2_l [1024*DFF];
static __device__ float g_cs[SS*32], g_sn[SS*32];

// ---------------- fp32 -> (hi,lo) bf16 split ----------------
__device__ __forceinline__ void split2(float v, __nv_bfloat16& h, __nv_bfloat16& l) {
    h = __float2bfloat16(v);
    l = __float2bfloat16(v - __bfloat162float(h));
}

__global__ void rope_table_kernel(const int* __restrict__ pos) {
    const int s = blockIdx.x, i = threadIdx.x;   // 2048 x 32
    const float inv = exp2f(-(float)i * (13.287712379549449f / 32.0f));
    const float a = (float)pos[s] * inv;
    float sn, cs;
    sincosf(a, &sn, &cs);
    g_cs[s*32 + i] = cs;
    g_sn[s*32 + i] = sn;
}

__global__ void split_kernel(const float* __restrict__ x,
                             __nv_bfloat16* __restrict__ h,
                             __nv_bfloat16* __restrict__ l, int n4) {
    int i = blockIdx.x * blockDim.x + threadIdx.x;
    if (i >= n4) return;
    float4 v = ((const float4*)x)[i];
    __nv_bfloat162 h0, h1, l0, l1;
    split2(v.x, h0.x, l0.x); split2(v.y, h0.y, l0.y);
    split2(v.z, h1.x, l1.x); split2(v.w, h1.y, l1.y);
    ((__nv_bfloat162*)h)[2*i]   = h0; ((__nv_bfloat162*)h)[2*i+1] = h1;
    ((__nv_bfloat162*)l)[2*i]   = l0; ((__nv_bfloat162*)l)[2*i+1] = l1;
}

// interleaved weight split: src row n -> dst row 2n+off  (K=1024)
__global__ void split_inter_kernel(const float* __restrict__ x,
                                   __nv_bfloat16* __restrict__ h,
                                   __nv_bfloat16* __restrict__ l,
                                   int n4, int off) {
    int i = blockIdx.x * blockDim.x + threadIdx.x;
    if (i >= n4) return;
    const int row = i >> 8;            // 256 float4 per row of 1024
    const int c4  = i & 255;
    float4 v = ((const float4*)x)[i];
    __nv_bfloat162 h0, h1, l0, l1;
    split2(v.x, h0.x, l0.x); split2(v.y, h0.y, l0.y);
    split2(v.z, h1.x, l1.x); split2(v.w, h1.y, l1.y);
    const size_t o2 = ((size_t)(2*row + off) * 1024 + c4*4) >> 1;
    ((__nv_bfloat162*)h)[o2]   = h0; ((__nv_bfloat162*)h)[o2+1] = h1;
    ((__nv_bfloat162*)l)[o2]   = l0; ((__nv_bfloat162*)l)[o2+1] = l1;
}

// ---------------- RMSNorm -> split bf16 ----------------
__global__ void rmsnorm_split_kernel(const float* __restrict__ x,
                                     const float* __restrict__ g,
                                     __nv_bfloat16* __restrict__ yh,
                                     __nv_bfloat16* __restrict__ yl) {
    const int row = blockIdx.x;
    const float4* xr = (const float4*)(x + (size_t)row * DM);
    const int t = threadIdx.x;
    float4 xv = xr[t];
    float ss = xv.x*xv.x + xv.y*xv.y + xv.z*xv.z + xv.w*xv.w;
    #pragma unroll
    for (int o = 16; o; o >>= 1) ss += __shfl_xor_sync(0xffffffffu, ss, o);
    __shared__ float sred[8];
    const int warp = t >> 5, lane = t & 31;
    if (lane == 0) sred[warp] = ss;
    __syncthreads();
    if (warp == 0) {
        float v = (lane < 8) ? sred[lane] : 0.f;
        #pragma unroll
        for (int o = 4; o; o >>= 1) v += __shfl_xor_sync(0xffffffffu, v, o);
        if (lane == 0) sred[0] = v;
    }
    __syncthreads();
    const float inv = rsqrtf(sred[0] * (1.0f/(float)DM) + 1e-5f);
    const float4 gv = ((const float4*)g)[t];
    float y0 = xv.x*inv*gv.x, y1 = xv.y*inv*gv.y, y2 = xv.z*inv*gv.z, y3 = xv.w*inv*gv.w;
    __nv_bfloat162 h0, h1, l0, l1;
    split2(y0, h0.x, l0.x); split2(y1, h0.y, l0.y);
    split2(y2, h1.x, l1.x); split2(y3, h1.y, l1.y);
    const size_t b2 = (size_t)row * (DM/2) + 2*t;
    ((__nv_bfloat162*)yh)[b2]   = h0; ((__nv_bfloat162*)yh)[b2+1] = h1;
    ((__nv_bfloat162*)yl)[b2]   = l0; ((__nv_bfloat162*)yl)[b2+1] = l1;
}

// ---------------- mma.sync bf16x3 GEMM, templated epilogue --------------------
// MODE 0: C fp32 (+R).  MODE 1: rope (cols<2048) + split -> Ch/Cl (stride N).
// MODE 2: swiglu on (even,odd) col pairs + split -> Ch/Cl (stride NC=N/2).
#define ROWB  144
#define TBUF  (128*ROWB)      // 18432
#define STAGE (4*TBUF)        // 73728
template<int MODE>
__global__ __launch_bounds__(256)
void gemm_mma_bf16x3(const __nv_bfloat16* __restrict__ Ah,
                     const __nv_bfloat16* __restrict__ Al,
                     const __nv_bfloat16* __restrict__ Bh,
                     const __nv_bfloat16* __restrict__ Bl,
                     const float* __restrict__ R,
                     float* __restrict__ C,
                     __nv_bfloat16* __restrict__ Ch,
                     __nv_bfloat16* __restrict__ Cl,
                     int N, int K) {
    extern __shared__ char smem[];
    const uint32_t sbase = smem_to_u32(smem);
    const int tid  = threadIdx.x;
    const int lane = tid & 31;
    const int wid  = tid >> 5;
    const int bm = blockIdx.y * 128;
    const int bn = blockIdx.x * 128;
    const int m0w = (wid & 3) * 32;
    const int n0w = (wid >> 2) * 64;

    float acc[2][8][4];
    #pragma unroll
    for (int i = 0; i < 2; i++)
        #pragma unroll
        for (int j = 0; j < 8; j++)
            #pragma unroll
            for (int q = 0; q < 4; q++) acc[i][j][q] = 0.f;

    const int nch = K >> 6;

    auto load_stage = [&](int s, int c) {
        const int k0 = c << 6;
        const uint32_t st = sbase + (uint32_t)s * STAGE;
        #pragma unroll
        for (int i = 0; i < 4; ++i) {
            const int idx = tid + (i << 8);
            const int row = idx >> 3, cc = idx & 7;
            const uint32_t so = (uint32_t)(row * ROWB + cc * 16);
            const size_t ga = (size_t)(bm + row) * K + k0 + cc * 8;
            const size_t gb = (size_t)(bn + row) * K + k0 + cc * 8;
            CP_ASYNC16(st + so,            (const char*)(Ah + ga));
            CP_ASYNC16(st + TBUF + so,     (const char*)(Al + ga));
            CP_ASYNC16(st + 2*TBUF + so,   (const char*)(Bh + gb));
            CP_ASYNC16(st + 3*TBUF + so,   (const char*)(Bl + gb));
        }
        CP_COMMIT();
    };

    const int g = lane >> 3, r = lane & 7;
    const int arow = m0w + (g & 1) * 8 + r;
    const int acol = (g >> 1) * 8;
    const int brow = n0w + (g >> 1) * 8 + r;
    const int bcol = (g & 1) * 8;

    load_stage(0, 0);

    for (int c = 0; c < nch; ++c) {
        if (c + 1 < nch) { load_stage((c + 1) & 1, c + 1); CP_WAIT1(); }
        else             { CP_WAIT0(); }
        __syncthreads();

        const uint32_t st = sbase + (uint32_t)(c & 1) * STAGE;
        #pragma unroll
        for (int ks = 0; ks < 4; ++ks) {
            const int k0 = ks * 16;
            uint32_t AhF[2][4], AlF[2][4], BhF[4][4], BlF[4][4];
            const uint32_t abase = st + (uint32_t)(arow * ROWB + (k0 + acol) * 2);
            #pragma unroll
            for (int mi = 0; mi < 2; ++mi) {
                LDSM4(AhF[mi], abase + (uint32_t)(mi * 16 * ROWB));
                LDSM4(AlF[mi], abase + TBUF + (uint32_t)(mi * 16 * ROWB));
            }
            const uint32_t bbase = st + 2*TBUF + (uint32_t)(brow * ROWB + (k0 + bcol) * 2);
            #pragma unroll
            for (int nb = 0; nb < 4; ++nb) {
                LDSM4(BhF[nb], bbase + (uint32_t)(nb * 16 * ROWB));
                LDSM4(BlF[nb], bbase + TBUF + (uint32_t)(nb * 16 * ROWB));
            }
            #pragma unroll
            for (int mi = 0; mi < 2; ++mi)
                #pragma unroll
                for (int nb = 0; nb < 4; ++nb)
                    #pragma unroll
                    for (int hf = 0; hf < 2; ++hf) {
                        float* d = acc[mi][nb * 2 + hf];
                        MMA16816(d, AhF[mi], BhF[nb][hf*2], BhF[nb][hf*2+1]);
                        MMA16816(d, AhF[mi], BlF[nb][hf*2], BlF[nb][hf*2+1]);
                        MMA16816(d, AlF[mi], BhF[nb][hf*2], BhF[nb][hf*2+1]);
                    }
        }
        __syncthreads();
    }

    const int erow = lane >> 2;
    const int ecol = (lane & 3) * 2;
    #pragma unroll
    for (int mi = 0; mi < 2; ++mi) {
        #pragma unroll
        for (int nj = 0; nj < 8; ++nj) {
            float* d = acc[mi][nj];
            const int row0 = bm + m0w + mi * 16 + erow;
            const int row1 = row0 + 8;
            const int cg   = bn + n0w + nj * 8 + ecol;
            if (MODE == 0) {
                const size_t o0 = (size_t)row0 * N + cg;
                const size_t o1 = (size_t)row1 * N + cg;
                float2 v0 = make_float2(d[0], d[1]);
                float2 v1 = make_float2(d[2], d[3]);
                if (R) {
                    const float2 r0 = *(const float2*)(R + o0);
                    const float2 r1 = *(const float2*)(R + o1);
                    v0.x += r0.x; v0.y += r0.y;
                    v1.x += r1.x; v1.y += r1.y;
                }
                *(float2*)(C + o0) = v0;
                *(float2*)(C + o1) = v1;
            } else if (MODE == 1) {
                float a0 = d[0], a1 = d[1], b0 = d[2], b1 = d[3];
                if (cg < 2048) {
                    const int i = (cg & 63) >> 1;
                    const int s0 = (row0 & (SS-1))*32 + i;
                    const int s1 = (row1 & (SS-1))*32 + i;
                    const float c0 = g_cs[s0], n0 = g_sn[s0];
                    const float c1 = g_cs[s1], n1 = g_sn[s1];
                    float t0 = a0*c0 - a1*n0, t1 = a0*n0 + a1*c0;
                    a0 = t0; a1 = t1;
                    float u0 = b0*c1 - b1*n1, u1 = b0*n1 + b1*c1;
                    b0 = u0; b1 = u1;
                }
                __nv_bfloat162 h0, l0, h1, l1;
                split2(a0, h0.x, l0.x); split2(a1, h0.y, l0.y);
                split2(b0, h1.x, l1.x); split2(b1, h1.y, l1.y);
                const size_t o0 = (size_t)row0 * N + cg;
                const size_t o1 = (size_t)row1 * N + cg;
                *(__nv_bfloat162*)(Ch + o0) = h0;
                *(__nv_bfloat162*)(Cl + o0) = l0;
                *(__nv_bfloat162*)(Ch + o1) = h1;
                *(__nv_bfloat162*)(Cl + o1) = l1;
            } else {  // MODE 2: swiglu, (even,odd) = (a, gate)
                const int j = cg >> 1;
                const int NC = N >> 1;
                const float sl0 = d[0] / (1.f + __expf(-d[0])) * d[1];
                const float sl1 = d[2] / (1.f + __expf(-d[2])) * d[3];
                __nv_bfloat16 h0, l0, h1, l1;
                split2(sl0, h0, l0);
                split2(sl1, h1, l1);
                Ch[(size_t)row0 * NC + j] = h0;
                Cl[(size_t)row0 * NC + j] = l0;
                Ch[(size_t)row1 * NC + j] = h1;
                Cl[(size_t)row1 * NC + j] = l1;
            }
        }
    }
}

// ---------------- HMMA flash attention (bf16x3 scores, fp32 softmax) ----------
// CTA: 64 q-rows x one (b,h); 4 warps, each owns 16 q-rows. K-tiles of 64.
// smem: Qh|Ql + 2 stages x [Kh|Kl|Vh|Vl], each 64 rows x 144B.
#define ATB (64*144)
#define ATT_SMEM (10*ATB)
__global__ __launch_bounds__(128)
void attn_mma_kernel(const __nv_bfloat16* __restrict__ Xh,
                     const __nv_bfloat16* __restrict__ Xl,
                     __nv_bfloat16* __restrict__ Oh,
                     __nv_bfloat16* __restrict__ Ol) {
    extern __shared__ char sm[];
    const uint32_t sQh = smem_to_u32(sm);
    const uint32_t sQl = sQh + ATB;
    const uint32_t sSt = sQh + 2*ATB;

    const int tid = threadIdx.x, lane = tid & 31, warp = tid >> 5;
    const int bh = blockIdx.y, b = bh >> 4, h = bh & (NH-1);
    const int qt = gridDim.x - 1 - blockIdx.x;      // big tiles first
    const int q0 = qt * 64;
    const size_t rowbase = (size_t)b * SS * LDX;
    const int colQ = h*DH, colK = 1024 + h*DH, colV = 2048 + h*DH;

    #pragma unroll
    for (int i = 0; i < 4; i++) {
        const int idx = tid + i*128;
        const int r = idx >> 3, c = idx & 7;
        const uint32_t so = (uint32_t)(r*144 + c*16);
        const size_t ga = rowbase + (size_t)(q0 + r)*LDX + colQ + c*8;
        CP_ASYNC16(sQh + so, (const char*)(Xh + ga));
        CP_ASYNC16(sQl + so, (const char*)(Xl + ga));
    }
    CP_COMMIT();

    auto load_kv = [&](int t, int s) {
        const int k0 = t * 64;
        #pragma unroll
        for (int i = 0; i < 4; i++) {
            const int idx = tid + i*128;
            const int r = idx >> 3, c = idx & 7;
            const uint32_t so = (uint32_t)s*4*ATB + (uint32_t)(r*144 + c*16);
            const size_t gk = rowbase + (size_t)(k0 + r)*LDX + colK + c*8;
            const size_t gv = rowbase + (size_t)(k0 + r)*LDX + colV + c*8;
            CP_ASYNC16(sSt + so,         (const char*)(Xh + gk));
            CP_ASYNC16(sSt + ATB + so,   (const char*)(Xl + gk));
            CP_ASYNC16(sSt + 2*ATB + so, (const char*)(Xh + gv));
            CP_ASYNC16(sSt + 3*ATB + so, (const char*)(Xl + gv));
        }
        CP_COMMIT();
    };
    load_kv(0, 0);

    const int g = lane >> 3, rr = lane & 7;
    const uint32_t aoff = (uint32_t)((warp*16 + (g&1)*8 + rr)*144 + (g>>1)*16);
    const uint32_t boff = (uint32_t)(((g>>1)*8 + rr)*144 + (g&1)*16);
    const uint32_t voff = (uint32_t)(((g&1)*8 + rr)*144 + (lane>>4)*16);

    float m0 = -CUDART_INF_F, m1 = -CUDART_INF_F, l0 = 0.f, l1 = 0.f;
    float o[8][4];
    #pragma unroll
    for (int j = 0; j < 8; j++)
        #pragma unroll
        for (int q = 0; q < 4; q++) o[j][q] = 0.f;

    const int r0g = q0 + warp*16 + (lane >> 2);
    const int r1g = r0g + 8;
    const int ntiles = qt + 1;

    for (int t = 0; t < ntiles; t++) {
        if (t + 1 < ntiles) { load_kv(t + 1, (t + 1) & 1); CP_WAIT1(); }
        else                { CP_WAIT0(); }
        __syncthreads();

        const uint32_t sK  = sSt + (uint32_t)(t & 1)*4*ATB;
        const uint32_t sKl = sK + ATB;
        const uint32_t sV  = sK + 2*ATB;
        const uint32_t sVl = sK + 3*ATB;

        // ---- S = Q K^T (bf16x3) ----
        float s[8][4];
        #pragma unroll
        for (int j = 0; j < 8; j++)
            #pragma unroll
            for (int q = 0; q < 4; q++) s[j][q] = 0.f;

        #pragma unroll
        for (int d = 0; d < 4; d++) {
            uint32_t qh[4], ql[4];
            LDSM4(qh, sQh + aoff + d*32);
            LDSM4(ql, sQl + aoff + d*32);
            #pragma unroll
            for (int nb = 0; nb < 4; nb++) {
                uint32_t kh[4], kl[4];
                LDSM4(kh, sK  + boff + (uint32_t)(nb*16*144) + d*32);
                LDSM4(kl, sKl + boff + (uint32_t)(nb*16*144) + d*32);
                #pragma unroll
                for (int f = 0; f < 2; f++) {
                    float* dd = s[nb*2 + f];
                    MMA16816(dd, qh, kh[2*f], kh[2*f+1]);
                    MMA16816(dd, qh, kl[2*f], kl[2*f+1]);
                    MMA16816(dd, ql, kh[2*f], kh[2*f+1]);
                }
            }
        }

        // ---- scale, mask (diagonal tile), online softmax ----
        const int k0 = t * 64;
        float mx0 = -CUDART_INF_F, mx1 = -CUDART_INF_F;
        #pragma unroll
        for (int j = 0; j < 8; j++) {
            s[j][0] *= 0.125f; s[j][1] *= 0.125f;
            s[j][2] *= 0.125f; s[j][3] *= 0.125f;
            if (t == qt) {
                const int c = k0 + j*8 + (lane & 3)*2;
                if (c     > r0g) s[j][0] = -CUDART_INF_F;
                if (c + 1 > r0g) s[j][1] = -CUDART_INF_F;
                if (c     > r1g) s[j][2] = -CUDART_INF_F;
                if (c + 1 > r1g) s[j][3] = -CUDART_INF_F;
            }
            mx0 = fmaxf(mx0, fmaxf(s[j][0], s[j][1]));
            mx1 = fmaxf(mx1, fmaxf(s[j][2], s[j][3]));
        }
        mx0 = fmaxf(mx0, __shfl_xor_sync(0xffffffffu, mx0, 1));
        mx0 = fmaxf(mx0, __shfl_xor_sync(0xffffffffu, mx0, 2));
        mx1 = fmaxf(mx1, __shfl_xor_sync(0xffffffffu, mx1, 1));
        mx1 = fmaxf(mx1, __shfl_xor_sync(0xffffffffu, mx1, 2));
        const float mn0 = fmaxf(m0, mx0), mn1 = fmaxf(m1, mx1);
        const float cr0 = __expf(m0 - mn0), cr1 = __expf(m1 - mn1);
        m0 = mn0; m1 = mn1;

        float sum0 = 0.f, sum1 = 0.f;
        #pragma unroll
        for (int j = 0; j < 8; j++) {
            s[j][0] = __expf(s[j][0] - mn0); s[j][1] = __expf(s[j][1] - mn0);
            s[j][2] = __expf(s[j][2] - mn1); s[j][3] = __expf(s[j][3] - mn1);
            sum0 += s[j][0] + s[j][1];
            sum1 += s[j][2] + s[j][3];
        }
        sum0 += __shfl_xor_sync(0xffffffffu, sum0, 1);
        sum0 += __shfl_xor_sync(0xffffffffu, sum0, 2);
        sum1 += __shfl_xor_sync(0xffffffffu, sum1, 1);
        sum1 += __shfl_xor_sync(0xffffffffu, sum1, 2);
        l0 = l0 * cr0 + sum0;
        l1 = l1 * cr1 + sum1;
        #pragma unroll
        for (int j = 0; j < 8; j++) {
            o[j][0] *= cr0; o[j][1] *= cr0;
            o[j][2] *= cr1; o[j][3] *= cr1;
        }

        // ---- O += P V (P hi/lo from S-acc registers, V via ldsm.trans) ----
        #pragma unroll
        for (int kt = 0; kt < 4; kt++) {
            uint32_t ph[4], pl[4];
            #pragma unroll
            for (int u = 0; u < 4; u++) {
                const int jj = 2*kt + (u >> 1);
                const float pa = s[jj][(u & 1)*2], pb = s[jj][(u & 1)*2 + 1];
                __nv_bfloat162 hh, ll;
                split2(pa, hh.x, ll.x);
                split2(pb, hh.y, ll.y);
                ph[u] = *(uint32_t*)&hh;
                pl[u] = *(uint32_t*)&ll;
            }
            // reorder: A-frag regs = {row r k-half0},{row r+8 k-half0},{row r k-half1},{row r+8 k-half1}
            uint32_t pha[4] = { ph[0], ph[1], ph[2], ph[3] };
            uint32_t pla[4] = { pl[0], pl[1], pl[2], pl[3] };
            #pragma unroll
            for (int nb = 0; nb < 4; nb++) {
                uint32_t vh[4], vl[4];
                const uint32_t va = voff + (uint32_t)(kt*16*144) + (uint32_t)(nb*32);
                LDSM4T(vh, sV  + va);
                LDSM4T(vl, sVl + va);
                #pragma unroll
                for (int f = 0; f < 2; f++) {
                    float* dd = o[nb*2 + f];
                    MMA16816(dd, pha, vh[2*f], vh[2*f+1]);
                    MMA16816(dd, pha, vl[2*f], vl[2*f+1]);
                    MMA16816(dd, pla, vh[2*f], vh[2*f+1]);
                }
            }
        }
        __syncthreads();
    }

    // ---- epilogue: normalize + bf16 split ----
    const float inv0 = 1.0f / l0, inv1 = 1.0f / l1;
    const size_t tok0 = (size_t)b * SS + r0g;
    const size_t tok1 = tok0 + 8;
    #pragma unroll
    for (int j = 0; j < 8; j++) {
        const int col = h*DH + j*8 + (lane & 3)*2;
        __nv_bfloat162 h0, l0b, h1, l1b;
        split2(o[j][0]*inv0, h0.x, l0b.x);
        split2(o[j][1]*inv0, h0.y, l0b.y);
        split2(o[j][2]*inv1, h1.x, l1b.x);
        split2(o[j][3]*inv1, h1.y, l1b.y);
        *(__nv_bfloat162*)(Oh + tok0*DM + col) = h0;
        *(__nv_bfloat162*)(Ol + tok0*DM + col) = l0b;
        *(__nv_bfloat162*)(Oh + tok1*DM + col) = h1;
        *(__nv_bfloat162*)(Ol + tok1*DM + col) = l1b;
    }
}

// A-frag register order note: ldmatrix x4 returns mats in address-group order
// mat0=(r,k0-7), mat1=(r+8,k0-7), mat2=(r,k8-15), mat3=(r+8,k8-15); my ph[u]
// packing above builds u0=(row r, khalf from jj=2kt)... mapping: u=0 -> jj=2kt,
// rows r (s[..][0..1]) = {r, khalf0}; u=1 -> jj=2kt, s[..][2..3] = {r+8, khalf0};
// u=2 -> jj=2kt+1 = {r, khalf1}; u=3 = {r+8, khalf1}.  Matches.

// ---------------- launch ----------------
extern "C" void kernel_launch(void* const* d_in, const int* in_sizes, int n_in,
                              void* d_out, int out_size) {
    const float* x   = (const float*)d_in[0];
    const int*   pos = (const int*)  d_in[1];
    const float* qw  = (const float*)d_in[2];
    const float* kw  = (const float*)d_in[3];
    const float* vw  = (const float*)d_in[4];
    const float* ow  = (const float*)d_in[5];
    const float* g1  = (const float*)d_in[6];
    const float* g2  = (const float*)d_in[7];
    const float* w1  = (const float*)d_in[8];
    const float* w2  = (const float*)d_in[9];
    const float* w3  = (const float*)d_in[10];
    float* out = (float*)d_out;

    __nv_bfloat16 *xnh, *xnl, *qkvh, *qkvl, *ath, *atl, *hnh, *hnl, *swh, *swl;
    __nv_bfloat16 *wqkvh, *wqkvl, *owh, *owl, *w13h, *w13l, *w2h, *w2l;
    float *res1;
    cudaGetSymbolAddress((void**)&xnh, g_xn_h);   cudaGetSymbolAddress((void**)&xnl, g_xn_l);
    cudaGetSymbolAddress((void**)&qkvh, g_qkv_h); cudaGetSymbolAddress((void**)&qkvl, g_qkv_l);
    cudaGetSymbolAddress((void**)&ath, g_at_h);   cudaGetSymbolAddress((void**)&atl, g_at_l);
    cudaGetSymbolAddress((void**)&res1, g_res1);
    cudaGetSymbolAddress((void**)&hnh, g_hn_h);   cudaGetSymbolAddress((void**)&hnl, g_hn_l);
    cudaGetSymbolAddress((void**)&swh, g_sw_h);   cudaGetSymbolAddress((void**)&swl, g_sw_l);
    cudaGetSymbolAddress((void**)&wqkvh, g_wqkv_h); cudaGetSymbolAddress((void**)&wqkvl, g_wqkv_l);
    cudaGetSymbolAddress((void**)&owh, g_ow_h);   cudaGetSymbolAddress((void**)&owl, g_ow_l);
    cudaGetSymbolAddress((void**)&w13h, g_w13_h); cudaGetSymbolAddress((void**)&w13l, g_w13_l);
    cudaGetSymbolAddress((void**)&w2h, g_w2_h);   cudaGetSymbolAddress((void**)&w2l, g_w2_l);

    const int GEMM_SMEM = 2 * STAGE;   // 147456
    cudaFuncSetAttribute(gemm_mma_bf16x3<0>, cudaFuncAttributeMaxDynamicSharedMemorySize, GEMM_SMEM);
    cudaFuncSetAttribute(gemm_mma_bf16x3<1>, cudaFuncAttributeMaxDynamicSharedMemorySize, GEMM_SMEM);
    cudaFuncSetAttribute(gemm_mma_bf16x3<2>, cudaFuncAttributeMaxDynamicSharedMemorySize, GEMM_SMEM);
    cudaFuncSetAttribute(attn_mma_kernel, cudaFuncAttributeMaxDynamicSharedMemorySize, ATT_SMEM);

    // rope table
    rope_table_kernel<<<SS, 32>>>(pos);

    // weight splits
    const int MM = 1024 * 1024;
    split_kernel<<<MM/4/256, 256>>>(qw, wqkvh,        wqkvl,        MM/4);
    split_kernel<<<MM/4/256, 256>>>(kw, wqkvh + MM,   wqkvl + MM,   MM/4);
    split_kernel<<<MM/4/256, 256>>>(vw, wqkvh + 2*MM, wqkvl + 2*MM, MM/4);
    split_inter_kernel<<<MM/256, 256>>>(w1, w13h, w13l, MM, 0);
    split_inter_kernel<<<MM/256, 256>>>(w3, w13h, w13l, MM, 1);
    split_kernel<<<MM/4/256, 256>>>(ow, owh, owl, MM/4);
    split_kernel<<<MM/256,   256>>>(w2, w2h, w2l, MM);

    // 1) rmsnorm(x) -> split
    rmsnorm_split_kernel<<<MTOK, 256>>>(x, g1, xnh, xnl);

    // 2) fused QKV projection + rope + split  [8192,3072]
    gemm_mma_bf16x3<1><<<dim3(LDX/128, MTOK/128), 256, GEMM_SMEM>>>(
        xnh, xnl, wqkvh, wqkvl, nullptr, nullptr, qkvh, qkvl, LDX, DM);

    // 3) HMMA flash attention -> split bf16
    attn_mma_kernel<<<dim3(SS/64, BB*NH), 128, ATT_SMEM>>>(qkvh, qkvl, ath, atl);

    // 4) O projection + residual(x) -> res1 fp32
    gemm_mma_bf16x3<0><<<dim3(DM/128, MTOK/128), 256, GEMM_SMEM>>>(
        ath, atl, owh, owl, x, res1, nullptr, nullptr, DM, DM);

    // 5) rmsnorm(res1) -> split
    rmsnorm_split_kernel<<<MTOK, 256>>>(res1, g2, hnh, hnl);

    // 6) fused W1||W3 (interleaved) + swiglu + split  [8192,8192]->[8192,4096]
    gemm_mma_bf16x3<2><<<dim3(2*DFF/128, MTOK/128), 256, GEMM_SMEM>>>(
        hnh, hnl, w13h, w13l, nullptr, nullptr, swh, swl, 2*DFF, DM);

    // 7) down projection + residual(res1) -> out
    gemm_mma_bf16x3<0><<<dim3(DM/128, MTOK/128), 256, GEMM_SMEM>>>(
        swh, swl, w2h, w2l, res1, out, nullptr, nullptr, DM, DFF);
}

// round 6
// speedup vs baseline: 3.7404x; 1.0503x over previous
#include <cuda_runtime.h>
#include <cuda_bf16.h>
#include <math.h>
#include <math_constants.h>
#include <cstdint>

#define BB   4
#define SS   2048
#define DM   1024
#define NH   16
#define DH   64
#define DFF  4096
#define MTOK (BB*SS)      // 8192
#define LDX  3072

// ---------------- helpers ----------------
__device__ __forceinline__ uint32_t smem_to_u32(const void* p) {
    uint32_t a;
    asm("{ .reg .u64 t; cvta.to.shared.u64 t, %1; cvt.u32.u64 %0, t; }" : "=r"(a) : "l"(p));
    return a;
}
#define CP_ASYNC16(s, g) asm volatile("cp.async.cg.shared.global [%0], [%1], 16;" :: "r"(s), "l"(g))
#define CP_COMMIT()      asm volatile("cp.async.commit_group;" ::: "memory")
#define CP_WAIT1()       asm volatile("cp.async.wait_group 1;" ::: "memory")
#define CP_WAIT0()       asm volatile("cp.async.wait_group 0;" ::: "memory")
#define LDSM4(rg, addr) \
    asm volatile("ldmatrix.sync.aligned.m8n8.x4.shared.b16 {%0,%1,%2,%3}, [%4];" \
        : "=r"((rg)[0]), "=r"((rg)[1]), "=r"((rg)[2]), "=r"((rg)[3]) : "r"(addr))
#define LDSM4T(rg, addr) \
    asm volatile("ldmatrix.sync.aligned.m8n8.x4.trans.shared.b16 {%0,%1,%2,%3}, [%4];" \
        : "=r"((rg)[0]), "=r"((rg)[1]), "=r"((rg)[2]), "=r"((rg)[3]) : "r"(addr))
#define MMA16816(d, a, b0v, b1v) \
    asm volatile("mma.sync.aligned.m16n8k16.row.col.f32.bf16.bf16.f32 " \
        "{%0,%1,%2,%3}, {%4,%5,%6,%7}, {%8,%9}, {%0,%1,%2,%3};" \
        : "+f"((d)[0]), "+f"((d)[1]), "+f"((d)[2]), "+f"((d)[3]) \
        : "r"((a)[0]), "r"((a)[1]), "r"((a)[2]), "r"((a)[3]), "r"(b0v), "r"(b1v))

// ---------------- scratch (__device__ globals) ----------------
static __device__ __nv_bfloat16 g_xn_h[(size_t)MTOK*DM],  g_xn_l[(size_t)MTOK*DM];
static __device__ __nv_bfloat16 g_qkv_h[(size_t)MTOK*LDX], g_qkv_l[(size_t)MTOK*LDX];
static __device__ __nv_bfloat16 g_at_h[(size_t)MTOK*DM],  g_at_l[(size_t)MTOK*DM];
static __device__ float         g_res1[(size_t)MTOK*DM];
static __device__ __nv_bfloat16 g_hn_h[(size_t)MTOK*DM],  g_hn_l[(size_t)MTOK*DM];
static __device__ __nv_bfloat16 g_sw_h[(size_t)MTOK*DFF], g_sw_l[(size_t)MTOK*DFF];
static __device__ __nv_bfloat16 g_wqkv_h[3072*1024], g_wqkv_l[3072*1024];
static __device__ __nv_bfloat16 g_ow_h [1024*1024],  g_ow_l [1024*1024];
static __device__ __nv_bfloat16 g_w13_h[2*DFF*1024], g_w13_l[2*DFF*1024];   // interleaved rows
static __device__ __nv_bfloat16 g_w2_h [1024*DFF],   g_w2_l [1024*DFF];
static __device__ float g_cs[SS*32], g_sn[SS*32];

// ---------------- fp32 -> (hi,lo) bf16 split ----------------
__device__ __forceinline__ void split2(float v, __nv_bfloat16& h, __nv_bfloat16& l) {
    h = __float2bfloat16(v);
    l = __float2bfloat16(v - __bfloat162float(h));
}

__global__ void rope_table_kernel(const int* __restrict__ pos) {
    const int s = blockIdx.x, i = threadIdx.x;   // 2048 x 32
    const float inv = exp2f(-(float)i * (13.287712379549449f / 32.0f));
    const float a = (float)pos[s] * inv;
    float sn, cs;
    sincosf(a, &sn, &cs);
    g_cs[s*32 + i] = cs;
    g_sn[s*32 + i] = sn;
}

__global__ void split_kernel(const float* __restrict__ x,
                             __nv_bfloat16* __restrict__ h,
                             __nv_bfloat16* __restrict__ l, int n4) {
    int i = blockIdx.x * blockDim.x + threadIdx.x;
    if (i >= n4) return;
    float4 v = ((const float4*)x)[i];
    __nv_bfloat162 h0, h1, l0, l1;
    split2(v.x, h0.x, l0.x); split2(v.y, h0.y, l0.y);
    split2(v.z, h1.x, l1.x); split2(v.w, h1.y, l1.y);
    ((__nv_bfloat162*)h)[2*i]   = h0; ((__nv_bfloat162*)h)[2*i+1] = h1;
    ((__nv_bfloat162*)l)[2*i]   = l0; ((__nv_bfloat162*)l)[2*i+1] = l1;
}

// interleaved weight split: src row n -> dst row 2n+off  (K=1024)
__global__ void split_inter_kernel(const float* __restrict__ x,
                                   __nv_bfloat16* __restrict__ h,
                                   __nv_bfloat16* __restrict__ l,
                                   int n4, int off) {
    int i = blockIdx.x * blockDim.x + threadIdx.x;
    if (i >= n4) return;
    const int row = i >> 8;            // 256 float4 per row of 1024
    const int c4  = i & 255;
    float4 v = ((const float4*)x)[i];
    __nv_bfloat162 h0, h1, l0, l1;
    split2(v.x, h0.x, l0.x); split2(v.y, h0.y, l0.y);
    split2(v.z, h1.x, l1.x); split2(v.w, h1.y, l1.y);
    const size_t o2 = ((size_t)(2*row + off) * 1024 + c4*4) >> 1;
    ((__nv_bfloat162*)h)[o2]   = h0; ((__nv_bfloat162*)h)[o2+1] = h1;
    ((__nv_bfloat162*)l)[o2]   = l0; ((__nv_bfloat162*)l)[o2+1] = l1;
}

// ---------------- RMSNorm -> split bf16 ----------------
__global__ void rmsnorm_split_kernel(const float* __restrict__ x,
                                     const float* __restrict__ g,
                                     __nv_bfloat16* __restrict__ yh,
                                     __nv_bfloat16* __restrict__ yl) {
    const int row = blockIdx.x;
    const float4* xr = (const float4*)(x + (size_t)row * DM);
    const int t = threadIdx.x;
    float4 xv = xr[t];
    float ss = xv.x*xv.x + xv.y*xv.y + xv.z*xv.z + xv.w*xv.w;
    #pragma unroll
    for (int o = 16; o; o >>= 1) ss += __shfl_xor_sync(0xffffffffu, ss, o);
    __shared__ float sred[8];
    const int warp = t >> 5, lane = t & 31;
    if (lane == 0) sred[warp] = ss;
    __syncthreads();
    if (warp == 0) {
        float v = (lane < 8) ? sred[lane] : 0.f;
        #pragma unroll
        for (int o = 4; o; o >>= 1) v += __shfl_xor_sync(0xffffffffu, v, o);
        if (lane == 0) sred[0] = v;
    }
    __syncthreads();
    const float inv = rsqrtf(sred[0] * (1.0f/(float)DM) + 1e-5f);
    const float4 gv = ((const float4*)g)[t];
    float y0 = xv.x*inv*gv.x, y1 = xv.y*inv*gv.y, y2 = xv.z*inv*gv.z, y3 = xv.w*inv*gv.w;
    __nv_bfloat162 h0, h1, l0, l1;
    split2(y0, h0.x, l0.x); split2(y1, h0.y, l0.y);
    split2(y2, h1.x, l1.x); split2(y3, h1.y, l1.y);
    const size_t b2 = (size_t)row * (DM/2) + 2*t;
    ((__nv_bfloat162*)yh)[b2]   = h0; ((__nv_bfloat162*)yh)[b2+1] = h1;
    ((__nv_bfloat162*)yl)[b2]   = l0; ((__nv_bfloat162*)yl)[b2+1] = l1;
}

// ---------------- mma.sync bf16x3 GEMM, CTA 128x256, warp 64x64 ---------------
// MODE 0: C fp32 (+R).  MODE 1: rope (cols<2048) + split -> Ch/Cl (stride N).
// MODE 2: swiglu on (even,odd) col pairs + split -> Ch/Cl (stride N/2).
#define ROWB   144
#define A_OFF_L 18432            // 128*144
#define B_OFF   36864            // 2*128*144
#define B_OFF_L 73728            // B_OFF + 256*144
#define STAGE  110592            // (128+128+256+256)*144
template<int MODE>
__global__ __launch_bounds__(256, 1)
void gemm_mma_bf16x3(const __nv_bfloat16* __restrict__ Ah,
                     const __nv_bfloat16* __restrict__ Al,
                     const __nv_bfloat16* __restrict__ Bh,
                     const __nv_bfloat16* __restrict__ Bl,
                     const float* __restrict__ R,
                     float* __restrict__ C,
                     __nv_bfloat16* __restrict__ Ch,
                     __nv_bfloat16* __restrict__ Cl,
                     int N, int K) {
    extern __shared__ char smem[];
    const uint32_t sbase = smem_to_u32(smem);
    const int tid  = threadIdx.x;
    const int lane = tid & 31;
    const int wid  = tid >> 5;
    const int bm = blockIdx.y * 128;
    const int bn = blockIdx.x * 256;
    const int m0w = (wid & 1) * 64;
    const int n0w = (wid >> 1) * 64;

    float acc[4][8][4];
    #pragma unroll
    for (int i = 0; i < 4; i++)
        #pragma unroll
        for (int j = 0; j < 8; j++)
            #pragma unroll
            for (int q = 0; q < 4; q++) acc[i][j][q] = 0.f;

    const int nch = K >> 6;

    auto load_stage = [&](int s, int c) {
        const int k0 = c << 6;
        const uint32_t st = sbase + (uint32_t)s * STAGE;
        #pragma unroll
        for (int i = 0; i < 4; ++i) {           // A: 128 rows, hi+lo
            const int idx = tid + (i << 8);
            const int row = idx >> 3, cc = idx & 7;
            const uint32_t so = (uint32_t)(row * ROWB + cc * 16);
            const size_t ga = (size_t)(bm + row) * K + k0 + cc * 8;
            CP_ASYNC16(st + so,           (const char*)(Ah + ga));
            CP_ASYNC16(st + A_OFF_L + so, (const char*)(Al + ga));
        }
        #pragma unroll
        for (int i = 0; i < 8; ++i) {           // B: 256 rows, hi+lo
            const int idx = tid + (i << 8);
            const int row = idx >> 3, cc = idx & 7;
            const uint32_t so = (uint32_t)(row * ROWB + cc * 16);
            const size_t gb = (size_t)(bn + row) * K + k0 + cc * 8;
            CP_ASYNC16(st + B_OFF + so,   (const char*)(Bh + gb));
            CP_ASYNC16(st + B_OFF_L + so, (const char*)(Bl + gb));
        }
        CP_COMMIT();
    };

    const int g = lane >> 3, r = lane & 7;
    const uint32_t aoff = (uint32_t)((m0w + (g & 1) * 8 + r) * ROWB + ((g >> 1) * 8) * 2);
    const uint32_t boff = (uint32_t)(B_OFF + (n0w + (g >> 1) * 8 + r) * ROWB + ((g & 1) * 8) * 2);

    load_stage(0, 0);

    for (int c = 0; c < nch; ++c) {
        if (c + 1 < nch) { load_stage((c + 1) & 1, c + 1); CP_WAIT1(); }
        else             { CP_WAIT0(); }
        __syncthreads();

        const uint32_t st = sbase + (uint32_t)(c & 1) * STAGE;
        #pragma unroll
        for (int ks = 0; ks < 4; ++ks) {
            uint32_t AhF[4][4], AlF[4][4];
            const uint32_t ab = st + aoff + (uint32_t)(ks * 32);
            #pragma unroll
            for (int mi = 0; mi < 4; ++mi) {
                LDSM4(AhF[mi], ab + (uint32_t)(mi * 16 * ROWB));
                LDSM4(AlF[mi], ab + A_OFF_L + (uint32_t)(mi * 16 * ROWB));
            }
            const uint32_t bb = st + boff + (uint32_t)(ks * 32);
            #pragma unroll
            for (int nb = 0; nb < 4; ++nb) {
                uint32_t BhF[4], BlF[4];
                LDSM4(BhF, bb + (uint32_t)(nb * 16 * ROWB));
                LDSM4(BlF, bb + (uint32_t)(256 * ROWB) + (uint32_t)(nb * 16 * ROWB));
                #pragma unroll
                for (int mi = 0; mi < 4; ++mi)
                    #pragma unroll
                    for (int hf = 0; hf < 2; ++hf) {
                        float* d = acc[mi][nb * 2 + hf];
                        MMA16816(d, AhF[mi], BhF[hf*2], BhF[hf*2+1]);
                        MMA16816(d, AhF[mi], BlF[hf*2], BlF[hf*2+1]);
                        MMA16816(d, AlF[mi], BhF[hf*2], BhF[hf*2+1]);
                    }
            }
        }
        __syncthreads();
    }

    const int erow = lane >> 2;
    const int ecol = (lane & 3) * 2;
    #pragma unroll
    for (int mi = 0; mi < 4; ++mi) {
        #pragma unroll
        for (int nj = 0; nj < 8; ++nj) {
            float* d = acc[mi][nj];
            const int row0 = bm + m0w + mi * 16 + erow;
            const int row1 = row0 + 8;
            const int cg   = bn + n0w + nj * 8 + ecol;
            if (MODE == 0) {
                const size_t o0 = (size_t)row0 * N + cg;
                const size_t o1 = (size_t)row1 * N + cg;
                float2 v0 = make_float2(d[0], d[1]);
                float2 v1 = make_float2(d[2], d[3]);
                if (R) {
                    const float2 r0 = *(const float2*)(R + o0);
                    const float2 r1 = *(const float2*)(R + o1);
                    v0.x += r0.x; v0.y += r0.y;
                    v1.x += r1.x; v1.y += r1.y;
                }
                *(float2*)(C + o0) = v0;
                *(float2*)(C + o1) = v1;
            } else if (MODE == 1) {
                float a0 = d[0], a1 = d[1], b0 = d[2], b1 = d[3];
                if (cg < 2048) {
                    const int i = (cg & 63) >> 1;
                    const int s0 = (row0 & (SS-1))*32 + i;
                    const int s1 = (row1 & (SS-1))*32 + i;
                    const float c0 = g_cs[s0], n0 = g_sn[s0];
                    const float c1 = g_cs[s1], n1 = g_sn[s1];
                    float t0 = a0*c0 - a1*n0, t1 = a0*n0 + a1*c0;
                    a0 = t0; a1 = t1;
                    float u0 = b0*c1 - b1*n1, u1 = b0*n1 + b1*c1;
                    b0 = u0; b1 = u1;
                }
                __nv_bfloat162 h0, l0, h1, l1;
                split2(a0, h0.x, l0.x); split2(a1, h0.y, l0.y);
                split2(b0, h1.x, l1.x); split2(b1, h1.y, l1.y);
                const size_t o0 = (size_t)row0 * N + cg;
                const size_t o1 = (size_t)row1 * N + cg;
                *(__nv_bfloat162*)(Ch + o0) = h0;
                *(__nv_bfloat162*)(Cl + o0) = l0;
                *(__nv_bfloat162*)(Ch + o1) = h1;
                *(__nv_bfloat162*)(Cl + o1) = l1;
            } else {  // MODE 2: swiglu, (even,odd) = (a, gate)
                const int j = cg >> 1;
                const int NC = N >> 1;
                const float sl0 = d[0] / (1.f + __expf(-d[0])) * d[1];
                const float sl1 = d[2] / (1.f + __expf(-d[2])) * d[3];
                __nv_bfloat16 h0, l0, h1, l1;
                split2(sl0, h0, l0);
                split2(sl1, h1, l1);
                Ch[(size_t)row0 * NC + j] = h0;
                Cl[(size_t)row0 * NC + j] = l0;
                Ch[(size_t)row1 * NC + j] = h1;
                Cl[(size_t)row1 * NC + j] = l1;
            }
        }
    }
}

// ---------------- HMMA flash attention (bf16x3 scores, fp32 softmax) ----------
#define ATB (64*144)
#define ATT_SMEM (10*ATB)
__global__ __launch_bounds__(128)
void attn_mma_kernel(const __nv_bfloat16* __restrict__ Xh,
                     const __nv_bfloat16* __restrict__ Xl,
                     __nv_bfloat16* __restrict__ Oh,
                     __nv_bfloat16* __restrict__ Ol) {
    extern __shared__ char sm[];
    const uint32_t sQh = smem_to_u32(sm);
    const uint32_t sQl = sQh + ATB;
    const uint32_t sSt = sQh + 2*ATB;

    const int tid = threadIdx.x, lane = tid & 31, warp = tid >> 5;
    const int bh = blockIdx.y, b = bh >> 4, h = bh & (NH-1);
    const int qt = gridDim.x - 1 - blockIdx.x;
    const int q0 = qt * 64;
    const size_t rowbase = (size_t)b * SS * LDX;
    const int colQ = h*DH, colK = 1024 + h*DH, colV = 2048 + h*DH;

    #pragma unroll
    for (int i = 0; i < 4; i++) {
        const int idx = tid + i*128;
        const int r = idx >> 3, c = idx & 7;
        const uint32_t so = (uint32_t)(r*144 + c*16);
        const size_t ga = rowbase + (size_t)(q0 + r)*LDX + colQ + c*8;
        CP_ASYNC16(sQh + so, (const char*)(Xh + ga));
        CP_ASYNC16(sQl + so, (const char*)(Xl + ga));
    }
    CP_COMMIT();

    auto load_kv = [&](int t, int s) {
        const int k0 = t * 64;
        #pragma unroll
        for (int i = 0; i < 4; i++) {
            const int idx = tid + i*128;
            const int r = idx >> 3, c = idx & 7;
            const uint32_t so = (uint32_t)s*4*ATB + (uint32_t)(r*144 + c*16);
            const size_t gk = rowbase + (size_t)(k0 + r)*LDX + colK + c*8;
            const size_t gv = rowbase + (size_t)(k0 + r)*LDX + colV + c*8;
            CP_ASYNC16(sSt + so,         (const char*)(Xh + gk));
            CP_ASYNC16(sSt + ATB + so,   (const char*)(Xl + gk));
            CP_ASYNC16(sSt + 2*ATB + so, (const char*)(Xh + gv));
            CP_ASYNC16(sSt + 3*ATB + so, (const char*)(Xl + gv));
        }
        CP_COMMIT();
    };
    load_kv(0, 0);

    const int g = lane >> 3, rr = lane & 7;
    const uint32_t aoff = (uint32_t)((warp*16 + (g&1)*8 + rr)*144 + (g>>1)*16);
    const uint32_t boff = (uint32_t)(((g>>1)*8 + rr)*144 + (g&1)*16);
    const uint32_t voff = (uint32_t)(((g&1)*8 + rr)*144 + (lane>>4)*16);

    float m0 = -CUDART_INF_F, m1 = -CUDART_INF_F, l0 = 0.f, l1 = 0.f;
    float o[8][4];
    #pragma unroll
    for (int j = 0; j < 8; j++)
        #pragma unroll
        for (int q = 0; q < 4; q++) o[j][q] = 0.f;

    const int r0g = q0 + warp*16 + (lane >> 2);
    const int r1g = r0g + 8;
    const int ntiles = qt + 1;

    for (int t = 0; t < ntiles; t++) {
        if (t + 1 < ntiles) { load_kv(t + 1, (t + 1) & 1); CP_WAIT1(); }
        else                { CP_WAIT0(); }
        __syncthreads();

        const uint32_t sK  = sSt + (uint32_t)(t & 1)*4*ATB;
        const uint32_t sKl = sK + ATB;
        const uint32_t sV  = sK + 2*ATB;
        const uint32_t sVl = sK + 3*ATB;

        float s[8][4];
        #pragma unroll
        for (int j = 0; j < 8; j++)
            #pragma unroll
            for (int q = 0; q < 4; q++) s[j][q] = 0.f;

        #pragma unroll
        for (int d = 0; d < 4; d++) {
            uint32_t qh[4], ql[4];
            LDSM4(qh, sQh + aoff + d*32);
            LDSM4(ql, sQl + aoff + d*32);
            #pragma unroll
            for (int nb = 0; nb < 4; nb++) {
                uint32_t kh[4], kl[4];
                LDSM4(kh, sK  + boff + (uint32_t)(nb*16*144) + d*32);
                LDSM4(kl, sKl + boff + (uint32_t)(nb*16*144) + d*32);
                #pragma unroll
                for (int f = 0; f < 2; f++) {
                    float* dd = s[nb*2 + f];
                    MMA16816(dd, qh, kh[2*f], kh[2*f+1]);
                    MMA16816(dd, qh, kl[2*f], kl[2*f+1]);
                    MMA16816(dd, ql, kh[2*f], kh[2*f+1]);
                }
            }
        }

        const int k0 = t * 64;
        float mx0 = -CUDART_INF_F, mx1 = -CUDART_INF_F;
        #pragma unroll
        for (int j = 0; j < 8; j++) {
            s[j][0] *= 0.125f; s[j][1] *= 0.125f;
            s[j][2] *= 0.125f; s[j][3] *= 0.125f;
            if (t == qt) {
                const int c = k0 + j*8 + (lane & 3)*2;
                if (c     > r0g) s[j][0] = -CUDART_INF_F;
                if (c + 1 > r0g) s[j][1] = -CUDART_INF_F;
                if (c     > r1g) s[j][2] = -CUDART_INF_F;
                if (c + 1 > r1g) s[j][3] = -CUDART_INF_F;
            }
            mx0 = fmaxf(mx0, fmaxf(s[j][0], s[j][1]));
            mx1 = fmaxf(mx1, fmaxf(s[j][2], s[j][3]));
        }
        mx0 = fmaxf(mx0, __shfl_xor_sync(0xffffffffu, mx0, 1));
        mx0 = fmaxf(mx0, __shfl_xor_sync(0xffffffffu, mx0, 2));
        mx1 = fmaxf(mx1, __shfl_xor_sync(0xffffffffu, mx1, 1));
        mx1 = fmaxf(mx1, __shfl_xor_sync(0xffffffffu, mx1, 2));
        const float mn0 = fmaxf(m0, mx0), mn1 = fmaxf(m1, mx1);
        const float cr0 = __expf(m0 - mn0), cr1 = __expf(m1 - mn1);
        m0 = mn0; m1 = mn1;

        float sum0 = 0.f, sum1 = 0.f;
        #pragma unroll
        for (int j = 0; j < 8; j++) {
            s[j][0] = __expf(s[j][0] - mn0); s[j][1] = __expf(s[j][1] - mn0);
            s[j][2] = __expf(s[j][2] - mn1); s[j][3] = __expf(s[j][3] - mn1);
            sum0 += s[j][0] + s[j][1];
            sum1 += s[j][2] + s[j][3];
        }
        sum0 += __shfl_xor_sync(0xffffffffu, sum0, 1);
        sum0 += __shfl_xor_sync(0xffffffffu, sum0, 2);
        sum1 += __shfl_xor_sync(0xffffffffu, sum1, 1);
        sum1 += __shfl_xor_sync(0xffffffffu, sum1, 2);
        l0 = l0 * cr0 + sum0;
        l1 = l1 * cr1 + sum1;
        #pragma unroll
        for (int j = 0; j < 8; j++) {
            o[j][0] *= cr0; o[j][1] *= cr0;
            o[j][2] *= cr1; o[j][3] *= cr1;
        }

        #pragma unroll
        for (int kt = 0; kt < 4; kt++) {
            uint32_t ph[4], pl[4];
            #pragma unroll
            for (int u = 0; u < 4; u++) {
                const int jj = 2*kt + (u >> 1);
                const float pa = s[jj][(u & 1)*2], pb = s[jj][(u & 1)*2 + 1];
                __nv_bfloat162 hh, ll;
                split2(pa, hh.x, ll.x);
                split2(pb, hh.y, ll.y);
                ph[u] = *(uint32_t*)&hh;
                pl[u] = *(uint32_t*)&ll;
            }
            uint32_t pha[4] = { ph[0], ph[1], ph[2], ph[3] };
            uint32_t pla[4] = { pl[0], pl[1], pl[2], pl[3] };
            #pragma unroll
            for (int nb = 0; nb < 4; nb++) {
                uint32_t vh[4], vl[4];
                const uint32_t va = voff + (uint32_t)(kt*16*144) + (uint32_t)(nb*32);
                LDSM4T(vh, sV  + va);
                LDSM4T(vl, sVl + va);
                #pragma unroll
                for (int f = 0; f < 2; f++) {
                    float* dd = o[nb*2 + f];
                    MMA16816(dd, pha, vh[2*f], vh[2*f+1]);
                    MMA16816(dd, pha, vl[2*f], vl[2*f+1]);
                    MMA16816(dd, pla, vh[2*f], vh[2*f+1]);
                }
            }
        }
        __syncthreads();
    }

    const float inv0 = 1.0f / l0, inv1 = 1.0f / l1;
    const size_t tok0 = (size_t)b * SS + r0g;
    const size_t tok1 = tok0 + 8;
    #pragma unroll
    for (int j = 0; j < 8; j++) {
        const int col = h*DH + j*8 + (lane & 3)*2;
        __nv_bfloat162 h0, l0b, h1, l1b;
        split2(o[j][0]*inv0, h0.x, l0b.x);
        split2(o[j][1]*inv0, h0.y, l0b.y);
        split2(o[j][2]*inv1, h1.x, l1b.x);
        split2(o[j][3]*inv1, h1.y, l1b.y);
        *(__nv_bfloat162*)(Oh + tok0*DM + col) = h0;
        *(__nv_bfloat162*)(Ol + tok0*DM + col) = l0b;
        *(__nv_bfloat162*)(Oh + tok1*DM + col) = h1;
        *(__nv_bfloat162*)(Ol + tok1*DM + col) = l1b;
    }
}

// ---------------- launch ----------------
extern "C" void kernel_launch(void* const* d_in, const int* in_sizes, int n_in,
                              void* d_out, int out_size) {
    const float* x   = (const float*)d_in[0];
    const int*   pos = (const int*)  d_in[1];
    const float* qw  = (const float*)d_in[2];
    const float* kw  = (const float*)d_in[3];
    const float* vw  = (const float*)d_in[4];
    const float* ow  = (const float*)d_in[5];
    const float* g1  = (const float*)d_in[6];
    const float* g2  = (const float*)d_in[7];
    const float* w1  = (const float*)d_in[8];
    const float* w2  = (const float*)d_in[9];
    const float* w3  = (const float*)d_in[10];
    float* out = (float*)d_out;

    __nv_bfloat16 *xnh, *xnl, *qkvh, *qkvl, *ath, *atl, *hnh, *hnl, *swh, *swl;
    __nv_bfloat16 *wqkvh, *wqkvl, *owh, *owl, *w13h, *w13l, *w2h, *w2l;
    float *res1;
    cudaGetSymbolAddress((void**)&xnh, g_xn_h);   cudaGetSymbolAddress((void**)&xnl, g_xn_l);
    cudaGetSymbolAddress((void**)&qkvh, g_qkv_h); cudaGetSymbolAddress((void**)&qkvl, g_qkv_l);
    cudaGetSymbolAddress((void**)&ath, g_at_h);   cudaGetSymbolAddress((void**)&atl, g_at_l);
    cudaGetSymbolAddress((void**)&res1, g_res1);
    cudaGetSymbolAddress((void**)&hnh, g_hn_h);   cudaGetSymbolAddress((void**)&hnl, g_hn_l);
    cudaGetSymbolAddress((void**)&swh, g_sw_h);   cudaGetSymbolAddress((void**)&swl, g_sw_l);
    cudaGetSymbolAddress((void**)&wqkvh, g_wqkv_h); cudaGetSymbolAddress((void**)&wqkvl, g_wqkv_l);
    cudaGetSymbolAddress((void**)&owh, g_ow_h);   cudaGetSymbolAddress((void**)&owl, g_ow_l);
    cudaGetSymbolAddress((void**)&w13h, g_w13_h); cudaGetSymbolAddress((void**)&w13l, g_w13_l);
    cudaGetSymbolAddress((void**)&w2h, g_w2_h);   cudaGetSymbolAddress((void**)&w2l, g_w2_l);

    const int GEMM_SMEM = 2 * STAGE;   // 221184
    cudaFuncSetAttribute(gemm_mma_bf16x3<0>, cudaFuncAttributeMaxDynamicSharedMemorySize, GEMM_SMEM);
    cudaFuncSetAttribute(gemm_mma_bf16x3<1>, cudaFuncAttributeMaxDynamicSharedMemorySize, GEMM_SMEM);
    cudaFuncSetAttribute(gemm_mma_bf16x3<2>, cudaFuncAttributeMaxDynamicSharedMemorySize, GEMM_SMEM);
    cudaFuncSetAttribute(attn_mma_kernel, cudaFuncAttributeMaxDynamicSharedMemorySize, ATT_SMEM);

    // rope table
    rope_table_kernel<<<SS, 32>>>(pos);

    // weight splits
    const int MM = 1024 * 1024;
    split_kernel<<<MM/4/256, 256>>>(qw, wqkvh,        wqkvl,        MM/4);
    split_kernel<<<MM/4/256, 256>>>(kw, wqkvh + MM,   wqkvl + MM,   MM/4);
    split_kernel<<<MM/4/256, 256>>>(vw, wqkvh + 2*MM, wqkvl + 2*MM, MM/4);
    split_inter_kernel<<<MM/256, 256>>>(w1, w13h, w13l, MM, 0);
    split_inter_kernel<<<MM/256, 256>>>(w3, w13h, w13l, MM, 1);
    split_kernel<<<MM/4/256, 256>>>(ow, owh, owl, MM/4);
    split_kernel<<<MM/256,   256>>>(w2, w2h, w2l, MM);

    // 1) rmsnorm(x) -> split
    rmsnorm_split_kernel<<<MTOK, 256>>>(x, g1, xnh, xnl);

    // 2) fused QKV projection + rope + split  [8192,3072]
    gemm_mma_bf16x3<1><<<dim3(LDX/256, MTOK/128), 256, GEMM_SMEM>>>(
        xnh, xnl, wqkvh, wqkvl, nullptr, nullptr, qkvh, qkvl, LDX, DM);

    // 3) HMMA flash attention -> split bf16
    attn_mma_kernel<<<dim3(SS/64, BB*NH), 128, ATT_SMEM>>>(qkvh, qkvl, ath, atl);

    // 4) O projection + residual(x) -> res1 fp32
    gemm_mma_bf16x3<0><<<dim3(DM/256, MTOK/128), 256, GEMM_SMEM>>>(
        ath, atl, owh, owl, x, res1, nullptr, nullptr, DM, DM);

    // 5) rmsnorm(res1) -> split
    rmsnorm_split_kernel<<<MTOK, 256>>>(res1, g2, hnh, hnl);

    // 6) fused W1||W3 (interleaved) + swiglu + split  [8192,8192]->[8192,4096]
    gemm_mma_bf16x3<2><<<dim3(2*DFF/256, MTOK/128), 256, GEMM_SMEM>>>(
        hnh, hnl, w13h, w13l, nullptr, nullptr, swh, swl, 2*DFF, DM);

    // 7) down projection + residual(res1) -> out
    gemm_mma_bf16x3<0><<<dim3(DM/256, MTOK/128), 256, GEMM_SMEM>>>(
        swh, swl, w2h, w2l, res1, out, nullptr, nullptr, DM, DFF);
}

// round 7
// speedup vs baseline: 3.7733x; 1.0088x over previous
#include <cuda_runtime.h>
#include <cuda_bf16.h>
#include <math.h>
#include <math_constants.h>
#include <cstdint>

#define BB   4
#define SS   2048
#define DM   1024
#define NH   16
#define DH   64
#define DFF  4096
#define MTOK (BB*SS)      // 8192
#define LDX  3072

// ---------------- helpers ----------------
__device__ __forceinline__ uint32_t smem_to_u32(const void* p) {
    uint32_t a;
    asm("{ .reg .u64 t; cvta.to.shared.u64 t, %1; cvt.u32.u64 %0, t; }" : "=r"(a) : "l"(p));
    return a;
}
#define CP_ASYNC16(s, g) asm volatile("cp.async.cg.shared.global [%0], [%1], 16;" :: "r"(s), "l"(g))
#define CP_COMMIT()      asm volatile("cp.async.commit_group;" ::: "memory")
#define CP_WAIT0()       asm volatile("cp.async.wait_group 0;" ::: "memory")
#define LDSM4(rg, addr) \
    asm volatile("ldmatrix.sync.aligned.m8n8.x4.shared.b16 {%0,%1,%2,%3}, [%4];" \
        : "=r"((rg)[0]), "=r"((rg)[1]), "=r"((rg)[2]), "=r"((rg)[3]) : "r"(addr))
#define LDSM4T(rg, addr) \
    asm volatile("ldmatrix.sync.aligned.m8n8.x4.trans.shared.b16 {%0,%1,%2,%3}, [%4];" \
        : "=r"((rg)[0]), "=r"((rg)[1]), "=r"((rg)[2]), "=r"((rg)[3]) : "r"(addr))
#define MMA16816(d, a, b0v, b1v) \
    asm volatile("mma.sync.aligned.m16n8k16.row.col.f32.bf16.bf16.f32 " \
        "{%0,%1,%2,%3}, {%4,%5,%6,%7}, {%8,%9}, {%0,%1,%2,%3};" \
        : "+f"((d)[0]), "+f"((d)[1]), "+f"((d)[2]), "+f"((d)[3]) \
        : "r"((a)[0]), "r"((a)[1]), "r"((a)[2]), "r"((a)[3]), "r"(b0v), "r"(b1v))

__device__ __forceinline__ float ex2(float x) {
    float r; asm("ex2.approx.f32 %0, %1;" : "=f"(r) : "f"(x)); return r;
}
__device__ __forceinline__ float rcpa(float x) {
    float r; asm("rcp.approx.f32 %0, %1;" : "=f"(r) : "f"(x)); return r;
}
// 2^y on the FMA pipe (magic round + deg-5 Taylor), rel err ~2e-6
__device__ __forceinline__ float fast_exp2(float y) {
    y = fmaxf(fminf(y, 126.f), -126.f);
    float z = __fadd_rn(y, 12582912.f);
    int   n = __float_as_int(z) - 0x4B400000;
    float f = __fadd_rn(y, -__fadd_rn(z, -12582912.f));
    float p = fmaf(f, 0.0013333558f, 0.0096181291f);
    p = fmaf(f, p, 0.0555041087f);
    p = fmaf(f, p, 0.2402265069f);
    p = fmaf(f, p, 0.6931471806f);
    p = fmaf(f, p, 1.0f);
    return __int_as_float(__float_as_int(p) + (n << 23));
}
// pack (p0,p1) -> bf16x2 hi + bf16x2 lo residual, layout {x=p0, y=p1}
__device__ __forceinline__ void split_pack2(float p0, float p1, uint32_t& h2, uint32_t& l2) {
    asm("cvt.rn.bf16x2.f32 %0, %1, %2;" : "=r"(h2) : "f"(p1), "f"(p0));
    float h0 = __int_as_float(h2 << 16);
    float h1 = __int_as_float(h2 & 0xFFFF0000u);
    float r0 = __fadd_rn(p0, -h0);
    float r1 = __fadd_rn(p1, -h1);
    asm("cvt.rn.bf16x2.f32 %0, %1, %2;" : "=r"(l2) : "f"(r1), "f"(r0));
}

// ---------------- scratch (__device__ globals) ----------------
static __device__ __nv_bfloat16 g_xn_h[(size_t)MTOK*DM],  g_xn_l[(size_t)MTOK*DM];
static __device__ __nv_bfloat16 g_qkv_h[(size_t)MTOK*LDX], g_qkv_l[(size_t)MTOK*LDX];
static __device__ __nv_bfloat16 g_at_h[(size_t)MTOK*DM],  g_at_l[(size_t)MTOK*DM];
static __device__ float         g_res1[(size_t)MTOK*DM];
static __device__ __nv_bfloat16 g_hn_h[(size_t)MTOK*DM],  g_hn_l[(size_t)MTOK*DM];
static __device__ __nv_bfloat16 g_sw_h[(size_t)MTOK*DFF], g_sw_l[(size_t)MTOK*DFF];
static __device__ __nv_bfloat16 g_wqkv_h[3072*1024], g_wqkv_l[3072*1024];
static __device__ __nv_bfloat16 g_ow_h [1024*1024],  g_ow_l [1024*1024];
static __device__ __nv_bfloat16 g_w13_h[2*DFF*1024], g_w13_l[2*DFF*1024];   // interleaved rows
static __device__ __nv_bfloat16 g_w2_h [1024*DFF],   g_w2_l [1024*DFF];
static __device__ float g_cs[SS*32], g_sn[SS*32];

// ---------------- fp32 -> (hi,lo) bf16 split ----------------
__device__ __forceinline__ void split2(float v, __nv_bfloat16& h, __nv_bfloat16& l) {
    h = __float2bfloat16(v);
    l = __float2bfloat16(v - __bfloat162float(h));
}

__global__ void rope_table_kernel(const int* __restrict__ pos) {
    const int s = blockIdx.x, i = threadIdx.x;   // 2048 x 32
    const float inv = exp2f(-(float)i * (13.287712379549449f / 32.0f));
    const float a = (float)pos[s] * inv;
    float sn, cs;
    sincosf(a, &sn, &cs);
    g_cs[s*32 + i] = cs;
    g_sn[s*32 + i] = sn;
}

__global__ void split_kernel(const float* __restrict__ x,
                             __nv_bfloat16* __restrict__ h,
                             __nv_bfloat16* __restrict__ l, int n4) {
    int i = blockIdx.x * blockDim.x + threadIdx.x;
    if (i >= n4) return;
    float4 v = ((const float4*)x)[i];
    uint32_t h0, l0, h1, l1;
    split_pack2(v.x, v.y, h0, l0);
    split_pack2(v.z, v.w, h1, l1);
    ((uint32_t*)h)[2*i]   = h0; ((uint32_t*)h)[2*i+1] = h1;
    ((uint32_t*)l)[2*i]   = l0; ((uint32_t*)l)[2*i+1] = l1;
}

// interleaved weight split: src row n -> dst row 2n+off  (K=1024)
__global__ void split_inter_kernel(const float* __restrict__ x,
                                   __nv_bfloat16* __restrict__ h,
                                   __nv_bfloat16* __restrict__ l,
                                   int n4, int off) {
    int i = blockIdx.x * blockDim.x + threadIdx.x;
    if (i >= n4) return;
    const int row = i >> 8;
    const int c4  = i & 255;
    float4 v = ((const float4*)x)[i];
    uint32_t h0, l0, h1, l1;
    split_pack2(v.x, v.y, h0, l0);
    split_pack2(v.z, v.w, h1, l1);
    const size_t o2 = ((size_t)(2*row + off) * 1024 + c4*4) >> 1;
    ((uint32_t*)h)[o2]   = h0; ((uint32_t*)h)[o2+1] = h1;
    ((uint32_t*)l)[o2]   = l0; ((uint32_t*)l)[o2+1] = l1;
}

// ---------------- RMSNorm -> split bf16 ----------------
__global__ void rmsnorm_split_kernel(const float* __restrict__ x,
                                     const float* __restrict__ g,
                                     __nv_bfloat16* __restrict__ yh,
                                     __nv_bfloat16* __restrict__ yl) {
    const int row = blockIdx.x;
    const float4* xr = (const float4*)(x + (size_t)row * DM);
    const int t = threadIdx.x;
    float4 xv = xr[t];
    float ss = xv.x*xv.x + xv.y*xv.y + xv.z*xv.z + xv.w*xv.w;
    #pragma unroll
    for (int o = 16; o; o >>= 1) ss += __shfl_xor_sync(0xffffffffu, ss, o);
    __shared__ float sred[8];
    const int warp = t >> 5, lane = t & 31;
    if (lane == 0) sred[warp] = ss;
    __syncthreads();
    if (warp == 0) {
        float v = (lane < 8) ? sred[lane] : 0.f;
        #pragma unroll
        for (int o = 4; o; o >>= 1) v += __shfl_xor_sync(0xffffffffu, v, o);
        if (lane == 0) sred[0] = v;
    }
    __syncthreads();
    const float inv = rsqrtf(sred[0] * (1.0f/(float)DM) + 1e-5f);
    const float4 gv = ((const float4*)g)[t];
    uint32_t h0, l0, h1, l1;
    split_pack2(xv.x*inv*gv.x, xv.y*inv*gv.y, h0, l0);
    split_pack2(xv.z*inv*gv.z, xv.w*inv*gv.w, h1, l1);
    const size_t b2 = (size_t)row * (DM/2) + 2*t;
    ((uint32_t*)yh)[b2]   = h0; ((uint32_t*)yh)[b2+1] = h1;
    ((uint32_t*)yl)[b2]   = l0; ((uint32_t*)yl)[b2+1] = l1;
}

// ---------------- mma.sync bf16x3 GEMM, CTA 128x256, warp 64x64 ---------------
// MODE 0: C fp32 (+R).  MODE 1: rope (cols<2048) + Q pre-scale (cols<1024)
//          + split -> Ch/Cl (stride N).
// MODE 2: swiglu on (even,odd) col pairs + split -> Ch/Cl (stride N/2).
#define ROWB   144
#define A_OFF_L 18432            // 128*144
#define B_OFF   36864            // 2*128*144
#define B_OFF_L 73728            // B_OFF + 256*144
#define STAGE  110592            // (128+128+256+256)*144
#define QSCALE 0.18033688f       // 0.125 * log2(e): softmax done in base 2
template<int MODE>
__global__ __launch_bounds__(256, 1)
void gemm_mma_bf16x3(const __nv_bfloat16* __restrict__ Ah,
                     const __nv_bfloat16* __restrict__ Al,
                     const __nv_bfloat16* __restrict__ Bh,
                     const __nv_bfloat16* __restrict__ Bl,
                     const float* __restrict__ R,
                     float* __restrict__ C,
                     __nv_bfloat16* __restrict__ Ch,
                     __nv_bfloat16* __restrict__ Cl,
                     int N, int K) {
    extern __shared__ char smem[];
    const uint32_t sbase = smem_to_u32(smem);
    const int tid  = threadIdx.x;
    const int lane = tid & 31;
    const int wid  = tid >> 5;
    const int bm = blockIdx.y * 128;
    const int bn = blockIdx.x * 256;
    const int m0w = (wid & 1) * 64;
    const int n0w = (wid >> 1) * 64;

    float acc[4][8][4];
    #pragma unroll
    for (int i = 0; i < 4; i++)
        #pragma unroll
        for (int j = 0; j < 8; j++)
            #pragma unroll
            for (int q = 0; q < 4; q++) acc[i][j][q] = 0.f;

    const int nch = K >> 6;

    auto load_stage = [&](int s, int c) {
        const int k0 = c << 6;
        const uint32_t st = sbase + (uint32_t)s * STAGE;
        #pragma unroll
        for (int i = 0; i < 4; ++i) {           // A: 128 rows, hi+lo
            const int idx = tid + (i << 8);
            const int row = idx >> 3, cc = idx & 7;
            const uint32_t so = (uint32_t)(row * ROWB + cc * 16);
            const size_t ga = (size_t)(bm + row) * K + k0 + cc * 8;
            CP_ASYNC16(st + so,           (const char*)(Ah + ga));
            CP_ASYNC16(st + A_OFF_L + so, (const char*)(Al + ga));
        }
        #pragma unroll
        for (int i = 0; i < 8; ++i) {           // B: 256 rows, hi+lo
            const int idx = tid + (i << 8);
            const int row = idx >> 3, cc = idx & 7;
            const uint32_t so = (uint32_t)(row * ROWB + cc * 16);
            const size_t gb = (size_t)(bn + row) * K + k0 + cc * 8;
            CP_ASYNC16(st + B_OFF + so,   (const char*)(Bh + gb));
            CP_ASYNC16(st + B_OFF_L + so, (const char*)(Bl + gb));
        }
        CP_COMMIT();
    };

    const int g = lane >> 3, r = lane & 7;
    const uint32_t aoff = (uint32_t)((m0w + (g & 1) * 8 + r) * ROWB + ((g >> 1) * 8) * 2);
    const uint32_t boff = (uint32_t)(B_OFF + (n0w + (g >> 1) * 8 + r) * ROWB + ((g & 1) * 8) * 2);

    load_stage(0, 0);

    for (int c = 0; c < nch; ++c) {
        CP_WAIT0();
        __syncthreads();
        if (c + 1 < nch) load_stage((c + 1) & 1, c + 1);

        const uint32_t st = sbase + (uint32_t)(c & 1) * STAGE;
        #pragma unroll
        for (int ks = 0; ks < 4; ++ks) {
            uint32_t AhF[4][4], AlF[4][4];
            const uint32_t ab = st + aoff + (uint32_t)(ks * 32);
            #pragma unroll
            for (int mi = 0; mi < 4; ++mi) {
                LDSM4(AhF[mi], ab + (uint32_t)(mi * 16 * ROWB));
                LDSM4(AlF[mi], ab + A_OFF_L + (uint32_t)(mi * 16 * ROWB));
            }
            const uint32_t bb = st + boff + (uint32_t)(ks * 32);
            #pragma unroll
            for (int nb = 0; nb < 4; ++nb) {
                uint32_t BhF[4], BlF[4];
                LDSM4(BhF, bb + (uint32_t)(nb * 16 * ROWB));
                LDSM4(BlF, bb + (uint32_t)(256 * ROWB) + (uint32_t)(nb * 16 * ROWB));
                #pragma unroll
                for (int mi = 0; mi < 4; ++mi)
                    #pragma unroll
                    for (int hf = 0; hf < 2; ++hf) {
                        float* d = acc[mi][nb * 2 + hf];
                        MMA16816(d, AhF[mi], BhF[hf*2], BhF[hf*2+1]);
                        MMA16816(d, AhF[mi], BlF[hf*2], BlF[hf*2+1]);
                        MMA16816(d, AlF[mi], BhF[hf*2], BhF[hf*2+1]);
                    }
            }
        }
    }

    const int erow = lane >> 2;
    const int ecol = (lane & 3) * 2;
    #pragma unroll
    for (int mi = 0; mi < 4; ++mi) {
        #pragma unroll
        for (int nj = 0; nj < 8; ++nj) {
            float* d = acc[mi][nj];
            const int row0 = bm + m0w + mi * 16 + erow;
            const int row1 = row0 + 8;
            const int cg   = bn + n0w + nj * 8 + ecol;
            if (MODE == 0) {
                const size_t o0 = (size_t)row0 * N + cg;
                const size_t o1 = (size_t)row1 * N + cg;
                float2 v0 = make_float2(d[0], d[1]);
                float2 v1 = make_float2(d[2], d[3]);
                if (R) {
                    const float2 r0 = *(const float2*)(R + o0);
                    const float2 r1 = *(const float2*)(R + o1);
                    v0.x += r0.x; v0.y += r0.y;
                    v1.x += r1.x; v1.y += r1.y;
                }
                *(float2*)(C + o0) = v0;
                *(float2*)(C + o1) = v1;
            } else if (MODE == 1) {
                float a0 = d[0], a1 = d[1], b0 = d[2], b1 = d[3];
                if (cg < 2048) {
                    const int i = (cg & 63) >> 1;
                    const int s0 = (row0 & (SS-1))*32 + i;
                    const int s1 = (row1 & (SS-1))*32 + i;
                    const float c0 = g_cs[s0], n0 = g_sn[s0];
                    const float c1 = g_cs[s1], n1 = g_sn[s1];
                    float t0 = a0*c0 - a1*n0, t1 = a0*n0 + a1*c0;
                    a0 = t0; a1 = t1;
                    float u0 = b0*c1 - b1*n1, u1 = b0*n1 + b1*c1;
                    b0 = u0; b1 = u1;
                }
                if (cg < 1024) {  // Q pre-scale into log2 domain
                    a0 *= QSCALE; a1 *= QSCALE; b0 *= QSCALE; b1 *= QSCALE;
                }
                uint32_t h0, l0, h1, l1;
                split_pack2(a0, a1, h0, l0);
                split_pack2(b0, b1, h1, l1);
                const size_t o0 = (size_t)row0 * N + cg;
                const size_t o1 = (size_t)row1 * N + cg;
                *(uint32_t*)(Ch + o0) = h0;
                *(uint32_t*)(Cl + o0) = l0;
                *(uint32_t*)(Ch + o1) = h1;
                *(uint32_t*)(Cl + o1) = l1;
            } else {  // MODE 2: swiglu, (even,odd) = (a, gate); hybrid silu
                const int j = cg >> 1;
                const int NC = N >> 1;
                float sl0, sl1;
                if (nj < 3) {   // MUFU path
                    const float e0 = ex2(-1.44269504f * d[0]);
                    const float e1 = ex2(-1.44269504f * d[2]);
                    const float dd0 = 1.f + e0, dd1 = 1.f + e1;
                    float r0 = rcpa(dd0); r0 = r0 * (2.f - dd0 * r0);
                    float r1 = rcpa(dd1); r1 = r1 * (2.f - dd1 * r1);
                    sl0 = d[0] * r0 * d[1];
                    sl1 = d[2] * r1 * d[3];
                } else {        // FMA-pipe path
                    const float e0 = fast_exp2(-1.44269504f * d[0]);
                    const float e1 = fast_exp2(-1.44269504f * d[2]);
                    const float dd0 = 1.f + e0, dd1 = 1.f + e1;
                    float r0 = __int_as_float(0x7EF311C3 - __float_as_int(dd0));
                    r0 = r0 * (2.f - dd0 * r0); r0 = r0 * (2.f - dd0 * r0);
                    float r1 = __int_as_float(0x7EF311C3 - __float_as_int(dd1));
                    r1 = r1 * (2.f - dd1 * r1); r1 = r1 * (2.f - dd1 * r1);
                    sl0 = d[0] * r0 * d[1];
                    sl1 = d[2] * r1 * d[3];
                }
                __nv_bfloat16 h0, l0, h1, l1;
                split2(sl0, h0, l0);
                split2(sl1, h1, l1);
                Ch[(size_t)row0 * NC + j] = h0;
                Cl[(size_t)row0 * NC + j] = l0;
                Ch[(size_t)row1 * NC + j] = h1;
                Cl[(size_t)row1 * NC + j] = l1;
            }
        }
    }
}

// ---------------- HMMA flash attention (bf16x3 scores, base-2 softmax) --------
#define ATB (64*144)
#define ATT_SMEM (10*ATB)
__global__ __launch_bounds__(128)
void attn_mma_kernel(const __nv_bfloat16* __restrict__ Xh,
                     const __nv_bfloat16* __restrict__ Xl,
                     __nv_bfloat16* __restrict__ Oh,
                     __nv_bfloat16* __restrict__ Ol) {
    extern __shared__ char sm[];
    const uint32_t sQh = smem_to_u32(sm);
    const uint32_t sQl = sQh + ATB;
    const uint32_t sSt = sQh + 2*ATB;

    const int tid = threadIdx.x, lane = tid & 31, warp = tid >> 5;
    const int bh = blockIdx.y, b = bh >> 4, h = bh & (NH-1);
    const int qt = gridDim.x - 1 - blockIdx.x;
    const int q0 = qt * 64;
    const size_t rowbase = (size_t)b * SS * LDX;
    const int colQ = h*DH, colK = 1024 + h*DH, colV = 2048 + h*DH;

    #pragma unroll
    for (int i = 0; i < 4; i++) {
        const int idx = tid + i*128;
        const int r = idx >> 3, c = idx & 7;
        const uint32_t so = (uint32_t)(r*144 + c*16);
        const size_t ga = rowbase + (size_t)(q0 + r)*LDX + colQ + c*8;
        CP_ASYNC16(sQh + so, (const char*)(Xh + ga));
        CP_ASYNC16(sQl + so, (const char*)(Xl + ga));
    }
    CP_COMMIT();

    auto load_kv = [&](int t, int s) {
        const int k0 = t * 64;
        #pragma unroll
        for (int i = 0; i < 4; i++) {
            const int idx = tid + i*128;
            const int r = idx >> 3, c = idx & 7;
            const uint32_t so = (uint32_t)s*4*ATB + (uint32_t)(r*144 + c*16);
            const size_t gk = rowbase + (size_t)(k0 + r)*LDX + colK + c*8;
            const size_t gv = rowbase + (size_t)(k0 + r)*LDX + colV + c*8;
            CP_ASYNC16(sSt + so,         (const char*)(Xh + gk));
            CP_ASYNC16(sSt + ATB + so,   (const char*)(Xl + gk));
            CP_ASYNC16(sSt + 2*ATB + so, (const char*)(Xh + gv));
            CP_ASYNC16(sSt + 3*ATB + so, (const char*)(Xl + gv));
        }
        CP_COMMIT();
    };
    load_kv(0, 0);

    const int g = lane >> 3, rr = lane & 7;
    const uint32_t aoff = (uint32_t)((warp*16 + (g&1)*8 + rr)*144 + (g>>1)*16);
    const uint32_t boff = (uint32_t)(((g>>1)*8 + rr)*144 + (g&1)*16);
    const uint32_t voff = (uint32_t)(((g&1)*8 + rr)*144 + (lane>>4)*16);

    float m0 = -CUDART_INF_F, m1 = -CUDART_INF_F, l0 = 0.f, l1 = 0.f;
    float o[8][4];
    #pragma unroll
    for (int j = 0; j < 8; j++)
        #pragma unroll
        for (int q = 0; q < 4; q++) o[j][q] = 0.f;

    const int r0g = q0 + warp*16 + (lane >> 2);
    const int r1g = r0g + 8;
    const int ntiles = qt + 1;

    for (int t = 0; t < ntiles; t++) {
        CP_WAIT0();
        __syncthreads();
        if (t + 1 < ntiles) load_kv(t + 1, (t + 1) & 1);

        const uint32_t sK  = sSt + (uint32_t)(t & 1)*4*ATB;
        const uint32_t sKl = sK + ATB;
        const uint32_t sV  = sK + 2*ATB;
        const uint32_t sVl = sK + 3*ATB;

        float s[8][4];
        #pragma unroll
        for (int j = 0; j < 8; j++)
            #pragma unroll
            for (int q = 0; q < 4; q++) s[j][q] = 0.f;

        #pragma unroll
        for (int d = 0; d < 4; d++) {
            uint32_t qh[4], ql[4];
            LDSM4(qh, sQh + aoff + d*32);
            LDSM4(ql, sQl + aoff + d*32);
            #pragma unroll
            for (int nb = 0; nb < 4; nb++) {
                uint32_t kh[4], kl[4];
                LDSM4(kh, sK  + boff + (uint32_t)(nb*16*144) + d*32);
                LDSM4(kl, sKl + boff + (uint32_t)(nb*16*144) + d*32);
                #pragma unroll
                for (int f = 0; f < 2; f++) {
                    float* dd = s[nb*2 + f];
                    MMA16816(dd, qh, kh[2*f], kh[2*f+1]);
                    MMA16816(dd, qh, kl[2*f], kl[2*f+1]);
                    MMA16816(dd, ql, kh[2*f], kh[2*f+1]);
                }
            }
        }

        // scores are already in log2 domain (Q pre-scaled by 0.125*log2e)
        const int k0 = t * 64;
        float mx0 = -CUDART_INF_F, mx1 = -CUDART_INF_F;
        #pragma unroll
        for (int j = 0; j < 8; j++) {
            if (t == qt) {
                const int c = k0 + j*8 + (lane & 3)*2;
                if (c     > r0g) s[j][0] = -CUDART_INF_F;
                if (c + 1 > r0g) s[j][1] = -CUDART_INF_F;
                if (c     > r1g) s[j][2] = -CUDART_INF_F;
                if (c + 1 > r1g) s[j][3] = -CUDART_INF_F;
            }
            mx0 = fmaxf(mx0, fmaxf(s[j][0], s[j][1]));
            mx1 = fmaxf(mx1, fmaxf(s[j][2], s[j][3]));
        }
        mx0 = fmaxf(mx0, __shfl_xor_sync(0xffffffffu, mx0, 1));
        mx0 = fmaxf(mx0, __shfl_xor_sync(0xffffffffu, mx0, 2));
        mx1 = fmaxf(mx1, __shfl_xor_sync(0xffffffffu, mx1, 1));
        mx1 = fmaxf(mx1, __shfl_xor_sync(0xffffffffu, mx1, 2));
        const float mn0 = fmaxf(m0, mx0), mn1 = fmaxf(m1, mx1);
        const float cr0 = ex2(m0 - mn0), cr1 = ex2(m1 - mn1);
        m0 = mn0; m1 = mn1;

        float sum0 = 0.f, sum1 = 0.f;
        #pragma unroll
        for (int j = 0; j < 8; j++) {
            if (j < 5) {     // MUFU path
                s[j][0] = ex2(s[j][0] - mn0); s[j][1] = ex2(s[j][1] - mn0);
                s[j][2] = ex2(s[j][2] - mn1); s[j][3] = ex2(s[j][3] - mn1);
            } else {         // FMA-pipe path
                s[j][0] = fast_exp2(s[j][0] - mn0); s[j][1] = fast_exp2(s[j][1] - mn0);
                s[j][2] = fast_exp2(s[j][2] - mn1); s[j][3] = fast_exp2(s[j][3] - mn1);
            }
            sum0 += s[j][0] + s[j][1];
            sum1 += s[j][2] + s[j][3];
        }
        sum0 += __shfl_xor_sync(0xffffffffu, sum0, 1);
        sum0 += __shfl_xor_sync(0xffffffffu, sum0, 2);
        sum1 += __shfl_xor_sync(0xffffffffu, sum1, 1);
        sum1 += __shfl_xor_sync(0xffffffffu, sum1, 2);
        l0 = l0 * cr0 + sum0;
        l1 = l1 * cr1 + sum1;
        #pragma unroll
        for (int j = 0; j < 8; j++) {
            o[j][0] *= cr0; o[j][1] *= cr0;
            o[j][2] *= cr1; o[j][3] *= cr1;
        }

        #pragma unroll
        for (int kt = 0; kt < 4; kt++) {
            uint32_t ph[4], pl[4];
            #pragma unroll
            for (int u = 0; u < 4; u++) {
                const int jj = 2*kt + (u >> 1);
                split_pack2(s[jj][(u & 1)*2], s[jj][(u & 1)*2 + 1], ph[u], pl[u]);
            }
            #pragma unroll
            for (int nb = 0; nb < 4; nb++) {
                uint32_t vh[4], vl[4];
                const uint32_t va = voff + (uint32_t)(kt*16*144) + (uint32_t)(nb*32);
                LDSM4T(vh, sV  + va);
                LDSM4T(vl, sVl + va);
                #pragma unroll
                for (int f = 0; f < 2; f++) {
                    float* dd = o[nb*2 + f];
                    MMA16816(dd, ph, vh[2*f], vh[2*f+1]);
                    MMA16816(dd, ph, vl[2*f], vl[2*f+1]);
                    MMA16816(dd, pl, vh[2*f], vh[2*f+1]);
                }
            }
        }
    }

    const float inv0 = 1.0f / l0, inv1 = 1.0f / l1;
    const size_t tok0 = (size_t)b * SS + r0g;
    const size_t tok1 = tok0 + 8;
    #pragma unroll
    for (int j = 0; j < 8; j++) {
        const int col = h*DH + j*8 + (lane & 3)*2;
        uint32_t h0, l0b, h1, l1b;
        split_pack2(o[j][0]*inv0, o[j][1]*inv0, h0, l0b);
        split_pack2(o[j][2]*inv1, o[j][3]*inv1, h1, l1b);
        *(uint32_t*)(Oh + tok0*DM + col) = h0;
        *(uint32_t*)(Ol + tok0*DM + col) = l0b;
        *(uint32_t*)(Oh + tok1*DM + col) = h1;
        *(uint32_t*)(Ol + tok1*DM + col) = l1b;
    }
}

// ---------------- launch ----------------
extern "C" void kernel_launch(void* const* d_in, const int* in_sizes, int n_in,
                              void* d_out, int out_size) {
    const float* x   = (const float*)d_in[0];
    const int*   pos = (const int*)  d_in[1];
    const float* qw  = (const float*)d_in[2];
    const float* kw  = (const float*)d_in[3];
    const float* vw  = (const float*)d_in[4];
    const float* ow  = (const float*)d_in[5];
    const float* g1  = (const float*)d_in[6];
    const float* g2  = (const float*)d_in[7];
    const float* w1  = (const float*)d_in[8];
    const float* w2  = (const float*)d_in[9];
    const float* w3  = (const float*)d_in[10];
    float* out = (float*)d_out;

    __nv_bfloat16 *xnh, *xnl, *qkvh, *qkvl, *ath, *atl, *hnh, *hnl, *swh, *swl;
    __nv_bfloat16 *wqkvh, *wqkvl, *owh, *owl, *w13h, *w13l, *w2h, *w2l;
    float *res1;
    cudaGetSymbolAddress((void**)&xnh, g_xn_h);   cudaGetSymbolAddress((void**)&xnl, g_xn_l);
    cudaGetSymbolAddress((void**)&qkvh, g_qkv_h); cudaGetSymbolAddress((void**)&qkvl, g_qkv_l);
    cudaGetSymbolAddress((void**)&ath, g_at_h);   cudaGetSymbolAddress((void**)&atl, g_at_l);
    cudaGetSymbolAddress((void**)&res1, g_res1);
    cudaGetSymbolAddress((void**)&hnh, g_hn_h);   cudaGetSymbolAddress((void**)&hnl, g_hn_l);
    cudaGetSymbolAddress((void**)&swh, g_sw_h);   cudaGetSymbolAddress((void**)&swl, g_sw_l);
    cudaGetSymbolAddress((void**)&wqkvh, g_wqkv_h); cudaGetSymbolAddress((void**)&wqkvl, g_wqkv_l);
    cudaGetSymbolAddress((void**)&owh, g_ow_h);   cudaGetSymbolAddress((void**)&owl, g_ow_l);
    cudaGetSymbolAddress((void**)&w13h, g_w13_h); cudaGetSymbolAddress((void**)&w13l, g_w13_l);
    cudaGetSymbolAddress((void**)&w2h, g_w2_h);   cudaGetSymbolAddress((void**)&w2l, g_w2_l);

    const int GEMM_SMEM = 2 * STAGE;   // 221184
    cudaFuncSetAttribute(gemm_mma_bf16x3<0>, cudaFuncAttributeMaxDynamicSharedMemorySize, GEMM_SMEM);
    cudaFuncSetAttribute(gemm_mma_bf16x3<1>, cudaFuncAttributeMaxDynamicSharedMemorySize, GEMM_SMEM);
    cudaFuncSetAttribute(gemm_mma_bf16x3<2>, cudaFuncAttributeMaxDynamicSharedMemorySize, GEMM_SMEM);
    cudaFuncSetAttribute(attn_mma_kernel, cudaFuncAttributeMaxDynamicSharedMemorySize, ATT_SMEM);

    // rope table
    rope_table_kernel<<<SS, 32>>>(pos);

    // weight splits
    const int MM = 1024 * 1024;
    split_kernel<<<MM/4/256, 256>>>(qw, wqkvh,        wqkvl,        MM/4);
    split_kernel<<<MM/4/256, 256>>>(kw, wqkvh + MM,   wqkvl + MM,   MM/4);
    split_kernel<<<MM/4/256, 256>>>(vw, wqkvh + 2*MM, wqkvl + 2*MM, MM/4);
    split_inter_kernel<<<MM/256, 256>>>(w1, w13h, w13l, MM, 0);
    split_inter_kernel<<<MM/256, 256>>>(w3, w13h, w13l, MM, 1);
    split_kernel<<<MM/4/256, 256>>>(ow, owh, owl, MM/4);
    split_kernel<<<MM/256,   256>>>(w2, w2h, w2l, MM);

    // 1) rmsnorm(x) -> split
    rmsnorm_split_kernel<<<MTOK, 256>>>(x, g1, xnh, xnl);

    // 2) fused QKV projection + rope + Q prescale + split  [8192,3072]
    gemm_mma_bf16x3<1><<<dim3(LDX/256, MTOK/128), 256, GEMM_SMEM>>>(
        xnh, xnl, wqkvh, wqkvl, nullptr, nullptr, qkvh, qkvl, LDX, DM);

    // 3) HMMA flash attention (base-2 softmax) -> split bf16
    attn_mma_kernel<<<dim3(SS/64, BB*NH), 128, ATT_SMEM>>>(qkvh, qkvl, ath, atl);

    // 4) O projection + residual(x) -> res1 fp32
    gemm_mma_bf16x3<0><<<dim3(DM/256, MTOK/128), 256, GEMM_SMEM>>>(
        ath, atl, owh, owl, x, res1, nullptr, nullptr, DM, DM);

    // 5) rmsnorm(res1) -> split
    rmsnorm_split_kernel<<<MTOK, 256>>>(res1, g2, hnh, hnl);

    // 6) fused W1||W3 (interleaved) + swiglu + split  [8192,8192]->[8192,4096]
    gemm_mma_bf16x3<2><<<dim3(2*DFF/256, MTOK/128), 256, GEMM_SMEM>>>(
        hnh, hnl, w13h, w13l, nullptr, nullptr, swh, swl, 2*DFF, DM);

    // 7) down projection + residual(res1) -> out
    gemm_mma_bf16x3<0><<<dim3(DM/256, MTOK/128), 256, GEMM_SMEM>>>(
        swh, swl, w2h, w2l, res1, out, nullptr, nullptr, DM, DFF);
}

// round 9
// speedup vs baseline: 4.7451x; 1.2575x over previous
#include <cuda_runtime.h>
#include <cuda_fp16.h>
#include <math.h>
#include <math_constants.h>
#include <cstdint>

#define BB   4
#define SS   2048
#define DM   1024
#define NH   16
#define DH   64
#define DFF  4096
#define MTOK (BB*SS)      // 8192
#define LDX  3072

// ---------------- helpers ----------------
__device__ __forceinline__ uint32_t smem_to_u32(const void* p) {
    uint32_t a;
    asm("{ .reg .u64 t; cvta.to.shared.u64 t, %1; cvt.u32.u64 %0, t; }" : "=r"(a) : "l"(p));
    return a;
}
#define CP_ASYNC16(s, g) asm volatile("cp.async.cg.shared.global [%0], [%1], 16;" :: "r"(s), "l"(g))
#define CP_COMMIT()      asm volatile("cp.async.commit_group;" ::: "memory")
#define CP_WAIT0()       asm volatile("cp.async.wait_group 0;" ::: "memory")
#define LDSM4(rg, addr) \
    asm volatile("ldmatrix.sync.aligned.m8n8.x4.shared.b16 {%0,%1,%2,%3}, [%4];" \
        : "=r"((rg)[0]), "=r"((rg)[1]), "=r"((rg)[2]), "=r"((rg)[3]) : "r"(addr))
#define LDSM4T(rg, addr) \
    asm volatile("ldmatrix.sync.aligned.m8n8.x4.trans.shared.b16 {%0,%1,%2,%3}, [%4];" \
        : "=r"((rg)[0]), "=r"((rg)[1]), "=r"((rg)[2]), "=r"((rg)[3]) : "r"(addr))
#define MMA16816(d, a, b0v, b1v) \
    asm volatile("mma.sync.aligned.m16n8k16.row.col.f32.f16.f16.f32 " \
        "{%0,%1,%2,%3}, {%4,%5,%6,%7}, {%8,%9}, {%0,%1,%2,%3};" \
        : "+f"((d)[0]), "+f"((d)[1]), "+f"((d)[2]), "+f"((d)[3]) \
        : "r"((a)[0]), "r"((a)[1]), "r"((a)[2]), "r"((a)[3]), "r"(b0v), "r"(b1v))

__device__ __forceinline__ float ex2(float x) {
    float r; asm("ex2.approx.f32 %0, %1;" : "=f"(r) : "f"(x)); return r;
}
__device__ __forceinline__ float rcpa(float x) {
    float r; asm("rcp.approx.f32 %0, %1;" : "=f"(r) : "f"(x)); return r;
}
// 2^y on the FMA pipe (magic round + deg-5 Taylor), rel err ~2e-6
__device__ __forceinline__ float fast_exp2(float y) {
    y = fmaxf(fminf(y, 126.f), -126.f);
    float z = __fadd_rn(y, 12582912.f);
    int   n = __float_as_int(z) - 0x4B400000;
    float f = __fadd_rn(y, -__fadd_rn(z, -12582912.f));
    float p = fmaf(f, 0.0013333558f, 0.0096181291f);
    p = fmaf(f, p, 0.0555041087f);
    p = fmaf(f, p, 0.2402265069f);
    p = fmaf(f, p, 0.6931471806f);
    p = fmaf(f, p, 1.0f);
    return __int_as_float(__float_as_int(p) + (n << 23));
}
// pack (p0,p1) -> f16x2 hi + f16x2 lo residual
__device__ __forceinline__ void split_pack2(float p0, float p1, uint32_t& h2, uint32_t& l2) {
    __half2 h = __floats2half2_rn(p0, p1);
    float2 hf = __half22float2(h);
    __half2 l = __floats2half2_rn(__fadd_rn(p0, -hf.x), __fadd_rn(p1, -hf.y));
    h2 = *(uint32_t*)&h;
    l2 = *(uint32_t*)&l;
}
__device__ __forceinline__ void split2(float v, __half& h, __half& l) {
    h = __float2half_rn(v);
    l = __float2half_rn(v - __half2float(h));
}

// ---------------- scratch (__device__ globals) ----------------
static __device__ __half g_xn_h[(size_t)MTOK*DM],  g_xn_l[(size_t)MTOK*DM];
static __device__ __half g_qkv_h[(size_t)MTOK*LDX], g_qkv_l[(size_t)MTOK*LDX];
static __device__ __half g_at_h[(size_t)MTOK*DM],  g_at_l[(size_t)MTOK*DM];
static __device__ float  g_res1[(size_t)MTOK*DM];
static __device__ __half g_hn_h[(size_t)MTOK*DM],  g_hn_l[(size_t)MTOK*DM];
static __device__ __half g_sw_h[(size_t)MTOK*DFF], g_sw_l[(size_t)MTOK*DFF];
static __device__ __half g_wqkv_h[3072*1024], g_wqkv_l[3072*1024];
static __device__ __half g_ow_h [1024*1024];
static __device__ __half g_w13_h[2*DFF*1024];   // interleaved rows
static __device__ __half g_w2_h [1024*DFF];
static __device__ float g_cs[SS*32], g_sn[SS*32];

__global__ void rope_table_kernel(const int* __restrict__ pos) {
    const int s = blockIdx.x, i = threadIdx.x;   // 2048 x 32
    const float inv = exp2f(-(float)i * (13.287712379549449f / 32.0f));
    const float a = (float)pos[s] * inv;
    float sn, cs;
    sincosf(a, &sn, &cs);
    g_cs[s*32 + i] = cs;
    g_sn[s*32 + i] = sn;
}

// hi-only weight conversion (for 2-term linear GEMMs)
__global__ void wsplit_kernel(const float* __restrict__ x,
                              __half* __restrict__ h, int n4) {
    int i = blockIdx.x * blockDim.x + threadIdx.x;
    if (i >= n4) return;
    float4 v = ((const float4*)x)[i];
    ((__half2*)h)[2*i]   = __floats2half2_rn(v.x, v.y);
    ((__half2*)h)[2*i+1] = __floats2half2_rn(v.z, v.w);
}

// hi+lo weight split (for the 3-term QKV GEMM)
__global__ void wsplit2_kernel(const float* __restrict__ x,
                               __half* __restrict__ h,
                               __half* __restrict__ l, int n4) {
    int i = blockIdx.x * blockDim.x + threadIdx.x;
    if (i >= n4) return;
    float4 v = ((const float4*)x)[i];
    uint32_t h0, l0, h1, l1;
    split_pack2(v.x, v.y, h0, l0);
    split_pack2(v.z, v.w, h1, l1);
    ((uint32_t*)h)[2*i]   = h0; ((uint32_t*)h)[2*i+1] = h1;
    ((uint32_t*)l)[2*i]   = l0; ((uint32_t*)l)[2*i+1] = l1;
}

// interleaved weight hi split: src row n -> dst row 2n+off  (K=1024)
__global__ void wsplit_inter_kernel(const float* __restrict__ x,
                                    __half* __restrict__ h,
                                    int n4, int off) {
    int i = blockIdx.x * blockDim.x + threadIdx.x;
    if (i >= n4) return;
    const int row = i >> 8;
    const int c4  = i & 255;
    float4 v = ((const float4*)x)[i];
    const size_t o2 = ((size_t)(2*row + off) * 1024 + c4*4) >> 1;
    ((__half2*)h)[o2]   = __floats2half2_rn(v.x, v.y);
    ((__half2*)h)[o2+1] = __floats2half2_rn(v.z, v.w);
}

// ---------------- RMSNorm -> split fp16 ----------------
__global__ void rmsnorm_split_kernel(const float* __restrict__ x,
                                     const float* __restrict__ g,
                                     __half* __restrict__ yh,
                                     __half* __restrict__ yl) {
    const int row = blockIdx.x;
    const float4* xr = (const float4*)(x + (size_t)row * DM);
    const int t = threadIdx.x;
    float4 xv = xr[t];
    float ss = xv.x*xv.x + xv.y*xv.y + xv.z*xv.z + xv.w*xv.w;
    #pragma unroll
    for (int o = 16; o; o >>= 1) ss += __shfl_xor_sync(0xffffffffu, ss, o);
    __shared__ float sred[8];
    const int warp = t >> 5, lane = t & 31;
    if (lane == 0) sred[warp] = ss;
    __syncthreads();
    if (warp == 0) {
        float v = (lane < 8) ? sred[lane] : 0.f;
        #pragma unroll
        for (int o = 4; o; o >>= 1) v += __shfl_xor_sync(0xffffffffu, v, o);
        if (lane == 0) sred[0] = v;
    }
    __syncthreads();
    const float inv = rsqrtf(sred[0] * (1.0f/(float)DM) + 1e-5f);
    const float4 gv = ((const float4*)g)[t];
    uint32_t h0, l0, h1, l1;
    split_pack2(xv.x*inv*gv.x, xv.y*inv*gv.y, h0, l0);
    split_pack2(xv.z*inv*gv.z, xv.w*inv*gv.w, h1, l1);
    const size_t b2 = (size_t)row * (DM/2) + 2*t;
    ((uint32_t*)yh)[b2]   = h0; ((uint32_t*)yh)[b2+1] = h1;
    ((uint32_t*)yl)[b2]   = l0; ((uint32_t*)yl)[b2+1] = l1;
}

// ------- mma.sync fp16 GEMM, CTA 128x256, warp 64x64, 2- or 3-term ------------
// Terms: Ah*Bh + Al*Bh (+ Ah*Bl when BLO).  MODE 0: C fp32 (+R).
// MODE 1: rope (cols<2048) + Q pre-scale (cols<1024) + split -> Ch/Cl.
// MODE 2: swiglu on (even,odd) col pairs + split -> Ch/Cl (stride N/2).
#define ROWB    144
#define A_OFF_L 18432            // 128*144
#define B_OFF   36864            // 2*128*144
#define B_OFF_L 73728            // B_OFF + 256*144
#define QSCALE  0.18033688f      // 0.125 * log2(e)
template<int MODE, bool BLO>
__global__ __launch_bounds__(256, 1)
void gemm_mma_fp16(const __half* __restrict__ Ah,
                   const __half* __restrict__ Al,
                   const __half* __restrict__ Bh,
                   const __half* __restrict__ Bl,
                   const float* __restrict__ R,
                   float* __restrict__ C,
                   __half* __restrict__ Ch,
                   __half* __restrict__ Cl,
                   int N, int K) {
    constexpr uint32_t STG = BLO ? 110592u : 73728u;
    extern __shared__ char smem[];
    const uint32_t sbase = smem_to_u32(smem);
    const int tid  = threadIdx.x;
    const int lane = tid & 31;
    const int wid  = tid >> 5;
    const int bm = blockIdx.y * 128;
    const int bn = blockIdx.x * 256;
    const int m0w = (wid & 1) * 64;
    const int n0w = (wid >> 1) * 64;

    float acc[4][8][4];
    #pragma unroll
    for (int i = 0; i < 4; i++)
        #pragma unroll
        for (int j = 0; j < 8; j++)
            #pragma unroll
            for (int q = 0; q < 4; q++) acc[i][j][q] = 0.f;

    const int nch = K >> 6;

    auto load_stage = [&](int s, int c) {
        const int k0 = c << 6;
        const uint32_t st = sbase + (uint32_t)s * STG;
        #pragma unroll
        for (int i = 0; i < 4; ++i) {           // A: 128 rows, hi+lo
            const int idx = tid + (i << 8);
            const int row = idx >> 3, cc = idx & 7;
            const uint32_t so = (uint32_t)(row * ROWB + cc * 16);
            const size_t ga = (size_t)(bm + row) * K + k0 + cc * 8;
            CP_ASYNC16(st + so,           (const char*)(Ah + ga));
            CP_ASYNC16(st + A_OFF_L + so, (const char*)(Al + ga));
        }
        #pragma unroll
        for (int i = 0; i < 8; ++i) {           // B: 256 rows, hi (+lo)
            const int idx = tid + (i << 8);
            const int row = idx >> 3, cc = idx & 7;
            const uint32_t so = (uint32_t)(row * ROWB + cc * 16);
            const size_t gb = (size_t)(bn + row) * K + k0 + cc * 8;
            CP_ASYNC16(st + B_OFF + so, (const char*)(Bh + gb));
            if (BLO) CP_ASYNC16(st + B_OFF_L + so, (const char*)(Bl + gb));
        }
        CP_COMMIT();
    };

    const int g = lane >> 3, r = lane & 7;
    const uint32_t aoff = (uint32_t)((m0w + (g & 1) * 8 + r) * ROWB + ((g >> 1) * 8) * 2);
    const uint32_t boff = (uint32_t)(B_OFF + (n0w + (g >> 1) * 8 + r) * ROWB + ((g & 1) * 8) * 2);

    load_stage(0, 0);

    for (int c = 0; c < nch; ++c) {
        CP_WAIT0();
        __syncthreads();
        if (c + 1 < nch) load_stage((c + 1) & 1, c + 1);

        const uint32_t st = sbase + (uint32_t)(c & 1) * STG;
        #pragma unroll
        for (int ks = 0; ks < 4; ++ks) {
            uint32_t AhF[4][4], AlF[4][4];
            const uint32_t ab = st + aoff + (uint32_t)(ks * 32);
            #pragma unroll
            for (int mi = 0; mi < 4; ++mi) {
                LDSM4(AhF[mi], ab + (uint32_t)(mi * 16 * ROWB));
                LDSM4(AlF[mi], ab + A_OFF_L + (uint32_t)(mi * 16 * ROWB));
            }
            const uint32_t bb = st + boff + (uint32_t)(ks * 32);
            #pragma unroll
            for (int nb = 0; nb < 4; ++nb) {
                uint32_t BhF[4], BlF[4];
                LDSM4(BhF, bb + (uint32_t)(nb * 16 * ROWB));
                if (BLO) LDSM4(BlF, bb + (uint32_t)(B_OFF_L - B_OFF) + (uint32_t)(nb * 16 * ROWB));
                #pragma unroll
                for (int mi = 0; mi < 4; ++mi)
                    #pragma unroll
                    for (int hf = 0; hf < 2; ++hf) {
                        float* d = acc[mi][nb * 2 + hf];
                        MMA16816(d, AhF[mi], BhF[hf*2], BhF[hf*2+1]);
                        MMA16816(d, AlF[mi], BhF[hf*2], BhF[hf*2+1]);
                        if (BLO) MMA16816(d, AhF[mi], BlF[hf*2], BlF[hf*2+1]);
                    }
            }
        }
    }

    const int erow = lane >> 2;
    const int ecol = (lane & 3) * 2;
    #pragma unroll
    for (int mi = 0; mi < 4; ++mi) {
        #pragma unroll
        for (int nj = 0; nj < 8; ++nj) {
            float* d = acc[mi][nj];
            const int row0 = bm + m0w + mi * 16 + erow;
            const int row1 = row0 + 8;
            const int cg   = bn + n0w + nj * 8 + ecol;
            if (MODE == 0) {
                const size_t o0 = (size_t)row0 * N + cg;
                const size_t o1 = (size_t)row1 * N + cg;
                float2 v0 = make_float2(d[0], d[1]);
                float2 v1 = make_float2(d[2], d[3]);
                if (R) {
                    const float2 r0 = *(const float2*)(R + o0);
                    const float2 r1 = *(const float2*)(R + o1);
                    v0.x += r0.x; v0.y += r0.y;
                    v1.x += r1.x; v1.y += r1.y;
                }
                *(float2*)(C + o0) = v0;
                *(float2*)(C + o1) = v1;
            } else if (MODE == 1) {
                float a0 = d[0], a1 = d[1], b0 = d[2], b1 = d[3];
                if (cg < 2048) {
                    const int i = (cg & 63) >> 1;
                    const int s0 = (row0 & (SS-1))*32 + i;
                    const int s1 = (row1 & (SS-1))*32 + i;
                    const float c0 = g_cs[s0], n0 = g_sn[s0];
                    const float c1 = g_cs[s1], n1 = g_sn[s1];
                    float t0 = a0*c0 - a1*n0, t1 = a0*n0 + a1*c0;
                    a0 = t0; a1 = t1;
                    float u0 = b0*c1 - b1*n1, u1 = b0*n1 + b1*c1;
                    b0 = u0; b1 = u1;
                }
                if (cg < 1024) {  // Q pre-scale into log2 domain
                    a0 *= QSCALE; a1 *= QSCALE; b0 *= QSCALE; b1 *= QSCALE;
                }
                uint32_t h0, l0, h1, l1;
                split_pack2(a0, a1, h0, l0);
                split_pack2(b0, b1, h1, l1);
                const size_t o0 = (size_t)row0 * N + cg;
                const size_t o1 = (size_t)row1 * N + cg;
                *(uint32_t*)(Ch + o0) = h0;
                *(uint32_t*)(Cl + o0) = l0;
                *(uint32_t*)(Ch + o1) = h1;
                *(uint32_t*)(Cl + o1) = l1;
            } else {  // MODE 2: swiglu, (even,odd) = (a, gate); hybrid silu
                const int j = cg >> 1;
                const int NC = N >> 1;
                float sl0, sl1;
                if (nj < 3) {   // MUFU path
                    const float e0 = ex2(-1.44269504f * d[0]);
                    const float e1 = ex2(-1.44269504f * d[2]);
                    const float dd0 = 1.f + e0, dd1 = 1.f + e1;
                    float r0 = rcpa(dd0); r0 = r0 * (2.f - dd0 * r0);
                    float r1 = rcpa(dd1); r1 = r1 * (2.f - dd1 * r1);
                    sl0 = d[0] * r0 * d[1];
                    sl1 = d[2] * r1 * d[3];
                } else {        // FMA-pipe path
                    const float e0 = fast_exp2(-1.44269504f * d[0]);
                    const float e1 = fast_exp2(-1.44269504f * d[2]);
                    const float dd0 = 1.f + e0, dd1 = 1.f + e1;
                    float r0 = __int_as_float(0x7EF311C3 - __float_as_int(dd0));
                    r0 = r0 * (2.f - dd0 * r0); r0 = r0 * (2.f - dd0 * r0);
                    float r1 = __int_as_float(0x7EF311C3 - __float_as_int(dd1));
                    r1 = r1 * (2.f - dd1 * r1); r1 = r1 * (2.f - dd1 * r1);
                    sl0 = d[0] * r0 * d[1];
                    sl1 = d[2] * r1 * d[3];
                }
                __half h0, l0, h1, l1;
                split2(sl0, h0, l0);
                split2(sl1, h1, l1);
                Ch[(size_t)row0 * NC + j] = h0;
                Cl[(size_t)row0 * NC + j] = l0;
                Ch[(size_t)row1 * NC + j] = h1;
                Cl[(size_t)row1 * NC + j] = l1;
            }
        }
    }
}

// ---------------- HMMA flash attention (fp16x3, base-2 softmax) ---------------
#define ATB (64*144)
#define ATT_SMEM (10*ATB)
__global__ __launch_bounds__(128)
void attn_mma_kernel(const __half* __restrict__ Xh,
                     const __half* __restrict__ Xl,
                     __half* __restrict__ Oh,
                     __half* __restrict__ Ol) {
    extern __shared__ char sm[];
    const uint32_t sQh = smem_to_u32(sm);
    const uint32_t sQl = sQh + ATB;
    const uint32_t sSt = sQh + 2*ATB;

    const int tid = threadIdx.x, lane = tid & 31, warp = tid >> 5;
    const int bh = blockIdx.y, b = bh >> 4, h = bh & (NH-1);
    const int qt = gridDim.x - 1 - blockIdx.x;
    const int q0 = qt * 64;
    const size_t rowbase = (size_t)b * SS * LDX;
    const int colQ = h*DH, colK = 1024 + h*DH, colV = 2048 + h*DH;

    #pragma unroll
    for (int i = 0; i < 4; i++) {
        const int idx = tid + i*128;
        const int r = idx >> 3, c = idx & 7;
        const uint32_t so = (uint32_t)(r*144 + c*16);
        const size_t ga = rowbase + (size_t)(q0 + r)*LDX + colQ + c*8;
        CP_ASYNC16(sQh + so, (const char*)(Xh + ga));
        CP_ASYNC16(sQl + so, (const char*)(Xl + ga));
    }
    CP_COMMIT();

    auto load_kv = [&](int t, int s) {
        const int k0 = t * 64;
        #pragma unroll
        for (int i = 0; i < 4; i++) {
            const int idx = tid + i*128;
            const int r = idx >> 3, c = idx & 7;
            const uint32_t so = (uint32_t)s*4*ATB + (uint32_t)(r*144 + c*16);
            const size_t gk = rowbase + (size_t)(k0 + r)*LDX + colK + c*8;
            const size_t gv = rowbase + (size_t)(k0 + r)*LDX + colV + c*8;
            CP_ASYNC16(sSt + so,         (const char*)(Xh + gk));
            CP_ASYNC16(sSt + ATB + so,   (const char*)(Xl + gk));
            CP_ASYNC16(sSt + 2*ATB + so, (const char*)(Xh + gv));
            CP_ASYNC16(sSt + 3*ATB + so, (const char*)(Xl + gv));
        }
        CP_COMMIT();
    };
    load_kv(0, 0);

    const int g = lane >> 3, rr = lane & 7;
    const uint32_t aoff = (uint32_t)((warp*16 + (g&1)*8 + rr)*144 + (g>>1)*16);
    const uint32_t boff = (uint32_t)(((g>>1)*8 + rr)*144 + (g&1)*16);
    const uint32_t voff = (uint32_t)(((g&1)*8 + rr)*144 + (lane>>4)*16);

    float m0 = -CUDART_INF_F, m1 = -CUDART_INF_F, l0 = 0.f, l1 = 0.f;
    float o[8][4];
    #pragma unroll
    for (int j = 0; j < 8; j++)
        #pragma unroll
        for (int q = 0; q < 4; q++) o[j][q] = 0.f;

    const int r0g = q0 + warp*16 + (lane >> 2);
    const int r1g = r0g + 8;
    const int ntiles = qt + 1;

    for (int t = 0; t < ntiles; t++) {
        CP_WAIT0();
        __syncthreads();
        if (t + 1 < ntiles) load_kv(t + 1, (t + 1) & 1);

        const uint32_t sK  = sSt + (uint32_t)(t & 1)*4*ATB;
        const uint32_t sKl = sK + ATB;
        const uint32_t sV  = sK + 2*ATB;
        const uint32_t sVl = sK + 3*ATB;

        float s[8][4];
        #pragma unroll
        for (int j = 0; j < 8; j++)
            #pragma unroll
            for (int q = 0; q < 4; q++) s[j][q] = 0.f;

        #pragma unroll
        for (int d = 0; d < 4; d++) {
            uint32_t qh[4], ql[4];
            LDSM4(qh, sQh + aoff + d*32);
            LDSM4(ql, sQl + aoff + d*32);
            #pragma unroll
            for (int nb = 0; nb < 4; nb++) {
                uint32_t kh[4], kl[4];
                LDSM4(kh, sK  + boff + (uint32_t)(nb*16*144) + d*32);
                LDSM4(kl, sKl + boff + (uint32_t)(nb*16*144) + d*32);
                #pragma unroll
                for (int f = 0; f < 2; f++) {
                    float* dd = s[nb*2 + f];
                    MMA16816(dd, qh, kh[2*f], kh[2*f+1]);
                    MMA16816(dd, qh, kl[2*f], kl[2*f+1]);
                    MMA16816(dd, ql, kh[2*f], kh[2*f+1]);
                }
            }
        }

        // scores already in log2 domain (Q pre-scaled by 0.125*log2e)
        const int k0 = t * 64;
        float mx0 = -CUDART_INF_F, mx1 = -CUDART_INF_F;
        #pragma unroll
        for (int j = 0; j < 8; j++) {
            if (t == qt) {
                const int c = k0 + j*8 + (lane & 3)*2;
                if (c     > r0g) s[j][0] = -CUDART_INF_F;
                if (c + 1 > r0g) s[j][1] = -CUDART_INF_F;
                if (c     > r1g) s[j][2] = -CUDART_INF_F;
                if (c + 1 > r1g) s[j][3] = -CUDART_INF_F;
            }
            mx0 = fmaxf(mx0, fmaxf(s[j][0], s[j][1]));
            mx1 = fmaxf(mx1, fmaxf(s[j][2], s[j][3]));
        }
        mx0 = fmaxf(mx0, __shfl_xor_sync(0xffffffffu, mx0, 1));
        mx0 = fmaxf(mx0, __shfl_xor_sync(0xffffffffu, mx0, 2));
        mx1 = fmaxf(mx1, __shfl_xor_sync(0xffffffffu, mx1, 1));
        mx1 = fmaxf(mx1, __shfl_xor_sync(0xffffffffu, mx1, 2));
        const float mn0 = fmaxf(m0, mx0), mn1 = fmaxf(m1, mx1);
        const float cr0 = ex2(m0 - mn0), cr1 = ex2(m1 - mn1);
        m0 = mn0; m1 = mn1;

        float sum0 = 0.f, sum1 = 0.f;
        #pragma unroll
        for (int j = 0; j < 8; j++) {
            if (j < 5) {     // MUFU path
                s[j][0] = ex2(s[j][0] - mn0); s[j][1] = ex2(s[j][1] - mn0);
                s[j][2] = ex2(s[j][2] - mn1); s[j][3] = ex2(s[j][3] - mn1);
            } else {         // FMA-pipe path
                s[j][0] = fast_exp2(s[j][0] - mn0); s[j][1] = fast_exp2(s[j][1] - mn0);
                s[j][2] = fast_exp2(s[j][2] - mn1); s[j][3] = fast_exp2(s[j][3] - mn1);
            }
            sum0 += s[j][0] + s[j][1];
            sum1 += s[j][2] + s[j][3];
        }
        sum0 += __shfl_xor_sync(0xffffffffu, sum0, 1);
        sum0 += __shfl_xor_sync(0xffffffffu, sum0, 2);
        sum1 += __shfl_xor_sync(0xffffffffu, sum1, 1);
        sum1 += __shfl_xor_sync(0xffffffffu, sum1, 2);
        l0 = l0 * cr0 + sum0;
        l1 = l1 * cr1 + sum1;
        #pragma unroll
        for (int j = 0; j < 8; j++) {
            o[j][0] *= cr0; o[j][1] *= cr0;
            o[j][2] *= cr1; o[j][3] *= cr1;
        }

        #pragma unroll
        for (int kt = 0; kt < 4; kt++) {
            uint32_t ph[4], pl[4];
            #pragma unroll
            for (int u = 0; u < 4; u++) {
                const int jj = 2*kt + (u >> 1);
                split_pack2(s[jj][(u & 1)*2], s[jj][(u & 1)*2 + 1], ph[u], pl[u]);
            }
            #pragma unroll
            for (int nb = 0; nb < 4; nb++) {
                uint32_t vh[4], vl[4];
                const uint32_t va = voff + (uint32_t)(kt*16*144) + (uint32_t)(nb*32);
                LDSM4T(vh, sV  + va);
                LDSM4T(vl, sVl + va);
                #pragma unroll
                for (int f = 0; f < 2; f++) {
                    float* dd = o[nb*2 + f];
                    MMA16816(dd, ph, vh[2*f], vh[2*f+1]);
                    MMA16816(dd, ph, vl[2*f], vl[2*f+1]);
                    MMA16816(dd, pl, vh[2*f], vh[2*f+1]);
                }
            }
        }
    }

    const float inv0 = 1.0f / l0, inv1 = 1.0f / l1;
    const size_t tok0 = (size_t)b * SS + r0g;
    const size_t tok1 = tok0 + 8;
    #pragma unroll
    for (int j = 0; j < 8; j++) {
        const int col = h*DH + j*8 + (lane & 3)*2;
        uint32_t h0, l0b, h1, l1b;
        split_pack2(o[j][0]*inv0, o[j][1]*inv0, h0, l0b);
        split_pack2(o[j][2]*inv1, o[j][3]*inv1, h1, l1b);
        *(uint32_t*)(Oh + tok0*DM + col) = h0;
        *(uint32_t*)(Ol + tok0*DM + col) = l0b;
        *(uint32_t*)(Oh + tok1*DM + col) = h1;
        *(uint32_t*)(Ol + tok1*DM + col) = l1b;
    }
}

// ---------------- launch ----------------
extern "C" void kernel_launch(void* const* d_in, const int* in_sizes, int n_in,
                              void* d_out, int out_size) {
    const float* x   = (const float*)d_in[0];
    const int*   pos = (const int*)  d_in[1];
    const float* qw  = (const float*)d_in[2];
    const float* kw  = (const float*)d_in[3];
    const float* vw  = (const float*)d_in[4];
    const float* ow  = (const float*)d_in[5];
    const float* g1  = (const float*)d_in[6];
    const float* g2  = (const float*)d_in[7];
    const float* w1  = (const float*)d_in[8];
    const float* w2  = (const float*)d_in[9];
    const float* w3  = (const float*)d_in[10];
    float* out = (float*)d_out;

    __half *xnh, *xnl, *qkvh, *qkvl, *ath, *atl, *hnh, *hnl, *swh, *swl;
    __half *wqkvh, *wqkvl, *owh, *w13h, *w2h;
    float *res1;
    cudaGetSymbolAddress((void**)&xnh, g_xn_h);   cudaGetSymbolAddress((void**)&xnl, g_xn_l);
    cudaGetSymbolAddress((void**)&qkvh, g_qkv_h); cudaGetSymbolAddress((void**)&qkvl, g_qkv_l);
    cudaGetSymbolAddress((void**)&ath, g_at_h);   cudaGetSymbolAddress((void**)&atl, g_at_l);
    cudaGetSymbolAddress((void**)&res1, g_res1);
    cudaGetSymbolAddress((void**)&hnh, g_hn_h);   cudaGetSymbolAddress((void**)&hnl, g_hn_l);
    cudaGetSymbolAddress((void**)&swh, g_sw_h);   cudaGetSymbolAddress((void**)&swl, g_sw_l);
    cudaGetSymbolAddress((void**)&wqkvh, g_wqkv_h); cudaGetSymbolAddress((void**)&wqkvl, g_wqkv_l);
    cudaGetSymbolAddress((void**)&owh, g_ow_h);
    cudaGetSymbolAddress((void**)&w13h, g_w13_h);
    cudaGetSymbolAddress((void**)&w2h, g_w2_h);

    const int GEMM_SMEM2 = 2 * 73728;    // 147456 (2-term)
    const int GEMM_SMEM3 = 2 * 110592;   // 221184 (3-term)
    cudaFuncSetAttribute((const void*)gemm_mma_fp16<0,false>, cudaFuncAttributeMaxDynamicSharedMemorySize, GEMM_SMEM2);
    cudaFuncSetAttribute((const void*)gemm_mma_fp16<1,true>,  cudaFuncAttributeMaxDynamicSharedMemorySize, GEMM_SMEM3);
    cudaFuncSetAttribute((const void*)gemm_mma_fp16<2,false>, cudaFuncAttributeMaxDynamicSharedMemorySize, GEMM_SMEM2);
    cudaFuncSetAttribute((const void*)attn_mma_kernel, cudaFuncAttributeMaxDynamicSharedMemorySize, ATT_SMEM);

    const int MM = 1024 * 1024;

    // launch order arranged so ncu's "-s 5" profiles the QKV GEMM (index 5)
    rope_table_kernel<<<SS, 32>>>(pos);                                    // 0
    wsplit2_kernel<<<MM/4/256, 256>>>(qw, wqkvh,        wqkvl,        MM/4); // 1
    wsplit2_kernel<<<MM/4/256, 256>>>(kw, wqkvh + MM,   wqkvl + MM,   MM/4); // 2
    wsplit2_kernel<<<MM/4/256, 256>>>(vw, wqkvh + 2*MM, wqkvl + 2*MM, MM/4); // 3
    rmsnorm_split_kernel<<<MTOK, 256>>>(x, g1, xnh, xnl);                  // 4

    // 5: fused QKV projection (3-term) + rope + Q prescale + split [8192,3072]
    gemm_mma_fp16<1,true><<<dim3(LDX/256, MTOK/128), 256, GEMM_SMEM3>>>(
        xnh, xnl, wqkvh, wqkvl, nullptr, nullptr, qkvh, qkvl, LDX, DM);

    // 6: HMMA flash attention (base-2 softmax) -> split fp16
    attn_mma_kernel<<<dim3(SS/64, BB*NH), 128, ATT_SMEM>>>(qkvh, qkvl, ath, atl);

    wsplit_kernel<<<MM/4/256, 256>>>(ow, owh, MM/4);                       // 7

    // 8: O projection (2-term) + residual(x) -> res1 fp32
    gemm_mma_fp16<0,false><<<dim3(DM/256, MTOK/128), 256, GEMM_SMEM2>>>(
        ath, atl, owh, nullptr, x, res1, nullptr, nullptr, DM, DM);

    rmsnorm_split_kernel<<<MTOK, 256>>>(res1, g2, hnh, hnl);               // 9
    wsplit_inter_kernel<<<MM/256, 256>>>(w1, w13h, MM, 0);                 // 10
    wsplit_inter_kernel<<<MM/256, 256>>>(w3, w13h, MM, 1);                 // 11

    // 12: fused W1||W3 (2-term, interleaved) + swiglu + split
    gemm_mma_fp16<2,false><<<dim3(2*DFF/256, MTOK/128), 256, GEMM_SMEM2>>>(
        hnh, hnl, w13h, nullptr, nullptr, nullptr, swh, swl, 2*DFF, DM);

    wsplit_kernel<<<MM/256, 256>>>(w2, w2h, MM);                           // 13

    // 14: down projection (2-term) + residual(res1) -> out
    gemm_mma_fp16<0,false><<<dim3(DM/256, MTOK/128), 256, GEMM_SMEM2>>>(
        swh, swl, w2h, nullptr, res1, out, nullptr, nullptr, DM, DFF);
}

// round 10
// speedup vs baseline: 6.3877x; 1.3462x over previous
#include <cuda_runtime.h>
#include <cuda_fp16.h>
#include <math.h>
#include <math_constants.h>
#include <cstdint>

#define BB   4
#define SS   2048
#define DM   1024
#define NH   16
#define DH   64
#define DFF  4096
#define MTOK (BB*SS)      // 8192
#define LDX  3072

// ---------------- helpers ----------------
__device__ __forceinline__ uint32_t smem_to_u32(const void* p) {
    uint32_t a;
    asm("{ .reg .u64 t; cvta.to.shared.u64 t, %1; cvt.u32.u64 %0, t; }" : "=r"(a) : "l"(p));
    return a;
}
#define CP_ASYNC16(s, g) asm volatile("cp.async.cg.shared.global [%0], [%1], 16;" :: "r"(s), "l"(g))
#define CP_COMMIT()      asm volatile("cp.async.commit_group;" ::: "memory")
#define CP_WAIT0()       asm volatile("cp.async.wait_group 0;" ::: "memory")
#define LDSM4(rg, addr) \
    asm volatile("ldmatrix.sync.aligned.m8n8.x4.shared.b16 {%0,%1,%2,%3}, [%4];" \
        : "=r"((rg)[0]), "=r"((rg)[1]), "=r"((rg)[2]), "=r"((rg)[3]) : "r"(addr))
#define LDSM4T(rg, addr) \
    asm volatile("ldmatrix.sync.aligned.m8n8.x4.trans.shared.b16 {%0,%1,%2,%3}, [%4];" \
        : "=r"((rg)[0]), "=r"((rg)[1]), "=r"((rg)[2]), "=r"((rg)[3]) : "r"(addr))
#define MMA16816(d, a, b0v, b1v) \
    asm volatile("mma.sync.aligned.m16n8k16.row.col.f32.f16.f16.f32 " \
        "{%0,%1,%2,%3}, {%4,%5,%6,%7}, {%8,%9}, {%0,%1,%2,%3};" \
        : "+f"((d)[0]), "+f"((d)[1]), "+f"((d)[2]), "+f"((d)[3]) \
        : "r"((a)[0]), "r"((a)[1]), "r"((a)[2]), "r"((a)[3]), "r"(b0v), "r"(b1v))

__device__ __forceinline__ float ex2(float x) {
    float r; asm("ex2.approx.f32 %0, %1;" : "=f"(r) : "f"(x)); return r;
}
__device__ __forceinline__ float rcpa(float x) {
    float r; asm("rcp.approx.f32 %0, %1;" : "=f"(r) : "f"(x)); return r;
}
// 2^y on the FMA pipe (magic round + deg-5 Taylor), rel err ~2e-6
__device__ __forceinline__ float fast_exp2(float y) {
    y = fmaxf(fminf(y, 126.f), -126.f);
    float z = __fadd_rn(y, 12582912.f);
    int   n = __float_as_int(z) - 0x4B400000;
    float f = __fadd_rn(y, -__fadd_rn(z, -12582912.f));
    float p = fmaf(f, 0.0013333558f, 0.0096181291f);
    p = fmaf(f, p, 0.0555041087f);
    p = fmaf(f, p, 0.2402265069f);
    p = fmaf(f, p, 0.6931471806f);
    p = fmaf(f, p, 1.0f);
    return __int_as_float(__float_as_int(p) + (n << 23));
}
// pack (p0,p1) -> f16x2 hi + f16x2 lo residual
__device__ __forceinline__ void split_pack2(float p0, float p1, uint32_t& h2, uint32_t& l2) {
    __half2 h = __floats2half2_rn(p0, p1);
    float2 hf = __half22float2(h);
    __half2 l = __floats2half2_rn(__fadd_rn(p0, -hf.x), __fadd_rn(p1, -hf.y));
    h2 = *(uint32_t*)&h;
    l2 = *(uint32_t*)&l;
}

// ---------------- scratch (__device__ globals) ----------------
static __device__ __half g_xn_h[(size_t)MTOK*DM],  g_xn_l[(size_t)MTOK*DM];
static __device__ __half g_qkv_h[(size_t)MTOK*LDX], g_qkv_l[(size_t)MTOK*LDX];
static __device__ __half g_at_h[(size_t)MTOK*DM],  g_at_l[(size_t)MTOK*DM];
static __device__ float  g_res1[(size_t)MTOK*DM];
static __device__ __half g_hn_h[(size_t)MTOK*DM],  g_hn_l[(size_t)MTOK*DM];
static __device__ __half g_sw_h[(size_t)MTOK*DFF];
static __device__ __half g_wqkv_h[3072*1024], g_wqkv_l[3072*1024];
static __device__ __half g_ow_h [1024*1024];
static __device__ __half g_w13_h[2*DFF*1024];   // interleaved rows
static __device__ __half g_w2_h [1024*DFF];
static __device__ float g_cs[SS*32], g_sn[SS*32];

__global__ void rope_table_kernel(const int* __restrict__ pos) {
    const int s = blockIdx.x, i = threadIdx.x;   // 2048 x 32
    const float inv = exp2f(-(float)i * (13.287712379549449f / 32.0f));
    const float a = (float)pos[s] * inv;
    float sn, cs;
    sincosf(a, &sn, &cs);
    g_cs[s*32 + i] = cs;
    g_sn[s*32 + i] = sn;
}

// hi-only weight conversion
__global__ void wsplit_kernel(const float* __restrict__ x,
                              __half* __restrict__ h, int n4) {
    int i = blockIdx.x * blockDim.x + threadIdx.x;
    if (i >= n4) return;
    float4 v = ((const float4*)x)[i];
    ((__half2*)h)[2*i]   = __floats2half2_rn(v.x, v.y);
    ((__half2*)h)[2*i+1] = __floats2half2_rn(v.z, v.w);
}

// hi+lo weight split (for the 3-term QKV GEMM)
__global__ void wsplit2_kernel(const float* __restrict__ x,
                               __half* __restrict__ h,
                               __half* __restrict__ l, int n4) {
    int i = blockIdx.x * blockDim.x + threadIdx.x;
    if (i >= n4) return;
    float4 v = ((const float4*)x)[i];
    uint32_t h0, l0, h1, l1;
    split_pack2(v.x, v.y, h0, l0);
    split_pack2(v.z, v.w, h1, l1);
    ((uint32_t*)h)[2*i]   = h0; ((uint32_t*)h)[2*i+1] = h1;
    ((uint32_t*)l)[2*i]   = l0; ((uint32_t*)l)[2*i+1] = l1;
}

// interleaved weight hi split: src row n -> dst row 2n+off  (K=1024)
__global__ void wsplit_inter_kernel(const float* __restrict__ x,
                                    __half* __restrict__ h,
                                    int n4, int off) {
    int i = blockIdx.x * blockDim.x + threadIdx.x;
    if (i >= n4) return;
    const int row = i >> 8;
    const int c4  = i & 255;
    float4 v = ((const float4*)x)[i];
    const size_t o2 = ((size_t)(2*row + off) * 1024 + c4*4) >> 1;
    ((__half2*)h)[o2]   = __floats2half2_rn(v.x, v.y);
    ((__half2*)h)[o2+1] = __floats2half2_rn(v.z, v.w);
}

// ---------------- RMSNorm -> split fp16 ----------------
__global__ void rmsnorm_split_kernel(const float* __restrict__ x,
                                     const float* __restrict__ g,
                                     __half* __restrict__ yh,
                                     __half* __restrict__ yl) {
    const int row = blockIdx.x;
    const float4* xr = (const float4*)(x + (size_t)row * DM);
    const int t = threadIdx.x;
    float4 xv = xr[t];
    float ss = xv.x*xv.x + xv.y*xv.y + xv.z*xv.z + xv.w*xv.w;
    #pragma unroll
    for (int o = 16; o; o >>= 1) ss += __shfl_xor_sync(0xffffffffu, ss, o);
    __shared__ float sred[8];
    const int warp = t >> 5, lane = t & 31;
    if (lane == 0) sred[warp] = ss;
    __syncthreads();
    if (warp == 0) {
        float v = (lane < 8) ? sred[lane] : 0.f;
        #pragma unroll
        for (int o = 4; o; o >>= 1) v += __shfl_xor_sync(0xffffffffu, v, o);
        if (lane == 0) sred[0] = v;
    }
    __syncthreads();
    const float inv = rsqrtf(sred[0] * (1.0f/(float)DM) + 1e-5f);
    const float4 gv = ((const float4*)g)[t];
    uint32_t h0, l0, h1, l1;
    split_pack2(xv.x*inv*gv.x, xv.y*inv*gv.y, h0, l0);
    split_pack2(xv.z*inv*gv.z, xv.w*inv*gv.w, h1, l1);
    const size_t b2 = (size_t)row * (DM/2) + 2*t;
    ((uint32_t*)yh)[b2]   = h0; ((uint32_t*)yh)[b2+1] = h1;
    ((uint32_t*)yl)[b2]   = l0; ((uint32_t*)yl)[b2+1] = l1;
}

// -------- mma.sync fp16 GEMM, CTA 128x256, warp 64x64, 1/2/3-term -------------
// Terms: Ah*Bh (+ Al*Bh when ALO) (+ Ah*Bl when BLO).
// MODE 0: C fp32 (+R). MODE 1: rope+Qscale+split -> Ch/Cl. MODE 2: swiglu -> Ch.
#define ROWB    144
#define QSCALE  0.18033688f      // 0.125 * log2(e)
template<int MODE, bool ALO, bool BLO>
__global__ __launch_bounds__(256, 1)
void gemm_mma_fp16(const __half* __restrict__ Ah,
                   const __half* __restrict__ Al,
                   const __half* __restrict__ Bh,
                   const __half* __restrict__ Bl,
                   const float* __restrict__ R,
                   float* __restrict__ C,
                   __half* __restrict__ Ch,
                   __half* __restrict__ Cl,
                   int N, int K) {
    constexpr uint32_t AL_OFF = 128u * ROWB;
    constexpr uint32_t B_OFFC = (ALO ? 2u : 1u) * 128u * ROWB;
    constexpr uint32_t BL_OFF = B_OFFC + 256u * ROWB;
    constexpr uint32_t STG = (128u*(ALO ? 2u : 1u) + 256u*(BLO ? 2u : 1u)) * ROWB;
    extern __shared__ char smem[];
    const uint32_t sbase = smem_to_u32(smem);
    const int tid  = threadIdx.x;
    const int lane = tid & 31;
    const int wid  = tid >> 5;
    const int bm = blockIdx.y * 128;
    const int bn = blockIdx.x * 256;
    const int m0w = (wid & 1) * 64;
    const int n0w = (wid >> 1) * 64;

    float acc[4][8][4];
    #pragma unroll
    for (int i = 0; i < 4; i++)
        #pragma unroll
        for (int j = 0; j < 8; j++)
            #pragma unroll
            for (int q = 0; q < 4; q++) acc[i][j][q] = 0.f;

    const int nch = K >> 6;

    auto load_stage = [&](int s, int c) {
        const int k0 = c << 6;
        const uint32_t st = sbase + (uint32_t)s * STG;
        #pragma unroll
        for (int i = 0; i < 4; ++i) {           // A: 128 rows
            const int idx = tid + (i << 8);
            const int row = idx >> 3, cc = idx & 7;
            const uint32_t so = (uint32_t)(row * ROWB + cc * 16);
            const size_t ga = (size_t)(bm + row) * K + k0 + cc * 8;
            CP_ASYNC16(st + so, (const char*)(Ah + ga));
            if (ALO) CP_ASYNC16(st + AL_OFF + so, (const char*)(Al + ga));
        }
        #pragma unroll
        for (int i = 0; i < 8; ++i) {           // B: 256 rows
            const int idx = tid + (i << 8);
            const int row = idx >> 3, cc = idx & 7;
            const uint32_t so = (uint32_t)(row * ROWB + cc * 16);
            const size_t gb = (size_t)(bn + row) * K + k0 + cc * 8;
            CP_ASYNC16(st + B_OFFC + so, (const char*)(Bh + gb));
            if (BLO) CP_ASYNC16(st + BL_OFF + so, (const char*)(Bl + gb));
        }
        CP_COMMIT();
    };

    const int g = lane >> 3, r = lane & 7;
    const uint32_t aoff = (uint32_t)((m0w + (g & 1) * 8 + r) * ROWB + ((g >> 1) * 8) * 2);
    const uint32_t boff = B_OFFC + (uint32_t)((n0w + (g >> 1) * 8 + r) * ROWB + ((g & 1) * 8) * 2);

    load_stage(0, 0);

    for (int c = 0; c < nch; ++c) {
        CP_WAIT0();
        __syncthreads();
        if (c + 1 < nch) load_stage((c + 1) & 1, c + 1);

        const uint32_t st = sbase + (uint32_t)(c & 1) * STG;
        #pragma unroll
        for (int ks = 0; ks < 4; ++ks) {
            uint32_t AhF[4][4], AlF[4][4];
            const uint32_t ab = st + aoff + (uint32_t)(ks * 32);
            #pragma unroll
            for (int mi = 0; mi < 4; ++mi) {
                LDSM4(AhF[mi], ab + (uint32_t)(mi * 16 * ROWB));
                if (ALO) LDSM4(AlF[mi], ab + AL_OFF + (uint32_t)(mi * 16 * ROWB));
            }
            const uint32_t bb = st + boff + (uint32_t)(ks * 32);
            #pragma unroll
            for (int nb = 0; nb < 4; ++nb) {
                uint32_t BhF[4], BlF[4];
                LDSM4(BhF, bb + (uint32_t)(nb * 16 * ROWB));
                if (BLO) LDSM4(BlF, bb + (uint32_t)(BL_OFF - B_OFFC) + (uint32_t)(nb * 16 * ROWB));
                #pragma unroll
                for (int mi = 0; mi < 4; ++mi)
                    #pragma unroll
                    for (int hf = 0; hf < 2; ++hf) {
                        float* d = acc[mi][nb * 2 + hf];
                        MMA16816(d, AhF[mi], BhF[hf*2], BhF[hf*2+1]);
                        if (ALO) MMA16816(d, AlF[mi], BhF[hf*2], BhF[hf*2+1]);
                        if (BLO) MMA16816(d, AhF[mi], BlF[hf*2], BlF[hf*2+1]);
                    }
            }
        }
    }

    const int erow = lane >> 2;
    const int ecol = (lane & 3) * 2;
    #pragma unroll
    for (int mi = 0; mi < 4; ++mi) {
        #pragma unroll
        for (int nj = 0; nj < 8; ++nj) {
            float* d = acc[mi][nj];
            const int row0 = bm + m0w + mi * 16 + erow;
            const int row1 = row0 + 8;
            const int cg   = bn + n0w + nj * 8 + ecol;
            if (MODE == 0) {
                const size_t o0 = (size_t)row0 * N + cg;
                const size_t o1 = (size_t)row1 * N + cg;
                float2 v0 = make_float2(d[0], d[1]);
                float2 v1 = make_float2(d[2], d[3]);
                if (R) {
                    const float2 r0 = *(const float2*)(R + o0);
                    const float2 r1 = *(const float2*)(R + o1);
                    v0.x += r0.x; v0.y += r0.y;
                    v1.x += r1.x; v1.y += r1.y;
                }
                *(float2*)(C + o0) = v0;
                *(float2*)(C + o1) = v1;
            } else if (MODE == 1) {
                float a0 = d[0], a1 = d[1], b0 = d[2], b1 = d[3];
                if (cg < 2048) {
                    const int i = (cg & 63) >> 1;
                    const int s0 = (row0 & (SS-1))*32 + i;
                    const int s1 = (row1 & (SS-1))*32 + i;
                    const float c0 = g_cs[s0], n0 = g_sn[s0];
                    const float c1 = g_cs[s1], n1 = g_sn[s1];
                    float t0 = a0*c0 - a1*n0, t1 = a0*n0 + a1*c0;
                    a0 = t0; a1 = t1;
                    float u0 = b0*c1 - b1*n1, u1 = b0*n1 + b1*c1;
                    b0 = u0; b1 = u1;
                }
                if (cg < 1024) {  // Q pre-scale into log2 domain
                    a0 *= QSCALE; a1 *= QSCALE; b0 *= QSCALE; b1 *= QSCALE;
                }
                uint32_t h0, l0, h1, l1;
                split_pack2(a0, a1, h0, l0);
                split_pack2(b0, b1, h1, l1);
                const size_t o0 = (size_t)row0 * N + cg;
                const size_t o1 = (size_t)row1 * N + cg;
                *(uint32_t*)(Ch + o0) = h0;
                *(uint32_t*)(Cl + o0) = l0;
                *(uint32_t*)(Ch + o1) = h1;
                *(uint32_t*)(Cl + o1) = l1;
            } else {  // MODE 2: swiglu, (even,odd) = (a, gate); hi-only output
                const int j = cg >> 1;
                const int NC = N >> 1;
                float sl0, sl1;
                if (nj < 3) {   // MUFU path
                    const float e0 = ex2(-1.44269504f * d[0]);
                    const float e1 = ex2(-1.44269504f * d[2]);
                    const float dd0 = 1.f + e0, dd1 = 1.f + e1;
                    float r0 = rcpa(dd0); r0 = r0 * (2.f - dd0 * r0);
                    float r1 = rcpa(dd1); r1 = r1 * (2.f - dd1 * r1);
                    sl0 = d[0] * r0 * d[1];
                    sl1 = d[2] * r1 * d[3];
                } else {        // FMA-pipe path
                    const float e0 = fast_exp2(-1.44269504f * d[0]);
                    const float e1 = fast_exp2(-1.44269504f * d[2]);
                    const float dd0 = 1.f + e0, dd1 = 1.f + e1;
                    float r0 = __int_as_float(0x7EF311C3 - __float_as_int(dd0));
                    r0 = r0 * (2.f - dd0 * r0); r0 = r0 * (2.f - dd0 * r0);
                    float r1 = __int_as_float(0x7EF311C3 - __float_as_int(dd1));
                    r1 = r1 * (2.f - dd1 * r1); r1 = r1 * (2.f - dd1 * r1);
                    sl0 = d[0] * r0 * d[1];
                    sl1 = d[2] * r1 * d[3];
                }
                Ch[(size_t)row0 * NC + j] = __float2half_rn(sl0);
                Ch[(size_t)row1 * NC + j] = __float2half_rn(sl1);
            }
        }
    }
}

// -------- HMMA flash attention (QK 3-term, PV 2-term, base-2 softmax) ---------
#define ATB (64*144)
#define ATT_SMEM (8*ATB)     // Qh,Ql + 2 stages x (Kh,Kl,Vh)
__global__ __launch_bounds__(128)
void attn_mma_kernel(const __half* __restrict__ Xh,
                     const __half* __restrict__ Xl,
                     __half* __restrict__ Oh,
                     __half* __restrict__ Ol) {
    extern __shared__ char sm[];
    const uint32_t sQh = smem_to_u32(sm);
    const uint32_t sQl = sQh + ATB;
    const uint32_t sSt = sQh + 2*ATB;

    const int tid = threadIdx.x, lane = tid & 31, warp = tid >> 5;
    const int bh = blockIdx.y, b = bh >> 4, h = bh & (NH-1);
    const int qt = gridDim.x - 1 - blockIdx.x;
    const int q0 = qt * 64;
    const size_t rowbase = (size_t)b * SS * LDX;
    const int colQ = h*DH, colK = 1024 + h*DH, colV = 2048 + h*DH;

    #pragma unroll
    for (int i = 0; i < 4; i++) {
        const int idx = tid + i*128;
        const int r = idx >> 3, c = idx & 7;
        const uint32_t so = (uint32_t)(r*144 + c*16);
        const size_t ga = rowbase + (size_t)(q0 + r)*LDX + colQ + c*8;
        CP_ASYNC16(sQh + so, (const char*)(Xh + ga));
        CP_ASYNC16(sQl + so, (const char*)(Xl + ga));
    }
    CP_COMMIT();

    auto load_kv = [&](int t, int s) {
        const int k0 = t * 64;
        #pragma unroll
        for (int i = 0; i < 4; i++) {
            const int idx = tid + i*128;
            const int r = idx >> 3, c = idx & 7;
            const uint32_t so = (uint32_t)s*3*ATB + (uint32_t)(r*144 + c*16);
            const size_t gk = rowbase + (size_t)(k0 + r)*LDX + colK + c*8;
            const size_t gv = rowbase + (size_t)(k0 + r)*LDX + colV + c*8;
            CP_ASYNC16(sSt + so,         (const char*)(Xh + gk));
            CP_ASYNC16(sSt + ATB + so,   (const char*)(Xl + gk));
            CP_ASYNC16(sSt + 2*ATB + so, (const char*)(Xh + gv));
        }
        CP_COMMIT();
    };
    load_kv(0, 0);

    const int g = lane >> 3, rr = lane & 7;
    const uint32_t aoff = (uint32_t)((warp*16 + (g&1)*8 + rr)*144 + (g>>1)*16);
    const uint32_t boff = (uint32_t)(((g>>1)*8 + rr)*144 + (g&1)*16);
    const uint32_t voff = (uint32_t)(((g&1)*8 + rr)*144 + (lane>>4)*16);

    float m0 = -CUDART_INF_F, m1 = -CUDART_INF_F, l0 = 0.f, l1 = 0.f;
    float o[8][4];
    #pragma unroll
    for (int j = 0; j < 8; j++)
        #pragma unroll
        for (int q = 0; q < 4; q++) o[j][q] = 0.f;

    const int r0g = q0 + warp*16 + (lane >> 2);
    const int r1g = r0g + 8;
    const int ntiles = qt + 1;

    for (int t = 0; t < ntiles; t++) {
        CP_WAIT0();
        __syncthreads();
        if (t + 1 < ntiles) load_kv(t + 1, (t + 1) & 1);

        const uint32_t sK  = sSt + (uint32_t)(t & 1)*3*ATB;
        const uint32_t sKl = sK + ATB;
        const uint32_t sV  = sK + 2*ATB;

        float s[8][4];
        #pragma unroll
        for (int j = 0; j < 8; j++)
            #pragma unroll
            for (int q = 0; q < 4; q++) s[j][q] = 0.f;

        #pragma unroll
        for (int d = 0; d < 4; d++) {
            uint32_t qh[4], ql[4];
            LDSM4(qh, sQh + aoff + d*32);
            LDSM4(ql, sQl + aoff + d*32);
            #pragma unroll
            for (int nb = 0; nb < 4; nb++) {
                uint32_t kh[4], kl[4];
                LDSM4(kh, sK  + boff + (uint32_t)(nb*16*144) + d*32);
                LDSM4(kl, sKl + boff + (uint32_t)(nb*16*144) + d*32);
                #pragma unroll
                for (int f = 0; f < 2; f++) {
                    float* dd = s[nb*2 + f];
                    MMA16816(dd, qh, kh[2*f], kh[2*f+1]);
                    MMA16816(dd, qh, kl[2*f], kl[2*f+1]);
                    MMA16816(dd, ql, kh[2*f], kh[2*f+1]);
                }
            }
        }

        // scores already in log2 domain (Q pre-scaled by 0.125*log2e)
        const int k0 = t * 64;
        float mx0 = -CUDART_INF_F, mx1 = -CUDART_INF_F;
        #pragma unroll
        for (int j = 0; j < 8; j++) {
            if (t == qt) {
                const int c = k0 + j*8 + (lane & 3)*2;
                if (c     > r0g) s[j][0] = -CUDART_INF_F;
                if (c + 1 > r0g) s[j][1] = -CUDART_INF_F;
                if (c     > r1g) s[j][2] = -CUDART_INF_F;
                if (c + 1 > r1g) s[j][3] = -CUDART_INF_F;
            }
            mx0 = fmaxf(mx0, fmaxf(s[j][0], s[j][1]));
            mx1 = fmaxf(mx1, fmaxf(s[j][2], s[j][3]));
        }
        mx0 = fmaxf(mx0, __shfl_xor_sync(0xffffffffu, mx0, 1));
        mx0 = fmaxf(mx0, __shfl_xor_sync(0xffffffffu, mx0, 2));
        mx1 = fmaxf(mx1, __shfl_xor_sync(0xffffffffu, mx1, 1));
        mx1 = fmaxf(mx1, __shfl_xor_sync(0xffffffffu, mx1, 2));
        const float mn0 = fmaxf(m0, mx0), mn1 = fmaxf(m1, mx1);
        const float cr0 = ex2(m0 - mn0), cr1 = ex2(m1 - mn1);
        m0 = mn0; m1 = mn1;

        float sum0 = 0.f, sum1 = 0.f;
        #pragma unroll
        for (int j = 0; j < 8; j++) {
            if (j < 5) {     // MUFU path
                s[j][0] = ex2(s[j][0] - mn0); s[j][1] = ex2(s[j][1] - mn0);
                s[j][2] = ex2(s[j][2] - mn1); s[j][3] = ex2(s[j][3] - mn1);
            } else {         // FMA-pipe path
                s[j][0] = fast_exp2(s[j][0] - mn0); s[j][1] = fast_exp2(s[j][1] - mn0);
                s[j][2] = fast_exp2(s[j][2] - mn1); s[j][3] = fast_exp2(s[j][3] - mn1);
            }
            sum0 += s[j][0] + s[j][1];
            sum1 += s[j][2] + s[j][3];
        }
        sum0 += __shfl_xor_sync(0xffffffffu, sum0, 1);
        sum0 += __shfl_xor_sync(0xffffffffu, sum0, 2);
        sum1 += __shfl_xor_sync(0xffffffffu, sum1, 1);
        sum1 += __shfl_xor_sync(0xffffffffu, sum1, 2);
        l0 = l0 * cr0 + sum0;
        l1 = l1 * cr1 + sum1;
        #pragma unroll
        for (int j = 0; j < 8; j++) {
            o[j][0] *= cr0; o[j][1] *= cr0;
            o[j][2] *= cr1; o[j][3] *= cr1;
        }

        #pragma unroll
        for (int kt = 0; kt < 4; kt++) {
            uint32_t ph[4], pl[4];
            #pragma unroll
            for (int u = 0; u < 4; u++) {
                const int jj = 2*kt + (u >> 1);
                split_pack2(s[jj][(u & 1)*2], s[jj][(u & 1)*2 + 1], ph[u], pl[u]);
            }
            #pragma unroll
            for (int nb = 0; nb < 4; nb++) {
                uint32_t vh[4];
                const uint32_t va = voff + (uint32_t)(kt*16*144) + (uint32_t)(nb*32);
                LDSM4T(vh, sV + va);
                #pragma unroll
                for (int f = 0; f < 2; f++) {
                    float* dd = o[nb*2 + f];
                    MMA16816(dd, ph, vh[2*f], vh[2*f+1]);
                    MMA16816(dd, pl, vh[2*f], vh[2*f+1]);
                }
            }
        }
    }

    const float inv0 = 1.0f / l0, inv1 = 1.0f / l1;
    const size_t tok0 = (size_t)b * SS + r0g;
    const size_t tok1 = tok0 + 8;
    #pragma unroll
    for (int j = 0; j < 8; j++) {
        const int col = h*DH + j*8 + (lane & 3)*2;
        uint32_t h0, l0b, h1, l1b;
        split_pack2(o[j][0]*inv0, o[j][1]*inv0, h0, l0b);
        split_pack2(o[j][2]*inv1, o[j][3]*inv1, h1, l1b);
        *(uint32_t*)(Oh + tok0*DM + col) = h0;
        *(uint32_t*)(Ol + tok0*DM + col) = l0b;
        *(uint32_t*)(Oh + tok1*DM + col) = h1;
        *(uint32_t*)(Ol + tok1*DM + col) = l1b;
    }
}

// ---------------- launch ----------------
extern "C" void kernel_launch(void* const* d_in, const int* in_sizes, int n_in,
                              void* d_out, int out_size) {
    const float* x   = (const float*)d_in[0];
    const int*   pos = (const int*)  d_in[1];
    const float* qw  = (const float*)d_in[2];
    const float* kw  = (const float*)d_in[3];
    const float* vw  = (const float*)d_in[4];
    const float* ow  = (const float*)d_in[5];
    const float* g1  = (const float*)d_in[6];
    const float* g2  = (const float*)d_in[7];
    const float* w1  = (const float*)d_in[8];
    const float* w2  = (const float*)d_in[9];
    const float* w3  = (const float*)d_in[10];
    float* out = (float*)d_out;

    __half *xnh, *xnl, *qkvh, *qkvl, *ath, *atl, *hnh, *hnl, *swh;
    __half *wqkvh, *wqkvl, *owh, *w13h, *w2h;
    float *res1;
    cudaGetSymbolAddress((void**)&xnh, g_xn_h);   cudaGetSymbolAddress((void**)&xnl, g_xn_l);
    cudaGetSymbolAddress((void**)&qkvh, g_qkv_h); cudaGetSymbolAddress((void**)&qkvl, g_qkv_l);
    cudaGetSymbolAddress((void**)&ath, g_at_h);   cudaGetSymbolAddress((void**)&atl, g_at_l);
    cudaGetSymbolAddress((void**)&res1, g_res1);
    cudaGetSymbolAddress((void**)&hnh, g_hn_h);   cudaGetSymbolAddress((void**)&hnl, g_hn_l);
    cudaGetSymbolAddress((void**)&swh, g_sw_h);
    cudaGetSymbolAddress((void**)&wqkvh, g_wqkv_h); cudaGetSymbolAddress((void**)&wqkvl, g_wqkv_l);
    cudaGetSymbolAddress((void**)&owh, g_ow_h);
    cudaGetSymbolAddress((void**)&w13h, g_w13_h);
    cudaGetSymbolAddress((void**)&w2h, g_w2_h);

    const int SM3 = 2 * (128*2 + 256*2) * ROWB;   // 221184  (3-term)
    const int SM2 = 2 * (128*2 + 256)   * ROWB;   // 147456  (2-term)
    const int SM1 = 2 * (128 + 256)     * ROWB;   // 110592  (1-term)
    cudaFuncSetAttribute((const void*)gemm_mma_fp16<1,true,true>,   cudaFuncAttributeMaxDynamicSharedMemorySize, SM3);
    cudaFuncSetAttribute((const void*)gemm_mma_fp16<0,true,false>,  cudaFuncAttributeMaxDynamicSharedMemorySize, SM2);
    cudaFuncSetAttribute((const void*)gemm_mma_fp16<2,false,false>, cudaFuncAttributeMaxDynamicSharedMemorySize, SM1);
    cudaFuncSetAttribute((const void*)gemm_mma_fp16<0,false,false>, cudaFuncAttributeMaxDynamicSharedMemorySize, SM1);
    cudaFuncSetAttribute((const void*)attn_mma_kernel, cudaFuncAttributeMaxDynamicSharedMemorySize, ATT_SMEM);

    const int MM = 1024 * 1024;

    // launch order arranged so ncu's "-s 5" profiles the QKV GEMM (index 5)
    rope_table_kernel<<<SS, 32>>>(pos);                                      // 0
    wsplit2_kernel<<<MM/4/256, 256>>>(qw, wqkvh,        wqkvl,        MM/4); // 1
    wsplit2_kernel<<<MM/4/256, 256>>>(kw, wqkvh + MM,   wqkvl + MM,   MM/4); // 2
    wsplit2_kernel<<<MM/4/256, 256>>>(vw, wqkvh + 2*MM, wqkvl + 2*MM, MM/4); // 3
    rmsnorm_split_kernel<<<MTOK, 256>>>(x, g1, xnh, xnl);                    // 4

    // 5: fused QKV projection (3-term) + rope + Q prescale + split [8192,3072]
    gemm_mma_fp16<1,true,true><<<dim3(LDX/256, MTOK/128), 256, SM3>>>(
        xnh, xnl, wqkvh, wqkvl, nullptr, nullptr, qkvh, qkvl, LDX, DM);

    // 6: HMMA flash attention -> split fp16
    attn_mma_kernel<<<dim3(SS/64, BB*NH), 128, ATT_SMEM>>>(qkvh, qkvl, ath, atl);

    wsplit_kernel<<<MM/4/256, 256>>>(ow, owh, MM/4);                         // 7

    // 8: O projection (2-term) + residual(x) -> res1 fp32
    gemm_mma_fp16<0,true,false><<<dim3(DM/256, MTOK/128), 256, SM2>>>(
        ath, atl, owh, nullptr, x, res1, nullptr, nullptr, DM, DM);

    rmsnorm_split_kernel<<<MTOK, 256>>>(res1, g2, hnh, hnl);                 // 9
    wsplit_inter_kernel<<<MM/256, 256>>>(w1, w13h, MM, 0);                   // 10
    wsplit_inter_kernel<<<MM/256, 256>>>(w3, w13h, MM, 1);                   // 11

    // 12: fused W1||W3 (1-term, interleaved) + swiglu -> sw hi
    gemm_mma_fp16<2,false,false><<<dim3(2*DFF/256, MTOK/128), 256, SM1>>>(
        hnh, nullptr, w13h, nullptr, nullptr, nullptr, swh, nullptr, 2*DFF, DM);

    wsplit_kernel<<<MM/256, 256>>>(w2, w2h, MM);                             // 13

    // 14: down projection (1-term) + residual(res1) -> out
    gemm_mma_fp16<0,false,false><<<dim3(DM/256, MTOK/128), 256, SM1>>>(
        swh, nullptr, w2h, nullptr, res1, out, nullptr, nullptr, DM, DFF);
}

// round 11
// speedup vs baseline: 6.6365x; 1.0390x over previous
#include <cuda_runtime.h>
#include <cuda_fp16.h>
#include <math.h>
#include <math_constants.h>
#include <cstdint>

#define BB   4
#define SS   2048
#define DM   1024
#define NH   16
#define DH   64
#define DFF  4096
#define MTOK (BB*SS)      // 8192
#define LDX  3072

// ---------------- helpers ----------------
__device__ __forceinline__ uint32_t smem_to_u32(const void* p) {
    uint32_t a;
    asm("{ .reg .u64 t; cvta.to.shared.u64 t, %1; cvt.u32.u64 %0, t; }" : "=r"(a) : "l"(p));
    return a;
}
#define CP_ASYNC16(s, g) asm volatile("cp.async.cg.shared.global [%0], [%1], 16;" :: "r"(s), "l"(g))
#define CP_COMMIT()      asm volatile("cp.async.commit_group;" ::: "memory")
#define CP_WAIT0()       asm volatile("cp.async.wait_group 0;" ::: "memory")
#define LDSM4(rg, addr) \
    asm volatile("ldmatrix.sync.aligned.m8n8.x4.shared.b16 {%0,%1,%2,%3}, [%4];" \
        : "=r"((rg)[0]), "=r"((rg)[1]), "=r"((rg)[2]), "=r"((rg)[3]) : "r"(addr))
#define LDSM4T(rg, addr) \
    asm volatile("ldmatrix.sync.aligned.m8n8.x4.trans.shared.b16 {%0,%1,%2,%3}, [%4];" \
        : "=r"((rg)[0]), "=r"((rg)[1]), "=r"((rg)[2]), "=r"((rg)[3]) : "r"(addr))
#define MMA16816(d, a, b0v, b1v) \
    asm volatile("mma.sync.aligned.m16n8k16.row.col.f32.f16.f16.f32 " \
        "{%0,%1,%2,%3}, {%4,%5,%6,%7}, {%8,%9}, {%0,%1,%2,%3};" \
        : "+f"((d)[0]), "+f"((d)[1]), "+f"((d)[2]), "+f"((d)[3]) \
        : "r"((a)[0]), "r"((a)[1]), "r"((a)[2]), "r"((a)[3]), "r"(b0v), "r"(b1v))

__device__ __forceinline__ float ex2(float x) {
    float r; asm("ex2.approx.f32 %0, %1;" : "=f"(r) : "f"(x)); return r;
}
__device__ __forceinline__ float rcpa(float x) {
    float r; asm("rcp.approx.f32 %0, %1;" : "=f"(r) : "f"(x)); return r;
}
// 2^y on the FMA pipe (magic round + deg-5 Taylor), rel err ~2e-6
__device__ __forceinline__ float fast_exp2(float y) {
    y = fmaxf(fminf(y, 126.f), -126.f);
    float z = __fadd_rn(y, 12582912.f);
    int   n = __float_as_int(z) - 0x4B400000;
    float f = __fadd_rn(y, -__fadd_rn(z, -12582912.f));
    float p = fmaf(f, 0.0013333558f, 0.0096181291f);
    p = fmaf(f, p, 0.0555041087f);
    p = fmaf(f, p, 0.2402265069f);
    p = fmaf(f, p, 0.6931471806f);
    p = fmaf(f, p, 1.0f);
    return __int_as_float(__float_as_int(p) + (n << 23));
}
// pack (p0,p1) -> f16x2 hi + f16x2 lo residual
__device__ __forceinline__ void split_pack2(float p0, float p1, uint32_t& h2, uint32_t& l2) {
    __half2 h = __floats2half2_rn(p0, p1);
    float2 hf = __half22float2(h);
    __half2 l = __floats2half2_rn(__fadd_rn(p0, -hf.x), __fadd_rn(p1, -hf.y));
    h2 = *(uint32_t*)&h;
    l2 = *(uint32_t*)&l;
}

// ---------------- scratch (__device__ globals) ----------------
static __device__ __half g_xn_h[(size_t)MTOK*DM],  g_xn_l[(size_t)MTOK*DM];
static __device__ __half g_qkv_h[(size_t)MTOK*LDX], g_qkv_l[(size_t)MTOK*LDX];
static __device__ __half g_at_h[(size_t)MTOK*DM],  g_at_l[(size_t)MTOK*DM];
static __device__ float  g_res1[(size_t)MTOK*DM];
static __device__ __half g_hn_h[(size_t)MTOK*DM],  g_hn_l[(size_t)MTOK*DM];
static __device__ __half g_sw_h[(size_t)MTOK*DFF];
static __device__ __half g_wqk_h[2048*1024], g_wqk_l[2048*1024];
static __device__ __half g_vw_h [1024*1024];
static __device__ __half g_ow_h [1024*1024];
static __device__ __half g_w13_h[2*DFF*1024];   // interleaved rows
static __device__ __half g_w2_h [1024*DFF];
static __device__ float g_cs[SS*32], g_sn[SS*32];

__global__ void rope_table_kernel(const int* __restrict__ pos) {
    const int s = blockIdx.x, i = threadIdx.x;   // 2048 x 32
    const float inv = exp2f(-(float)i * (13.287712379549449f / 32.0f));
    const float a = (float)pos[s] * inv;
    float sn, cs;
    sincosf(a, &sn, &cs);
    g_cs[s*32 + i] = cs;
    g_sn[s*32 + i] = sn;
}

// hi-only weight conversion
__global__ void wsplit_kernel(const float* __restrict__ x,
                              __half* __restrict__ h, int n4) {
    int i = blockIdx.x * blockDim.x + threadIdx.x;
    if (i >= n4) return;
    float4 v = ((const float4*)x)[i];
    ((__half2*)h)[2*i]   = __floats2half2_rn(v.x, v.y);
    ((__half2*)h)[2*i+1] = __floats2half2_rn(v.z, v.w);
}

// hi+lo weight split (for the 3-term QK GEMM)
__global__ void wsplit2_kernel(const float* __restrict__ x,
                               __half* __restrict__ h,
                               __half* __restrict__ l, int n4) {
    int i = blockIdx.x * blockDim.x + threadIdx.x;
    if (i >= n4) return;
    float4 v = ((const float4*)x)[i];
    uint32_t h0, l0, h1, l1;
    split_pack2(v.x, v.y, h0, l0);
    split_pack2(v.z, v.w, h1, l1);
    ((uint32_t*)h)[2*i]   = h0; ((uint32_t*)h)[2*i+1] = h1;
    ((uint32_t*)l)[2*i]   = l0; ((uint32_t*)l)[2*i+1] = l1;
}

// interleaved weight hi split: src row n -> dst row 2n+off  (K=1024)
__global__ void wsplit_inter_kernel(const float* __restrict__ x,
                                    __half* __restrict__ h,
                                    int n4, int off) {
    int i = blockIdx.x * blockDim.x + threadIdx.x;
    if (i >= n4) return;
    const int row = i >> 8;
    const int c4  = i & 255;
    float4 v = ((const float4*)x)[i];
    const size_t o2 = ((size_t)(2*row + off) * 1024 + c4*4) >> 1;
    ((__half2*)h)[o2]   = __floats2half2_rn(v.x, v.y);
    ((__half2*)h)[o2+1] = __floats2half2_rn(v.z, v.w);
}

// ---------------- RMSNorm -> split fp16 ----------------
__global__ void rmsnorm_split_kernel(const float* __restrict__ x,
                                     const float* __restrict__ g,
                                     __half* __restrict__ yh,
                                     __half* __restrict__ yl) {
    const int row = blockIdx.x;
    const float4* xr = (const float4*)(x + (size_t)row * DM);
    const int t = threadIdx.x;
    float4 xv = xr[t];
    float ss = xv.x*xv.x + xv.y*xv.y + xv.z*xv.z + xv.w*xv.w;
    #pragma unroll
    for (int o = 16; o; o >>= 1) ss += __shfl_xor_sync(0xffffffffu, ss, o);
    __shared__ float sred[8];
    const int warp = t >> 5, lane = t & 31;
    if (lane == 0) sred[warp] = ss;
    __syncthreads();
    if (warp == 0) {
        float v = (lane < 8) ? sred[lane] : 0.f;
        #pragma unroll
        for (int o = 4; o; o >>= 1) v += __shfl_xor_sync(0xffffffffu, v, o);
        if (lane == 0) sred[0] = v;
    }
    __syncthreads();
    const float inv = rsqrtf(sred[0] * (1.0f/(float)DM) + 1e-5f);
    const float4 gv = ((const float4*)g)[t];
    uint32_t h0, l0, h1, l1;
    split_pack2(xv.x*inv*gv.x, xv.y*inv*gv.y, h0, l0);
    split_pack2(xv.z*inv*gv.z, xv.w*inv*gv.w, h1, l1);
    const size_t b2 = (size_t)row * (DM/2) + 2*t;
    ((uint32_t*)yh)[b2]   = h0; ((uint32_t*)yh)[b2+1] = h1;
    ((uint32_t*)yl)[b2]   = l0; ((uint32_t*)yl)[b2+1] = l1;
}

// -------- mma.sync fp16 GEMM, CTA 128x256, warp 64x64, 1/2/3-term -------------
// Terms: Ah*Bh (+ Al*Bh when ALO) (+ Ah*Bl when BLO).
// MODE 0: C fp32 (+R). MODE 1: rope+Qscale+split -> Ch/Cl (stride ldc).
// MODE 2: swiglu -> Ch (stride ldc). MODE 3: plain split -> Ch/Cl (stride ldc).
#define ROWB    144
#define QSCALE  0.18033688f      // 0.125 * log2(e)
template<int MODE, bool ALO, bool BLO>
__global__ __launch_bounds__(256, 1)
void gemm_mma_fp16(const __half* __restrict__ Ah,
                   const __half* __restrict__ Al,
                   const __half* __restrict__ Bh,
                   const __half* __restrict__ Bl,
                   const float* __restrict__ R,
                   float* __restrict__ C,
                   __half* __restrict__ Ch,
                   __half* __restrict__ Cl,
                   int N, int K, int ldc) {
    constexpr uint32_t AL_OFF = 128u * ROWB;
    constexpr uint32_t B_OFFC = (ALO ? 2u : 1u) * 128u * ROWB;
    constexpr uint32_t BL_OFF = B_OFFC + 256u * ROWB;
    constexpr uint32_t STG = (128u*(ALO ? 2u : 1u) + 256u*(BLO ? 2u : 1u)) * ROWB;
    extern __shared__ char smem[];
    const uint32_t sbase = smem_to_u32(smem);
    const int tid  = threadIdx.x;
    const int lane = tid & 31;
    const int wid  = tid >> 5;
    const int bm = blockIdx.y * 128;
    const int bn = blockIdx.x * 256;
    const int m0w = (wid & 1) * 64;
    const int n0w = (wid >> 1) * 64;

    float acc[4][8][4];
    #pragma unroll
    for (int i = 0; i < 4; i++)
        #pragma unroll
        for (int j = 0; j < 8; j++)
            #pragma unroll
            for (int q = 0; q < 4; q++) acc[i][j][q] = 0.f;

    const int nch = K >> 6;

    auto load_stage = [&](int s, int c) {
        const int k0 = c << 6;
        const uint32_t st = sbase + (uint32_t)s * STG;
        #pragma unroll
        for (int i = 0; i < 4; ++i) {           // A: 128 rows
            const int idx = tid + (i << 8);
            const int row = idx >> 3, cc = idx & 7;
            const uint32_t so = (uint32_t)(row * ROWB + cc * 16);
            const size_t ga = (size_t)(bm + row) * K + k0 + cc * 8;
            CP_ASYNC16(st + so, (const char*)(Ah + ga));
            if (ALO) CP_ASYNC16(st + AL_OFF + so, (const char*)(Al + ga));
        }
        #pragma unroll
        for (int i = 0; i < 8; ++i) {           // B: 256 rows
            const int idx = tid + (i << 8);
            const int row = idx >> 3, cc = idx & 7;
            const uint32_t so = (uint32_t)(row * ROWB + cc * 16);
            const size_t gb = (size_t)(bn + row) * K + k0 + cc * 8;
            CP_ASYNC16(st + B_OFFC + so, (const char*)(Bh + gb));
            if (BLO) CP_ASYNC16(st + BL_OFF + so, (const char*)(Bl + gb));
        }
        CP_COMMIT();
    };

    const int g = lane >> 3, r = lane & 7;
    const uint32_t aoff = (uint32_t)((m0w + (g & 1) * 8 + r) * ROWB + ((g >> 1) * 8) * 2);
    const uint32_t boff = B_OFFC + (uint32_t)((n0w + (g >> 1) * 8 + r) * ROWB + ((g & 1) * 8) * 2);

    load_stage(0, 0);

    for (int c = 0; c < nch; ++c) {
        CP_WAIT0();
        __syncthreads();
        if (c + 1 < nch) load_stage((c + 1) & 1, c + 1);

        const uint32_t st = sbase + (uint32_t)(c & 1) * STG;
        #pragma unroll
        for (int ks = 0; ks < 4; ++ks) {
            uint32_t AhF[4][4], AlF[4][4];
            const uint32_t ab = st + aoff + (uint32_t)(ks * 32);
            #pragma unroll
            for (int mi = 0; mi < 4; ++mi) {
                LDSM4(AhF[mi], ab + (uint32_t)(mi * 16 * ROWB));
                if (ALO) LDSM4(AlF[mi], ab + AL_OFF + (uint32_t)(mi * 16 * ROWB));
            }
            const uint32_t bb = st + boff + (uint32_t)(ks * 32);
            #pragma unroll
            for (int nb = 0; nb < 4; ++nb) {
                uint32_t BhF[4], BlF[4];
                LDSM4(BhF, bb + (uint32_t)(nb * 16 * ROWB));
                if (BLO) LDSM4(BlF, bb + (uint32_t)(BL_OFF - B_OFFC) + (uint32_t)(nb * 16 * ROWB));
                #pragma unroll
                for (int mi = 0; mi < 4; ++mi)
                    #pragma unroll
                    for (int hf = 0; hf < 2; ++hf) {
                        float* d = acc[mi][nb * 2 + hf];
                        MMA16816(d, AhF[mi], BhF[hf*2], BhF[hf*2+1]);
                        if (ALO) MMA16816(d, AlF[mi], BhF[hf*2], BhF[hf*2+1]);
                        if (BLO) MMA16816(d, AhF[mi], BlF[hf*2], BlF[hf*2+1]);
                    }
            }
        }
    }

    const int erow = lane >> 2;
    const int ecol = (lane & 3) * 2;
    #pragma unroll
    for (int mi = 0; mi < 4; ++mi) {
        #pragma unroll
        for (int nj = 0; nj < 8; ++nj) {
            float* d = acc[mi][nj];
            const int row0 = bm + m0w + mi * 16 + erow;
            const int row1 = row0 + 8;
            const int cg   = bn + n0w + nj * 8 + ecol;
            if (MODE == 0) {
                const size_t o0 = (size_t)row0 * ldc + cg;
                const size_t o1 = (size_t)row1 * ldc + cg;
                float2 v0 = make_float2(d[0], d[1]);
                float2 v1 = make_float2(d[2], d[3]);
                if (R) {
                    const float2 r0 = *(const float2*)(R + o0);
                    const float2 r1 = *(const float2*)(R + o1);
                    v0.x += r0.x; v0.y += r0.y;
                    v1.x += r1.x; v1.y += r1.y;
                }
                *(float2*)(C + o0) = v0;
                *(float2*)(C + o1) = v1;
            } else if (MODE == 1) {   // QK epilogue: rope all cols, Qscale cols<1024
                float a0 = d[0], a1 = d[1], b0 = d[2], b1 = d[3];
                {
                    const int i = (cg & 63) >> 1;
                    const int s0 = (row0 & (SS-1))*32 + i;
                    const int s1 = (row1 & (SS-1))*32 + i;
                    const float c0 = g_cs[s0], n0 = g_sn[s0];
                    const float c1 = g_cs[s1], n1 = g_sn[s1];
                    float t0 = a0*c0 - a1*n0, t1 = a0*n0 + a1*c0;
                    a0 = t0; a1 = t1;
                    float u0 = b0*c1 - b1*n1, u1 = b0*n1 + b1*c1;
                    b0 = u0; b1 = u1;
                }
                if (cg < 1024) {  // Q pre-scale into log2 domain
                    a0 *= QSCALE; a1 *= QSCALE; b0 *= QSCALE; b1 *= QSCALE;
                }
                uint32_t h0, l0, h1, l1;
                split_pack2(a0, a1, h0, l0);
                split_pack2(b0, b1, h1, l1);
                const size_t o0 = (size_t)row0 * ldc + cg;
                const size_t o1 = (size_t)row1 * ldc + cg;
                *(uint32_t*)(Ch + o0) = h0;
                *(uint32_t*)(Cl + o0) = l0;
                *(uint32_t*)(Ch + o1) = h1;
                *(uint32_t*)(Cl + o1) = l1;
            } else if (MODE == 3) {   // plain split (V projection)
                uint32_t h0, l0, h1, l1;
                split_pack2(d[0], d[1], h0, l0);
                split_pack2(d[2], d[3], h1, l1);
                const size_t o0 = (size_t)row0 * ldc + cg;
                const size_t o1 = (size_t)row1 * ldc + cg;
                *(uint32_t*)(Ch + o0) = h0;
                *(uint32_t*)(Cl + o0) = l0;
                *(uint32_t*)(Ch + o1) = h1;
                *(uint32_t*)(Cl + o1) = l1;
            } else {  // MODE 2: swiglu, (even,odd) = (a, gate); hi-only output
                const int j = cg >> 1;
                float sl0, sl1;
                if (nj < 3) {   // MUFU path
                    const float e0 = ex2(-1.44269504f * d[0]);
                    const float e1 = ex2(-1.44269504f * d[2]);
                    const float dd0 = 1.f + e0, dd1 = 1.f + e1;
                    float r0 = rcpa(dd0); r0 = r0 * (2.f - dd0 * r0);
                    float r1 = rcpa(dd1); r1 = r1 * (2.f - dd1 * r1);
                    sl0 = d[0] * r0 * d[1];
                    sl1 = d[2] * r1 * d[3];
                } else {        // FMA-pipe path
                    const float e0 = fast_exp2(-1.44269504f * d[0]);
                    const float e1 = fast_exp2(-1.44269504f * d[2]);
                    const float dd0 = 1.f + e0, dd1 = 1.f + e1;
                    float r0 = __int_as_float(0x7EF311C3 - __float_as_int(dd0));
                    r0 = r0 * (2.f - dd0 * r0); r0 = r0 * (2.f - dd0 * r0);
                    float r1 = __int_as_float(0x7EF311C3 - __float_as_int(dd1));
                    r1 = r1 * (2.f - dd1 * r1); r1 = r1 * (2.f - dd1 * r1);
                    sl0 = d[0] * r0 * d[1];
                    sl1 = d[2] * r1 * d[3];
                }
                Ch[(size_t)row0 * ldc + j] = __float2half_rn(sl0);
                Ch[(size_t)row1 * ldc + j] = __float2half_rn(sl1);
            }
        }
    }
}

// ----- HMMA flash attention (QK 3-term, PV 1-term, base-2 softmax) ------------
#define ATB (64*144)
#define ATT_SMEM (8*ATB)     // Qh,Ql + 2 stages x (Kh,Kl,Vh)
__global__ __launch_bounds__(128)
void attn_mma_kernel(const __half* __restrict__ Xh,
                     const __half* __restrict__ Xl,
                     __half* __restrict__ Oh,
                     __half* __restrict__ Ol) {
    extern __shared__ char sm[];
    const uint32_t sQh = smem_to_u32(sm);
    const uint32_t sQl = sQh + ATB;
    const uint32_t sSt = sQh + 2*ATB;

    const int tid = threadIdx.x, lane = tid & 31, warp = tid >> 5;
    const int bh = blockIdx.y, b = bh >> 4, h = bh & (NH-1);
    const int qt = gridDim.x - 1 - blockIdx.x;
    const int q0 = qt * 64;
    const size_t rowbase = (size_t)b * SS * LDX;
    const int colQ = h*DH, colK = 1024 + h*DH, colV = 2048 + h*DH;

    #pragma unroll
    for (int i = 0; i < 4; i++) {
        const int idx = tid + i*128;
        const int r = idx >> 3, c = idx & 7;
        const uint32_t so = (uint32_t)(r*144 + c*16);
        const size_t ga = rowbase + (size_t)(q0 + r)*LDX + colQ + c*8;
        CP_ASYNC16(sQh + so, (const char*)(Xh + ga));
        CP_ASYNC16(sQl + so, (const char*)(Xl + ga));
    }
    CP_COMMIT();

    auto load_kv = [&](int t, int s) {
        const int k0 = t * 64;
        #pragma unroll
        for (int i = 0; i < 4; i++) {
            const int idx = tid + i*128;
            const int r = idx >> 3, c = idx & 7;
            const uint32_t so = (uint32_t)s*3*ATB + (uint32_t)(r*144 + c*16);
            const size_t gk = rowbase + (size_t)(k0 + r)*LDX + colK + c*8;
            const size_t gv = rowbase + (size_t)(k0 + r)*LDX + colV + c*8;
            CP_ASYNC16(sSt + so,         (const char*)(Xh + gk));
            CP_ASYNC16(sSt + ATB + so,   (const char*)(Xl + gk));
            CP_ASYNC16(sSt + 2*ATB + so, (const char*)(Xh + gv));
        }
        CP_COMMIT();
    };
    load_kv(0, 0);

    const int g = lane >> 3, rr = lane & 7;
    const uint32_t aoff = (uint32_t)((warp*16 + (g&1)*8 + rr)*144 + (g>>1)*16);
    const uint32_t boff = (uint32_t)(((g>>1)*8 + rr)*144 + (g&1)*16);
    const uint32_t voff = (uint32_t)(((g&1)*8 + rr)*144 + (lane>>4)*16);

    float m0 = -CUDART_INF_F, m1 = -CUDART_INF_F, l0 = 0.f, l1 = 0.f;
    float o[8][4];
    #pragma unroll
    for (int j = 0; j < 8; j++)
        #pragma unroll
        for (int q = 0; q < 4; q++) o[j][q] = 0.f;

    const int r0g = q0 + warp*16 + (lane >> 2);
    const int r1g = r0g + 8;
    const int ntiles = qt + 1;

    for (int t = 0; t < ntiles; t++) {
        CP_WAIT0();
        __syncthreads();
        if (t + 1 < ntiles) load_kv(t + 1, (t + 1) & 1);

        const uint32_t sK  = sSt + (uint32_t)(t & 1)*3*ATB;
        const uint32_t sKl = sK + ATB;
        const uint32_t sV  = sK + 2*ATB;

        float s[8][4];
        #pragma unroll
        for (int j = 0; j < 8; j++)
            #pragma unroll
            for (int q = 0; q < 4; q++) s[j][q] = 0.f;

        #pragma unroll
        for (int d = 0; d < 4; d++) {
            uint32_t qh[4], ql[4];
            LDSM4(qh, sQh + aoff + d*32);
            LDSM4(ql, sQl + aoff + d*32);
            #pragma unroll
            for (int nb = 0; nb < 4; nb++) {
                uint32_t kh[4], kl[4];
                LDSM4(kh, sK  + boff + (uint32_t)(nb*16*144) + d*32);
                LDSM4(kl, sKl + boff + (uint32_t)(nb*16*144) + d*32);
                #pragma unroll
                for (int f = 0; f < 2; f++) {
                    float* dd = s[nb*2 + f];
                    MMA16816(dd, qh, kh[2*f], kh[2*f+1]);
                    MMA16816(dd, qh, kl[2*f], kl[2*f+1]);
                    MMA16816(dd, ql, kh[2*f], kh[2*f+1]);
                }
            }
        }

        // scores already in log2 domain (Q pre-scaled by 0.125*log2e)
        const int k0 = t * 64;
        float mx0 = -CUDART_INF_F, mx1 = -CUDART_INF_F;
        #pragma unroll
        for (int j = 0; j < 8; j++) {
            if (t == qt) {
                const int c = k0 + j*8 + (lane & 3)*2;
                if (c     > r0g) s[j][0] = -CUDART_INF_F;
                if (c + 1 > r0g) s[j][1] = -CUDART_INF_F;
                if (c     > r1g) s[j][2] = -CUDART_INF_F;
                if (c + 1 > r1g) s[j][3] = -CUDART_INF_F;
            }
            mx0 = fmaxf(mx0, fmaxf(s[j][0], s[j][1]));
            mx1 = fmaxf(mx1, fmaxf(s[j][2], s[j][3]));
        }
        mx0 = fmaxf(mx0, __shfl_xor_sync(0xffffffffu, mx0, 1));
        mx0 = fmaxf(mx0, __shfl_xor_sync(0xffffffffu, mx0, 2));
        mx1 = fmaxf(mx1, __shfl_xor_sync(0xffffffffu, mx1, 1));
        mx1 = fmaxf(mx1, __shfl_xor_sync(0xffffffffu, mx1, 2));
        const float mn0 = fmaxf(m0, mx0), mn1 = fmaxf(m1, mx1);
        const float cr0 = ex2(m0 - mn0), cr1 = ex2(m1 - mn1);
        m0 = mn0; m1 = mn1;

        float sum0 = 0.f, sum1 = 0.f;
        #pragma unroll
        for (int j = 0; j < 8; j++) {
            if (j < 5) {     // MUFU path
                s[j][0] = ex2(s[j][0] - mn0); s[j][1] = ex2(s[j][1] - mn0);
                s[j][2] = ex2(s[j][2] - mn1); s[j][3] = ex2(s[j][3] - mn1);
            } else {         // FMA-pipe path
                s[j][0] = fast_exp2(s[j][0] - mn0); s[j][1] = fast_exp2(s[j][1] - mn0);
                s[j][2] = fast_exp2(s[j][2] - mn1); s[j][3] = fast_exp2(s[j][3] - mn1);
            }
            sum0 += s[j][0] + s[j][1];
            sum1 += s[j][2] + s[j][3];
        }
        sum0 += __shfl_xor_sync(0xffffffffu, sum0, 1);
        sum0 += __shfl_xor_sync(0xffffffffu, sum0, 2);
        sum1 += __shfl_xor_sync(0xffffffffu, sum1, 1);
        sum1 += __shfl_xor_sync(0xffffffffu, sum1, 2);
        l0 = l0 * cr0 + sum0;
        l1 = l1 * cr1 + sum1;
        #pragma unroll
        for (int j = 0; j < 8; j++) {
            o[j][0] *= cr0; o[j][1] *= cr0;
            o[j][2] *= cr1; o[j][3] *= cr1;
        }

        // ---- O += P V (P fp16 hi only; 1-term PV) ----
        #pragma unroll
        for (int kt = 0; kt < 4; kt++) {
            uint32_t ph[4];
            #pragma unroll
            for (int u = 0; u < 4; u++) {
                const int jj = 2*kt + (u >> 1);
                __half2 hh = __floats2half2_rn(s[jj][(u & 1)*2], s[jj][(u & 1)*2 + 1]);
                ph[u] = *(uint32_t*)&hh;
            }
            #pragma unroll
            for (int nb = 0; nb < 4; nb++) {
                uint32_t vh[4];
                const uint32_t va = voff + (uint32_t)(kt*16*144) + (uint32_t)(nb*32);
                LDSM4T(vh, sV + va);
                #pragma unroll
                for (int f = 0; f < 2; f++) {
                    float* dd = o[nb*2 + f];
                    MMA16816(dd, ph, vh[2*f], vh[2*f+1]);
                }
            }
        }
    }

    const float inv0 = 1.0f / l0, inv1 = 1.0f / l1;
    const size_t tok0 = (size_t)b * SS + r0g;
    const size_t tok1 = tok0 + 8;
    #pragma unroll
    for (int j = 0; j < 8; j++) {
        const int col = h*DH + j*8 + (lane & 3)*2;
        uint32_t h0, l0b, h1, l1b;
        split_pack2(o[j][0]*inv0, o[j][1]*inv0, h0, l0b);
        split_pack2(o[j][2]*inv1, o[j][3]*inv1, h1, l1b);
        *(uint32_t*)(Oh + tok0*DM + col) = h0;
        *(uint32_t*)(Ol + tok0*DM + col) = l0b;
        *(uint32_t*)(Oh + tok1*DM + col) = h1;
        *(uint32_t*)(Ol + tok1*DM + col) = l1b;
    }
}

// ---------------- launch ----------------
extern "C" void kernel_launch(void* const* d_in, const int* in_sizes, int n_in,
                              void* d_out, int out_size) {
    const float* x   = (const float*)d_in[0];
    const int*   pos = (const int*)  d_in[1];
    const float* qw  = (const float*)d_in[2];
    const float* kw  = (const float*)d_in[3];
    const float* vw  = (const float*)d_in[4];
    const float* ow  = (const float*)d_in[5];
    const float* g1  = (const float*)d_in[6];
    const float* g2  = (const float*)d_in[7];
    const float* w1  = (const float*)d_in[8];
    const float* w2  = (const float*)d_in[9];
    const float* w3  = (const float*)d_in[10];
    float* out = (float*)d_out;

    __half *xnh, *xnl, *qkvh, *qkvl, *ath, *atl, *hnh, *hnl, *swh;
    __half *wqkh, *wqkl, *vwh, *owh, *w13h, *w2h;
    float *res1;
    cudaGetSymbolAddress((void**)&xnh, g_xn_h);   cudaGetSymbolAddress((void**)&xnl, g_xn_l);
    cudaGetSymbolAddress((void**)&qkvh, g_qkv_h); cudaGetSymbolAddress((void**)&qkvl, g_qkv_l);
    cudaGetSymbolAddress((void**)&ath, g_at_h);   cudaGetSymbolAddress((void**)&atl, g_at_l);
    cudaGetSymbolAddress((void**)&res1, g_res1);
    cudaGetSymbolAddress((void**)&hnh, g_hn_h);   cudaGetSymbolAddress((void**)&hnl, g_hn_l);
    cudaGetSymbolAddress((void**)&swh, g_sw_h);
    cudaGetSymbolAddress((void**)&wqkh, g_wqk_h); cudaGetSymbolAddress((void**)&wqkl, g_wqk_l);
    cudaGetSymbolAddress((void**)&vwh, g_vw_h);
    cudaGetSymbolAddress((void**)&owh, g_ow_h);
    cudaGetSymbolAddress((void**)&w13h, g_w13_h);
    cudaGetSymbolAddress((void**)&w2h, g_w2_h);

    const int SM3 = 2 * (128*2 + 256*2) * ROWB;   // 221184  (3-term)
    const int SM2 = 2 * (128*2 + 256)   * ROWB;   // 147456  (2-term)
    const int SM1 = 2 * (128 + 256)     * ROWB;   // 110592  (1-term)
    cudaFuncSetAttribute((const void*)gemm_mma_fp16<1,true,true>,   cudaFuncAttributeMaxDynamicSharedMemorySize, SM3);
    cudaFuncSetAttribute((const void*)gemm_mma_fp16<3,true,false>,  cudaFuncAttributeMaxDynamicSharedMemorySize, SM2);
    cudaFuncSetAttribute((const void*)gemm_mma_fp16<0,true,false>,  cudaFuncAttributeMaxDynamicSharedMemorySize, SM2);
    cudaFuncSetAttribute((const void*)gemm_mma_fp16<2,false,false>, cudaFuncAttributeMaxDynamicSharedMemorySize, SM1);
    cudaFuncSetAttribute((const void*)gemm_mma_fp16<0,false,false>, cudaFuncAttributeMaxDynamicSharedMemorySize, SM1);
    cudaFuncSetAttribute((const void*)attn_mma_kernel, cudaFuncAttributeMaxDynamicSharedMemorySize, ATT_SMEM);

    const int MM = 1024 * 1024;

    // launch order arranged so ncu's "-s 5" profiles the QK GEMM (index 5)
    rope_table_kernel<<<SS, 32>>>(pos);                                      // 0
    wsplit2_kernel<<<MM/4/256, 256>>>(qw, wqkh,      wqkl,      MM/4);       // 1
    wsplit2_kernel<<<MM/4/256, 256>>>(kw, wqkh + MM, wqkl + MM, MM/4);       // 2
    wsplit_kernel<<<MM/4/256, 256>>>(vw, vwh, MM/4);                         // 3
    rmsnorm_split_kernel<<<MTOK, 256>>>(x, g1, xnh, xnl);                    // 4

    // 5: QK projection (3-term) + rope + Q prescale + split  [8192,2048]
    gemm_mma_fp16<1,true,true><<<dim3(2048/256, MTOK/128), 256, SM3>>>(
        xnh, xnl, wqkh, wqkl, nullptr, nullptr, qkvh, qkvl, 2048, DM, LDX);

    // 6: V projection (2-term) + split  [8192,1024] -> qkv cols 2048..3071
    gemm_mma_fp16<3,true,false><<<dim3(DM/256, MTOK/128), 256, SM2>>>(
        xnh, xnl, vwh, nullptr, nullptr, nullptr, qkvh + 2048, qkvl + 2048, DM, DM, LDX);

    // 7: HMMA flash attention (PV 1-term) -> split fp16
    attn_mma_kernel<<<dim3(SS/64, BB*NH), 128, ATT_SMEM>>>(qkvh, qkvl, ath, atl);

    wsplit_kernel<<<MM/4/256, 256>>>(ow, owh, MM/4);                         // 8

    // 9: O projection (2-term) + residual(x) -> res1 fp32
    gemm_mma_fp16<0,true,false><<<dim3(DM/256, MTOK/128), 256, SM2>>>(
        ath, atl, owh, nullptr, x, res1, nullptr, nullptr, DM, DM, DM);

    rmsnorm_split_kernel<<<MTOK, 256>>>(res1, g2, hnh, hnl);                 // 10
    wsplit_inter_kernel<<<MM/256, 256>>>(w1, w13h, MM, 0);                   // 11
    wsplit_inter_kernel<<<MM/256, 256>>>(w3, w13h, MM, 1);                   // 12

    // 13: fused W1||W3 (1-term, interleaved) + swiglu -> sw hi
    gemm_mma_fp16<2,false,false><<<dim3(2*DFF/256, MTOK/128), 256, SM1>>>(
        hnh, nullptr, w13h, nullptr, nullptr, nullptr, swh, nullptr, 2*DFF, DM, DFF);

    wsplit_kernel<<<MM/256, 256>>>(w2, w2h, MM);                             // 14

    // 15: down projection (1-term) + residual(res1) -> out
    gemm_mma_fp16<0,false,false><<<dim3(DM/256, MTOK/128), 256, SM1>>>(
        swh, nullptr, w2h, nullptr, res1, out, nullptr, nullptr, DM, DFF, DM);
}

// round 12
// speedup vs baseline: 7.0791x; 1.0667x over previous
#include <cuda_runtime.h>
#include <cuda_fp16.h>
#include <math.h>
#include <math_constants.h>
#include <cstdint>

#define BB   4
#define SS   2048
#define DM   1024
#define NH   16
#define DH   64
#define DFF  4096
#define MTOK (BB*SS)      // 8192
#define LDX  3072

// ---------------- helpers ----------------
__device__ __forceinline__ uint32_t smem_to_u32(const void* p) {
    uint32_t a;
    asm("{ .reg .u64 t; cvta.to.shared.u64 t, %1; cvt.u32.u64 %0, t; }" : "=r"(a) : "l"(p));
    return a;
}
#define CP_ASYNC16(s, g) asm volatile("cp.async.cg.shared.global [%0], [%1], 16;" :: "r"(s), "l"(g))
#define CP_COMMIT()      asm volatile("cp.async.commit_group;" ::: "memory")
#define CP_WAIT0()       asm volatile("cp.async.wait_group 0;" ::: "memory")
#define LDSM4(rg, addr) \
    asm volatile("ldmatrix.sync.aligned.m8n8.x4.shared.b16 {%0,%1,%2,%3}, [%4];" \
        : "=r"((rg)[0]), "=r"((rg)[1]), "=r"((rg)[2]), "=r"((rg)[3]) : "r"(addr))
#define LDSM4T(rg, addr) \
    asm volatile("ldmatrix.sync.aligned.m8n8.x4.trans.shared.b16 {%0,%1,%2,%3}, [%4];" \
        : "=r"((rg)[0]), "=r"((rg)[1]), "=r"((rg)[2]), "=r"((rg)[3]) : "r"(addr))
#define MMA16816(d, a, b0v, b1v) \
    asm volatile("mma.sync.aligned.m16n8k16.row.col.f32.f16.f16.f32 " \
        "{%0,%1,%2,%3}, {%4,%5,%6,%7}, {%8,%9}, {%0,%1,%2,%3};" \
        : "+f"((d)[0]), "+f"((d)[1]), "+f"((d)[2]), "+f"((d)[3]) \
        : "r"((a)[0]), "r"((a)[1]), "r"((a)[2]), "r"((a)[3]), "r"(b0v), "r"(b1v))

__device__ __forceinline__ float ex2(float x) {
    float r; asm("ex2.approx.f32 %0, %1;" : "=f"(r) : "f"(x)); return r;
}
__device__ __forceinline__ float rcpa(float x) {
    float r; asm("rcp.approx.f32 %0, %1;" : "=f"(r) : "f"(x)); return r;
}
// 2^y on the FMA pipe (magic round + deg-5 Taylor), rel err ~2e-6
__device__ __forceinline__ float fast_exp2(float y) {
    y = fmaxf(fminf(y, 126.f), -126.f);
    float z = __fadd_rn(y, 12582912.f);
    int   n = __float_as_int(z) - 0x4B400000;
    float f = __fadd_rn(y, -__fadd_rn(z, -12582912.f));
    float p = fmaf(f, 0.0013333558f, 0.0096181291f);
    p = fmaf(f, p, 0.0555041087f);
    p = fmaf(f, p, 0.2402265069f);
    p = fmaf(f, p, 0.6931471806f);
    p = fmaf(f, p, 1.0f);
    return __int_as_float(__float_as_int(p) + (n << 23));
}
// pack (p0,p1) -> f16x2 hi + f16x2 lo residual
__device__ __forceinline__ void split_pack2(float p0, float p1, uint32_t& h2, uint32_t& l2) {
    __half2 h = __floats2half2_rn(p0, p1);
    float2 hf = __half22float2(h);
    __half2 l = __floats2half2_rn(__fadd_rn(p0, -hf.x), __fadd_rn(p1, -hf.y));
    h2 = *(uint32_t*)&h;
    l2 = *(uint32_t*)&l;
}

// ---------------- scratch (__device__ globals) ----------------
static __device__ __half g_xn_h[(size_t)MTOK*DM],  g_xn_l[(size_t)MTOK*DM];
static __device__ __half g_qkv_h[(size_t)MTOK*LDX], g_qkv_l[(size_t)MTOK*LDX];
static __device__ __half g_at_h[(size_t)MTOK*DM];
static __device__ float  g_res1[(size_t)MTOK*DM];
static __device__ __half g_hn_h[(size_t)MTOK*DM];
static __device__ __half g_sw_h[(size_t)MTOK*DFF];
static __device__ __half g_wqk_h[2048*1024], g_wqk_l[2048*1024];
static __device__ __half g_vw_h [1024*1024];
static __device__ __half g_ow_h [1024*1024];
static __device__ __half g_w13_h[2*DFF*1024];   // interleaved rows
static __device__ __half g_w2_h [1024*DFF];
static __device__ float g_cs[SS*32], g_sn[SS*32];

__global__ void rope_table_kernel(const int* __restrict__ pos) {
    const int s = blockIdx.x, i = threadIdx.x;   // 2048 x 32
    const float inv = exp2f(-(float)i * (13.287712379549449f / 32.0f));
    const float a = (float)pos[s] * inv;
    float sn, cs;
    sincosf(a, &sn, &cs);
    g_cs[s*32 + i] = cs;
    g_sn[s*32 + i] = sn;
}

// ------------- merged weight prep: one launch for all 7 weight tensors --------
// f4-index regions: [0,Q4) qw | [Q4,2Q4) kw | [2Q4,3Q4) vw | [3Q4,4Q4) ow |
//                   [4Q4,+W4) w1 | [+W4,+2W4) w3 | [+2W4,+3W4) w2
#define Q4 262144          // (1024*1024)/4
#define W4 1048576         // (4096*1024)/4
__global__ void prep_weights_kernel(const float* __restrict__ qw,
                                    const float* __restrict__ kw,
                                    const float* __restrict__ vw,
                                    const float* __restrict__ ow,
                                    const float* __restrict__ w1,
                                    const float* __restrict__ w3,
                                    const float* __restrict__ w2,
                                    __half* __restrict__ wqkh,
                                    __half* __restrict__ wqkl,
                                    __half* __restrict__ vwh,
                                    __half* __restrict__ owh,
                                    __half* __restrict__ w13h,
                                    __half* __restrict__ w2h) {
    const int i = blockIdx.x * blockDim.x + threadIdx.x;
    if (i < 2*Q4) {                        // qw | kw -> hi+lo split
        const int j = (i < Q4) ? i : i - Q4;
        const float4 v = (i < Q4) ? ((const float4*)qw)[j] : ((const float4*)kw)[j];
        uint32_t h0, l0, h1, l1;
        split_pack2(v.x, v.y, h0, l0);
        split_pack2(v.z, v.w, h1, l1);
        const uint32_t base = ((i < Q4) ? 0u : (1024u*1024u/2u)) + 2u*(uint32_t)j;
        ((uint32_t*)wqkh)[base] = h0; ((uint32_t*)wqkh)[base+1] = h1;
        ((uint32_t*)wqkl)[base] = l0; ((uint32_t*)wqkl)[base+1] = l1;
    } else if (i < 4*Q4) {                 // vw | ow -> hi only
        const int j = (i < 3*Q4) ? i - 2*Q4 : i - 3*Q4;
        const float4 v = (i < 3*Q4) ? ((const float4*)vw)[j] : ((const float4*)ow)[j];
        __half* dst = (i < 3*Q4) ? vwh : owh;
        ((__half2*)dst)[2*j]   = __floats2half2_rn(v.x, v.y);
        ((__half2*)dst)[2*j+1] = __floats2half2_rn(v.z, v.w);
    } else if (i < 4*Q4 + 2*W4) {          // w1 | w3 -> interleaved hi
        const int off = (i < 4*Q4 + W4) ? 0 : 1;
        const int j = i - 4*Q4 - off*W4;
        const float4 v = off ? ((const float4*)w3)[j] : ((const float4*)w1)[j];
        const int row = j >> 8, c4 = j & 255;
        const size_t o2 = ((size_t)(2*row + off) * 1024 + c4*4) >> 1;
        ((__half2*)w13h)[o2]   = __floats2half2_rn(v.x, v.y);
        ((__half2*)w13h)[o2+1] = __floats2half2_rn(v.z, v.w);
    } else {                               // w2 -> hi only
        const int j = i - 4*Q4 - 2*W4;
        const float4 v = ((const float4*)w2)[j];
        ((__half2*)w2h)[2*j]   = __floats2half2_rn(v.x, v.y);
        ((__half2*)w2h)[2*j+1] = __floats2half2_rn(v.z, v.w);
    }
}

// ---------------- RMSNorm -> split fp16 (hi+lo) ----------------
__global__ void rmsnorm_split_kernel(const float* __restrict__ x,
                                     const float* __restrict__ g,
                                     __half* __restrict__ yh,
                                     __half* __restrict__ yl) {
    const int row = blockIdx.x;
    const float4* xr = (const float4*)(x + (size_t)row * DM);
    const int t = threadIdx.x;
    float4 xv = xr[t];
    float ss = xv.x*xv.x + xv.y*xv.y + xv.z*xv.z + xv.w*xv.w;
    #pragma unroll
    for (int o = 16; o; o >>= 1) ss += __shfl_xor_sync(0xffffffffu, ss, o);
    __shared__ float sred[8];
    const int warp = t >> 5, lane = t & 31;
    if (lane == 0) sred[warp] = ss;
    __syncthreads();
    if (warp == 0) {
        float v = (lane < 8) ? sred[lane] : 0.f;
        #pragma unroll
        for (int o = 4; o; o >>= 1) v += __shfl_xor_sync(0xffffffffu, v, o);
        if (lane == 0) sred[0] = v;
    }
    __syncthreads();
    const float inv = rsqrtf(sred[0] * (1.0f/(float)DM) + 1e-5f);
    const float4 gv = ((const float4*)g)[t];
    uint32_t h0, l0, h1, l1;
    split_pack2(xv.x*inv*gv.x, xv.y*inv*gv.y, h0, l0);
    split_pack2(xv.z*inv*gv.z, xv.w*inv*gv.w, h1, l1);
    const size_t b2 = (size_t)row * (DM/2) + 2*t;
    ((uint32_t*)yh)[b2]   = h0; ((uint32_t*)yh)[b2+1] = h1;
    ((uint32_t*)yl)[b2]   = l0; ((uint32_t*)yl)[b2+1] = l1;
}

// ---------------- RMSNorm -> fp16 hi only ----------------
__global__ void rmsnorm_h_kernel(const float* __restrict__ x,
                                 const float* __restrict__ g,
                                 __half* __restrict__ yh) {
    const int row = blockIdx.x;
    const float4* xr = (const float4*)(x + (size_t)row * DM);
    const int t = threadIdx.x;
    float4 xv = xr[t];
    float ss = xv.x*xv.x + xv.y*xv.y + xv.z*xv.z + xv.w*xv.w;
    #pragma unroll
    for (int o = 16; o; o >>= 1) ss += __shfl_xor_sync(0xffffffffu, ss, o);
    __shared__ float sred[8];
    const int warp = t >> 5, lane = t & 31;
    if (lane == 0) sred[warp] = ss;
    __syncthreads();
    if (warp == 0) {
        float v = (lane < 8) ? sred[lane] : 0.f;
        #pragma unroll
        for (int o = 4; o; o >>= 1) v += __shfl_xor_sync(0xffffffffu, v, o);
        if (lane == 0) sred[0] = v;
    }
    __syncthreads();
    const float inv = rsqrtf(sred[0] * (1.0f/(float)DM) + 1e-5f);
    const float4 gv = ((const float4*)g)[t];
    const size_t b2 = (size_t)row * (DM/2) + 2*t;
    ((__half2*)yh)[b2]   = __floats2half2_rn(xv.x*inv*gv.x, xv.y*inv*gv.y);
    ((__half2*)yh)[b2+1] = __floats2half2_rn(xv.z*inv*gv.z, xv.w*inv*gv.w);
}

// -------- mma.sync fp16 GEMM, CTA 128x256, warp 64x64, 1/2/3-term -------------
// Terms: Ah*Bh (+ Al*Bh when ALO) (+ Ah*Bl when BLO).
// MODE 0: C fp32 (+R). MODE 1: rope+Qscale+split -> Ch/Cl (stride ldc).
// MODE 2: swiglu -> Ch (stride ldc). MODE 3: hi-only -> Ch (stride ldc).
#define ROWB    144
#define QSCALE  0.18033688f      // 0.125 * log2(e)
template<int MODE, bool ALO, bool BLO>
__global__ __launch_bounds__(256, 1)
void gemm_mma_fp16(const __half* __restrict__ Ah,
                   const __half* __restrict__ Al,
                   const __half* __restrict__ Bh,
                   const __half* __restrict__ Bl,
                   const float* __restrict__ R,
                   float* __restrict__ C,
                   __half* __restrict__ Ch,
                   __half* __restrict__ Cl,
                   int N, int K, int ldc) {
    constexpr uint32_t AL_OFF = 128u * ROWB;
    constexpr uint32_t B_OFFC = (ALO ? 2u : 1u) * 128u * ROWB;
    constexpr uint32_t BL_OFF = B_OFFC + 256u * ROWB;
    constexpr uint32_t STG = (128u*(ALO ? 2u : 1u) + 256u*(BLO ? 2u : 1u)) * ROWB;
    extern __shared__ char smem[];
    const uint32_t sbase = smem_to_u32(smem);
    const int tid  = threadIdx.x;
    const int lane = tid & 31;
    const int wid  = tid >> 5;
    const int bm = blockIdx.y * 128;
    const int bn = blockIdx.x * 256;
    const int m0w = (wid & 1) * 64;
    const int n0w = (wid >> 1) * 64;

    float acc[4][8][4];
    #pragma unroll
    for (int i = 0; i < 4; i++)
        #pragma unroll
        for (int j = 0; j < 8; j++)
            #pragma unroll
            for (int q = 0; q < 4; q++) acc[i][j][q] = 0.f;

    const int nch = K >> 6;

    auto load_stage = [&](int s, int c) {
        const int k0 = c << 6;
        const uint32_t st = sbase + (uint32_t)s * STG;
        #pragma unroll
        for (int i = 0; i < 4; ++i) {           // A: 128 rows
            const int idx = tid + (i << 8);
            const int row = idx >> 3, cc = idx & 7;
            const uint32_t so = (uint32_t)(row * ROWB + cc * 16);
            const size_t ga = (size_t)(bm + row) * K + k0 + cc * 8;
            CP_ASYNC16(st + so, (const char*)(Ah + ga));
            if (ALO) CP_ASYNC16(st + AL_OFF + so, (const char*)(Al + ga));
        }
        #pragma unroll
        for (int i = 0; i < 8; ++i) {           // B: 256 rows
            const int idx = tid + (i << 8);
            const int row = idx >> 3, cc = idx & 7;
            const uint32_t so = (uint32_t)(row * ROWB + cc * 16);
            const size_t gb = (size_t)(bn + row) * K + k0 + cc * 8;
            CP_ASYNC16(st + B_OFFC + so, (const char*)(Bh + gb));
            if (BLO) CP_ASYNC16(st + BL_OFF + so, (const char*)(Bl + gb));
        }
        CP_COMMIT();
    };

    const int g = lane >> 3, r = lane & 7;
    const uint32_t aoff = (uint32_t)((m0w + (g & 1) * 8 + r) * ROWB + ((g >> 1) * 8) * 2);
    const uint32_t boff = B_OFFC + (uint32_t)((n0w + (g >> 1) * 8 + r) * ROWB + ((g & 1) * 8) * 2);

    load_stage(0, 0);

    for (int c = 0; c < nch; ++c) {
        CP_WAIT0();
        __syncthreads();
        if (c + 1 < nch) load_stage((c + 1) & 1, c + 1);

        const uint32_t st = sbase + (uint32_t)(c & 1) * STG;
        #pragma unroll
        for (int ks = 0; ks < 4; ++ks) {
            uint32_t AhF[4][4], AlF[4][4];
            const uint32_t ab = st + aoff + (uint32_t)(ks * 32);
            #pragma unroll
            for (int mi = 0; mi < 4; ++mi) {
                LDSM4(AhF[mi], ab + (uint32_t)(mi * 16 * ROWB));
                if (ALO) LDSM4(AlF[mi], ab + AL_OFF + (uint32_t)(mi * 16 * ROWB));
            }
            const uint32_t bb = st + boff + (uint32_t)(ks * 32);
            #pragma unroll
            for (int nb = 0; nb < 4; ++nb) {
                uint32_t BhF[4], BlF[4];
                LDSM4(BhF, bb + (uint32_t)(nb * 16 * ROWB));
                if (BLO) LDSM4(BlF, bb + (uint32_t)(BL_OFF - B_OFFC) + (uint32_t)(nb * 16 * ROWB));
                #pragma unroll
                for (int mi = 0; mi < 4; ++mi)
                    #pragma unroll
                    for (int hf = 0; hf < 2; ++hf) {
                        float* d = acc[mi][nb * 2 + hf];
                        MMA16816(d, AhF[mi], BhF[hf*2], BhF[hf*2+1]);
                        if (ALO) MMA16816(d, AlF[mi], BhF[hf*2], BhF[hf*2+1]);
                        if (BLO) MMA16816(d, AhF[mi], BlF[hf*2], BlF[hf*2+1]);
                    }
            }
        }
    }

    const int erow = lane >> 2;
    const int ecol = (lane & 3) * 2;
    #pragma unroll
    for (int mi = 0; mi < 4; ++mi) {
        #pragma unroll
        for (int nj = 0; nj < 8; ++nj) {
            float* d = acc[mi][nj];
            const int row0 = bm + m0w + mi * 16 + erow;
            const int row1 = row0 + 8;
            const int cg   = bn + n0w + nj * 8 + ecol;
            if (MODE == 0) {
                const size_t o0 = (size_t)row0 * ldc + cg;
                const size_t o1 = (size_t)row1 * ldc + cg;
                float2 v0 = make_float2(d[0], d[1]);
                float2 v1 = make_float2(d[2], d[3]);
                if (R) {
                    const float2 r0 = *(const float2*)(R + o0);
                    const float2 r1 = *(const float2*)(R + o1);
                    v0.x += r0.x; v0.y += r0.y;
                    v1.x += r1.x; v1.y += r1.y;
                }
                *(float2*)(C + o0) = v0;
                *(float2*)(C + o1) = v1;
            } else if (MODE == 1) {   // QK epilogue: rope all cols, Qscale cols<1024
                float a0 = d[0], a1 = d[1], b0 = d[2], b1 = d[3];
                {
                    const int i = (cg & 63) >> 1;
                    const int s0 = (row0 & (SS-1))*32 + i;
                    const int s1 = (row1 & (SS-1))*32 + i;
                    const float c0 = g_cs[s0], n0 = g_sn[s0];
                    const float c1 = g_cs[s1], n1 = g_sn[s1];
                    float t0 = a0*c0 - a1*n0, t1 = a0*n0 + a1*c0;
                    a0 = t0; a1 = t1;
                    float u0 = b0*c1 - b1*n1, u1 = b0*n1 + b1*c1;
                    b0 = u0; b1 = u1;
                }
                if (cg < 1024) {  // Q pre-scale into log2 domain
                    a0 *= QSCALE; a1 *= QSCALE; b0 *= QSCALE; b1 *= QSCALE;
                }
                uint32_t h0, l0, h1, l1;
                split_pack2(a0, a1, h0, l0);
                split_pack2(b0, b1, h1, l1);
                const size_t o0 = (size_t)row0 * ldc + cg;
                const size_t o1 = (size_t)row1 * ldc + cg;
                *(uint32_t*)(Ch + o0) = h0;
                *(uint32_t*)(Cl + o0) = l0;
                *(uint32_t*)(Ch + o1) = h1;
                *(uint32_t*)(Cl + o1) = l1;
            } else if (MODE == 3) {   // hi-only fp16 out (V projection)
                const size_t o0 = (size_t)row0 * ldc + cg;
                const size_t o1 = (size_t)row1 * ldc + cg;
                __half2 h0 = __floats2half2_rn(d[0], d[1]);
                __half2 h1 = __floats2half2_rn(d[2], d[3]);
                *(__half2*)(Ch + o0) = h0;
                *(__half2*)(Ch + o1) = h1;
            } else {  // MODE 2: swiglu, (even,odd) = (a, gate); hi-only output
                const int j = cg >> 1;
                float sl0, sl1;
                if (nj < 3) {   // MUFU path
                    const float e0 = ex2(-1.44269504f * d[0]);
                    const float e1 = ex2(-1.44269504f * d[2]);
                    const float dd0 = 1.f + e0, dd1 = 1.f + e1;
                    float r0 = rcpa(dd0); r0 = r0 * (2.f - dd0 * r0);
                    float r1 = rcpa(dd1); r1 = r1 * (2.f - dd1 * r1);
                    sl0 = d[0] * r0 * d[1];
                    sl1 = d[2] * r1 * d[3];
                } else {        // FMA-pipe path
                    const float e0 = fast_exp2(-1.44269504f * d[0]);
                    const float e1 = fast_exp2(-1.44269504f * d[2]);
                    const float dd0 = 1.f + e0, dd1 = 1.f + e1;
                    float r0 = __int_as_float(0x7EF311C3 - __float_as_int(dd0));
                    r0 = r0 * (2.f - dd0 * r0); r0 = r0 * (2.f - dd0 * r0);
                    float r1 = __int_as_float(0x7EF311C3 - __float_as_int(dd1));
                    r1 = r1 * (2.f - dd1 * r1); r1 = r1 * (2.f - dd1 * r1);
                    sl0 = d[0] * r0 * d[1];
                    sl1 = d[2] * r1 * d[3];
                }
                Ch[(size_t)row0 * ldc + j] = __float2half_rn(sl0);
                Ch[(size_t)row1 * ldc + j] = __float2half_rn(sl1);
            }
        }
    }
}

// ----- HMMA flash attention (QK 3-term, PV 1-term, base-2 softmax) ------------
#define ATB (64*144)
#define ATT_SMEM (8*ATB)     // Qh,Ql + 2 stages x (Kh,Kl,Vh)
__global__ __launch_bounds__(128)
void attn_mma_kernel(const __half* __restrict__ Xh,
                     const __half* __restrict__ Xl,
                     __half* __restrict__ Oh) {
    extern __shared__ char sm[];
    const uint32_t sQh = smem_to_u32(sm);
    const uint32_t sQl = sQh + ATB;
    const uint32_t sSt = sQh + 2*ATB;

    const int tid = threadIdx.x, lane = tid & 31, warp = tid >> 5;
    const int bh = blockIdx.y, b = bh >> 4, h = bh & (NH-1);
    const int qt = gridDim.x - 1 - blockIdx.x;
    const int q0 = qt * 64;
    const size_t rowbase = (size_t)b * SS * LDX;
    const int colQ = h*DH, colK = 1024 + h*DH, colV = 2048 + h*DH;

    #pragma unroll
    for (int i = 0; i < 4; i++) {
        const int idx = tid + i*128;
        const int r = idx >> 3, c = idx & 7;
        const uint32_t so = (uint32_t)(r*144 + c*16);
        const size_t ga = rowbase + (size_t)(q0 + r)*LDX + colQ + c*8;
        CP_ASYNC16(sQh + so, (const char*)(Xh + ga));
        CP_ASYNC16(sQl + so, (const char*)(Xl + ga));
    }
    CP_COMMIT();

    auto load_kv = [&](int t, int s) {
        const int k0 = t * 64;
        #pragma unroll
        for (int i = 0; i < 4; i++) {
            const int idx = tid + i*128;
            const int r = idx >> 3, c = idx & 7;
            const uint32_t so = (uint32_t)s*3*ATB + (uint32_t)(r*144 + c*16);
            const size_t gk = rowbase + (size_t)(k0 + r)*LDX + colK + c*8;
            const size_t gv = rowbase + (size_t)(k0 + r)*LDX + colV + c*8;
            CP_ASYNC16(sSt + so,         (const char*)(Xh + gk));
            CP_ASYNC16(sSt + ATB + so,   (const char*)(Xl + gk));
            CP_ASYNC16(sSt + 2*ATB + so, (const char*)(Xh + gv));
        }
        CP_COMMIT();
    };
    load_kv(0, 0);

    const int g = lane >> 3, rr = lane & 7;
    const uint32_t aoff = (uint32_t)((warp*16 + (g&1)*8 + rr)*144 + (g>>1)*16);
    const uint32_t boff = (uint32_t)(((g>>1)*8 + rr)*144 + (g&1)*16);
    const uint32_t voff = (uint32_t)(((g&1)*8 + rr)*144 + (lane>>4)*16);

    float m0 = -CUDART_INF_F, m1 = -CUDART_INF_F, l0 = 0.f, l1 = 0.f;
    float o[8][4];
    #pragma unroll
    for (int j = 0; j < 8; j++)
        #pragma unroll
        for (int q = 0; q < 4; q++) o[j][q] = 0.f;

    const int r0g = q0 + warp*16 + (lane >> 2);
    const int r1g = r0g + 8;
    const int ntiles = qt + 1;

    for (int t = 0; t < ntiles; t++) {
        CP_WAIT0();
        __syncthreads();
        if (t + 1 < ntiles) load_kv(t + 1, (t + 1) & 1);

        const uint32_t sK  = sSt + (uint32_t)(t & 1)*3*ATB;
        const uint32_t sKl = sK + ATB;
        const uint32_t sV  = sK + 2*ATB;

        float s[8][4];
        #pragma unroll
        for (int j = 0; j < 8; j++)
            #pragma unroll
            for (int q = 0; q < 4; q++) s[j][q] = 0.f;

        #pragma unroll
        for (int d = 0; d < 4; d++) {
            uint32_t qh[4], ql[4];
            LDSM4(qh, sQh + aoff + d*32);
            LDSM4(ql, sQl + aoff + d*32);
            #pragma unroll
            for (int nb = 0; nb < 4; nb++) {
                uint32_t kh[4], kl[4];
                LDSM4(kh, sK  + boff + (uint32_t)(nb*16*144) + d*32);
                LDSM4(kl, sKl + boff + (uint32_t)(nb*16*144) + d*32);
                #pragma unroll
                for (int f = 0; f < 2; f++) {
                    float* dd = s[nb*2 + f];
                    MMA16816(dd, qh, kh[2*f], kh[2*f+1]);
                    MMA16816(dd, qh, kl[2*f], kl[2*f+1]);
                    MMA16816(dd, ql, kh[2*f], kh[2*f+1]);
                }
            }
        }

        // scores already in log2 domain (Q pre-scaled by 0.125*log2e)
        const int k0 = t * 64;
        float mx0 = -CUDART_INF_F, mx1 = -CUDART_INF_F;
        #pragma unroll
        for (int j = 0; j < 8; j++) {
            if (t == qt) {
                const int c = k0 + j*8 + (lane & 3)*2;
                if (c     > r0g) s[j][0] = -CUDART_INF_F;
                if (c + 1 > r0g) s[j][1] = -CUDART_INF_F;
                if (c     > r1g) s[j][2] = -CUDART_INF_F;
                if (c + 1 > r1g) s[j][3] = -CUDART_INF_F;
            }
            mx0 = fmaxf(mx0, fmaxf(s[j][0], s[j][1]));
            mx1 = fmaxf(mx1, fmaxf(s[j][2], s[j][3]));
        }
        mx0 = fmaxf(mx0, __shfl_xor_sync(0xffffffffu, mx0, 1));
        mx0 = fmaxf(mx0, __shfl_xor_sync(0xffffffffu, mx0, 2));
        mx1 = fmaxf(mx1, __shfl_xor_sync(0xffffffffu, mx1, 1));
        mx1 = fmaxf(mx1, __shfl_xor_sync(0xffffffffu, mx1, 2));
        const float mn0 = fmaxf(m0, mx0), mn1 = fmaxf(m1, mx1);
        const float cr0 = ex2(m0 - mn0), cr1 = ex2(m1 - mn1);
        m0 = mn0; m1 = mn1;

        float sum0 = 0.f, sum1 = 0.f;
        #pragma unroll
        for (int j = 0; j < 8; j++) {
            if (j < 5) {     // MUFU path
                s[j][0] = ex2(s[j][0] - mn0); s[j][1] = ex2(s[j][1] - mn0);
                s[j][2] = ex2(s[j][2] - mn1); s[j][3] = ex2(s[j][3] - mn1);
            } else {         // FMA-pipe path
                s[j][0] = fast_exp2(s[j][0] - mn0); s[j][1] = fast_exp2(s[j][1] - mn0);
                s[j][2] = fast_exp2(s[j][2] - mn1); s[j][3] = fast_exp2(s[j][3] - mn1);
            }
            sum0 += s[j][0] + s[j][1];
            sum1 += s[j][2] + s[j][3];
        }
        sum0 += __shfl_xor_sync(0xffffffffu, sum0, 1);
        sum0 += __shfl_xor_sync(0xffffffffu, sum0, 2);
        sum1 += __shfl_xor_sync(0xffffffffu, sum1, 1);
        sum1 += __shfl_xor_sync(0xffffffffu, sum1, 2);
        l0 = l0 * cr0 + sum0;
        l1 = l1 * cr1 + sum1;
        #pragma unroll
        for (int j = 0; j < 8; j++) {
            o[j][0] *= cr0; o[j][1] *= cr0;
            o[j][2] *= cr1; o[j][3] *= cr1;
        }

        // ---- O += P V (P fp16 hi only; 1-term PV) ----
        #pragma unroll
        for (int kt = 0; kt < 4; kt++) {
            uint32_t ph[4];
            #pragma unroll
            for (int u = 0; u < 4; u++) {
                const int jj = 2*kt + (u >> 1);
                __half2 hh = __floats2half2_rn(s[jj][(u & 1)*2], s[jj][(u & 1)*2 + 1]);
                ph[u] = *(uint32_t*)&hh;
            }
            #pragma unroll
            for (int nb = 0; nb < 4; nb++) {
                uint32_t vh[4];
                const uint32_t va = voff + (uint32_t)(kt*16*144) + (uint32_t)(nb*32);
                LDSM4T(vh, sV + va);
                #pragma unroll
                for (int f = 0; f < 2; f++) {
                    float* dd = o[nb*2 + f];
                    MMA16816(dd, ph, vh[2*f], vh[2*f+1]);
                }
            }
        }
    }

    const float inv0 = 1.0f / l0, inv1 = 1.0f / l1;
    const size_t tok0 = (size_t)b * SS + r0g;
    const size_t tok1 = tok0 + 8;
    #pragma unroll
    for (int j = 0; j < 8; j++) {
        const int col = h*DH + j*8 + (lane & 3)*2;
        __half2 h0 = __floats2half2_rn(o[j][0]*inv0, o[j][1]*inv0);
        __half2 h1 = __floats2half2_rn(o[j][2]*inv1, o[j][3]*inv1);
        *(__half2*)(Oh + tok0*DM + col) = h0;
        *(__half2*)(Oh + tok1*DM + col) = h1;
    }
}

// ---------------- launch ----------------
extern "C" void kernel_launch(void* const* d_in, const int* in_sizes, int n_in,
                              void* d_out, int out_size) {
    const float* x   = (const float*)d_in[0];
    const int*   pos = (const int*)  d_in[1];
    const float* qw  = (const float*)d_in[2];
    const float* kw  = (const float*)d_in[3];
    const float* vw  = (const float*)d_in[4];
    const float* ow  = (const float*)d_in[5];
    const float* g1  = (const float*)d_in[6];
    const float* g2  = (const float*)d_in[7];
    const float* w1  = (const float*)d_in[8];
    const float* w2  = (const float*)d_in[9];
    const float* w3  = (const float*)d_in[10];
    float* out = (float*)d_out;

    __half *xnh, *xnl, *qkvh, *qkvl, *ath, *hnh, *swh;
    __half *wqkh, *wqkl, *vwh, *owh, *w13h, *w2h;
    float *res1;
    cudaGetSymbolAddress((void**)&xnh, g_xn_h);   cudaGetSymbolAddress((void**)&xnl, g_xn_l);
    cudaGetSymbolAddress((void**)&qkvh, g_qkv_h); cudaGetSymbolAddress((void**)&qkvl, g_qkv_l);
    cudaGetSymbolAddress((void**)&ath, g_at_h);
    cudaGetSymbolAddress((void**)&res1, g_res1);
    cudaGetSymbolAddress((void**)&hnh, g_hn_h);
    cudaGetSymbolAddress((void**)&swh, g_sw_h);
    cudaGetSymbolAddress((void**)&wqkh, g_wqk_h); cudaGetSymbolAddress((void**)&wqkl, g_wqk_l);
    cudaGetSymbolAddress((void**)&vwh, g_vw_h);
    cudaGetSymbolAddress((void**)&owh, g_ow_h);
    cudaGetSymbolAddress((void**)&w13h, g_w13_h);
    cudaGetSymbolAddress((void**)&w2h, g_w2_h);

    const int SM3 = 2 * (128*2 + 256*2) * ROWB;   // 221184  (3-term)
    const int SM1 = 2 * (128 + 256)     * ROWB;   // 110592  (1-term)
    cudaFuncSetAttribute((const void*)gemm_mma_fp16<1,true,true>,   cudaFuncAttributeMaxDynamicSharedMemorySize, SM3);
    cudaFuncSetAttribute((const void*)gemm_mma_fp16<3,false,false>, cudaFuncAttributeMaxDynamicSharedMemorySize, SM1);
    cudaFuncSetAttribute((const void*)gemm_mma_fp16<0,false,false>, cudaFuncAttributeMaxDynamicSharedMemorySize, SM1);
    cudaFuncSetAttribute((const void*)gemm_mma_fp16<2,false,false>, cudaFuncAttributeMaxDynamicSharedMemorySize, SM1);
    cudaFuncSetAttribute((const void*)attn_mma_kernel, cudaFuncAttributeMaxDynamicSharedMemorySize, ATT_SMEM);

    // 0: rope table
    rope_table_kernel<<<SS, 32>>>(pos);

    // 1: all weight conversions in one launch (4*Q4 + 3*W4 = 4194304 f4)
    prep_weights_kernel<<<(4*Q4 + 3*W4)/256, 256>>>(
        qw, kw, vw, ow, w1, w3, w2, wqkh, wqkl, vwh, owh, w13h, w2h);

    // 2: rmsnorm(x) -> split
    rmsnorm_split_kernel<<<MTOK, 256>>>(x, g1, xnh, xnl);

    // 3: QK projection (3-term) + rope + Q prescale + split  [8192,2048]
    gemm_mma_fp16<1,true,true><<<dim3(2048/256, MTOK/128), 256, SM3>>>(
        xnh, xnl, wqkh, wqkl, nullptr, nullptr, qkvh, qkvl, 2048, DM, LDX);

    // 4: V projection (1-term) hi-only  [8192,1024] -> qkv cols 2048..3071
    gemm_mma_fp16<3,false,false><<<dim3(DM/256, MTOK/128), 256, SM1>>>(
        xnh, nullptr, vwh, nullptr, nullptr, nullptr, qkvh + 2048, nullptr, DM, DM, LDX);

    // 5: HMMA flash attention (PV 1-term) -> fp16 hi
    attn_mma_kernel<<<dim3(SS/64, BB*NH), 128, ATT_SMEM>>>(qkvh, qkvl, ath);

    // 6: O projection (1-term) + residual(x) -> res1 fp32
    gemm_mma_fp16<0,false,false><<<dim3(DM/256, MTOK/128), 256, SM1>>>(
        ath, nullptr, owh, nullptr, x, res1, nullptr, nullptr, DM, DM, DM);

    // 7: rmsnorm(res1) -> hi only
    rmsnorm_h_kernel<<<MTOK, 256>>>(res1, g2, hnh);

    // 8: fused W1||W3 (1-term, interleaved) + swiglu -> sw hi
    gemm_mma_fp16<2,false,false><<<dim3(2*DFF/256, MTOK/128), 256, SM1>>>(
        hnh, nullptr, w13h, nullptr, nullptr, nullptr, swh, nullptr, 2*DFF, DM, DFF);

    // 9: down projection (1-term) + residual(res1) -> out
    gemm_mma_fp16<0,false,false><<<dim3(DM/256, MTOK/128), 256, SM1>>>(
        swh, nullptr, w2h, nullptr, res1, out, nullptr, nullptr, DM, DFF, DM);
}

// round 13
// speedup vs baseline: 7.5234x; 1.0628x over previous
#include <cuda_runtime.h>
#include <cuda_fp16.h>
#include <math.h>
#include <math_constants.h>
#include <cstdint>

#define BB   4
#define SS   2048
#define DM   1024
#define NH   16
#define DH   64
#define DFF  4096
#define MTOK (BB*SS)      // 8192
#define LDX  3072

// ---------------- helpers ----------------
__device__ __forceinline__ uint32_t smem_to_u32(const void* p) {
    uint32_t a;
    asm("{ .reg .u64 t; cvta.to.shared.u64 t, %1; cvt.u32.u64 %0, t; }" : "=r"(a) : "l"(p));
    return a;
}
#define CP_ASYNC16(s, g) asm volatile("cp.async.cg.shared.global [%0], [%1], 16;" :: "r"(s), "l"(g))
#define CP_COMMIT()      asm volatile("cp.async.commit_group;" ::: "memory")
#define CP_WAIT0()       asm volatile("cp.async.wait_group 0;" ::: "memory")
#define LDSM4(rg, addr) \
    asm volatile("ldmatrix.sync.aligned.m8n8.x4.shared.b16 {%0,%1,%2,%3}, [%4];" \
        : "=r"((rg)[0]), "=r"((rg)[1]), "=r"((rg)[2]), "=r"((rg)[3]) : "r"(addr))
#define LDSM4T(rg, addr) \
    asm volatile("ldmatrix.sync.aligned.m8n8.x4.trans.shared.b16 {%0,%1,%2,%3}, [%4];" \
        : "=r"((rg)[0]), "=r"((rg)[1]), "=r"((rg)[2]), "=r"((rg)[3]) : "r"(addr))
#define MMA16816(d, a, b0v, b1v) \
    asm volatile("mma.sync.aligned.m16n8k16.row.col.f32.f16.f16.f32 " \
        "{%0,%1,%2,%3}, {%4,%5,%6,%7}, {%8,%9}, {%0,%1,%2,%3};" \
        : "+f"((d)[0]), "+f"((d)[1]), "+f"((d)[2]), "+f"((d)[3]) \
        : "r"((a)[0]), "r"((a)[1]), "r"((a)[2]), "r"((a)[3]), "r"(b0v), "r"(b1v))

__device__ __forceinline__ float ex2(float x) {
    float r; asm("ex2.approx.f32 %0, %1;" : "=f"(r) : "f"(x)); return r;
}
__device__ __forceinline__ float rcpa(float x) {
    float r; asm("rcp.approx.f32 %0, %1;" : "=f"(r) : "f"(x)); return r;
}
// 2^y on the FMA pipe (magic round + deg-5 Taylor), rel err ~2e-6
__device__ __forceinline__ float fast_exp2(float y) {
    y = fmaxf(fminf(y, 126.f), -126.f);
    float z = __fadd_rn(y, 12582912.f);
    int   n = __float_as_int(z) - 0x4B400000;
    float f = __fadd_rn(y, -__fadd_rn(z, -12582912.f));
    float p = fmaf(f, 0.0013333558f, 0.0096181291f);
    p = fmaf(f, p, 0.0555041087f);
    p = fmaf(f, p, 0.2402265069f);
    p = fmaf(f, p, 0.6931471806f);
    p = fmaf(f, p, 1.0f);
    return __int_as_float(__float_as_int(p) + (n << 23));
}
// pack (p0,p1) -> f16x2 hi + f16x2 lo residual
__device__ __forceinline__ void split_pack2(float p0, float p1, uint32_t& h2, uint32_t& l2) {
    __half2 h = __floats2half2_rn(p0, p1);
    float2 hf = __half22float2(h);
    __half2 l = __floats2half2_rn(__fadd_rn(p0, -hf.x), __fadd_rn(p1, -hf.y));
    h2 = *(uint32_t*)&h;
    l2 = *(uint32_t*)&l;
}

// ---------------- scratch (__device__ globals) ----------------
static __device__ __half g_xn_h[(size_t)MTOK*DM],  g_xn_l[(size_t)MTOK*DM];
static __device__ __half g_qkv_h[(size_t)MTOK*LDX], g_qkv_l[(size_t)MTOK*LDX];
static __device__ __half g_at_h[(size_t)MTOK*DM];
static __device__ float  g_res1[(size_t)MTOK*DM];
static __device__ __half g_hn_h[(size_t)MTOK*DM];
static __device__ __half g_sw_h[(size_t)MTOK*DFF];
static __device__ __half g_wqk_h[2048*1024], g_wqk_l[2048*1024];
static __device__ __half g_vw_h [1024*1024];
static __device__ __half g_ow_h [1024*1024];
static __device__ __half g_w13_h[2*DFF*1024];   // interleaved rows
static __device__ __half g_w2_h [1024*DFF];
static __device__ float g_cs[SS*32], g_sn[SS*32];

__global__ void rope_table_kernel(const int* __restrict__ pos) {
    const int s = blockIdx.x, i = threadIdx.x;   // 2048 x 32
    const float inv = exp2f(-(float)i * (13.287712379549449f / 32.0f));
    const float a = (float)pos[s] * inv;
    float sn, cs;
    sincosf(a, &sn, &cs);
    g_cs[s*32 + i] = cs;
    g_sn[s*32 + i] = sn;
}

// ------------- merged weight prep: one launch for all 7 weight tensors --------
#define Q4 262144          // (1024*1024)/4
#define W4 1048576         // (4096*1024)/4
__global__ void prep_weights_kernel(const float* __restrict__ qw,
                                    const float* __restrict__ kw,
                                    const float* __restrict__ vw,
                                    const float* __restrict__ ow,
                                    const float* __restrict__ w1,
                                    const float* __restrict__ w3,
                                    const float* __restrict__ w2,
                                    __half* __restrict__ wqkh,
                                    __half* __restrict__ wqkl,
                                    __half* __restrict__ vwh,
                                    __half* __restrict__ owh,
                                    __half* __restrict__ w13h,
                                    __half* __restrict__ w2h) {
    const int i = blockIdx.x * blockDim.x + threadIdx.x;
    if (i < 2*Q4) {                        // qw | kw -> hi+lo split
        const int j = (i < Q4) ? i : i - Q4;
        const float4 v = (i < Q4) ? ((const float4*)qw)[j] : ((const float4*)kw)[j];
        uint32_t h0, l0, h1, l1;
        split_pack2(v.x, v.y, h0, l0);
        split_pack2(v.z, v.w, h1, l1);
        const uint32_t base = ((i < Q4) ? 0u : (1024u*1024u/2u)) + 2u*(uint32_t)j;
        ((uint32_t*)wqkh)[base] = h0; ((uint32_t*)wqkh)[base+1] = h1;
        ((uint32_t*)wqkl)[base] = l0; ((uint32_t*)wqkl)[base+1] = l1;
    } else if (i < 4*Q4) {                 // vw | ow -> hi only
        const int j = (i < 3*Q4) ? i - 2*Q4 : i - 3*Q4;
        const float4 v = (i < 3*Q4) ? ((const float4*)vw)[j] : ((const float4*)ow)[j];
        __half* dst = (i < 3*Q4) ? vwh : owh;
        ((__half2*)dst)[2*j]   = __floats2half2_rn(v.x, v.y);
        ((__half2*)dst)[2*j+1] = __floats2half2_rn(v.z, v.w);
    } else if (i < 4*Q4 + 2*W4) {          // w1 | w3 -> interleaved hi
        const int off = (i < 4*Q4 + W4) ? 0 : 1;
        const int j = i - 4*Q4 - off*W4;
        const float4 v = off ? ((const float4*)w3)[j] : ((const float4*)w1)[j];
        const int row = j >> 8, c4 = j & 255;
        const size_t o2 = ((size_t)(2*row + off) * 1024 + c4*4) >> 1;
        ((__half2*)w13h)[o2]   = __floats2half2_rn(v.x, v.y);
        ((__half2*)w13h)[o2+1] = __floats2half2_rn(v.z, v.w);
    } else {                               // w2 -> hi only
        const int j = i - 4*Q4 - 2*W4;
        const float4 v = ((const float4*)w2)[j];
        ((__half2*)w2h)[2*j]   = __floats2half2_rn(v.x, v.y);
        ((__half2*)w2h)[2*j+1] = __floats2half2_rn(v.z, v.w);
    }
}

// ---------------- RMSNorm -> split fp16 (hi+lo) ----------------
__global__ void rmsnorm_split_kernel(const float* __restrict__ x,
                                     const float* __restrict__ g,
                                     __half* __restrict__ yh,
                                     __half* __restrict__ yl) {
    const int row = blockIdx.x;
    const float4* xr = (const float4*)(x + (size_t)row * DM);
    const int t = threadIdx.x;
    float4 xv = xr[t];
    float ss = xv.x*xv.x + xv.y*xv.y + xv.z*xv.z + xv.w*xv.w;
    #pragma unroll
    for (int o = 16; o; o >>= 1) ss += __shfl_xor_sync(0xffffffffu, ss, o);
    __shared__ float sred[8];
    const int warp = t >> 5, lane = t & 31;
    if (lane == 0) sred[warp] = ss;
    __syncthreads();
    if (warp == 0) {
        float v = (lane < 8) ? sred[lane] : 0.f;
        #pragma unroll
        for (int o = 4; o; o >>= 1) v += __shfl_xor_sync(0xffffffffu, v, o);
        if (lane == 0) sred[0] = v;
    }
    __syncthreads();
    const float inv = rsqrtf(sred[0] * (1.0f/(float)DM) + 1e-5f);
    const float4 gv = ((const float4*)g)[t];
    uint32_t h0, l0, h1, l1;
    split_pack2(xv.x*inv*gv.x, xv.y*inv*gv.y, h0, l0);
    split_pack2(xv.z*inv*gv.z, xv.w*inv*gv.w, h1, l1);
    const size_t b2 = (size_t)row * (DM/2) + 2*t;
    ((uint32_t*)yh)[b2]   = h0; ((uint32_t*)yh)[b2+1] = h1;
    ((uint32_t*)yl)[b2]   = l0; ((uint32_t*)yl)[b2+1] = l1;
}

// ---------------- RMSNorm -> fp16 hi only ----------------
__global__ void rmsnorm_h_kernel(const float* __restrict__ x,
                                 const float* __restrict__ g,
                                 __half* __restrict__ yh) {
    const int row = blockIdx.x;
    const float4* xr = (const float4*)(x + (size_t)row * DM);
    const int t = threadIdx.x;
    float4 xv = xr[t];
    float ss = xv.x*xv.x + xv.y*xv.y + xv.z*xv.z + xv.w*xv.w;
    #pragma unroll
    for (int o = 16; o; o >>= 1) ss += __shfl_xor_sync(0xffffffffu, ss, o);
    __shared__ float sred[8];
    const int warp = t >> 5, lane = t & 31;
    if (lane == 0) sred[warp] = ss;
    __syncthreads();
    if (warp == 0) {
        float v = (lane < 8) ? sred[lane] : 0.f;
        #pragma unroll
        for (int o = 4; o; o >>= 1) v += __shfl_xor_sync(0xffffffffu, v, o);
        if (lane == 0) sred[0] = v;
    }
    __syncthreads();
    const float inv = rsqrtf(sred[0] * (1.0f/(float)DM) + 1e-5f);
    const float4 gv = ((const float4*)g)[t];
    const size_t b2 = (size_t)row * (DM/2) + 2*t;
    ((__half2*)yh)[b2]   = __floats2half2_rn(xv.x*inv*gv.x, xv.y*inv*gv.y);
    ((__half2*)yh)[b2+1] = __floats2half2_rn(xv.z*inv*gv.z, xv.w*inv*gv.w);
}

#define ROWB    144
#define QSCALE  0.18033688f      // 0.125 * log2(e)

// -------- BIG 3-term GEMM: CTA 128x256, warp 64x64 (QK projection only) -------
// MODE 1: rope all cols + Qscale cols<1024 + split -> Ch/Cl (stride ldc).
__global__ __launch_bounds__(256, 1)
void gemm_qk_fp16x3(const __half* __restrict__ Ah,
                    const __half* __restrict__ Al,
                    const __half* __restrict__ Bh,
                    const __half* __restrict__ Bl,
                    __half* __restrict__ Ch,
                    __half* __restrict__ Cl,
                    int N, int K, int ldc) {
    constexpr uint32_t AL_OFF = 128u * ROWB;
    constexpr uint32_t B_OFFC = 2u * 128u * ROWB;
    constexpr uint32_t BL_OFF = B_OFFC + 256u * ROWB;
    constexpr uint32_t STG = (128u*2u + 256u*2u) * ROWB;
    extern __shared__ char smem[];
    const uint32_t sbase = smem_to_u32(smem);
    const int tid  = threadIdx.x;
    const int lane = tid & 31;
    const int wid  = tid >> 5;
    const int bm = blockIdx.y * 128;
    const int bn = blockIdx.x * 256;
    const int m0w = (wid & 1) * 64;
    const int n0w = (wid >> 1) * 64;

    float acc[4][8][4];
    #pragma unroll
    for (int i = 0; i < 4; i++)
        #pragma unroll
        for (int j = 0; j < 8; j++)
            #pragma unroll
            for (int q = 0; q < 4; q++) acc[i][j][q] = 0.f;

    const int nch = K >> 6;

    auto load_stage = [&](int s, int c) {
        const int k0 = c << 6;
        const uint32_t st = sbase + (uint32_t)s * STG;
        #pragma unroll
        for (int i = 0; i < 4; ++i) {
            const int idx = tid + (i << 8);
            const int row = idx >> 3, cc = idx & 7;
            const uint32_t so = (uint32_t)(row * ROWB + cc * 16);
            const size_t ga = (size_t)(bm + row) * K + k0 + cc * 8;
            CP_ASYNC16(st + so, (const char*)(Ah + ga));
            CP_ASYNC16(st + AL_OFF + so, (const char*)(Al + ga));
        }
        #pragma unroll
        for (int i = 0; i < 8; ++i) {
            const int idx = tid + (i << 8);
            const int row = idx >> 3, cc = idx & 7;
            const uint32_t so = (uint32_t)(row * ROWB + cc * 16);
            const size_t gb = (size_t)(bn + row) * K + k0 + cc * 8;
            CP_ASYNC16(st + B_OFFC + so, (const char*)(Bh + gb));
            CP_ASYNC16(st + BL_OFF + so, (const char*)(Bl + gb));
        }
        CP_COMMIT();
    };

    const int g = lane >> 3, r = lane & 7;
    const uint32_t aoff = (uint32_t)((m0w + (g & 1) * 8 + r) * ROWB + ((g >> 1) * 8) * 2);
    const uint32_t boff = B_OFFC + (uint32_t)((n0w + (g >> 1) * 8 + r) * ROWB + ((g & 1) * 8) * 2);

    load_stage(0, 0);

    for (int c = 0; c < nch; ++c) {
        CP_WAIT0();
        __syncthreads();
        if (c + 1 < nch) load_stage((c + 1) & 1, c + 1);

        const uint32_t st = sbase + (uint32_t)(c & 1) * STG;
        #pragma unroll
        for (int ks = 0; ks < 4; ++ks) {
            uint32_t AhF[4][4], AlF[4][4];
            const uint32_t ab = st + aoff + (uint32_t)(ks * 32);
            #pragma unroll
            for (int mi = 0; mi < 4; ++mi) {
                LDSM4(AhF[mi], ab + (uint32_t)(mi * 16 * ROWB));
                LDSM4(AlF[mi], ab + AL_OFF + (uint32_t)(mi * 16 * ROWB));
            }
            const uint32_t bb = st + boff + (uint32_t)(ks * 32);
            #pragma unroll
            for (int nb = 0; nb < 4; ++nb) {
                uint32_t BhF[4], BlF[4];
                LDSM4(BhF, bb + (uint32_t)(nb * 16 * ROWB));
                LDSM4(BlF, bb + (uint32_t)(BL_OFF - B_OFFC) + (uint32_t)(nb * 16 * ROWB));
                #pragma unroll
                for (int mi = 0; mi < 4; ++mi)
                    #pragma unroll
                    for (int hf = 0; hf < 2; ++hf) {
                        float* d = acc[mi][nb * 2 + hf];
                        MMA16816(d, AhF[mi], BhF[hf*2], BhF[hf*2+1]);
                        MMA16816(d, AlF[mi], BhF[hf*2], BhF[hf*2+1]);
                        MMA16816(d, AhF[mi], BlF[hf*2], BlF[hf*2+1]);
                    }
            }
        }
    }

    const int erow = lane >> 2;
    const int ecol = (lane & 3) * 2;
    #pragma unroll
    for (int mi = 0; mi < 4; ++mi) {
        #pragma unroll
        for (int nj = 0; nj < 8; ++nj) {
            float* d = acc[mi][nj];
            const int row0 = bm + m0w + mi * 16 + erow;
            const int row1 = row0 + 8;
            const int cg   = bn + n0w + nj * 8 + ecol;
            float a0 = d[0], a1 = d[1], b0 = d[2], b1 = d[3];
            {
                const int i = (cg & 63) >> 1;
                const int s0 = (row0 & (SS-1))*32 + i;
                const int s1 = (row1 & (SS-1))*32 + i;
                const float c0 = g_cs[s0], n0 = g_sn[s0];
                const float c1 = g_cs[s1], n1 = g_sn[s1];
                float t0 = a0*c0 - a1*n0, t1 = a0*n0 + a1*c0;
                a0 = t0; a1 = t1;
                float u0 = b0*c1 - b1*n1, u1 = b0*n1 + b1*c1;
                b0 = u0; b1 = u1;
            }
            if (cg < 1024) {  // Q pre-scale into log2 domain
                a0 *= QSCALE; a1 *= QSCALE; b0 *= QSCALE; b1 *= QSCALE;
            }
            uint32_t h0, l0, h1, l1;
            split_pack2(a0, a1, h0, l0);
            split_pack2(b0, b1, h1, l1);
            const size_t o0 = (size_t)row0 * ldc + cg;
            const size_t o1 = (size_t)row1 * ldc + cg;
            *(uint32_t*)(Ch + o0) = h0;
            *(uint32_t*)(Cl + o0) = l0;
            *(uint32_t*)(Ch + o1) = h1;
            *(uint32_t*)(Cl + o1) = l1;
        }
    }
}

// -------- SMALL 1-term GEMM: CTA 128x128, warp 32x64, 2 CTAs/SM ---------------
// MODE 0: C fp32 (+R). MODE 2: swiglu -> Ch. MODE 3: hi-only -> Ch.
__global__ __launch_bounds__(256, 2)
void gemm1_mma_fp16_m0(const __half* __restrict__ Ah, const __half* __restrict__ Bh,
                       const float* __restrict__ R, float* __restrict__ C,
                       __half* __restrict__ Ch, int N, int K, int ldc);
template<int MODE>
__global__ __launch_bounds__(256, 2)
void gemm1_mma_fp16(const __half* __restrict__ Ah,
                    const __half* __restrict__ Bh,
                    const float* __restrict__ R,
                    float* __restrict__ C,
                    __half* __restrict__ Ch,
                    int N, int K, int ldc) {
    constexpr uint32_t B_OFFC = 128u * ROWB;
    constexpr uint32_t STG = 256u * ROWB;          // 36864
    extern __shared__ char smem[];
    const uint32_t sbase = smem_to_u32(smem);
    const int tid  = threadIdx.x;
    const int lane = tid & 31;
    const int wid  = tid >> 5;
    const int bm = blockIdx.y * 128;
    const int bn = blockIdx.x * 128;
    const int m0w = (wid & 3) * 32;
    const int n0w = (wid >> 2) * 64;

    float acc[2][8][4];
    #pragma unroll
    for (int i = 0; i < 2; i++)
        #pragma unroll
        for (int j = 0; j < 8; j++)
            #pragma unroll
            for (int q = 0; q < 4; q++) acc[i][j][q] = 0.f;

    const int nch = K >> 6;

    auto load_stage = [&](int s, int c) {
        const int k0 = c << 6;
        const uint32_t st = sbase + (uint32_t)s * STG;
        #pragma unroll
        for (int i = 0; i < 4; ++i) {           // A: 128 rows
            const int idx = tid + (i << 8);
            const int row = idx >> 3, cc = idx & 7;
            const uint32_t so = (uint32_t)(row * ROWB + cc * 16);
            const size_t ga = (size_t)(bm + row) * K + k0 + cc * 8;
            CP_ASYNC16(st + so, (const char*)(Ah + ga));
        }
        #pragma unroll
        for (int i = 0; i < 4; ++i) {           // B: 128 rows
            const int idx = tid + (i << 8);
            const int row = idx >> 3, cc = idx & 7;
            const uint32_t so = (uint32_t)(row * ROWB + cc * 16);
            const size_t gb = (size_t)(bn + row) * K + k0 + cc * 8;
            CP_ASYNC16(st + B_OFFC + so, (const char*)(Bh + gb));
        }
        CP_COMMIT();
    };

    const int g = lane >> 3, r = lane & 7;
    const uint32_t aoff = (uint32_t)((m0w + (g & 1) * 8 + r) * ROWB + ((g >> 1) * 8) * 2);
    const uint32_t boff = B_OFFC + (uint32_t)((n0w + (g >> 1) * 8 + r) * ROWB + ((g & 1) * 8) * 2);

    load_stage(0, 0);

    for (int c = 0; c < nch; ++c) {
        CP_WAIT0();
        __syncthreads();
        if (c + 1 < nch) load_stage((c + 1) & 1, c + 1);

        const uint32_t st = sbase + (uint32_t)(c & 1) * STG;
        #pragma unroll
        for (int ks = 0; ks < 4; ++ks) {
            uint32_t AhF[2][4];
            const uint32_t ab = st + aoff + (uint32_t)(ks * 32);
            #pragma unroll
            for (int mi = 0; mi < 2; ++mi)
                LDSM4(AhF[mi], ab + (uint32_t)(mi * 16 * ROWB));
            const uint32_t bb = st + boff + (uint32_t)(ks * 32);
            #pragma unroll
            for (int nb = 0; nb < 4; ++nb) {
                uint32_t BhF[4];
                LDSM4(BhF, bb + (uint32_t)(nb * 16 * ROWB));
                #pragma unroll
                for (int mi = 0; mi < 2; ++mi)
                    #pragma unroll
                    for (int hf = 0; hf < 2; ++hf)
                        MMA16816(acc[mi][nb * 2 + hf], AhF[mi], BhF[hf*2], BhF[hf*2+1]);
            }
        }
    }

    const int erow = lane >> 2;
    const int ecol = (lane & 3) * 2;
    #pragma unroll
    for (int mi = 0; mi < 2; ++mi) {
        #pragma unroll
        for (int nj = 0; nj < 8; ++nj) {
            float* d = acc[mi][nj];
            const int row0 = bm + m0w + mi * 16 + erow;
            const int row1 = row0 + 8;
            const int cg   = bn + n0w + nj * 8 + ecol;
            if (MODE == 0) {
                const size_t o0 = (size_t)row0 * ldc + cg;
                const size_t o1 = (size_t)row1 * ldc + cg;
                float2 v0 = make_float2(d[0], d[1]);
                float2 v1 = make_float2(d[2], d[3]);
                if (R) {
                    const float2 r0 = *(const float2*)(R + o0);
                    const float2 r1 = *(const float2*)(R + o1);
                    v0.x += r0.x; v0.y += r0.y;
                    v1.x += r1.x; v1.y += r1.y;
                }
                *(float2*)(C + o0) = v0;
                *(float2*)(C + o1) = v1;
            } else if (MODE == 3) {   // hi-only fp16 out (V projection)
                const size_t o0 = (size_t)row0 * ldc + cg;
                const size_t o1 = (size_t)row1 * ldc + cg;
                *(__half2*)(Ch + o0) = __floats2half2_rn(d[0], d[1]);
                *(__half2*)(Ch + o1) = __floats2half2_rn(d[2], d[3]);
            } else {  // MODE 2: swiglu, (even,odd) = (a, gate); hi-only output
                const int j = cg >> 1;
                float sl0, sl1;
                if (nj < 3) {   // MUFU path
                    const float e0 = ex2(-1.44269504f * d[0]);
                    const float e1 = ex2(-1.44269504f * d[2]);
                    const float dd0 = 1.f + e0, dd1 = 1.f + e1;
                    float r0 = rcpa(dd0); r0 = r0 * (2.f - dd0 * r0);
                    float r1 = rcpa(dd1); r1 = r1 * (2.f - dd1 * r1);
                    sl0 = d[0] * r0 * d[1];
                    sl1 = d[2] * r1 * d[3];
                } else {        // FMA-pipe path
                    const float e0 = fast_exp2(-1.44269504f * d[0]);
                    const float e1 = fast_exp2(-1.44269504f * d[2]);
                    const float dd0 = 1.f + e0, dd1 = 1.f + e1;
                    float r0 = __int_as_float(0x7EF311C3 - __float_as_int(dd0));
                    r0 = r0 * (2.f - dd0 * r0); r0 = r0 * (2.f - dd0 * r0);
                    float r1 = __int_as_float(0x7EF311C3 - __float_as_int(dd1));
                    r1 = r1 * (2.f - dd1 * r1); r1 = r1 * (2.f - dd1 * r1);
                    sl0 = d[0] * r0 * d[1];
                    sl1 = d[2] * r1 * d[3];
                }
                Ch[(size_t)row0 * ldc + j] = __float2half_rn(sl0);
                Ch[(size_t)row1 * ldc + j] = __float2half_rn(sl1);
            }
        }
    }
}

// ----- HMMA flash attention (QK 3-term, PV 1-term, base-2 softmax) ------------
#define ATB (64*144)
#define ATT_SMEM (8*ATB)     // Qh,Ql + 2 stages x (Kh,Kl,Vh)
__global__ __launch_bounds__(128)
void attn_mma_kernel(const __half* __restrict__ Xh,
                     const __half* __restrict__ Xl,
                     __half* __restrict__ Oh) {
    extern __shared__ char sm[];
    const uint32_t sQh = smem_to_u32(sm);
    const uint32_t sQl = sQh + ATB;
    const uint32_t sSt = sQh + 2*ATB;

    const int tid = threadIdx.x, lane = tid & 31, warp = tid >> 5;
    const int bh = blockIdx.y, b = bh >> 4, h = bh & (NH-1);
    const int qt = gridDim.x - 1 - blockIdx.x;
    const int q0 = qt * 64;
    const size_t rowbase = (size_t)b * SS * LDX;
    const int colQ = h*DH, colK = 1024 + h*DH, colV = 2048 + h*DH;

    #pragma unroll
    for (int i = 0; i < 4; i++) {
        const int idx = tid + i*128;
        const int r = idx >> 3, c = idx & 7;
        const uint32_t so = (uint32_t)(r*144 + c*16);
        const size_t ga = rowbase + (size_t)(q0 + r)*LDX + colQ + c*8;
        CP_ASYNC16(sQh + so, (const char*)(Xh + ga));
        CP_ASYNC16(sQl + so, (const char*)(Xl + ga));
    }
    CP_COMMIT();

    auto load_kv = [&](int t, int s) {
        const int k0 = t * 64;
        #pragma unroll
        for (int i = 0; i < 4; i++) {
            const int idx = tid + i*128;
            const int r = idx >> 3, c = idx & 7;
            const uint32_t so = (uint32_t)s*3*ATB + (uint32_t)(r*144 + c*16);
            const size_t gk = rowbase + (size_t)(k0 + r)*LDX + colK + c*8;
            const size_t gv = rowbase + (size_t)(k0 + r)*LDX + colV + c*8;
            CP_ASYNC16(sSt + so,         (const char*)(Xh + gk));
            CP_ASYNC16(sSt + ATB + so,   (const char*)(Xl + gk));
            CP_ASYNC16(sSt + 2*ATB + so, (const char*)(Xh + gv));
        }
        CP_COMMIT();
    };
    load_kv(0, 0);

    const int g = lane >> 3, rr = lane & 7;
    const uint32_t aoff = (uint32_t)((warp*16 + (g&1)*8 + rr)*144 + (g>>1)*16);
    const uint32_t boff = (uint32_t)(((g>>1)*8 + rr)*144 + (g&1)*16);
    const uint32_t voff = (uint32_t)(((g&1)*8 + rr)*144 + (lane>>4)*16);

    float m0 = -CUDART_INF_F, m1 = -CUDART_INF_F, l0 = 0.f, l1 = 0.f;
    float o[8][4];
    #pragma unroll
    for (int j = 0; j < 8; j++)
        #pragma unroll
        for (int q = 0; q < 4; q++) o[j][q] = 0.f;

    const int r0g = q0 + warp*16 + (lane >> 2);
    const int r1g = r0g + 8;
    const int ntiles = qt + 1;

    for (int t = 0; t < ntiles; t++) {
        CP_WAIT0();
        __syncthreads();
        if (t + 1 < ntiles) load_kv(t + 1, (t + 1) & 1);

        const uint32_t sK  = sSt + (uint32_t)(t & 1)*3*ATB;
        const uint32_t sKl = sK + ATB;
        const uint32_t sV  = sK + 2*ATB;

        float s[8][4];
        #pragma unroll
        for (int j = 0; j < 8; j++)
            #pragma unroll
            for (int q = 0; q < 4; q++) s[j][q] = 0.f;

        #pragma unroll
        for (int d = 0; d < 4; d++) {
            uint32_t qh[4], ql[4];
            LDSM4(qh, sQh + aoff + d*32);
            LDSM4(ql, sQl + aoff + d*32);
            #pragma unroll
            for (int nb = 0; nb < 4; nb++) {
                uint32_t kh[4], kl[4];
                LDSM4(kh, sK  + boff + (uint32_t)(nb*16*144) + d*32);
                LDSM4(kl, sKl + boff + (uint32_t)(nb*16*144) + d*32);
                #pragma unroll
                for (int f = 0; f < 2; f++) {
                    float* dd = s[nb*2 + f];
                    MMA16816(dd, qh, kh[2*f], kh[2*f+1]);
                    MMA16816(dd, qh, kl[2*f], kl[2*f+1]);
                    MMA16816(dd, ql, kh[2*f], kh[2*f+1]);
                }
            }
        }

        // scores already in log2 domain (Q pre-scaled by 0.125*log2e)
        const int k0 = t * 64;
        float mx0 = -CUDART_INF_F, mx1 = -CUDART_INF_F;
        #pragma unroll
        for (int j = 0; j < 8; j++) {
            if (t == qt) {
                const int c = k0 + j*8 + (lane & 3)*2;
                if (c     > r0g) s[j][0] = -CUDART_INF_F;
                if (c + 1 > r0g) s[j][1] = -CUDART_INF_F;
                if (c     > r1g) s[j][2] = -CUDART_INF_F;
                if (c + 1 > r1g) s[j][3] = -CUDART_INF_F;
            }
            mx0 = fmaxf(mx0, fmaxf(s[j][0], s[j][1]));
            mx1 = fmaxf(mx1, fmaxf(s[j][2], s[j][3]));
        }
        mx0 = fmaxf(mx0, __shfl_xor_sync(0xffffffffu, mx0, 1));
        mx0 = fmaxf(mx0, __shfl_xor_sync(0xffffffffu, mx0, 2));
        mx1 = fmaxf(mx1, __shfl_xor_sync(0xffffffffu, mx1, 1));
        mx1 = fmaxf(mx1, __shfl_xor_sync(0xffffffffu, mx1, 2));
        const float mn0 = fmaxf(m0, mx0), mn1 = fmaxf(m1, mx1);
        const float cr0 = ex2(m0 - mn0), cr1 = ex2(m1 - mn1);
        m0 = mn0; m1 = mn1;

        float sum0 = 0.f, sum1 = 0.f;
        #pragma unroll
        for (int j = 0; j < 8; j++) {
            if (j < 5) {     // MUFU path
                s[j][0] = ex2(s[j][0] - mn0); s[j][1] = ex2(s[j][1] - mn0);
                s[j][2] = ex2(s[j][2] - mn1); s[j][3] = ex2(s[j][3] - mn1);
            } else {         // FMA-pipe path
                s[j][0] = fast_exp2(s[j][0] - mn0); s[j][1] = fast_exp2(s[j][1] - mn0);
                s[j][2] = fast_exp2(s[j][2] - mn1); s[j][3] = fast_exp2(s[j][3] - mn1);
            }
            sum0 += s[j][0] + s[j][1];
            sum1 += s[j][2] + s[j][3];
        }
        sum0 += __shfl_xor_sync(0xffffffffu, sum0, 1);
        sum0 += __shfl_xor_sync(0xffffffffu, sum0, 2);
        sum1 += __shfl_xor_sync(0xffffffffu, sum1, 1);
        sum1 += __shfl_xor_sync(0xffffffffu, sum1, 2);
        l0 = l0 * cr0 + sum0;
        l1 = l1 * cr1 + sum1;
        #pragma unroll
        for (int j = 0; j < 8; j++) {
            o[j][0] *= cr0; o[j][1] *= cr0;
            o[j][2] *= cr1; o[j][3] *= cr1;
        }

        // ---- O += P V (P fp16 hi only; 1-term PV) ----
        #pragma unroll
        for (int kt = 0; kt < 4; kt++) {
            uint32_t ph[4];
            #pragma unroll
            for (int u = 0; u < 4; u++) {
                const int jj = 2*kt + (u >> 1);
                __half2 hh = __floats2half2_rn(s[jj][(u & 1)*2], s[jj][(u & 1)*2 + 1]);
                ph[u] = *(uint32_t*)&hh;
            }
            #pragma unroll
            for (int nb = 0; nb < 4; nb++) {
                uint32_t vh[4];
                const uint32_t va = voff + (uint32_t)(kt*16*144) + (uint32_t)(nb*32);
                LDSM4T(vh, sV + va);
                #pragma unroll
                for (int f = 0; f < 2; f++) {
                    float* dd = o[nb*2 + f];
                    MMA16816(dd, ph, vh[2*f], vh[2*f+1]);
                }
            }
        }
    }

    const float inv0 = 1.0f / l0, inv1 = 1.0f / l1;
    const size_t tok0 = (size_t)b * SS + r0g;
    const size_t tok1 = tok0 + 8;
    #pragma unroll
    for (int j = 0; j < 8; j++) {
        const int col = h*DH + j*8 + (lane & 3)*2;
        __half2 h0 = __floats2half2_rn(o[j][0]*inv0, o[j][1]*inv0);
        __half2 h1 = __floats2half2_rn(o[j][2]*inv1, o[j][3]*inv1);
        *(__half2*)(Oh + tok0*DM + col) = h0;
        *(__half2*)(Oh + tok1*DM + col) = h1;
    }
}

// ---------------- launch ----------------
extern "C" void kernel_launch(void* const* d_in, const int* in_sizes, int n_in,
                              void* d_out, int out_size) {
    const float* x   = (const float*)d_in[0];
    const int*   pos = (const int*)  d_in[1];
    const float* qw  = (const float*)d_in[2];
    const float* kw  = (const float*)d_in[3];
    const float* vw  = (const float*)d_in[4];
    const float* ow  = (const float*)d_in[5];
    const float* g1  = (const float*)d_in[6];
    const float* g2  = (const float*)d_in[7];
    const float* w1  = (const float*)d_in[8];
    const float* w2  = (const float*)d_in[9];
    const float* w3  = (const float*)d_in[10];
    float* out = (float*)d_out;

    __half *xnh, *xnl, *qkvh, *qkvl, *ath, *hnh, *swh;
    __half *wqkh, *wqkl, *vwh, *owh, *w13h, *w2h;
    float *res1;
    cudaGetSymbolAddress((void**)&xnh, g_xn_h);   cudaGetSymbolAddress((void**)&xnl, g_xn_l);
    cudaGetSymbolAddress((void**)&qkvh, g_qkv_h); cudaGetSymbolAddress((void**)&qkvl, g_qkv_l);
    cudaGetSymbolAddress((void**)&ath, g_at_h);
    cudaGetSymbolAddress((void**)&res1, g_res1);
    cudaGetSymbolAddress((void**)&hnh, g_hn_h);
    cudaGetSymbolAddress((void**)&swh, g_sw_h);
    cudaGetSymbolAddress((void**)&wqkh, g_wqk_h); cudaGetSymbolAddress((void**)&wqkl, g_wqk_l);
    cudaGetSymbolAddress((void**)&vwh, g_vw_h);
    cudaGetSymbolAddress((void**)&owh, g_ow_h);
    cudaGetSymbolAddress((void**)&w13h, g_w13_h);
    cudaGetSymbolAddress((void**)&w2h, g_w2_h);

    const int SM3 = 2 * (128*2 + 256*2) * ROWB;   // 221184  (3-term big)
    const int SMS = 2 * 256 * ROWB;               // 73728   (1-term small)
    cudaFuncSetAttribute((const void*)gemm_qk_fp16x3,      cudaFuncAttributeMaxDynamicSharedMemorySize, SM3);
    cudaFuncSetAttribute((const void*)gemm1_mma_fp16<0>,   cudaFuncAttributeMaxDynamicSharedMemorySize, SMS);
    cudaFuncSetAttribute((const void*)gemm1_mma_fp16<2>,   cudaFuncAttributeMaxDynamicSharedMemorySize, SMS);
    cudaFuncSetAttribute((const void*)gemm1_mma_fp16<3>,   cudaFuncAttributeMaxDynamicSharedMemorySize, SMS);
    cudaFuncSetAttribute((const void*)attn_mma_kernel,     cudaFuncAttributeMaxDynamicSharedMemorySize, ATT_SMEM);

    // 0: rope table
    rope_table_kernel<<<SS, 32>>>(pos);

    // 1: all weight conversions in one launch
    prep_weights_kernel<<<(4*Q4 + 3*W4)/256, 256>>>(
        qw, kw, vw, ow, w1, w3, w2, wqkh, wqkl, vwh, owh, w13h, w2h);

    // 2: rmsnorm(x) -> split
    rmsnorm_split_kernel<<<MTOK, 256>>>(x, g1, xnh, xnl);

    // 3: QK projection (3-term) + rope + Q prescale + split  [8192,2048]
    gemm_qk_fp16x3<<<dim3(2048/256, MTOK/128), 256, SM3>>>(
        xnh, xnl, wqkh, wqkl, qkvh, qkvl, 2048, DM, LDX);

    // 4: V projection (1-term) hi-only  [8192,1024] -> qkv cols 2048..3071
    gemm1_mma_fp16<3><<<dim3(DM/128, MTOK/128), 256, SMS>>>(
        xnh, vwh, nullptr, nullptr, qkvh + 2048, DM, DM, LDX);

    // 5: HMMA flash attention (PV 1-term) -> fp16 hi
    attn_mma_kernel<<<dim3(SS/64, BB*NH), 128, ATT_SMEM>>>(qkvh, qkvl, ath);

    // 6: O projection (1-term) + residual(x) -> res1 fp32
    gemm1_mma_fp16<0><<<dim3(DM/128, MTOK/128), 256, SMS>>>(
        ath, owh, x, res1, nullptr, DM, DM, DM);

    // 7: rmsnorm(res1) -> hi only
    rmsnorm_h_kernel<<<MTOK, 256>>>(res1, g2, hnh);

    // 8: fused W1||W3 (1-term, interleaved) + swiglu -> sw hi
    gemm1_mma_fp16<2><<<dim3(2*DFF/128, MTOK/128), 256, SMS>>>(
        hnh, w13h, nullptr, nullptr, swh, 2*DFF, DM, DFF);

    // 9: down projection (1-term) + residual(res1) -> out
    gemm1_mma_fp16<0><<<dim3(DM/128, MTOK/128), 256, SMS>>>(
        swh, w2h, res1, out, nullptr, DM, DFF, DM);
}

// round 14
// speedup vs baseline: 7.7127x; 1.0252x over previous
#include <cuda_runtime.h>
#include <cuda_fp16.h>
#include <math.h>
#include <math_constants.h>
#include <cstdint>

#define BB   4
#define SS   2048
#define DM   1024
#define NH   16
#define DH   64
#define DFF  4096
#define MTOK (BB*SS)      // 8192
#define LDX  3072

// ---------------- helpers ----------------
__device__ __forceinline__ uint32_t smem_to_u32(const void* p) {
    uint32_t a;
    asm("{ .reg .u64 t; cvta.to.shared.u64 t, %1; cvt.u32.u64 %0, t; }" : "=r"(a) : "l"(p));
    return a;
}
#define CP_ASYNC16(s, g) asm volatile("cp.async.cg.shared.global [%0], [%1], 16;" :: "r"(s), "l"(g))
#define CP_COMMIT()      asm volatile("cp.async.commit_group;" ::: "memory")
#define CP_WAIT0()       asm volatile("cp.async.wait_group 0;" ::: "memory")
#define LDSM4(rg, addr) \
    asm volatile("ldmatrix.sync.aligned.m8n8.x4.shared.b16 {%0,%1,%2,%3}, [%4];" \
        : "=r"((rg)[0]), "=r"((rg)[1]), "=r"((rg)[2]), "=r"((rg)[3]) : "r"(addr))
#define LDSM4T(rg, addr) \
    asm volatile("ldmatrix.sync.aligned.m8n8.x4.trans.shared.b16 {%0,%1,%2,%3}, [%4];" \
        : "=r"((rg)[0]), "=r"((rg)[1]), "=r"((rg)[2]), "=r"((rg)[3]) : "r"(addr))
#define MMA16816(d, a, b0v, b1v) \
    asm volatile("mma.sync.aligned.m16n8k16.row.col.f32.f16.f16.f32 " \
        "{%0,%1,%2,%3}, {%4,%5,%6,%7}, {%8,%9}, {%0,%1,%2,%3};" \
        : "+f"((d)[0]), "+f"((d)[1]), "+f"((d)[2]), "+f"((d)[3]) \
        : "r"((a)[0]), "r"((a)[1]), "r"((a)[2]), "r"((a)[3]), "r"(b0v), "r"(b1v))

__device__ __forceinline__ float ex2(float x) {
    float r; asm("ex2.approx.f32 %0, %1;" : "=f"(r) : "f"(x)); return r;
}
__device__ __forceinline__ float rcpa(float x) {
    float r; asm("rcp.approx.f32 %0, %1;" : "=f"(r) : "f"(x)); return r;
}
// 2^y on the FMA pipe (magic round + deg-5 Taylor), rel err ~2e-6
__device__ __forceinline__ float fast_exp2(float y) {
    y = fmaxf(fminf(y, 126.f), -126.f);
    float z = __fadd_rn(y, 12582912.f);
    int   n = __float_as_int(z) - 0x4B400000;
    float f = __fadd_rn(y, -__fadd_rn(z, -12582912.f));
    float p = fmaf(f, 0.0013333558f, 0.0096181291f);
    p = fmaf(f, p, 0.0555041087f);
    p = fmaf(f, p, 0.2402265069f);
    p = fmaf(f, p, 0.6931471806f);
    p = fmaf(f, p, 1.0f);
    return __int_as_float(__float_as_int(p) + (n << 23));
}
// pack (p0,p1) -> f16x2 hi + f16x2 lo residual
__device__ __forceinline__ void split_pack2(float p0, float p1, uint32_t& h2, uint32_t& l2) {
    __half2 h = __floats2half2_rn(p0, p1);
    float2 hf = __half22float2(h);
    __half2 l = __floats2half2_rn(__fadd_rn(p0, -hf.x), __fadd_rn(p1, -hf.y));
    h2 = *(uint32_t*)&h;
    l2 = *(uint32_t*)&l;
}

// ---------------- scratch (__device__ globals) ----------------
static __device__ __half g_xn_h[(size_t)MTOK*DM],  g_xn_l[(size_t)MTOK*DM];
static __device__ __half g_qkv_h[(size_t)MTOK*LDX], g_qkv_l[(size_t)MTOK*LDX];
static __device__ __half g_at_h[(size_t)MTOK*DM];
static __device__ float  g_res1[(size_t)MTOK*DM];
static __device__ __half g_hn_h[(size_t)MTOK*DM];
static __device__ __half g_sw_h[(size_t)MTOK*DFF];
static __device__ __half g_wqk_h[2048*1024], g_wqk_l[2048*1024];
static __device__ __half g_vw_h [1024*1024];
static __device__ __half g_ow_h [1024*1024];
static __device__ __half g_w13_h[2*DFF*1024];   // interleaved rows
static __device__ __half g_w2_h [1024*DFF];
static __device__ float g_cs[SS*32], g_sn[SS*32];

__global__ void rope_table_kernel(const int* __restrict__ pos) {
    const int s = blockIdx.x, i = threadIdx.x;   // 2048 x 32
    const float inv = exp2f(-(float)i * (13.287712379549449f / 32.0f));
    const float a = (float)pos[s] * inv;
    float sn, cs;
    sincosf(a, &sn, &cs);
    g_cs[s*32 + i] = cs;
    g_sn[s*32 + i] = sn;
}

// ------------- merged weight prep: one launch for all 7 weight tensors --------
#define Q4 262144          // (1024*1024)/4
#define W4 1048576         // (4096*1024)/4
__global__ void prep_weights_kernel(const float* __restrict__ qw,
                                    const float* __restrict__ kw,
                                    const float* __restrict__ vw,
                                    const float* __restrict__ ow,
                                    const float* __restrict__ w1,
                                    const float* __restrict__ w3,
                                    const float* __restrict__ w2,
                                    __half* __restrict__ wqkh,
                                    __half* __restrict__ wqkl,
                                    __half* __restrict__ vwh,
                                    __half* __restrict__ owh,
                                    __half* __restrict__ w13h,
                                    __half* __restrict__ w2h) {
    const int i = blockIdx.x * blockDim.x + threadIdx.x;
    if (i < 2*Q4) {                        // qw | kw -> hi+lo split
        const int j = (i < Q4) ? i : i - Q4;
        const float4 v = (i < Q4) ? ((const float4*)qw)[j] : ((const float4*)kw)[j];
        uint32_t h0, l0, h1, l1;
        split_pack2(v.x, v.y, h0, l0);
        split_pack2(v.z, v.w, h1, l1);
        const uint32_t base = ((i < Q4) ? 0u : (1024u*1024u/2u)) + 2u*(uint32_t)j;
        ((uint32_t*)wqkh)[base] = h0; ((uint32_t*)wqkh)[base+1] = h1;
        ((uint32_t*)wqkl)[base] = l0; ((uint32_t*)wqkl)[base+1] = l1;
    } else if (i < 4*Q4) {                 // vw | ow -> hi only
        const int j = (i < 3*Q4) ? i - 2*Q4 : i - 3*Q4;
        const float4 v = (i < 3*Q4) ? ((const float4*)vw)[j] : ((const float4*)ow)[j];
        __half* dst = (i < 3*Q4) ? vwh : owh;
        ((__half2*)dst)[2*j]   = __floats2half2_rn(v.x, v.y);
        ((__half2*)dst)[2*j+1] = __floats2half2_rn(v.z, v.w);
    } else if (i < 4*Q4 + 2*W4) {          // w1 | w3 -> interleaved hi
        const int off = (i < 4*Q4 + W4) ? 0 : 1;
        const int j = i - 4*Q4 - off*W4;
        const float4 v = off ? ((const float4*)w3)[j] : ((const float4*)w1)[j];
        const int row = j >> 8, c4 = j & 255;
        const size_t o2 = ((size_t)(2*row + off) * 1024 + c4*4) >> 1;
        ((__half2*)w13h)[o2]   = __floats2half2_rn(v.x, v.y);
        ((__half2*)w13h)[o2+1] = __floats2half2_rn(v.z, v.w);
    } else {                               // w2 -> hi only
        const int j = i - 4*Q4 - 2*W4;
        const float4 v = ((const float4*)w2)[j];
        ((__half2*)w2h)[2*j]   = __floats2half2_rn(v.x, v.y);
        ((__half2*)w2h)[2*j+1] = __floats2half2_rn(v.z, v.w);
    }
}

// ---------------- RMSNorm -> split fp16 (hi+lo) ----------------
__global__ void rmsnorm_split_kernel(const float* __restrict__ x,
                                     const float* __restrict__ g,
                                     __half* __restrict__ yh,
                                     __half* __restrict__ yl) {
    const int row = blockIdx.x;
    const float4* xr = (const float4*)(x + (size_t)row * DM);
    const int t = threadIdx.x;
    float4 xv = xr[t];
    float ss = xv.x*xv.x + xv.y*xv.y + xv.z*xv.z + xv.w*xv.w;
    #pragma unroll
    for (int o = 16; o; o >>= 1) ss += __shfl_xor_sync(0xffffffffu, ss, o);
    __shared__ float sred[8];
    const int warp = t >> 5, lane = t & 31;
    if (lane == 0) sred[warp] = ss;
    __syncthreads();
    if (warp == 0) {
        float v = (lane < 8) ? sred[lane] : 0.f;
        #pragma unroll
        for (int o = 4; o; o >>= 1) v += __shfl_xor_sync(0xffffffffu, v, o);
        if (lane == 0) sred[0] = v;
    }
    __syncthreads();
    const float inv = rsqrtf(sred[0] * (1.0f/(float)DM) + 1e-5f);
    const float4 gv = ((const float4*)g)[t];
    uint32_t h0, l0, h1, l1;
    split_pack2(xv.x*inv*gv.x, xv.y*inv*gv.y, h0, l0);
    split_pack2(xv.z*inv*gv.z, xv.w*inv*gv.w, h1, l1);
    const size_t b2 = (size_t)row * (DM/2) + 2*t;
    ((uint32_t*)yh)[b2]   = h0; ((uint32_t*)yh)[b2+1] = h1;
    ((uint32_t*)yl)[b2]   = l0; ((uint32_t*)yl)[b2+1] = l1;
}

// ---------------- RMSNorm -> fp16 hi only ----------------
__global__ void rmsnorm_h_kernel(const float* __restrict__ x,
                                 const float* __restrict__ g,
                                 __half* __restrict__ yh) {
    const int row = blockIdx.x;
    const float4* xr = (const float4*)(x + (size_t)row * DM);
    const int t = threadIdx.x;
    float4 xv = xr[t];
    float ss = xv.x*xv.x + xv.y*xv.y + xv.z*xv.z + xv.w*xv.w;
    #pragma unroll
    for (int o = 16; o; o >>= 1) ss += __shfl_xor_sync(0xffffffffu, ss, o);
    __shared__ float sred[8];
    const int warp = t >> 5, lane = t & 31;
    if (lane == 0) sred[warp] = ss;
    __syncthreads();
    if (warp == 0) {
        float v = (lane < 8) ? sred[lane] : 0.f;
        #pragma unroll
        for (int o = 4; o; o >>= 1) v += __shfl_xor_sync(0xffffffffu, v, o);
        if (lane == 0) sred[0] = v;
    }
    __syncthreads();
    const float inv = rsqrtf(sred[0] * (1.0f/(float)DM) + 1e-5f);
    const float4 gv = ((const float4*)g)[t];
    const size_t b2 = (size_t)row * (DM/2) + 2*t;
    ((__half2*)yh)[b2]   = __floats2half2_rn(xv.x*inv*gv.x, xv.y*inv*gv.y);
    ((__half2*)yh)[b2+1] = __floats2half2_rn(xv.z*inv*gv.z, xv.w*inv*gv.w);
}

#define ROWB    144
#define QSCALE  0.18033688f      // 0.125 * log2(e)

// -------- QK 3-term GEMM v2: CTA 128x128, warp 32x64, BK=32, 2 CTAs/SM --------
// rope all cols + Qscale cols<1024 + split -> Ch/Cl (stride ldc).
#define QROWB 80                 // 32 halfs + 16B pad
#define QAL   (128u*QROWB)       // A-lo offset
#define QBH   (2u*128u*QROWB)    // B-hi
#define QBL   (3u*128u*QROWB)    // B-lo
#define QSTG  (4u*128u*QROWB)    // 40960 per stage
__global__ __launch_bounds__(256, 2)
void gemm_qk_fp16x3(const __half* __restrict__ Ah,
                    const __half* __restrict__ Al,
                    const __half* __restrict__ Bh,
                    const __half* __restrict__ Bl,
                    __half* __restrict__ Ch,
                    __half* __restrict__ Cl,
                    int N, int K, int ldc) {
    extern __shared__ char smem[];
    const uint32_t sbase = smem_to_u32(smem);
    const int tid  = threadIdx.x;
    const int lane = tid & 31;
    const int wid  = tid >> 5;
    const int bm = blockIdx.y * 128;
    const int bn = blockIdx.x * 128;
    const int m0w = (wid & 3) * 32;
    const int n0w = (wid >> 2) * 64;

    float acc[2][8][4];
    #pragma unroll
    for (int i = 0; i < 2; i++)
        #pragma unroll
        for (int j = 0; j < 8; j++)
            #pragma unroll
            for (int q = 0; q < 4; q++) acc[i][j][q] = 0.f;

    const int nch = K >> 5;   // BK=32

    auto load_stage = [&](int s, int c) {
        const int k0 = c << 5;
        const uint32_t st = sbase + (uint32_t)s * QSTG;
        #pragma unroll
        for (int i = 0; i < 2; ++i) {
            const int idx = tid + (i << 8);          // 0..511
            const int row = idx >> 2, cc = idx & 3;  // 4 x 16B per 32-half row
            const uint32_t so = (uint32_t)(row * QROWB + cc * 16);
            const size_t ga = (size_t)(bm + row) * K + k0 + cc * 8;
            const size_t gb = (size_t)(bn + row) * K + k0 + cc * 8;
            CP_ASYNC16(st + so,       (const char*)(Ah + ga));
            CP_ASYNC16(st + QAL + so, (const char*)(Al + ga));
            CP_ASYNC16(st + QBH + so, (const char*)(Bh + gb));
            CP_ASYNC16(st + QBL + so, (const char*)(Bl + gb));
        }
        CP_COMMIT();
    };

    const int g = lane >> 3, r = lane & 7;
    const uint32_t aoff = (uint32_t)((m0w + (g & 1) * 8 + r) * QROWB + ((g >> 1) * 8) * 2);
    const uint32_t boff = QBH + (uint32_t)((n0w + (g >> 1) * 8 + r) * QROWB + ((g & 1) * 8) * 2);

    load_stage(0, 0);

    for (int c = 0; c < nch; ++c) {
        CP_WAIT0();
        __syncthreads();
        if (c + 1 < nch) load_stage((c + 1) & 1, c + 1);

        const uint32_t st = sbase + (uint32_t)(c & 1) * QSTG;
        #pragma unroll
        for (int ks = 0; ks < 2; ++ks) {
            uint32_t AhF[2][4], AlF[2][4];
            const uint32_t ab = st + aoff + (uint32_t)(ks * 32);
            #pragma unroll
            for (int mi = 0; mi < 2; ++mi) {
                LDSM4(AhF[mi], ab + (uint32_t)(mi * 16 * QROWB));
                LDSM4(AlF[mi], ab + QAL + (uint32_t)(mi * 16 * QROWB));
            }
            const uint32_t bb = st + boff + (uint32_t)(ks * 32);
            #pragma unroll
            for (int nb = 0; nb < 4; ++nb) {
                uint32_t BhF[4], BlF[4];
                LDSM4(BhF, bb + (uint32_t)(nb * 16 * QROWB));
                LDSM4(BlF, bb + (QBL - QBH) + (uint32_t)(nb * 16 * QROWB));
                #pragma unroll
                for (int mi = 0; mi < 2; ++mi)
                    #pragma unroll
                    for (int hf = 0; hf < 2; ++hf) {
                        float* d = acc[mi][nb * 2 + hf];
                        MMA16816(d, AhF[mi], BhF[hf*2], BhF[hf*2+1]);
                        MMA16816(d, AlF[mi], BhF[hf*2], BhF[hf*2+1]);
                        MMA16816(d, AhF[mi], BlF[hf*2], BlF[hf*2+1]);
                    }
            }
        }
    }

    const int erow = lane >> 2;
    const int ecol = (lane & 3) * 2;
    #pragma unroll
    for (int mi = 0; mi < 2; ++mi) {
        #pragma unroll
        for (int nj = 0; nj < 8; ++nj) {
            float* d = acc[mi][nj];
            const int row0 = bm + m0w + mi * 16 + erow;
            const int row1 = row0 + 8;
            const int cg   = bn + n0w + nj * 8 + ecol;
            float a0 = d[0], a1 = d[1], b0 = d[2], b1 = d[3];
            {
                const int i = (cg & 63) >> 1;
                const int s0 = (row0 & (SS-1))*32 + i;
                const int s1 = (row1 & (SS-1))*32 + i;
                const float c0 = g_cs[s0], n0 = g_sn[s0];
                const float c1 = g_cs[s1], n1 = g_sn[s1];
                float t0 = a0*c0 - a1*n0, t1 = a0*n0 + a1*c0;
                a0 = t0; a1 = t1;
                float u0 = b0*c1 - b1*n1, u1 = b0*n1 + b1*c1;
                b0 = u0; b1 = u1;
            }
            if (cg < 1024) {  // Q pre-scale into log2 domain
                a0 *= QSCALE; a1 *= QSCALE; b0 *= QSCALE; b1 *= QSCALE;
            }
            uint32_t h0, l0, h1, l1;
            split_pack2(a0, a1, h0, l0);
            split_pack2(b0, b1, h1, l1);
            const size_t o0 = (size_t)row0 * ldc + cg;
            const size_t o1 = (size_t)row1 * ldc + cg;
            *(uint32_t*)(Ch + o0) = h0;
            *(uint32_t*)(Cl + o0) = l0;
            *(uint32_t*)(Ch + o1) = h1;
            *(uint32_t*)(Cl + o1) = l1;
        }
    }
}

// -------- SMALL 1-term GEMM: CTA 128x128, warp 32x64, 2 CTAs/SM ---------------
// MODE 0: C fp32 (+R). MODE 2: swiglu -> Ch. MODE 3: hi-only -> Ch.
template<int MODE>
__global__ __launch_bounds__(256, 2)
void gemm1_mma_fp16(const __half* __restrict__ Ah,
                    const __half* __restrict__ Bh,
                    const float* __restrict__ R,
                    float* __restrict__ C,
                    __half* __restrict__ Ch,
                    int N, int K, int ldc) {
    constexpr uint32_t B_OFFC = 128u * ROWB;
    constexpr uint32_t STG = 256u * ROWB;          // 36864
    extern __shared__ char smem[];
    const uint32_t sbase = smem_to_u32(smem);
    const int tid  = threadIdx.x;
    const int lane = tid & 31;
    const int wid  = tid >> 5;
    const int bm = blockIdx.y * 128;
    const int bn = blockIdx.x * 128;
    const int m0w = (wid & 3) * 32;
    const int n0w = (wid >> 2) * 64;

    float acc[2][8][4];
    #pragma unroll
    for (int i = 0; i < 2; i++)
        #pragma unroll
        for (int j = 0; j < 8; j++)
            #pragma unroll
            for (int q = 0; q < 4; q++) acc[i][j][q] = 0.f;

    const int nch = K >> 6;

    auto load_stage = [&](int s, int c) {
        const int k0 = c << 6;
        const uint32_t st = sbase + (uint32_t)s * STG;
        #pragma unroll
        for (int i = 0; i < 4; ++i) {           // A: 128 rows
            const int idx = tid + (i << 8);
            const int row = idx >> 3, cc = idx & 7;
            const uint32_t so = (uint32_t)(row * ROWB + cc * 16);
            const size_t ga = (size_t)(bm + row) * K + k0 + cc * 8;
            CP_ASYNC16(st + so, (const char*)(Ah + ga));
        }
        #pragma unroll
        for (int i = 0; i < 4; ++i) {           // B: 128 rows
            const int idx = tid + (i << 8);
            const int row = idx >> 3, cc = idx & 7;
            const uint32_t so = (uint32_t)(row * ROWB + cc * 16);
            const size_t gb = (size_t)(bn + row) * K + k0 + cc * 8;
            CP_ASYNC16(st + B_OFFC + so, (const char*)(Bh + gb));
        }
        CP_COMMIT();
    };

    const int g = lane >> 3, r = lane & 7;
    const uint32_t aoff = (uint32_t)((m0w + (g & 1) * 8 + r) * ROWB + ((g >> 1) * 8) * 2);
    const uint32_t boff = B_OFFC + (uint32_t)((n0w + (g >> 1) * 8 + r) * ROWB + ((g & 1) * 8) * 2);

    load_stage(0, 0);

    for (int c = 0; c < nch; ++c) {
        CP_WAIT0();
        __syncthreads();
        if (c + 1 < nch) load_stage((c + 1) & 1, c + 1);

        const uint32_t st = sbase + (uint32_t)(c & 1) * STG;
        #pragma unroll
        for (int ks = 0; ks < 4; ++ks) {
            uint32_t AhF[2][4];
            const uint32_t ab = st + aoff + (uint32_t)(ks * 32);
            #pragma unroll
            for (int mi = 0; mi < 2; ++mi)
                LDSM4(AhF[mi], ab + (uint32_t)(mi * 16 * ROWB));
            const uint32_t bb = st + boff + (uint32_t)(ks * 32);
            #pragma unroll
            for (int nb = 0; nb < 4; ++nb) {
                uint32_t BhF[4];
                LDSM4(BhF, bb + (uint32_t)(nb * 16 * ROWB));
                #pragma unroll
                for (int mi = 0; mi < 2; ++mi)
                    #pragma unroll
                    for (int hf = 0; hf < 2; ++hf)
                        MMA16816(acc[mi][nb * 2 + hf], AhF[mi], BhF[hf*2], BhF[hf*2+1]);
            }
        }
    }

    const int erow = lane >> 2;
    const int ecol = (lane & 3) * 2;
    #pragma unroll
    for (int mi = 0; mi < 2; ++mi) {
        #pragma unroll
        for (int nj = 0; nj < 8; ++nj) {
            float* d = acc[mi][nj];
            const int row0 = bm + m0w + mi * 16 + erow;
            const int row1 = row0 + 8;
            const int cg   = bn + n0w + nj * 8 + ecol;
            if (MODE == 0) {
                const size_t o0 = (size_t)row0 * ldc + cg;
                const size_t o1 = (size_t)row1 * ldc + cg;
                float2 v0 = make_float2(d[0], d[1]);
                float2 v1 = make_float2(d[2], d[3]);
                if (R) {
                    const float2 r0 = *(const float2*)(R + o0);
                    const float2 r1 = *(const float2*)(R + o1);
                    v0.x += r0.x; v0.y += r0.y;
                    v1.x += r1.x; v1.y += r1.y;
                }
                *(float2*)(C + o0) = v0;
                *(float2*)(C + o1) = v1;
            } else if (MODE == 3) {   // hi-only fp16 out (V projection)
                const size_t o0 = (size_t)row0 * ldc + cg;
                const size_t o1 = (size_t)row1 * ldc + cg;
                *(__half2*)(Ch + o0) = __floats2half2_rn(d[0], d[1]);
                *(__half2*)(Ch + o1) = __floats2half2_rn(d[2], d[3]);
            } else {  // MODE 2: swiglu, (even,odd) = (a, gate); hi-only output
                const int j = cg >> 1;
                float sl0, sl1;
                if (nj < 3) {   // MUFU path
                    const float e0 = ex2(-1.44269504f * d[0]);
                    const float e1 = ex2(-1.44269504f * d[2]);
                    const float dd0 = 1.f + e0, dd1 = 1.f + e1;
                    float r0 = rcpa(dd0); r0 = r0 * (2.f - dd0 * r0);
                    float r1 = rcpa(dd1); r1 = r1 * (2.f - dd1 * r1);
                    sl0 = d[0] * r0 * d[1];
                    sl1 = d[2] * r1 * d[3];
                } else {        // FMA-pipe path
                    const float e0 = fast_exp2(-1.44269504f * d[0]);
                    const float e1 = fast_exp2(-1.44269504f * d[2]);
                    const float dd0 = 1.f + e0, dd1 = 1.f + e1;
                    float r0 = __int_as_float(0x7EF311C3 - __float_as_int(dd0));
                    r0 = r0 * (2.f - dd0 * r0); r0 = r0 * (2.f - dd0 * r0);
                    float r1 = __int_as_float(0x7EF311C3 - __float_as_int(dd1));
                    r1 = r1 * (2.f - dd1 * r1); r1 = r1 * (2.f - dd1 * r1);
                    sl0 = d[0] * r0 * d[1];
                    sl1 = d[2] * r1 * d[3];
                }
                Ch[(size_t)row0 * ldc + j] = __float2half_rn(sl0);
                Ch[(size_t)row1 * ldc + j] = __float2half_rn(sl1);
            }
        }
    }
}

// ----- HMMA flash attention (QK 3-term, PV 1-term, base-2 softmax) ------------
#define ATB (64*144)
#define ATT_SMEM (8*ATB)     // Qh,Ql + 2 stages x (Kh,Kl,Vh)
__global__ __launch_bounds__(128, 2)
void attn_mma_kernel(const __half* __restrict__ Xh,
                     const __half* __restrict__ Xl,
                     __half* __restrict__ Oh) {
    extern __shared__ char sm[];
    const uint32_t sQh = smem_to_u32(sm);
    const uint32_t sQl = sQh + ATB;
    const uint32_t sSt = sQh + 2*ATB;

    const int tid = threadIdx.x, lane = tid & 31, warp = tid >> 5;
    const int bh = blockIdx.y, b = bh >> 4, h = bh & (NH-1);
    const int qt = gridDim.x - 1 - blockIdx.x;
    const int q0 = qt * 64;
    const size_t rowbase = (size_t)b * SS * LDX;
    const int colQ = h*DH, colK = 1024 + h*DH, colV = 2048 + h*DH;

    #pragma unroll
    for (int i = 0; i < 4; i++) {
        const int idx = tid + i*128;
        const int r = idx >> 3, c = idx & 7;
        const uint32_t so = (uint32_t)(r*144 + c*16);
        const size_t ga = rowbase + (size_t)(q0 + r)*LDX + colQ + c*8;
        CP_ASYNC16(sQh + so, (const char*)(Xh + ga));
        CP_ASYNC16(sQl + so, (const char*)(Xl + ga));
    }
    CP_COMMIT();

    auto load_kv = [&](int t, int s) {
        const int k0 = t * 64;
        #pragma unroll
        for (int i = 0; i < 4; i++) {
            const int idx = tid + i*128;
            const int r = idx >> 3, c = idx & 7;
            const uint32_t so = (uint32_t)s*3*ATB + (uint32_t)(r*144 + c*16);
            const size_t gk = rowbase + (size_t)(k0 + r)*LDX + colK + c*8;
            const size_t gv = rowbase + (size_t)(k0 + r)*LDX + colV + c*8;
            CP_ASYNC16(sSt + so,         (const char*)(Xh + gk));
            CP_ASYNC16(sSt + ATB + so,   (const char*)(Xl + gk));
            CP_ASYNC16(sSt + 2*ATB + so, (const char*)(Xh + gv));
        }
        CP_COMMIT();
    };
    load_kv(0, 0);

    const int g = lane >> 3, rr = lane & 7;
    const uint32_t aoff = (uint32_t)((warp*16 + (g&1)*8 + rr)*144 + (g>>1)*16);
    const uint32_t boff = (uint32_t)(((g>>1)*8 + rr)*144 + (g&1)*16);
    const uint32_t voff = (uint32_t)(((g&1)*8 + rr)*144 + (lane>>4)*16);

    float m0 = -CUDART_INF_F, m1 = -CUDART_INF_F, l0 = 0.f, l1 = 0.f;
    float o[8][4];
    #pragma unroll
    for (int j = 0; j < 8; j++)
        #pragma unroll
        for (int q = 0; q < 4; q++) o[j][q] = 0.f;

    const int r0g = q0 + warp*16 + (lane >> 2);
    const int r1g = r0g + 8;
    const int ntiles = qt + 1;

    for (int t = 0; t < ntiles; t++) {
        CP_WAIT0();
        __syncthreads();
        if (t + 1 < ntiles) load_kv(t + 1, (t + 1) & 1);

        const uint32_t sK  = sSt + (uint32_t)(t & 1)*3*ATB;
        const uint32_t sKl = sK + ATB;
        const uint32_t sV  = sK + 2*ATB;

        float s[8][4];
        #pragma unroll
        for (int j = 0; j < 8; j++)
            #pragma unroll
            for (int q = 0; q < 4; q++) s[j][q] = 0.f;

        #pragma unroll
        for (int d = 0; d < 4; d++) {
            uint32_t qh[4], ql[4];
            LDSM4(qh, sQh + aoff + d*32);
            LDSM4(ql, sQl + aoff + d*32);
            #pragma unroll
            for (int nb = 0; nb < 4; nb++) {
                uint32_t kh[4], kl[4];
                LDSM4(kh, sK  + boff + (uint32_t)(nb*16*144) + d*32);
                LDSM4(kl, sKl + boff + (uint32_t)(nb*16*144) + d*32);
                #pragma unroll
                for (int f = 0; f < 2; f++) {
                    float* dd = s[nb*2 + f];
                    MMA16816(dd, qh, kh[2*f], kh[2*f+1]);
                    MMA16816(dd, qh, kl[2*f], kl[2*f+1]);
                    MMA16816(dd, ql, kh[2*f], kh[2*f+1]);
                }
            }
        }

        // scores already in log2 domain (Q pre-scaled by 0.125*log2e)
        const int k0 = t * 64;
        float mx0 = -CUDART_INF_F, mx1 = -CUDART_INF_F;
        #pragma unroll
        for (int j = 0; j < 8; j++) {
            if (t == qt) {
                const int c = k0 + j*8 + (lane & 3)*2;
                if (c     > r0g) s[j][0] = -CUDART_INF_F;
                if (c + 1 > r0g) s[j][1] = -CUDART_INF_F;
                if (c     > r1g) s[j][2] = -CUDART_INF_F;
                if (c + 1 > r1g) s[j][3] = -CUDART_INF_F;
            }
            mx0 = fmaxf(mx0, fmaxf(s[j][0], s[j][1]));
            mx1 = fmaxf(mx1, fmaxf(s[j][2], s[j][3]));
        }
        mx0 = fmaxf(mx0, __shfl_xor_sync(0xffffffffu, mx0, 1));
        mx0 = fmaxf(mx0, __shfl_xor_sync(0xffffffffu, mx0, 2));
        mx1 = fmaxf(mx1, __shfl_xor_sync(0xffffffffu, mx1, 1));
        mx1 = fmaxf(mx1, __shfl_xor_sync(0xffffffffu, mx1, 2));
        const float mn0 = fmaxf(m0, mx0), mn1 = fmaxf(m1, mx1);
        const float cr0 = ex2(m0 - mn0), cr1 = ex2(m1 - mn1);
        m0 = mn0; m1 = mn1;

        float sum0 = 0.f, sum1 = 0.f;
        #pragma unroll
        for (int j = 0; j < 8; j++) {
            if (j < 5) {     // MUFU path
                s[j][0] = ex2(s[j][0] - mn0); s[j][1] = ex2(s[j][1] - mn0);
                s[j][2] = ex2(s[j][2] - mn1); s[j][3] = ex2(s[j][3] - mn1);
            } else {         // FMA-pipe path
                s[j][0] = fast_exp2(s[j][0] - mn0); s[j][1] = fast_exp2(s[j][1] - mn0);
                s[j][2] = fast_exp2(s[j][2] - mn1); s[j][3] = fast_exp2(s[j][3] - mn1);
            }
            sum0 += s[j][0] + s[j][1];
            sum1 += s[j][2] + s[j][3];
        }
        sum0 += __shfl_xor_sync(0xffffffffu, sum0, 1);
        sum0 += __shfl_xor_sync(0xffffffffu, sum0, 2);
        sum1 += __shfl_xor_sync(0xffffffffu, sum1, 1);
        sum1 += __shfl_xor_sync(0xffffffffu, sum1, 2);
        l0 = l0 * cr0 + sum0;
        l1 = l1 * cr1 + sum1;
        #pragma unroll
        for (int j = 0; j < 8; j++) {
            o[j][0] *= cr0; o[j][1] *= cr0;
            o[j][2] *= cr1; o[j][3] *= cr1;
        }

        // ---- O += P V (P fp16 hi only; 1-term PV) ----
        #pragma unroll
        for (int kt = 0; kt < 4; kt++) {
            uint32_t ph[4];
            #pragma unroll
            for (int u = 0; u < 4; u++) {
                const int jj = 2*kt + (u >> 1);
                __half2 hh = __floats2half2_rn(s[jj][(u & 1)*2], s[jj][(u & 1)*2 + 1]);
                ph[u] = *(uint32_t*)&hh;
            }
            #pragma unroll
            for (int nb = 0; nb < 4; nb++) {
                uint32_t vh[4];
                const uint32_t va = voff + (uint32_t)(kt*16*144) + (uint32_t)(nb*32);
                LDSM4T(vh, sV + va);
                #pragma unroll
                for (int f = 0; f < 2; f++) {
                    float* dd = o[nb*2 + f];
                    MMA16816(dd, ph, vh[2*f], vh[2*f+1]);
                }
            }
        }
    }

    const float inv0 = 1.0f / l0, inv1 = 1.0f / l1;
    const size_t tok0 = (size_t)b * SS + r0g;
    const size_t tok1 = tok0 + 8;
    #pragma unroll
    for (int j = 0; j < 8; j++) {
        const int col = h*DH + j*8 + (lane & 3)*2;
        __half2 h0 = __floats2half2_rn(o[j][0]*inv0, o[j][1]*inv0);
        __half2 h1 = __floats2half2_rn(o[j][2]*inv1, o[j][3]*inv1);
        *(__half2*)(Oh + tok0*DM + col) = h0;
        *(__half2*)(Oh + tok1*DM + col) = h1;
    }
}

// ---------------- launch ----------------
extern "C" void kernel_launch(void* const* d_in, const int* in_sizes, int n_in,
                              void* d_out, int out_size) {
    const float* x   = (const float*)d_in[0];
    const int*   pos = (const int*)  d_in[1];
    const float* qw  = (const float*)d_in[2];
    const float* kw  = (const float*)d_in[3];
    const float* vw  = (const float*)d_in[4];
    const float* ow  = (const float*)d_in[5];
    const float* g1  = (const float*)d_in[6];
    const float* g2  = (const float*)d_in[7];
    const float* w1  = (const float*)d_in[8];
    const float* w2  = (const float*)d_in[9];
    const float* w3  = (const float*)d_in[10];
    float* out = (float*)d_out;

    __half *xnh, *xnl, *qkvh, *qkvl, *ath, *hnh, *swh;
    __half *wqkh, *wqkl, *vwh, *owh, *w13h, *w2h;
    float *res1;
    cudaGetSymbolAddress((void**)&xnh, g_xn_h);   cudaGetSymbolAddress((void**)&xnl, g_xn_l);
    cudaGetSymbolAddress((void**)&qkvh, g_qkv_h); cudaGetSymbolAddress((void**)&qkvl, g_qkv_l);
    cudaGetSymbolAddress((void**)&ath, g_at_h);
    cudaGetSymbolAddress((void**)&res1, g_res1);
    cudaGetSymbolAddress((void**)&hnh, g_hn_h);
    cudaGetSymbolAddress((void**)&swh, g_sw_h);
    cudaGetSymbolAddress((void**)&wqkh, g_wqk_h); cudaGetSymbolAddress((void**)&wqkl, g_wqk_l);
    cudaGetSymbolAddress((void**)&vwh, g_vw_h);
    cudaGetSymbolAddress((void**)&owh, g_ow_h);
    cudaGetSymbolAddress((void**)&w13h, g_w13_h);
    cudaGetSymbolAddress((void**)&w2h, g_w2_h);

    const int SMQ = 2 * (int)QSTG;                // 81920   (3-term QK v2)
    const int SMS = 2 * 256 * ROWB;               // 73728   (1-term small)
    cudaFuncSetAttribute((const void*)gemm_qk_fp16x3,      cudaFuncAttributeMaxDynamicSharedMemorySize, SMQ);
    cudaFuncSetAttribute((const void*)gemm1_mma_fp16<0>,   cudaFuncAttributeMaxDynamicSharedMemorySize, SMS);
    cudaFuncSetAttribute((const void*)gemm1_mma_fp16<2>,   cudaFuncAttributeMaxDynamicSharedMemorySize, SMS);
    cudaFuncSetAttribute((const void*)gemm1_mma_fp16<3>,   cudaFuncAttributeMaxDynamicSharedMemorySize, SMS);
    cudaFuncSetAttribute((const void*)attn_mma_kernel,     cudaFuncAttributeMaxDynamicSharedMemorySize, ATT_SMEM);

    // 0: rope table
    rope_table_kernel<<<SS, 32>>>(pos);

    // 1: all weight conversions in one launch
    prep_weights_kernel<<<(4*Q4 + 3*W4)/256, 256>>>(
        qw, kw, vw, ow, w1, w3, w2, wqkh, wqkl, vwh, owh, w13h, w2h);

    // 2: rmsnorm(x) -> split
    rmsnorm_split_kernel<<<MTOK, 256>>>(x, g1, xnh, xnl);

    // 3: QK projection (3-term, BK=32, 2 CTA/SM) + rope + Qscale + split
    gemm_qk_fp16x3<<<dim3(2048/128, MTOK/128), 256, SMQ>>>(
        xnh, xnl, wqkh, wqkl, qkvh, qkvl, 2048, DM, LDX);

    // 4: V projection (1-term) hi-only  [8192,1024] -> qkv cols 2048..3071
    gemm1_mma_fp16<3><<<dim3(DM/128, MTOK/128), 256, SMS>>>(
        xnh, vwh, nullptr, nullptr, qkvh + 2048, DM, DM, LDX);

    // 5: HMMA flash attention (PV 1-term) -> fp16 hi
    attn_mma_kernel<<<dim3(SS/64, BB*NH), 128, ATT_SMEM>>>(qkvh, qkvl, ath);

    // 6: O projection (1-term) + residual(x) -> res1 fp32
    gemm1_mma_fp16<0><<<dim3(DM/128, MTOK/128), 256, SMS>>>(
        ath, owh, x, res1, nullptr, DM, DM, DM);

    // 7: rmsnorm(res1) -> hi only
    rmsnorm_h_kernel<<<MTOK, 256>>>(res1, g2, hnh);

    // 8: fused W1||W3 (1-term, interleaved) + swiglu -> sw hi
    gemm1_mma_fp16<2><<<dim3(2*DFF/128, MTOK/128), 256, SMS>>>(
        hnh, w13h, nullptr, nullptr, swh, 2*DFF, DM, DFF);

    // 9: down projection (1-term) + residual(res1) -> out
    gemm1_mma_fp16<0><<<dim3(DM/128, MTOK/128), 256, SMS>>>(
        swh, w2h, res1, out, nullptr, DM, DFF, DM);
}

// round 15
// speedup vs baseline: 7.7161x; 1.0004x over previous
#include <cuda_runtime.h>
#include <cuda_fp16.h>
#include <math.h>
#include <math_constants.h>
#include <cstdint>

#define BB   4
#define SS   2048
#define DM   1024
#define NH   16
#define DH   64
#define DFF  4096
#define MTOK (BB*SS)      // 8192
#define LDX  3072

// ---------------- helpers ----------------
__device__ __forceinline__ uint32_t smem_to_u32(const void* p) {
    uint32_t a;
    asm("{ .reg .u64 t; cvta.to.shared.u64 t, %1; cvt.u32.u64 %0, t; }" : "=r"(a) : "l"(p));
    return a;
}
#define CP_ASYNC16(s, g) asm volatile("cp.async.cg.shared.global [%0], [%1], 16;" :: "r"(s), "l"(g))
#define CP_COMMIT()      asm volatile("cp.async.commit_group;" ::: "memory")
#define CP_WAIT0()       asm volatile("cp.async.wait_group 0;" ::: "memory")
#define LDSM4(rg, addr) \
    asm volatile("ldmatrix.sync.aligned.m8n8.x4.shared.b16 {%0,%1,%2,%3}, [%4];" \
        : "=r"((rg)[0]), "=r"((rg)[1]), "=r"((rg)[2]), "=r"((rg)[3]) : "r"(addr))
#define LDSM4T(rg, addr) \
    asm volatile("ldmatrix.sync.aligned.m8n8.x4.trans.shared.b16 {%0,%1,%2,%3}, [%4];" \
        : "=r"((rg)[0]), "=r"((rg)[1]), "=r"((rg)[2]), "=r"((rg)[3]) : "r"(addr))
#define MMA16816(d, a, b0v, b1v) \
    asm volatile("mma.sync.aligned.m16n8k16.row.col.f32.f16.f16.f32 " \
        "{%0,%1,%2,%3}, {%4,%5,%6,%7}, {%8,%9}, {%0,%1,%2,%3};" \
        : "+f"((d)[0]), "+f"((d)[1]), "+f"((d)[2]), "+f"((d)[3]) \
        : "r"((a)[0]), "r"((a)[1]), "r"((a)[2]), "r"((a)[3]), "r"(b0v), "r"(b1v))

__device__ __forceinline__ float ex2(float x) {
    float r; asm("ex2.approx.f32 %0, %1;" : "=f"(r) : "f"(x)); return r;
}
__device__ __forceinline__ float rcpa(float x) {
    float r; asm("rcp.approx.f32 %0, %1;" : "=f"(r) : "f"(x)); return r;
}
// 2^y on the FMA pipe (magic round + deg-5 Taylor), rel err ~2e-6
__device__ __forceinline__ float fast_exp2(float y) {
    y = fmaxf(fminf(y, 126.f), -126.f);
    float z = __fadd_rn(y, 12582912.f);
    int   n = __float_as_int(z) - 0x4B400000;
    float f = __fadd_rn(y, -__fadd_rn(z, -12582912.f));
    float p = fmaf(f, 0.0013333558f, 0.0096181291f);
    p = fmaf(f, p, 0.0555041087f);
    p = fmaf(f, p, 0.2402265069f);
    p = fmaf(f, p, 0.6931471806f);
    p = fmaf(f, p, 1.0f);
    return __int_as_float(__float_as_int(p) + (n << 23));
}
// pack (p0,p1) -> f16x2 hi + f16x2 lo residual
__device__ __forceinline__ void split_pack2(float p0, float p1, uint32_t& h2, uint32_t& l2) {
    __half2 h = __floats2half2_rn(p0, p1);
    float2 hf = __half22float2(h);
    __half2 l = __floats2half2_rn(__fadd_rn(p0, -hf.x), __fadd_rn(p1, -hf.y));
    h2 = *(uint32_t*)&h;
    l2 = *(uint32_t*)&l;
}

// ---------------- scratch (__device__ globals) ----------------
static __device__ __half g_xn_h[(size_t)MTOK*DM],  g_xn_l[(size_t)MTOK*DM];
static __device__ __half g_qkv_h[(size_t)MTOK*LDX], g_qkv_l[(size_t)MTOK*LDX];
static __device__ __half g_at_h[(size_t)MTOK*DM];
static __device__ float  g_res1[(size_t)MTOK*DM];
static __device__ __half g_hn_h[(size_t)MTOK*DM];
static __device__ __half g_sw_h[(size_t)MTOK*DFF];
static __device__ __half g_wqk_h[2048*1024], g_wqk_l[2048*1024];
static __device__ __half g_vw_h [1024*1024];
static __device__ __half g_ow_h [1024*1024];
static __device__ __half g_w13_h[2*DFF*1024];   // interleaved rows
static __device__ __half g_w2_h [1024*DFF];
static __device__ float g_cs[SS*32], g_sn[SS*32];

__global__ void rope_table_kernel(const int* __restrict__ pos) {
    const int s = blockIdx.x, i = threadIdx.x;   // 2048 x 32
    const float inv = exp2f(-(float)i * (13.287712379549449f / 32.0f));
    const float a = (float)pos[s] * inv;
    float sn, cs;
    sincosf(a, &sn, &cs);
    g_cs[s*32 + i] = cs;
    g_sn[s*32 + i] = sn;
}

// ------------- merged weight prep: one launch for all 7 weight tensors --------
#define Q4 262144          // (1024*1024)/4
#define W4 1048576         // (4096*1024)/4
__global__ void prep_weights_kernel(const float* __restrict__ qw,
                                    const float* __restrict__ kw,
                                    const float* __restrict__ vw,
                                    const float* __restrict__ ow,
                                    const float* __restrict__ w1,
                                    const float* __restrict__ w3,
                                    const float* __restrict__ w2,
                                    __half* __restrict__ wqkh,
                                    __half* __restrict__ wqkl,
                                    __half* __restrict__ vwh,
                                    __half* __restrict__ owh,
                                    __half* __restrict__ w13h,
                                    __half* __restrict__ w2h) {
    const int i = blockIdx.x * blockDim.x + threadIdx.x;
    if (i < 2*Q4) {                        // qw | kw -> hi+lo split
        const int j = (i < Q4) ? i : i - Q4;
        const float4 v = (i < Q4) ? ((const float4*)qw)[j] : ((const float4*)kw)[j];
        uint32_t h0, l0, h1, l1;
        split_pack2(v.x, v.y, h0, l0);
        split_pack2(v.z, v.w, h1, l1);
        const uint32_t base = ((i < Q4) ? 0u : (1024u*1024u/2u)) + 2u*(uint32_t)j;
        ((uint32_t*)wqkh)[base] = h0; ((uint32_t*)wqkh)[base+1] = h1;
        ((uint32_t*)wqkl)[base] = l0; ((uint32_t*)wqkl)[base+1] = l1;
    } else if (i < 4*Q4) {                 // vw | ow -> hi only
        const int j = (i < 3*Q4) ? i - 2*Q4 : i - 3*Q4;
        const float4 v = (i < 3*Q4) ? ((const float4*)vw)[j] : ((const float4*)ow)[j];
        __half* dst = (i < 3*Q4) ? vwh : owh;
        ((__half2*)dst)[2*j]   = __floats2half2_rn(v.x, v.y);
        ((__half2*)dst)[2*j+1] = __floats2half2_rn(v.z, v.w);
    } else if (i < 4*Q4 + 2*W4) {          // w1 | w3 -> interleaved hi
        const int off = (i < 4*Q4 + W4) ? 0 : 1;
        const int j = i - 4*Q4 - off*W4;
        const float4 v = off ? ((const float4*)w3)[j] : ((const float4*)w1)[j];
        const int row = j >> 8, c4 = j & 255;
        const size_t o2 = ((size_t)(2*row + off) * 1024 + c4*4) >> 1;
        ((__half2*)w13h)[o2]   = __floats2half2_rn(v.x, v.y);
        ((__half2*)w13h)[o2+1] = __floats2half2_rn(v.z, v.w);
    } else {                               // w2 -> hi only
        const int j = i - 4*Q4 - 2*W4;
        const float4 v = ((const float4*)w2)[j];
        ((__half2*)w2h)[2*j]   = __floats2half2_rn(v.x, v.y);
        ((__half2*)w2h)[2*j+1] = __floats2half2_rn(v.z, v.w);
    }
}

// ---------------- RMSNorm -> split fp16 (hi+lo) ----------------
__global__ void rmsnorm_split_kernel(const float* __restrict__ x,
                                     const float* __restrict__ g,
                                     __half* __restrict__ yh,
                                     __half* __restrict__ yl) {
    const int row = blockIdx.x;
    const float4* xr = (const float4*)(x + (size_t)row * DM);
    const int t = threadIdx.x;
    float4 xv = xr[t];
    float ss = xv.x*xv.x + xv.y*xv.y + xv.z*xv.z + xv.w*xv.w;
    #pragma unroll
    for (int o = 16; o; o >>= 1) ss += __shfl_xor_sync(0xffffffffu, ss, o);
    __shared__ float sred[8];
    const int warp = t >> 5, lane = t & 31;
    if (lane == 0) sred[warp] = ss;
    __syncthreads();
    if (warp == 0) {
        float v = (lane < 8) ? sred[lane] : 0.f;
        #pragma unroll
        for (int o = 4; o; o >>= 1) v += __shfl_xor_sync(0xffffffffu, v, o);
        if (lane == 0) sred[0] = v;
    }
    __syncthreads();
    const float inv = rsqrtf(sred[0] * (1.0f/(float)DM) + 1e-5f);
    const float4 gv = ((const float4*)g)[t];
    uint32_t h0, l0, h1, l1;
    split_pack2(xv.x*inv*gv.x, xv.y*inv*gv.y, h0, l0);
    split_pack2(xv.z*inv*gv.z, xv.w*inv*gv.w, h1, l1);
    const size_t b2 = (size_t)row * (DM/2) + 2*t;
    ((uint32_t*)yh)[b2]   = h0; ((uint32_t*)yh)[b2+1] = h1;
    ((uint32_t*)yl)[b2]   = l0; ((uint32_t*)yl)[b2+1] = l1;
}

// ---------------- RMSNorm -> fp16 hi only ----------------
__global__ void rmsnorm_h_kernel(const float* __restrict__ x,
                                 const float* __restrict__ g,
                                 __half* __restrict__ yh) {
    const int row = blockIdx.x;
    const float4* xr = (const float4*)(x + (size_t)row * DM);
    const int t = threadIdx.x;
    float4 xv = xr[t];
    float ss = xv.x*xv.x + xv.y*xv.y + xv.z*xv.z + xv.w*xv.w;
    #pragma unroll
    for (int o = 16; o; o >>= 1) ss += __shfl_xor_sync(0xffffffffu, ss, o);
    __shared__ float sred[8];
    const int warp = t >> 5, lane = t & 31;
    if (lane == 0) sred[warp] = ss;
    __syncthreads();
    if (warp == 0) {
        float v = (lane < 8) ? sred[lane] : 0.f;
        #pragma unroll
        for (int o = 4; o; o >>= 1) v += __shfl_xor_sync(0xffffffffu, v, o);
        if (lane == 0) sred[0] = v;
    }
    __syncthreads();
    const float inv = rsqrtf(sred[0] * (1.0f/(float)DM) + 1e-5f);
    const float4 gv = ((const float4*)g)[t];
    const size_t b2 = (size_t)row * (DM/2) + 2*t;
    ((__half2*)yh)[b2]   = __floats2half2_rn(xv.x*inv*gv.x, xv.y*inv*gv.y);
    ((__half2*)yh)[b2+1] = __floats2half2_rn(xv.z*inv*gv.z, xv.w*inv*gv.w);
}

#define ROWB    144
#define QSCALE  0.18033688f      // 0.125 * log2(e)

// -------- QK 3-term GEMM v2: CTA 128x128, warp 32x64, BK=32, 2 CTAs/SM --------
#define QROWB 80                 // 32 halfs + 16B pad
#define QAL   (128u*QROWB)       // A-lo offset
#define QBH   (2u*128u*QROWB)    // B-hi
#define QBL   (3u*128u*QROWB)    // B-lo
#define QSTG  (4u*128u*QROWB)    // 40960 per stage
__global__ __launch_bounds__(256, 2)
void gemm_qk_fp16x3(const __half* __restrict__ Ah,
                    const __half* __restrict__ Al,
                    const __half* __restrict__ Bh,
                    const __half* __restrict__ Bl,
                    __half* __restrict__ Ch,
                    __half* __restrict__ Cl,
                    int N, int K, int ldc) {
    extern __shared__ char smem[];
    const uint32_t sbase = smem_to_u32(smem);
    const int tid  = threadIdx.x;
    const int lane = tid & 31;
    const int wid  = tid >> 5;
    const int bm = blockIdx.y * 128;
    const int bn = blockIdx.x * 128;
    const int m0w = (wid & 3) * 32;
    const int n0w = (wid >> 2) * 64;

    float acc[2][8][4];
    #pragma unroll
    for (int i = 0; i < 2; i++)
        #pragma unroll
        for (int j = 0; j < 8; j++)
            #pragma unroll
            for (int q = 0; q < 4; q++) acc[i][j][q] = 0.f;

    const int nch = K >> 5;   // BK=32

    auto load_stage = [&](int s, int c) {
        const int k0 = c << 5;
        const uint32_t st = sbase + (uint32_t)s * QSTG;
        #pragma unroll
        for (int i = 0; i < 2; ++i) {
            const int idx = tid + (i << 8);          // 0..511
            const int row = idx >> 2, cc = idx & 3;
            const uint32_t so = (uint32_t)(row * QROWB + cc * 16);
            const size_t ga = (size_t)(bm + row) * K + k0 + cc * 8;
            const size_t gb = (size_t)(bn + row) * K + k0 + cc * 8;
            CP_ASYNC16(st + so,       (const char*)(Ah + ga));
            CP_ASYNC16(st + QAL + so, (const char*)(Al + ga));
            CP_ASYNC16(st + QBH + so, (const char*)(Bh + gb));
            CP_ASYNC16(st + QBL + so, (const char*)(Bl + gb));
        }
        CP_COMMIT();
    };

    const int g = lane >> 3, r = lane & 7;
    const uint32_t aoff = (uint32_t)((m0w + (g & 1) * 8 + r) * QROWB + ((g >> 1) * 8) * 2);
    const uint32_t boff = QBH + (uint32_t)((n0w + (g >> 1) * 8 + r) * QROWB + ((g & 1) * 8) * 2);

    load_stage(0, 0);

    for (int c = 0; c < nch; ++c) {
        CP_WAIT0();
        __syncthreads();
        if (c + 1 < nch) load_stage((c + 1) & 1, c + 1);

        const uint32_t st = sbase + (uint32_t)(c & 1) * QSTG;
        #pragma unroll
        for (int ks = 0; ks < 2; ++ks) {
            uint32_t AhF[2][4], AlF[2][4];
            const uint32_t ab = st + aoff + (uint32_t)(ks * 32);
            #pragma unroll
            for (int mi = 0; mi < 2; ++mi) {
                LDSM4(AhF[mi], ab + (uint32_t)(mi * 16 * QROWB));
                LDSM4(AlF[mi], ab + QAL + (uint32_t)(mi * 16 * QROWB));
            }
            const uint32_t bb = st + boff + (uint32_t)(ks * 32);
            #pragma unroll
            for (int nb = 0; nb < 4; ++nb) {
                uint32_t BhF[4], BlF[4];
                LDSM4(BhF, bb + (uint32_t)(nb * 16 * QROWB));
                LDSM4(BlF, bb + (QBL - QBH) + (uint32_t)(nb * 16 * QROWB));
                #pragma unroll
                for (int mi = 0; mi < 2; ++mi)
                    #pragma unroll
                    for (int hf = 0; hf < 2; ++hf) {
                        float* d = acc[mi][nb * 2 + hf];
                        MMA16816(d, AhF[mi], BhF[hf*2], BhF[hf*2+1]);
                        MMA16816(d, AlF[mi], BhF[hf*2], BhF[hf*2+1]);
                        MMA16816(d, AhF[mi], BlF[hf*2], BlF[hf*2+1]);
                    }
            }
        }
    }

    const int erow = lane >> 2;
    const int ecol = (lane & 3) * 2;
    #pragma unroll
    for (int mi = 0; mi < 2; ++mi) {
        #pragma unroll
        for (int nj = 0; nj < 8; ++nj) {
            float* d = acc[mi][nj];
            const int row0 = bm + m0w + mi * 16 + erow;
            const int row1 = row0 + 8;
            const int cg   = bn + n0w + nj * 8 + ecol;
            float a0 = d[0], a1 = d[1], b0 = d[2], b1 = d[3];
            {
                const int i = (cg & 63) >> 1;
                const int s0 = (row0 & (SS-1))*32 + i;
                const int s1 = (row1 & (SS-1))*32 + i;
                const float c0 = g_cs[s0], n0 = g_sn[s0];
                const float c1 = g_cs[s1], n1 = g_sn[s1];
                float t0 = a0*c0 - a1*n0, t1 = a0*n0 + a1*c0;
                a0 = t0; a1 = t1;
                float u0 = b0*c1 - b1*n1, u1 = b0*n1 + b1*c1;
                b0 = u0; b1 = u1;
            }
            if (cg < 1024) {
                a0 *= QSCALE; a1 *= QSCALE; b0 *= QSCALE; b1 *= QSCALE;
            }
            uint32_t h0, l0, h1, l1;
            split_pack2(a0, a1, h0, l0);
            split_pack2(b0, b1, h1, l1);
            const size_t o0 = (size_t)row0 * ldc + cg;
            const size_t o1 = (size_t)row1 * ldc + cg;
            *(uint32_t*)(Ch + o0) = h0;
            *(uint32_t*)(Cl + o0) = l0;
            *(uint32_t*)(Ch + o1) = h1;
            *(uint32_t*)(Cl + o1) = l1;
        }
    }
}

// -------- SMALL 1-term GEMM: CTA 128x128, warp 32x64, 2 CTAs/SM ---------------
// MODE 0: C fp32 (+R). MODE 2: swiglu -> Ch. MODE 3: hi-only -> Ch.
template<int MODE>
__global__ __launch_bounds__(256, 2)
void gemm1_mma_fp16(const __half* __restrict__ Ah,
                    const __half* __restrict__ Bh,
                    const float* __restrict__ R,
                    float* __restrict__ C,
                    __half* __restrict__ Ch,
                    int N, int K, int ldc) {
    constexpr uint32_t B_OFFC = 128u * ROWB;
    constexpr uint32_t STG = 256u * ROWB;          // 36864
    extern __shared__ char smem[];
    const uint32_t sbase = smem_to_u32(smem);
    const int tid  = threadIdx.x;
    const int lane = tid & 31;
    const int wid  = tid >> 5;
    const int bm = blockIdx.y * 128;
    const int bn = blockIdx.x * 128;
    const int m0w = (wid & 3) * 32;
    const int n0w = (wid >> 2) * 64;

    float acc[2][8][4];
    #pragma unroll
    for (int i = 0; i < 2; i++)
        #pragma unroll
        for (int j = 0; j < 8; j++)
            #pragma unroll
            for (int q = 0; q < 4; q++) acc[i][j][q] = 0.f;

    const int nch = K >> 6;

    auto load_stage = [&](int s, int c) {
        const int k0 = c << 6;
        const uint32_t st = sbase + (uint32_t)s * STG;
        #pragma unroll
        for (int i = 0; i < 4; ++i) {
            const int idx = tid + (i << 8);
            const int row = idx >> 3, cc = idx & 7;
            const uint32_t so = (uint32_t)(row * ROWB + cc * 16);
            const size_t ga = (size_t)(bm + row) * K + k0 + cc * 8;
            CP_ASYNC16(st + so, (const char*)(Ah + ga));
        }
        #pragma unroll
        for (int i = 0; i < 4; ++i) {
            const int idx = tid + (i << 8);
            const int row = idx >> 3, cc = idx & 7;
            const uint32_t so = (uint32_t)(row * ROWB + cc * 16);
            const size_t gb = (size_t)(bn + row) * K + k0 + cc * 8;
            CP_ASYNC16(st + B_OFFC + so, (const char*)(Bh + gb));
        }
        CP_COMMIT();
    };

    const int g = lane >> 3, r = lane & 7;
    const uint32_t aoff = (uint32_t)((m0w + (g & 1) * 8 + r) * ROWB + ((g >> 1) * 8) * 2);
    const uint32_t boff = B_OFFC + (uint32_t)((n0w + (g >> 1) * 8 + r) * ROWB + ((g & 1) * 8) * 2);

    load_stage(0, 0);

    for (int c = 0; c < nch; ++c) {
        CP_WAIT0();
        __syncthreads();
        if (c + 1 < nch) load_stage((c + 1) & 1, c + 1);

        const uint32_t st = sbase + (uint32_t)(c & 1) * STG;
        #pragma unroll
        for (int ks = 0; ks < 4; ++ks) {
            uint32_t AhF[2][4];
            const uint32_t ab = st + aoff + (uint32_t)(ks * 32);
            #pragma unroll
            for (int mi = 0; mi < 2; ++mi)
                LDSM4(AhF[mi], ab + (uint32_t)(mi * 16 * ROWB));
            const uint32_t bb = st + boff + (uint32_t)(ks * 32);
            #pragma unroll
            for (int nb = 0; nb < 4; ++nb) {
                uint32_t BhF[4];
                LDSM4(BhF, bb + (uint32_t)(nb * 16 * ROWB));
                #pragma unroll
                for (int mi = 0; mi < 2; ++mi)
                    #pragma unroll
                    for (int hf = 0; hf < 2; ++hf)
                        MMA16816(acc[mi][nb * 2 + hf], AhF[mi], BhF[hf*2], BhF[hf*2+1]);
            }
        }
    }

    const int erow = lane >> 2;
    const int ecol = (lane & 3) * 2;
    #pragma unroll
    for (int mi = 0; mi < 2; ++mi) {
        #pragma unroll
        for (int nj = 0; nj < 8; ++nj) {
            float* d = acc[mi][nj];
            const int row0 = bm + m0w + mi * 16 + erow;
            const int row1 = row0 + 8;
            const int cg   = bn + n0w + nj * 8 + ecol;
            if (MODE == 0) {
                const size_t o0 = (size_t)row0 * ldc + cg;
                const size_t o1 = (size_t)row1 * ldc + cg;
                float2 v0 = make_float2(d[0], d[1]);
                float2 v1 = make_float2(d[2], d[3]);
                if (R) {
                    const float2 r0 = *(const float2*)(R + o0);
                    const float2 r1 = *(const float2*)(R + o1);
                    v0.x += r0.x; v0.y += r0.y;
                    v1.x += r1.x; v1.y += r1.y;
                }
                *(float2*)(C + o0) = v0;
                *(float2*)(C + o1) = v1;
            } else if (MODE == 3) {
                const size_t o0 = (size_t)row0 * ldc + cg;
                const size_t o1 = (size_t)row1 * ldc + cg;
                *(__half2*)(Ch + o0) = __floats2half2_rn(d[0], d[1]);
                *(__half2*)(Ch + o1) = __floats2half2_rn(d[2], d[3]);
            } else {  // MODE 2: swiglu
                const int j = cg >> 1;
                float sl0, sl1;
                if (nj < 3) {
                    const float e0 = ex2(-1.44269504f * d[0]);
                    const float e1 = ex2(-1.44269504f * d[2]);
                    const float dd0 = 1.f + e0, dd1 = 1.f + e1;
                    float r0 = rcpa(dd0); r0 = r0 * (2.f - dd0 * r0);
                    float r1 = rcpa(dd1); r1 = r1 * (2.f - dd1 * r1);
                    sl0 = d[0] * r0 * d[1];
                    sl1 = d[2] * r1 * d[3];
                } else {
                    const float e0 = fast_exp2(-1.44269504f * d[0]);
                    const float e1 = fast_exp2(-1.44269504f * d[2]);
                    const float dd0 = 1.f + e0, dd1 = 1.f + e1;
                    float r0 = __int_as_float(0x7EF311C3 - __float_as_int(dd0));
                    r0 = r0 * (2.f - dd0 * r0); r0 = r0 * (2.f - dd0 * r0);
                    float r1 = __int_as_float(0x7EF311C3 - __float_as_int(dd1));
                    r1 = r1 * (2.f - dd1 * r1); r1 = r1 * (2.f - dd1 * r1);
                    sl0 = d[0] * r0 * d[1];
                    sl1 = d[2] * r1 * d[3];
                }
                Ch[(size_t)row0 * ldc + j] = __float2half_rn(sl0);
                Ch[(size_t)row1 * ldc + j] = __float2half_rn(sl1);
            }
        }
    }
}

// ----- HMMA flash attention (QK 3-term, PV 1-term), 3 CTAs/SM -----------------
#define ATB (64*144)
#define ATT_SMEM (8*ATB)     // Qh,Ql + 2 stages x (Kh,Kl,Vh) = 73728
__global__ __launch_bounds__(128, 3)
void attn_mma_kernel(const __half* __restrict__ Xh,
                     const __half* __restrict__ Xl,
                     __half* __restrict__ Oh) {
    extern __shared__ char sm[];
    const uint32_t sQh = smem_to_u32(sm);
    const uint32_t sQl = sQh + ATB;
    const uint32_t sSt = sQh + 2*ATB;

    const int tid = threadIdx.x, lane = tid & 31, warp = tid >> 5;
    const int bh = blockIdx.y, b = bh >> 4, h = bh & (NH-1);
    const int qt = gridDim.x - 1 - blockIdx.x;
    const int q0 = qt * 64;
    const size_t rowbase = (size_t)b * SS * LDX;
    const int colQ = h*DH, colK = 1024 + h*DH, colV = 2048 + h*DH;

    #pragma unroll
    for (int i = 0; i < 4; i++) {
        const int idx = tid + i*128;
        const int r = idx >> 3, c = idx & 7;
        const uint32_t so = (uint32_t)(r*144 + c*16);
        const size_t ga = rowbase + (size_t)(q0 + r)*LDX + colQ + c*8;
        CP_ASYNC16(sQh + so, (const char*)(Xh + ga));
        CP_ASYNC16(sQl + so, (const char*)(Xl + ga));
    }
    CP_COMMIT();

    auto load_kv = [&](int t, int s) {
        const int k0 = t * 64;
        #pragma unroll
        for (int i = 0; i < 4; i++) {
            const int idx = tid + i*128;
            const int r = idx >> 3, c = idx & 7;
            const uint32_t so = (uint32_t)s*3*ATB + (uint32_t)(r*144 + c*16);
            const size_t gk = rowbase + (size_t)(k0 + r)*LDX + colK + c*8;
            const size_t gv = rowbase + (size_t)(k0 + r)*LDX + colV + c*8;
            CP_ASYNC16(sSt + so,         (const char*)(Xh + gk));
            CP_ASYNC16(sSt + ATB + so,   (const char*)(Xl + gk));
            CP_ASYNC16(sSt + 2*ATB + so, (const char*)(Xh + gv));
        }
        CP_COMMIT();
    };
    load_kv(0, 0);

    const int g = lane >> 3, rr = lane & 7;
    const uint32_t aoff = (uint32_t)((warp*16 + (g&1)*8 + rr)*144 + (g>>1)*16);
    const uint32_t boff = (uint32_t)(((g>>1)*8 + rr)*144 + (g&1)*16);
    const uint32_t voff = (uint32_t)(((g&1)*8 + rr)*144 + (lane>>4)*16);

    float m0 = -CUDART_INF_F, m1 = -CUDART_INF_F, l0 = 0.f, l1 = 0.f;
    float o[8][4];
    #pragma unroll
    for (int j = 0; j < 8; j++)
        #pragma unroll
        for (int q = 0; q < 4; q++) o[j][q] = 0.f;

    const int r0g = q0 + warp*16 + (lane >> 2);
    const int r1g = r0g + 8;
    const int ntiles = qt + 1;

    for (int t = 0; t < ntiles; t++) {
        CP_WAIT0();
        __syncthreads();
        if (t + 1 < ntiles) load_kv(t + 1, (t + 1) & 1);

        const uint32_t sK  = sSt + (uint32_t)(t & 1)*3*ATB;
        const uint32_t sKl = sK + ATB;
        const uint32_t sV  = sK + 2*ATB;

        float s[8][4];
        #pragma unroll
        for (int j = 0; j < 8; j++)
            #pragma unroll
            for (int q = 0; q < 4; q++) s[j][q] = 0.f;

        #pragma unroll
        for (int d = 0; d < 4; d++) {
            uint32_t qh[4], ql[4];
            LDSM4(qh, sQh + aoff + d*32);
            LDSM4(ql, sQl + aoff + d*32);
            #pragma unroll
            for (int nb = 0; nb < 4; nb++) {
                uint32_t kh[4], kl[4];
                LDSM4(kh, sK  + boff + (uint32_t)(nb*16*144) + d*32);
                LDSM4(kl, sKl + boff + (uint32_t)(nb*16*144) + d*32);
                #pragma unroll
                for (int f = 0; f < 2; f++) {
                    float* dd = s[nb*2 + f];
                    MMA16816(dd, qh, kh[2*f], kh[2*f+1]);
                    MMA16816(dd, qh, kl[2*f], kl[2*f+1]);
                    MMA16816(dd, ql, kh[2*f], kh[2*f+1]);
                }
            }
        }

        const int k0 = t * 64;
        float mx0 = -CUDART_INF_F, mx1 = -CUDART_INF_F;
        #pragma unroll
        for (int j = 0; j < 8; j++) {
            if (t == qt) {
                const int c = k0 + j*8 + (lane & 3)*2;
                if (c     > r0g) s[j][0] = -CUDART_INF_F;
                if (c + 1 > r0g) s[j][1] = -CUDART_INF_F;
                if (c     > r1g) s[j][2] = -CUDART_INF_F;
                if (c + 1 > r1g) s[j][3] = -CUDART_INF_F;
            }
            mx0 = fmaxf(mx0, fmaxf(s[j][0], s[j][1]));
            mx1 = fmaxf(mx1, fmaxf(s[j][2], s[j][3]));
        }
        mx0 = fmaxf(mx0, __shfl_xor_sync(0xffffffffu, mx0, 1));
        mx0 = fmaxf(mx0, __shfl_xor_sync(0xffffffffu, mx0, 2));
        mx1 = fmaxf(mx1, __shfl_xor_sync(0xffffffffu, mx1, 1));
        mx1 = fmaxf(mx1, __shfl_xor_sync(0xffffffffu, mx1, 2));
        const float mn0 = fmaxf(m0, mx0), mn1 = fmaxf(m1, mx1);
        const float cr0 = ex2(m0 - mn0), cr1 = ex2(m1 - mn1);
        m0 = mn0; m1 = mn1;

        float sum0 = 0.f, sum1 = 0.f;
        #pragma unroll
        for (int j = 0; j < 8; j++) {
            if (j < 5) {
                s[j][0] = ex2(s[j][0] - mn0); s[j][1] = ex2(s[j][1] - mn0);
                s[j][2] = ex2(s[j][2] - mn1); s[j][3] = ex2(s[j][3] - mn1);
            } else {
                s[j][0] = fast_exp2(s[j][0] - mn0); s[j][1] = fast_exp2(s[j][1] - mn0);
                s[j][2] = fast_exp2(s[j][2] - mn1); s[j][3] = fast_exp2(s[j][3] - mn1);
            }
            sum0 += s[j][0] + s[j][1];
            sum1 += s[j][2] + s[j][3];
        }
        sum0 += __shfl_xor_sync(0xffffffffu, sum0, 1);
        sum0 += __shfl_xor_sync(0xffffffffu, sum0, 2);
        sum1 += __shfl_xor_sync(0xffffffffu, sum1, 1);
        sum1 += __shfl_xor_sync(0xffffffffu, sum1, 2);
        l0 = l0 * cr0 + sum0;
        l1 = l1 * cr1 + sum1;
        #pragma unroll
        for (int j = 0; j < 8; j++) {
            o[j][0] *= cr0; o[j][1] *= cr0;
            o[j][2] *= cr1; o[j][3] *= cr1;
        }

        #pragma unroll
        for (int kt = 0; kt < 4; kt++) {
            uint32_t ph[4];
            #pragma unroll
            for (int u = 0; u < 4; u++) {
                const int jj = 2*kt + (u >> 1);
                __half2 hh = __floats2half2_rn(s[jj][(u & 1)*2], s[jj][(u & 1)*2 + 1]);
                ph[u] = *(uint32_t*)&hh;
            }
            #pragma unroll
            for (int nb = 0; nb < 4; nb++) {
                uint32_t vh[4];
                const uint32_t va = voff + (uint32_t)(kt*16*144) + (uint32_t)(nb*32);
                LDSM4T(vh, sV + va);
                #pragma unroll
                for (int f = 0; f < 2; f++) {
                    float* dd = o[nb*2 + f];
                    MMA16816(dd, ph, vh[2*f], vh[2*f+1]);
                }
            }
        }
    }

    const float inv0 = 1.0f / l0, inv1 = 1.0f / l1;
    const size_t tok0 = (size_t)b * SS + r0g;
    const size_t tok1 = tok0 + 8;
    #pragma unroll
    for (int j = 0; j < 8; j++) {
        const int col = h*DH + j*8 + (lane & 3)*2;
        __half2 h0 = __floats2half2_rn(o[j][0]*inv0, o[j][1]*inv0);
        __half2 h1 = __floats2half2_rn(o[j][2]*inv1, o[j][3]*inv1);
        *(__half2*)(Oh + tok0*DM + col) = h0;
        *(__half2*)(Oh + tok1*DM + col) = h1;
    }
}

// ---------------- launch ----------------
extern "C" void kernel_launch(void* const* d_in, const int* in_sizes, int n_in,
                              void* d_out, int out_size) {
    const float* x   = (const float*)d_in[0];
    const int*   pos = (const int*)  d_in[1];
    const float* qw  = (const float*)d_in[2];
    const float* kw  = (const float*)d_in[3];
    const float* vw  = (const float*)d_in[4];
    const float* ow  = (const float*)d_in[5];
    const float* g1  = (const float*)d_in[6];
    const float* g2  = (const float*)d_in[7];
    const float* w1  = (const float*)d_in[8];
    const float* w2  = (const float*)d_in[9];
    const float* w3  = (const float*)d_in[10];
    float* out = (float*)d_out;

    __half *xnh, *xnl, *qkvh, *qkvl, *ath, *hnh, *swh;
    __half *wqkh, *wqkl, *vwh, *owh, *w13h, *w2h;
    float *res1;
    cudaGetSymbolAddress((void**)&xnh, g_xn_h);   cudaGetSymbolAddress((void**)&xnl, g_xn_l);
    cudaGetSymbolAddress((void**)&qkvh, g_qkv_h); cudaGetSymbolAddress((void**)&qkvl, g_qkv_l);
    cudaGetSymbolAddress((void**)&ath, g_at_h);
    cudaGetSymbolAddress((void**)&res1, g_res1);
    cudaGetSymbolAddress((void**)&hnh, g_hn_h);
    cudaGetSymbolAddress((void**)&swh, g_sw_h);
    cudaGetSymbolAddress((void**)&wqkh, g_wqk_h); cudaGetSymbolAddress((void**)&wqkl, g_wqk_l);
    cudaGetSymbolAddress((void**)&vwh, g_vw_h);
    cudaGetSymbolAddress((void**)&owh, g_ow_h);
    cudaGetSymbolAddress((void**)&w13h, g_w13_h);
    cudaGetSymbolAddress((void**)&w2h, g_w2_h);

    const int SMQ = 2 * (int)QSTG;                // 81920
    const int SMS = 2 * 256 * ROWB;               // 73728
    cudaFuncSetAttribute((const void*)gemm_qk_fp16x3,      cudaFuncAttributeMaxDynamicSharedMemorySize, SMQ);
    cudaFuncSetAttribute((const void*)gemm1_mma_fp16<0>,   cudaFuncAttributeMaxDynamicSharedMemorySize, SMS);
    cudaFuncSetAttribute((const void*)gemm1_mma_fp16<2>,   cudaFuncAttributeMaxDynamicSharedMemorySize, SMS);
    cudaFuncSetAttribute((const void*)gemm1_mma_fp16<3>,   cudaFuncAttributeMaxDynamicSharedMemorySize, SMS);
    cudaFuncSetAttribute((const void*)attn_mma_kernel,     cudaFuncAttributeMaxDynamicSharedMemorySize, ATT_SMEM);

    // 0: rope table
    rope_table_kernel<<<SS, 32>>>(pos);

    // 1: all weight conversions in one launch
    prep_weights_kernel<<<(4*Q4 + 3*W4)/256, 256>>>(
        qw, kw, vw, ow, w1, w3, w2, wqkh, wqkl, vwh, owh, w13h, w2h);

    // 2: rmsnorm(x) -> split
    rmsnorm_split_kernel<<<MTOK, 256>>>(x, g1, xnh, xnl);

    // 3: QK projection (3-term, BK=32, 2 CTA/SM) + rope + Qscale + split
    gemm_qk_fp16x3<<<dim3(2048/128, MTOK/128), 256, SMQ>>>(
        xnh, xnl, wqkh, wqkl, qkvh, qkvl, 2048, DM, LDX);

    // 4: V projection (1-term) hi-only
    gemm1_mma_fp16<3><<<dim3(DM/128, MTOK/128), 256, SMS>>>(
        xnh, vwh, nullptr, nullptr, qkvh + 2048, DM, DM, LDX);

    // 5: HMMA flash attention (3 CTAs/SM) -> fp16 hi
    attn_mma_kernel<<<dim3(SS/64, BB*NH), 128, ATT_SMEM>>>(qkvh, qkvl, ath);

    // 6: O projection (1-term) + residual(x) -> res1 fp32
    gemm1_mma_fp16<0><<<dim3(DM/128, MTOK/128), 256, SMS>>>(
        ath, owh, x, res1, nullptr, DM, DM, DM);

    // 7: rmsnorm(res1) -> hi only
    rmsnorm_h_kernel<<<MTOK, 256>>>(res1, g2, hnh);

    // 8: fused W1||W3 (1-term, interleaved) + swiglu -> sw hi
    gemm1_mma_fp16<2><<<dim3(2*DFF/128, MTOK/128), 256, SMS>>>(
        hnh, w13h, nullptr, nullptr, swh, 2*DFF, DM, DFF);

    // 9: down projection (1-term) + residual(res1) -> out
    gemm1_mma_fp16<0><<<dim3(DM/128, MTOK/128), 256, SMS>>>(
        swh, w2h, res1, out, nullptr, DM, DFF, DM);
}